// round 1
// baseline (speedup 1.0000x reference)
#include <cuda_runtime.h>
#include <cuda_bf16.h>
#include <math.h>

// Problem constants
#define SEQ   8192
#define HID   2048
#define NH    16
#define NKV   4
#define DH    128
#define TK    2048
#define SK    640
#define NQF   (TK + SK)        // 2688
#define KAI   32               // used rows of kron_a's 128 columns (S=8192 -> i<32)

// ---------------- scratch (device globals; no allocation) ----------------
__device__ float g_T[SEQ * 64];
__device__ float g_logits[SEQ];
__device__ float g_weights[SEQ];
__device__ float g_q[SEQ * NH * DH];       // normalized q  [s][h][d]
__device__ float g_k[SEQ * NKV * DH];      // normalized k
__device__ float g_v[SEQ * NKV * DH];
__device__ int   g_topk[TK];
__device__ int   g_istop[SEQ];
__device__ float g_P[NH * 32 * 32 * DH];   // sketch stage-A scratch (max = q case)
__device__ float g_qf[NQF * NH * DH];
__device__ float g_kf[NQF * NKV * DH];
__device__ float g_vf[NQF * NKV * DH];
__device__ float g_AO[NQF * NH * DH];      // attention output [q][h][d]
__device__ float g_E1[32 * 32 * HID];      // expand stage-C scratch [i][kb][hd]
__device__ float g_FULL[SEQ * HID];

// ---------------- generic tiled SGEMM: C = A(MxK) @ B(KxN) ----------------
template<int BM, int BN, int BK, int TM, int TN>
__global__ void sgemm_kernel(const float* __restrict__ A, const float* __restrict__ B,
                             float* __restrict__ C, int M, int N, int K) {
    constexpr int TX = BN / TN, TY = BM / TM, THREADS = TX * TY;
    __shared__ float As[BK][BM];
    __shared__ float Bs[BK][BN];
    const int tid = threadIdx.x;
    const int tc = (tid % TX) * TN;
    const int tr = (tid / TX) * TM;
    const int row0 = blockIdx.y * BM;
    const int col0 = blockIdx.x * BN;

    const float* Ab = A + (size_t)row0 * K;
    const float* Bb = B + col0;
    float acc[TM][TN] = {};

    constexpr int A_LOADS = BM * BK / (4 * THREADS);
    constexpr int B_LOADS = BK * BN / (4 * THREADS);

    for (int k0 = 0; k0 < K; k0 += BK) {
#pragma unroll
        for (int i = 0; i < A_LOADS; i++) {
            int idx = tid + i * THREADS;         // float4 index over BM x (BK/4)
            int ar  = idx / (BK / 4);
            int ac4 = idx % (BK / 4);
            float4 v = *reinterpret_cast<const float4*>(&Ab[(size_t)ar * K + k0 + ac4 * 4]);
            As[ac4 * 4 + 0][ar] = v.x;
            As[ac4 * 4 + 1][ar] = v.y;
            As[ac4 * 4 + 2][ar] = v.z;
            As[ac4 * 4 + 3][ar] = v.w;
        }
#pragma unroll
        for (int i = 0; i < B_LOADS; i++) {
            int idx = tid + i * THREADS;         // float4 index over BK x (BN/4)
            int br  = idx / (BN / 4);
            int bc4 = idx % (BN / 4);
            *reinterpret_cast<float4*>(&Bs[br][bc4 * 4]) =
                *reinterpret_cast<const float4*>(&Bb[(size_t)(k0 + br) * N + bc4 * 4]);
        }
        __syncthreads();
#pragma unroll
        for (int k = 0; k < BK; k++) {
            float ra[TM], rb[TN];
#pragma unroll
            for (int m = 0; m < TM; m++) ra[m] = As[k][tr + m];
#pragma unroll
            for (int n = 0; n < TN; n++) rb[n] = Bs[k][tc + n];
#pragma unroll
            for (int m = 0; m < TM; m++)
#pragma unroll
                for (int n = 0; n < TN; n++)
                    acc[m][n] += ra[m] * rb[n];
        }
        __syncthreads();
    }
#pragma unroll
    for (int m = 0; m < TM; m++)
#pragma unroll
        for (int n = 0; n < TN; n += 4) {
            float4 v = make_float4(acc[m][n], acc[m][n + 1], acc[m][n + 2], acc[m][n + 3]);
            *reinterpret_cast<float4*>(&C[(size_t)(row0 + tr + m) * N + col0 + tc + n]) = v;
        }
}

// ---------------- importance logits epilogue ----------------
__global__ void imp_logits_kernel(const float* __restrict__ T, const float* __restrict__ b1,
                                  const float* __restrict__ w2, const float* __restrict__ b2,
                                  float* __restrict__ logits, float* __restrict__ weights) {
    const float LOG_ADJ = 2.5494451709255714f;   // log(8192/640)
    int s = blockIdx.x;
    int j = threadIdx.x;  // 32
    float v = tanhf(T[s * 64 + j] + b1[j]) * w2[j]
            + tanhf(T[s * 64 + j + 32] + b1[j + 32]) * w2[j + 32];
#pragma unroll
    for (int o = 16; o > 0; o >>= 1) v += __shfl_xor_sync(0xffffffffu, v, o);
    if (j == 0) {
        float lg = v + b2[0] - LOG_ADJ;
        logits[s] = lg;
        weights[s] = 1.0f / (1.0f + expf(-lg));
    }
}

// ---------------- RMSNorm (in-place, rows of 128) ----------------
__global__ void rmsnorm_kernel(float* __restrict__ X, const float* __restrict__ w) {
    size_t row = blockIdx.x;
    int d = threadIdx.x;   // 128
    float x = X[row * DH + d];
    float ss = x * x;
#pragma unroll
    for (int o = 16; o > 0; o >>= 1) ss += __shfl_xor_sync(0xffffffffu, ss, o);
    __shared__ float sm[4];
    if ((d & 31) == 0) sm[d >> 5] = ss;
    __syncthreads();
    float tot = sm[0] + sm[1] + sm[2] + sm[3];
    X[row * DH + d] = x * rsqrtf(tot * (1.0f / 128.0f) + 1e-6f) * w[d];
}

// ---------------- top-k via single-block bitonic sort ----------------
__global__ void topk_kernel(const float* __restrict__ logits,
                            int* __restrict__ topk_list, int* __restrict__ is_topk) {
    extern __shared__ unsigned long long skeys[];
    int tid = threadIdx.x;  // 1024
    for (int i = tid; i < SEQ; i += 1024) {
        unsigned u = __float_as_uint(logits[i]);
        u = (u & 0x80000000u) ? ~u : (u | 0x80000000u);
        skeys[i] = ((unsigned long long)(~u) << 32) | (unsigned)i;  // asc key = desc value, ties asc idx
        is_topk[i] = 0;
    }
    __syncthreads();
    for (int k = 2; k <= SEQ; k <<= 1) {
        for (int j = k >> 1; j > 0; j >>= 1) {
            for (int i = tid; i < SEQ; i += 1024) {
                int ixj = i ^ j;
                if (ixj > i) {
                    bool up = ((i & k) == 0);
                    unsigned long long a = skeys[i], b = skeys[ixj];
                    if ((a > b) == up) { skeys[i] = b; skeys[ixj] = a; }
                }
            }
            __syncthreads();
        }
    }
    for (int i = tid; i < TK; i += 1024) {
        int pos = (int)(skeys[i] & 0xffffffffu);
        topk_list[i] = pos;
        is_topk[pos] = 1;
    }
}

// ---------------- sketch stage A: P[h][kb][i][d] = sum_j x[i*256+j,h,d]*w * kb[kb,j]
__global__ void sketchA_kernel(const float* __restrict__ X, int heads,
                               const float* __restrict__ weights,
                               const int* __restrict__ is_topk, int rest,
                               const float* __restrict__ kb, float* __restrict__ P) {
    int h = blockIdx.x;
    int ib = blockIdx.y;   // 0..31
    int d = threadIdx.x;   // 128
    __shared__ float kbs[32 * 256];
    for (int t = d; t < 32 * 256; t += 128) kbs[t] = kb[t];
    __shared__ float ws[256];
    for (int j = d; j < 256; j += 128) {
        int t = ib * 256 + j;
        float w = weights[t];
        if (rest && is_topk[t]) w = 0.0f;
        ws[j] = w;
    }
    __syncthreads();
    float acc[32] = {};
    for (int j = 0; j < 256; j++) {
        float xv = X[((size_t)(ib * 256 + j) * heads + h) * DH + d] * ws[j];
#pragma unroll
        for (int kbo = 0; kbo < 32; kbo++) acc[kbo] += xv * kbs[kbo * 256 + j];
    }
#pragma unroll
    for (int kbo = 0; kbo < 32; kbo++)
        P[(((size_t)h * 32 + kbo) * 32 + ib) * DH + d] = acc[kbo];
}

// ---------------- sketch stage B: dst[2048 + kb*20+ka][h][d] = scale * sum_i P * ka[ka,i]
__global__ void sketchB_kernel(const float* __restrict__ P, int heads,
                               const float* __restrict__ ka,
                               const float* __restrict__ scale_p,
                               float* __restrict__ dst) {
    int h = blockIdx.x;
    int kbo = blockIdx.y;
    int d = threadIdx.x;   // 128
    __shared__ float kas[20 * 32];
    for (int t = d; t < 20 * 32; t += 128) kas[t] = ka[(t / 32) * DH + (t % 32)];
    __syncthreads();
    float p[32];
#pragma unroll
    for (int i = 0; i < 32; i++) p[i] = P[(((size_t)h * 32 + kbo) * 32 + i) * DH + d];
    float scale = scale_p[0];
#pragma unroll
    for (int kao = 0; kao < 20; kao++) {
        float acc = 0.f;
#pragma unroll
        for (int i = 0; i < 32; i++) acc += p[i] * kas[kao * 32 + i];
        int s = TK + kbo * 20 + kao;
        dst[((size_t)s * heads + h) * DH + d] = acc * scale;
    }
}

// ---------------- gather + RoPE for top-k rows ----------------
__global__ void gather_rope_kernel(const float* __restrict__ q, const float* __restrict__ k,
                                   const float* __restrict__ v,
                                   const float* __restrict__ cosb, const float* __restrict__ sinb,
                                   const int* __restrict__ topk_list,
                                   float* __restrict__ qf, float* __restrict__ kf,
                                   float* __restrict__ vf) {
    int j = blockIdx.x;    // 0..2047
    int hy = blockIdx.y;   // 0..23  (16 q heads, 4 k heads, 4 v heads)
    int d = threadIdx.x;
    int pos = topk_list[j];
    float c = cosb[(size_t)pos * DH + d];
    float s = sinb[(size_t)pos * DH + d];
    if (hy < 16) {
        const float* src = q + ((size_t)pos * NH + hy) * DH;
        float x = src[d];
        float r = (d < 64) ? -src[d + 64] : src[d - 64];
        qf[((size_t)j * NH + hy) * DH + d] = x * c + r * s;
    } else if (hy < 20) {
        int h = hy - 16;
        const float* src = k + ((size_t)pos * NKV + h) * DH;
        float x = src[d];
        float r = (d < 64) ? -src[d + 64] : src[d - 64];
        kf[((size_t)j * NKV + h) * DH + d] = x * c + r * s;
    } else {
        int h = hy - 20;
        vf[((size_t)j * NKV + h) * DH + d] = v[((size_t)pos * NKV + h) * DH + d];
    }
}

// ---------------- flash attention: 2688 q x 2688 k, D=128, 16 heads (GQA 4:1) ------
#define FA_SMEM ((128*65 + 128*65 + 64*128 + 64*65 + 192) * 4)
__global__ void fa_kernel(const float* __restrict__ qf, const float* __restrict__ kf,
                          const float* __restrict__ vf, float* __restrict__ AO) {
    extern __shared__ float smf[];
    float* Qs = smf;                 // [128][65]  (d-major, padded)
    float* Ks = Qs + 128 * 65;       // [128][65]
    float* Vs = Ks + 128 * 65;       // [64][128]
    float* Ss = Vs + 64 * 128;       // [64][65]
    float* mrow = Ss + 64 * 65;
    float* lrow = mrow + 64;
    float* crow = lrow + 64;

    const int h = blockIdx.y;
    const int kvh = h >> 2;
    const int q0 = blockIdx.x * 64;
    const int tid = threadIdx.x;       // 256
    const int tc = tid % 16, tr = tid / 16;
    const float scale = 0.08838834764831843f;  // 1/sqrt(128)

    {
        int d4 = tid % 32, qi0 = tid / 32;
        for (int qi = qi0; qi < 64; qi += 8) {
            float4 vq = *reinterpret_cast<const float4*>(
                &qf[(((size_t)(q0 + qi)) * NH + h) * DH + d4 * 4]);
            Qs[(d4 * 4 + 0) * 65 + qi] = vq.x;
            Qs[(d4 * 4 + 1) * 65 + qi] = vq.y;
            Qs[(d4 * 4 + 2) * 65 + qi] = vq.z;
            Qs[(d4 * 4 + 3) * 65 + qi] = vq.w;
        }
    }
    if (tid < 64) { mrow[tid] = -3.0e38f; lrow[tid] = 0.f; }

    float o[4][8] = {};
    __syncthreads();

    for (int kt = 0; kt < NQF / 64; kt++) {
        int k0 = kt * 64;
        {
            int d4 = tid % 32, ki0 = tid / 32;
            for (int ki = ki0; ki < 64; ki += 8) {
                float4 vk = *reinterpret_cast<const float4*>(
                    &kf[(((size_t)(k0 + ki)) * NKV + kvh) * DH + d4 * 4]);
                Ks[(d4 * 4 + 0) * 65 + ki] = vk.x;
                Ks[(d4 * 4 + 1) * 65 + ki] = vk.y;
                Ks[(d4 * 4 + 2) * 65 + ki] = vk.z;
                Ks[(d4 * 4 + 3) * 65 + ki] = vk.w;
                float4 vv = *reinterpret_cast<const float4*>(
                    &vf[(((size_t)(k0 + ki)) * NKV + kvh) * DH + d4 * 4]);
                *reinterpret_cast<float4*>(&Vs[ki * 128 + d4 * 4]) = vv;
            }
        }
        __syncthreads();

        // S = Q K^T (4x4 micro-tile)
        float s4[4][4] = {};
        for (int dd = 0; dd < 128; dd++) {
            float ra[4], rb[4];
#pragma unroll
            for (int i = 0; i < 4; i++) ra[i] = Qs[dd * 65 + tr * 4 + i];
#pragma unroll
            for (int jj = 0; jj < 4; jj++) rb[jj] = Ks[dd * 65 + tc * 4 + jj];
#pragma unroll
            for (int i = 0; i < 4; i++)
#pragma unroll
                for (int jj = 0; jj < 4; jj++) s4[i][jj] += ra[i] * rb[jj];
        }
#pragma unroll
        for (int i = 0; i < 4; i++)
#pragma unroll
            for (int jj = 0; jj < 4; jj++)
                Ss[(tr * 4 + i) * 65 + tc * 4 + jj] = s4[i][jj] * scale;
        __syncthreads();

        // online softmax per row
        if (tid < 64) {
            float mold = mrow[tid];
            float mx = mold;
            for (int jj = 0; jj < 64; jj++) mx = fmaxf(mx, Ss[tid * 65 + jj]);
            float corr = __expf(mold - mx);
            float sum = 0.f;
            for (int jj = 0; jj < 64; jj++) {
                float p = __expf(Ss[tid * 65 + jj] - mx);
                Ss[tid * 65 + jj] = p;
                sum += p;
            }
            mrow[tid] = mx;
            lrow[tid] = lrow[tid] * corr + sum;
            crow[tid] = corr;
        }
        __syncthreads();

        // rescale O, accumulate P @ V
#pragma unroll
        for (int i = 0; i < 4; i++) {
            float c = crow[tr * 4 + i];
#pragma unroll
            for (int jj = 0; jj < 8; jj++) o[i][jj] *= c;
        }
        for (int kk = 0; kk < 64; kk++) {
            float rp[4];
#pragma unroll
            for (int i = 0; i < 4; i++) rp[i] = Ss[(tr * 4 + i) * 65 + kk];
            float4 v0 = *reinterpret_cast<const float4*>(&Vs[kk * 128 + tc * 8]);
            float4 v1 = *reinterpret_cast<const float4*>(&Vs[kk * 128 + tc * 8 + 4]);
#pragma unroll
            for (int i = 0; i < 4; i++) {
                o[i][0] += rp[i] * v0.x; o[i][1] += rp[i] * v0.y;
                o[i][2] += rp[i] * v0.z; o[i][3] += rp[i] * v0.w;
                o[i][4] += rp[i] * v1.x; o[i][5] += rp[i] * v1.y;
                o[i][6] += rp[i] * v1.z; o[i][7] += rp[i] * v1.w;
            }
        }
        __syncthreads();
    }

#pragma unroll
    for (int i = 0; i < 4; i++) {
        float inv = 1.0f / lrow[tr * 4 + i];
        size_t qrow = q0 + tr * 4 + i;
        float4 w0 = make_float4(o[i][0] * inv, o[i][1] * inv, o[i][2] * inv, o[i][3] * inv);
        float4 w1 = make_float4(o[i][4] * inv, o[i][5] * inv, o[i][6] * inv, o[i][7] * inv);
        *reinterpret_cast<float4*>(&AO[(qrow * NH + h) * DH + tc * 8]) = w0;
        *reinterpret_cast<float4*>(&AO[(qrow * NH + h) * DH + tc * 8 + 4]) = w1;
    }
}

// ---------------- expand stage C: E1[i][kb][hd] = sum_ka AO_sk[kb*20+ka][hd]*ka[ka,i]
__global__ void expandC_kernel(const float* __restrict__ AO, const float* __restrict__ ka,
                               float* __restrict__ E1) {
    int i = blockIdx.y;                               // 0..31
    int hd = blockIdx.x * 256 + threadIdx.x;          // 0..2047
    __shared__ float kav[20];
    if (threadIdx.x < 20) kav[threadIdx.x] = ka[threadIdx.x * DH + i];
    __syncthreads();
    for (int kbo = 0; kbo < 32; kbo++) {
        float acc = 0.f;
#pragma unroll
        for (int kao = 0; kao < 20; kao++)
            acc += AO[((size_t)(TK + kbo * 20 + kao)) * HID + hd] * kav[kao];
        E1[((size_t)i * 32 + kbo) * HID + hd] = acc;
    }
}

// ---------------- expand stage D: FULL[i*256+j][hd] = sum_kb E1[i][kb][hd]*kb[kb,j]
__global__ void expandD_kernel(const float* __restrict__ E1, const float* __restrict__ kb,
                               float* __restrict__ FULL) {
    int i = blockIdx.y;                               // 0..31
    int hd = blockIdx.x * 128 + threadIdx.x;          // 0..2047
    __shared__ float kbs[32 * 256];
    for (int t = threadIdx.x; t < 32 * 256; t += 128) kbs[t] = kb[t];
    float e[32];
#pragma unroll
    for (int kbo = 0; kbo < 32; kbo++) e[kbo] = E1[((size_t)i * 32 + kbo) * HID + hd];
    __syncthreads();
    for (int j = 0; j < 256; j++) {
        float acc = 0.f;
#pragma unroll
        for (int kbo = 0; kbo < 32; kbo++) acc += e[kbo] * kbs[kbo * 256 + j];
        FULL[((size_t)(i * 256 + j)) * HID + hd] = acc;
    }
}

// ---------------- scatter deterministic rows over the expansion ----------------
__global__ void scatter_det_kernel(const float* __restrict__ AO, const int* __restrict__ topk_list,
                                   float* __restrict__ FULL) {
    int j = blockIdx.x;    // 0..2047
    int pos = topk_list[j];
    for (int t = threadIdx.x; t < HID; t += blockDim.x)
        FULL[(size_t)pos * HID + t] = AO[(size_t)j * HID + t];
}

// ---------------- host launcher ----------------
extern "C" void kernel_launch(void* const* d_in, const int* in_sizes, int n_in,
                              void* d_out, int out_size) {
    const float* hs    = (const float*)d_in[0];
    const float* cosb  = (const float*)d_in[1];
    const float* sinb  = (const float*)d_in[2];
    const float* wq    = (const float*)d_in[3];
    const float* wk    = (const float*)d_in[4];
    const float* wv    = (const float*)d_in[5];
    const float* wo    = (const float*)d_in[6];
    const float* qnw   = (const float*)d_in[7];
    const float* knw   = (const float*)d_in[8];
    const float* w1    = (const float*)d_in[9];
    const float* b1    = (const float*)d_in[10];
    const float* w2    = (const float*)d_in[11];
    const float* b2    = (const float*)d_in[12];
    const float* ka    = (const float*)d_in[13];
    const float* kb    = (const float*)d_in[14];
    const float* sscale= (const float*)d_in[15];
    float* out = (float*)d_out;

    float *pT, *pLg, *pW, *pQ, *pK, *pV, *pP, *pQF, *pKF, *pVF, *pAO, *pE1, *pFULL;
    int *pTop, *pIs;
    cudaGetSymbolAddress((void**)&pT, g_T);
    cudaGetSymbolAddress((void**)&pLg, g_logits);
    cudaGetSymbolAddress((void**)&pW, g_weights);
    cudaGetSymbolAddress((void**)&pQ, g_q);
    cudaGetSymbolAddress((void**)&pK, g_k);
    cudaGetSymbolAddress((void**)&pV, g_v);
    cudaGetSymbolAddress((void**)&pP, g_P);
    cudaGetSymbolAddress((void**)&pQF, g_qf);
    cudaGetSymbolAddress((void**)&pKF, g_kf);
    cudaGetSymbolAddress((void**)&pVF, g_vf);
    cudaGetSymbolAddress((void**)&pAO, g_AO);
    cudaGetSymbolAddress((void**)&pE1, g_E1);
    cudaGetSymbolAddress((void**)&pFULL, g_FULL);
    cudaGetSymbolAddress((void**)&pTop, g_topk);
    cudaGetSymbolAddress((void**)&pIs, g_istop);

    cudaFuncSetAttribute(topk_kernel, cudaFuncAttributeMaxDynamicSharedMemorySize, SEQ * 8);
    cudaFuncSetAttribute(fa_kernel, cudaFuncAttributeMaxDynamicSharedMemorySize, FA_SMEM);

    // 1) importance MLP first GEMM: T = hs @ w1   (8192x2048 @ 2048x64)
    sgemm_kernel<128, 64, 16, 8, 4><<<dim3(1, SEQ / 128), 256>>>(hs, w1, pT, SEQ, 64, HID);
    // 2) logits + weights
    imp_logits_kernel<<<SEQ, 32>>>(pT, b1, w2, b2, pLg, pW);
    // 3-5) QKV projections
    sgemm_kernel<128, 128, 16, 8, 8><<<dim3(HID / 128, SEQ / 128), 256>>>(hs, wq, pQ, SEQ, HID, HID);
    sgemm_kernel<128, 128, 16, 8, 8><<<dim3(512 / 128, SEQ / 128), 256>>>(hs, wk, pK, SEQ, 512, HID);
    sgemm_kernel<128, 128, 16, 8, 8><<<dim3(512 / 128, SEQ / 128), 256>>>(hs, wv, pV, SEQ, 512, HID);
    // 6-7) RMSNorm q, k
    rmsnorm_kernel<<<SEQ * NH, DH>>>(pQ, qnw);
    rmsnorm_kernel<<<SEQ * NKV, DH>>>(pK, knw);
    // 8) top-k selection
    topk_kernel<<<1, 1024, SEQ * 8>>>(pLg, pTop, pIs);
    // 9-14) sketches (q uses full weights; k,v use rest weights)
    sketchA_kernel<<<dim3(NH, 32), DH>>>(pQ, NH, pW, pIs, 0, kb, pP);
    sketchB_kernel<<<dim3(NH, 32), DH>>>(pP, NH, ka, sscale, pQF);
    sketchA_kernel<<<dim3(NKV, 32), DH>>>(pK, NKV, pW, pIs, 1, kb, pP);
    sketchB_kernel<<<dim3(NKV, 32), DH>>>(pP, NKV, ka, sscale, pKF);
    sketchA_kernel<<<dim3(NKV, 32), DH>>>(pV, NKV, pW, pIs, 1, kb, pP);
    sketchB_kernel<<<dim3(NKV, 32), DH>>>(pP, NKV, ka, sscale, pVF);
    // 15) gather top-k rows + RoPE
    gather_rope_kernel<<<dim3(TK, 24), DH>>>(pQ, pK, pV, cosb, sinb, pTop, pQF, pKF, pVF);
    // 16) attention
    fa_kernel<<<dim3(NQF / 64, NH), 256, FA_SMEM>>>(pQF, pKF, pVF, pAO);
    // 17-18) expand sketch part of attention output to all positions
    expandC_kernel<<<dim3(HID / 256, 32), 256>>>(pAO, ka, pE1);
    expandD_kernel<<<dim3(HID / 128, 32), DH>>>(pE1, kb, pFULL);
    // 19) overwrite top-k positions with deterministic attention output
    scatter_det_kernel<<<TK, 256>>>(pAO, pTop, pFULL);
    // 20) output projection
    sgemm_kernel<128, 128, 16, 8, 8><<<dim3(HID / 128, SEQ / 128), 256>>>(pFULL, wo, out, SEQ, HID, HID);
}

// round 3
// speedup vs baseline: 1.4061x; 1.4061x over previous
#include <cuda_runtime.h>
#include <cuda_bf16.h>
#include <math.h>
#include <cstdint>

// Problem constants
#define SEQ   8192
#define HID   2048
#define NH    16
#define NKV   4
#define DH    128
#define TK    2048
#define SK    640
#define NQF   (TK + SK)        // 2688

// ---------------- scratch (device globals; no allocation) ----------------
__device__ float g_T[SEQ * 64];
__device__ float g_logits[SEQ];
__device__ float g_weights[SEQ];
__device__ float g_q[SEQ * NH * DH];       // normalized q  [s][h][d]
__device__ float g_k[SEQ * NKV * DH];      // normalized k
__device__ float g_v[SEQ * NKV * DH];
__device__ int   g_topk[TK];
__device__ int   g_istop[SEQ];
__device__ float g_P[NH * 32 * 32 * DH];   // sketch stage-A scratch
__device__ float g_qf[NQF * NH * DH];
__device__ float g_kf[NQF * NKV * DH];
__device__ float g_vf[NQF * NKV * DH];
__device__ float g_AO[NQF * NH * DH];      // attention output [q][h][d]
__device__ float g_E1[32 * 32 * HID];      // expand stage-C scratch [i][kb][hd]
__device__ float g_FULL[SEQ * HID];
__device__ float g_BT[HID * HID];          // transposed weight scratch [N][K]

// ======================= tf32 mma.sync GEMM =======================
__device__ __forceinline__ float tf32f(float x) {
    uint32_t r; asm("cvt.rna.tf32.f32 %0, %1;" : "=r"(r) : "f"(x));
    return __uint_as_float(r);
}

__device__ __forceinline__ void mma_tf32(float* c, const uint32_t* a, const uint32_t* b) {
    asm volatile("mma.sync.aligned.m16n8k8.row.col.f32.tf32.tf32.f32 "
        "{%0,%1,%2,%3}, {%4,%5,%6,%7}, {%8,%9}, {%0,%1,%2,%3};"
        : "+f"(c[0]), "+f"(c[1]), "+f"(c[2]), "+f"(c[3])
        : "r"(a[0]), "r"(a[1]), "r"(a[2]), "r"(a[3]), "r"(b[0]), "r"(b[1]));
}

// fragment-major staging stores
__device__ __forceinline__ void frag_store_A(float* sAbuf, int r, int c4, float4 v) {
    int k8 = c4 >> 1, khi = c4 & 1;
    int mf = r >> 4, gid = r & 7, mhi = (r >> 3) & 1;
    int base = ((k8 * 8 + mf) * 32 + gid * 4) * 4 + khi * 2 + mhi;
    sAbuf[base + 0]  = tf32f(v.x);
    sAbuf[base + 4]  = tf32f(v.y);
    sAbuf[base + 8]  = tf32f(v.z);
    sAbuf[base + 12] = tf32f(v.w);
}
__device__ __forceinline__ void frag_store_B(float* sBbuf, int r, int c4, float4 v) {
    int k8 = c4 >> 1, half = c4 & 1;
    int nf = r >> 3, gid = r & 7;
    int base = ((k8 * 16 + nf) * 32 + gid * 4) * 2 + half;
    sBbuf[base + 0] = tf32f(v.x);
    sBbuf[base + 2] = tf32f(v.y);
    sBbuf[base + 4] = tf32f(v.z);
    sBbuf[base + 6] = tf32f(v.w);
}

// C[M,N] = A[M,K] @ BT[N,K]^T via m16n8k8 tf32 mma.sync.
// CTA tile 128x128, BK=16, 256 threads (8 warps, 2x4), warp tile 64x32.
__global__ void __launch_bounds__(256) mma_gemm_kernel(
    const float* __restrict__ A, const float* __restrict__ BT,
    float* __restrict__ C, int M, int N, int K)
{
    __shared__ float sA[2][2048];   // [buf][(k8*8+mf)*32+lane -> float4]
    __shared__ float sB[2][2048];   // [buf][(k8*16+nf)*32+lane -> float2]

    const int tid = threadIdx.x;
    const int lane = tid & 31;
    const int wid = tid >> 5;
    const int wm = wid >> 2;        // 0..1
    const int wn = wid & 3;         // 0..3
    const int row0 = blockIdx.y * 128;
    const int col0 = blockIdx.x * 128;

    const float* Ab = A + (size_t)row0 * K;
    const float* Bb = BT + (size_t)col0 * K;

    // loader coordinates (512 float4 per tile side, 2 per thread)
    const int r0 = tid >> 2,          c40 = tid & 3;
    const int r1 = (tid + 256) >> 2,  c41 = c40;

    float acc[4][4][4] = {};
    float4 pa0, pa1, pb0, pb1;

    // chunk 0
    pa0 = *reinterpret_cast<const float4*>(Ab + (size_t)r0 * K + c40 * 4);
    pa1 = *reinterpret_cast<const float4*>(Ab + (size_t)r1 * K + c41 * 4);
    pb0 = *reinterpret_cast<const float4*>(Bb + (size_t)r0 * K + c40 * 4);
    pb1 = *reinterpret_cast<const float4*>(Bb + (size_t)r1 * K + c41 * 4);
    frag_store_A(sA[0], r0, c40, pa0);
    frag_store_A(sA[0], r1, c41, pa1);
    frag_store_B(sB[0], r0, c40, pb0);
    frag_store_B(sB[0], r1, c41, pb1);
    __syncthreads();

    const int NC = K >> 4;
    for (int c = 0; c < NC; c++) {
        const int buf = c & 1;
        if (c + 1 < NC) {
            const float* An = Ab + (c + 1) * 16;
            const float* Bn = Bb + (c + 1) * 16;
            pa0 = *reinterpret_cast<const float4*>(An + (size_t)r0 * K + c40 * 4);
            pa1 = *reinterpret_cast<const float4*>(An + (size_t)r1 * K + c41 * 4);
            pb0 = *reinterpret_cast<const float4*>(Bn + (size_t)r0 * K + c40 * 4);
            pb1 = *reinterpret_cast<const float4*>(Bn + (size_t)r1 * K + c41 * 4);
        }
        const float4* A4 = reinterpret_cast<const float4*>(sA[buf]);
        const float2* B2 = reinterpret_cast<const float2*>(sB[buf]);
#pragma unroll
        for (int k8 = 0; k8 < 2; k8++) {
            float4 af[4];
            float2 bf[4];
#pragma unroll
            for (int mf = 0; mf < 4; mf++)
                af[mf] = A4[(k8 * 8 + wm * 4 + mf) * 32 + lane];
#pragma unroll
            for (int nf = 0; nf < 4; nf++)
                bf[nf] = B2[(k8 * 16 + wn * 4 + nf) * 32 + lane];
#pragma unroll
            for (int mf = 0; mf < 4; mf++)
#pragma unroll
                for (int nf = 0; nf < 4; nf++)
                    mma_tf32(acc[mf][nf],
                             reinterpret_cast<const uint32_t*>(&af[mf]),
                             reinterpret_cast<const uint32_t*>(&bf[nf]));
        }
        if (c + 1 < NC) {
            const int nb = (c + 1) & 1;
            frag_store_A(sA[nb], r0, c40, pa0);
            frag_store_A(sA[nb], r1, c41, pa1);
            frag_store_B(sB[nb], r0, c40, pb0);
            frag_store_B(sB[nb], r1, c41, pb1);
        }
        __syncthreads();
    }

    // epilogue
    const int gid = lane >> 2, tig = lane & 3;
#pragma unroll
    for (int mf = 0; mf < 4; mf++) {
#pragma unroll
        for (int nf = 0; nf < 4; nf++) {
            int m = row0 + wm * 64 + mf * 16 + gid;
            int n = col0 + wn * 32 + nf * 8 + tig * 2;
            float2 lo = make_float2(acc[mf][nf][0], acc[mf][nf][1]);
            float2 hi = make_float2(acc[mf][nf][2], acc[mf][nf][3]);
            *reinterpret_cast<float2*>(&C[(size_t)m * N + n]) = lo;
            *reinterpret_cast<float2*>(&C[(size_t)(m + 8) * N + n]) = hi;
        }
    }
}

// ---------------- transpose: in[R][C] -> out[C][R] ----------------
__global__ void transpose_kernel(const float* __restrict__ in, float* __restrict__ out,
                                 int R, int C) {
    __shared__ float t[32][33];
    int c0 = blockIdx.x * 32, r0 = blockIdx.y * 32;
    int x = threadIdx.x, y = threadIdx.y;  // 32 x 8
#pragma unroll
    for (int i = y; i < 32; i += 8) t[i][x] = in[(size_t)(r0 + i) * C + c0 + x];
    __syncthreads();
#pragma unroll
    for (int i = y; i < 32; i += 8) out[(size_t)(c0 + i) * R + r0 + x] = t[x][i];
}

// ---------------- generic tiled SGEMM (fp32; importance MLP only) -----------
template<int BM, int BN, int BK, int TM, int TN>
__global__ void sgemm_kernel(const float* __restrict__ A, const float* __restrict__ B,
                             float* __restrict__ C, int M, int N, int K) {
    constexpr int TX = BN / TN, TY = BM / TM, THREADS = TX * TY;
    __shared__ float As[BK][BM];
    __shared__ float Bs[BK][BN];
    const int tid = threadIdx.x;
    const int tc = (tid % TX) * TN;
    const int tr = (tid / TX) * TM;
    const int row0 = blockIdx.y * BM;
    const int col0 = blockIdx.x * BN;

    const float* Ab = A + (size_t)row0 * K;
    const float* Bb = B + col0;
    float acc[TM][TN] = {};

    constexpr int A_LOADS = BM * BK / (4 * THREADS);
    constexpr int B_LOADS = BK * BN / (4 * THREADS);

    for (int k0 = 0; k0 < K; k0 += BK) {
#pragma unroll
        for (int i = 0; i < A_LOADS; i++) {
            int idx = tid + i * THREADS;
            int ar  = idx / (BK / 4);
            int ac4 = idx % (BK / 4);
            float4 v = *reinterpret_cast<const float4*>(&Ab[(size_t)ar * K + k0 + ac4 * 4]);
            As[ac4 * 4 + 0][ar] = v.x;
            As[ac4 * 4 + 1][ar] = v.y;
            As[ac4 * 4 + 2][ar] = v.z;
            As[ac4 * 4 + 3][ar] = v.w;
        }
#pragma unroll
        for (int i = 0; i < B_LOADS; i++) {
            int idx = tid + i * THREADS;
            int br  = idx / (BN / 4);
            int bc4 = idx % (BN / 4);
            *reinterpret_cast<float4*>(&Bs[br][bc4 * 4]) =
                *reinterpret_cast<const float4*>(&Bb[(size_t)(k0 + br) * N + bc4 * 4]);
        }
        __syncthreads();
#pragma unroll
        for (int k = 0; k < BK; k++) {
            float ra[TM], rb[TN];
#pragma unroll
            for (int m = 0; m < TM; m++) ra[m] = As[k][tr + m];
#pragma unroll
            for (int n = 0; n < TN; n++) rb[n] = Bs[k][tc + n];
#pragma unroll
            for (int m = 0; m < TM; m++)
#pragma unroll
                for (int n = 0; n < TN; n++)
                    acc[m][n] += ra[m] * rb[n];
        }
        __syncthreads();
    }
#pragma unroll
    for (int m = 0; m < TM; m++)
#pragma unroll
        for (int n = 0; n < TN; n += 4) {
            float4 v = make_float4(acc[m][n], acc[m][n + 1], acc[m][n + 2], acc[m][n + 3]);
            *reinterpret_cast<float4*>(&C[(size_t)(row0 + tr + m) * N + col0 + tc + n]) = v;
        }
}

// ---------------- importance logits epilogue ----------------
__global__ void imp_logits_kernel(const float* __restrict__ T, const float* __restrict__ b1,
                                  const float* __restrict__ w2, const float* __restrict__ b2,
                                  float* __restrict__ logits, float* __restrict__ weights) {
    const float LOG_ADJ = 2.5494451709255714f;   // log(8192/640)
    int s = blockIdx.x;
    int j = threadIdx.x;  // 32
    float v = tanhf(T[s * 64 + j] + b1[j]) * w2[j]
            + tanhf(T[s * 64 + j + 32] + b1[j + 32]) * w2[j + 32];
#pragma unroll
    for (int o = 16; o > 0; o >>= 1) v += __shfl_xor_sync(0xffffffffu, v, o);
    if (j == 0) {
        float lg = v + b2[0] - LOG_ADJ;
        logits[s] = lg;
        weights[s] = 1.0f / (1.0f + expf(-lg));
    }
}

// ---------------- RMSNorm (in-place, rows of 128) ----------------
__global__ void rmsnorm_kernel(float* __restrict__ X, const float* __restrict__ w) {
    size_t row = blockIdx.x;
    int d = threadIdx.x;   // 128
    float x = X[row * DH + d];
    float ss = x * x;
#pragma unroll
    for (int o = 16; o > 0; o >>= 1) ss += __shfl_xor_sync(0xffffffffu, ss, o);
    __shared__ float sm[4];
    if ((d & 31) == 0) sm[d >> 5] = ss;
    __syncthreads();
    float tot = sm[0] + sm[1] + sm[2] + sm[3];
    X[row * DH + d] = x * rsqrtf(tot * (1.0f / 128.0f) + 1e-6f) * w[d];
}

// ---------------- top-k via single-block bitonic sort ----------------
__global__ void topk_kernel(const float* __restrict__ logits,
                            int* __restrict__ topk_list, int* __restrict__ is_topk) {
    extern __shared__ unsigned long long skeys[];
    int tid = threadIdx.x;  // 1024
    for (int i = tid; i < SEQ; i += 1024) {
        unsigned u = __float_as_uint(logits[i]);
        u = (u & 0x80000000u) ? ~u : (u | 0x80000000u);
        skeys[i] = ((unsigned long long)(~u) << 32) | (unsigned)i;
        is_topk[i] = 0;
    }
    __syncthreads();
    for (int k = 2; k <= SEQ; k <<= 1) {
        for (int j = k >> 1; j > 0; j >>= 1) {
            for (int i = tid; i < SEQ; i += 1024) {
                int ixj = i ^ j;
                if (ixj > i) {
                    bool up = ((i & k) == 0);
                    unsigned long long a = skeys[i], b = skeys[ixj];
                    if ((a > b) == up) { skeys[i] = b; skeys[ixj] = a; }
                }
            }
            __syncthreads();
        }
    }
    for (int i = tid; i < TK; i += 1024) {
        int pos = (int)(skeys[i] & 0xffffffffu);
        topk_list[i] = pos;
        is_topk[pos] = 1;
    }
}

// ---------------- sketch stage A ----------------
__global__ void sketchA_kernel(const float* __restrict__ X, int heads,
                               const float* __restrict__ weights,
                               const int* __restrict__ is_topk, int rest,
                               const float* __restrict__ kb, float* __restrict__ P) {
    int h = blockIdx.x;
    int ib = blockIdx.y;   // 0..31
    int d = threadIdx.x;   // 128
    __shared__ float kbs[32 * 256];
    for (int t = d; t < 32 * 256; t += 128) kbs[t] = kb[t];
    __shared__ float ws[256];
    for (int j = d; j < 256; j += 128) {
        int t = ib * 256 + j;
        float w = weights[t];
        if (rest && is_topk[t]) w = 0.0f;
        ws[j] = w;
    }
    __syncthreads();
    float acc[32] = {};
    for (int j = 0; j < 256; j++) {
        float xv = X[((size_t)(ib * 256 + j) * heads + h) * DH + d] * ws[j];
#pragma unroll
        for (int kbo = 0; kbo < 32; kbo++) acc[kbo] += xv * kbs[kbo * 256 + j];
    }
#pragma unroll
    for (int kbo = 0; kbo < 32; kbo++)
        P[(((size_t)h * 32 + kbo) * 32 + ib) * DH + d] = acc[kbo];
}

// ---------------- sketch stage B ----------------
__global__ void sketchB_kernel(const float* __restrict__ P, int heads,
                               const float* __restrict__ ka,
                               const float* __restrict__ scale_p,
                               float* __restrict__ dst) {
    int h = blockIdx.x;
    int kbo = blockIdx.y;
    int d = threadIdx.x;   // 128
    __shared__ float kas[20 * 32];
    for (int t = d; t < 20 * 32; t += 128) kas[t] = ka[(t / 32) * DH + (t % 32)];
    __syncthreads();
    float p[32];
#pragma unroll
    for (int i = 0; i < 32; i++) p[i] = P[(((size_t)h * 32 + kbo) * 32 + i) * DH + d];
    float scale = scale_p[0];
#pragma unroll
    for (int kao = 0; kao < 20; kao++) {
        float acc = 0.f;
#pragma unroll
        for (int i = 0; i < 32; i++) acc += p[i] * kas[kao * 32 + i];
        int s = TK + kbo * 20 + kao;
        dst[((size_t)s * heads + h) * DH + d] = acc * scale;
    }
}

// ---------------- gather + RoPE for top-k rows ----------------
__global__ void gather_rope_kernel(const float* __restrict__ q, const float* __restrict__ k,
                                   const float* __restrict__ v,
                                   const float* __restrict__ cosb, const float* __restrict__ sinb,
                                   const int* __restrict__ topk_list,
                                   float* __restrict__ qf, float* __restrict__ kf,
                                   float* __restrict__ vf) {
    int j = blockIdx.x;    // 0..2047
    int hy = blockIdx.y;   // 0..23
    int d = threadIdx.x;
    int pos = topk_list[j];
    float c = cosb[(size_t)pos * DH + d];
    float s = sinb[(size_t)pos * DH + d];
    if (hy < 16) {
        const float* src = q + ((size_t)pos * NH + hy) * DH;
        float x = src[d];
        float r = (d < 64) ? -src[d + 64] : src[d - 64];
        qf[((size_t)j * NH + hy) * DH + d] = x * c + r * s;
    } else if (hy < 20) {
        int h = hy - 16;
        const float* src = k + ((size_t)pos * NKV + h) * DH;
        float x = src[d];
        float r = (d < 64) ? -src[d + 64] : src[d - 64];
        kf[((size_t)j * NKV + h) * DH + d] = x * c + r * s;
    } else {
        int h = hy - 20;
        vf[((size_t)j * NKV + h) * DH + d] = v[((size_t)pos * NKV + h) * DH + d];
    }
}

// ---------------- flash attention ----------------
#define FA_SMEM ((128*65 + 128*65 + 64*128 + 64*65 + 192) * 4)
__global__ void fa_kernel(const float* __restrict__ qf, const float* __restrict__ kf,
                          const float* __restrict__ vf, float* __restrict__ AO) {
    extern __shared__ float smf[];
    float* Qs = smf;                 // [128][65]
    float* Ks = Qs + 128 * 65;       // [128][65]
    float* Vs = Ks + 128 * 65;       // [64][128]
    float* Ss = Vs + 64 * 128;       // [64][65]
    float* mrow = Ss + 64 * 65;
    float* lrow = mrow + 64;
    float* crow = lrow + 64;

    const int h = blockIdx.y;
    const int kvh = h >> 2;
    const int q0 = blockIdx.x * 64;
    const int tid = threadIdx.x;       // 256
    const int tc = tid % 16, tr = tid / 16;
    const float scale = 0.08838834764831843f;

    {
        int d4 = tid % 32, qi0 = tid / 32;
        for (int qi = qi0; qi < 64; qi += 8) {
            float4 vq = *reinterpret_cast<const float4*>(
                &qf[(((size_t)(q0 + qi)) * NH + h) * DH + d4 * 4]);
            Qs[(d4 * 4 + 0) * 65 + qi] = vq.x;
            Qs[(d4 * 4 + 1) * 65 + qi] = vq.y;
            Qs[(d4 * 4 + 2) * 65 + qi] = vq.z;
            Qs[(d4 * 4 + 3) * 65 + qi] = vq.w;
        }
    }
    if (tid < 64) { mrow[tid] = -3.0e38f; lrow[tid] = 0.f; }

    float o[4][8] = {};
    __syncthreads();

    for (int kt = 0; kt < NQF / 64; kt++) {
        int k0 = kt * 64;
        {
            int d4 = tid % 32, ki0 = tid / 32;
            for (int ki = ki0; ki < 64; ki += 8) {
                float4 vk = *reinterpret_cast<const float4*>(
                    &kf[(((size_t)(k0 + ki)) * NKV + kvh) * DH + d4 * 4]);
                Ks[(d4 * 4 + 0) * 65 + ki] = vk.x;
                Ks[(d4 * 4 + 1) * 65 + ki] = vk.y;
                Ks[(d4 * 4 + 2) * 65 + ki] = vk.z;
                Ks[(d4 * 4 + 3) * 65 + ki] = vk.w;
                float4 vv = *reinterpret_cast<const float4*>(
                    &vf[(((size_t)(k0 + ki)) * NKV + kvh) * DH + d4 * 4]);
                *reinterpret_cast<float4*>(&Vs[ki * 128 + d4 * 4]) = vv;
            }
        }
        __syncthreads();

        float s4[4][4] = {};
        for (int dd = 0; dd < 128; dd++) {
            float ra[4], rb[4];
#pragma unroll
            for (int i = 0; i < 4; i++) ra[i] = Qs[dd * 65 + tr * 4 + i];
#pragma unroll
            for (int jj = 0; jj < 4; jj++) rb[jj] = Ks[dd * 65 + tc * 4 + jj];
#pragma unroll
            for (int i = 0; i < 4; i++)
#pragma unroll
                for (int jj = 0; jj < 4; jj++) s4[i][jj] += ra[i] * rb[jj];
        }
#pragma unroll
        for (int i = 0; i < 4; i++)
#pragma unroll
            for (int jj = 0; jj < 4; jj++)
                Ss[(tr * 4 + i) * 65 + tc * 4 + jj] = s4[i][jj] * scale;
        __syncthreads();

        if (tid < 64) {
            float mold = mrow[tid];
            float mx = mold;
            for (int jj = 0; jj < 64; jj++) mx = fmaxf(mx, Ss[tid * 65 + jj]);
            float corr = __expf(mold - mx);
            float sum = 0.f;
            for (int jj = 0; jj < 64; jj++) {
                float p = __expf(Ss[tid * 65 + jj] - mx);
                Ss[tid * 65 + jj] = p;
                sum += p;
            }
            mrow[tid] = mx;
            lrow[tid] = lrow[tid] * corr + sum;
            crow[tid] = corr;
        }
        __syncthreads();

#pragma unroll
        for (int i = 0; i < 4; i++) {
            float c = crow[tr * 4 + i];
#pragma unroll
            for (int jj = 0; jj < 8; jj++) o[i][jj] *= c;
        }
        for (int kk = 0; kk < 64; kk++) {
            float rp[4];
#pragma unroll
            for (int i = 0; i < 4; i++) rp[i] = Ss[(tr * 4 + i) * 65 + kk];
            float4 v0 = *reinterpret_cast<const float4*>(&Vs[kk * 128 + tc * 8]);
            float4 v1 = *reinterpret_cast<const float4*>(&Vs[kk * 128 + tc * 8 + 4]);
#pragma unroll
            for (int i = 0; i < 4; i++) {
                o[i][0] += rp[i] * v0.x; o[i][1] += rp[i] * v0.y;
                o[i][2] += rp[i] * v0.z; o[i][3] += rp[i] * v0.w;
                o[i][4] += rp[i] * v1.x; o[i][5] += rp[i] * v1.y;
                o[i][6] += rp[i] * v1.z; o[i][7] += rp[i] * v1.w;
            }
        }
        __syncthreads();
    }

#pragma unroll
    for (int i = 0; i < 4; i++) {
        float inv = 1.0f / lrow[tr * 4 + i];
        size_t qrow = q0 + tr * 4 + i;
        float4 w0 = make_float4(o[i][0] * inv, o[i][1] * inv, o[i][2] * inv, o[i][3] * inv);
        float4 w1 = make_float4(o[i][4] * inv, o[i][5] * inv, o[i][6] * inv, o[i][7] * inv);
        *reinterpret_cast<float4*>(&AO[(qrow * NH + h) * DH + tc * 8]) = w0;
        *reinterpret_cast<float4*>(&AO[(qrow * NH + h) * DH + tc * 8 + 4]) = w1;
    }
}

// ---------------- expand stage C ----------------
__global__ void expandC_kernel(const float* __restrict__ AO, const float* __restrict__ ka,
                               float* __restrict__ E1) {
    int i = blockIdx.y;
    int hd = blockIdx.x * 256 + threadIdx.x;
    __shared__ float kav[20];
    if (threadIdx.x < 20) kav[threadIdx.x] = ka[threadIdx.x * DH + i];
    __syncthreads();
    for (int kbo = 0; kbo < 32; kbo++) {
        float acc = 0.f;
#pragma unroll
        for (int kao = 0; kao < 20; kao++)
            acc += AO[((size_t)(TK + kbo * 20 + kao)) * HID + hd] * kav[kao];
        E1[((size_t)i * 32 + kbo) * HID + hd] = acc;
    }
}

// ---------------- expand stage D ----------------
__global__ void expandD_kernel(const float* __restrict__ E1, const float* __restrict__ kb,
                               float* __restrict__ FULL) {
    int i = blockIdx.y;
    int hd = blockIdx.x * 128 + threadIdx.x;
    __shared__ float kbs[32 * 256];
    for (int t = threadIdx.x; t < 32 * 256; t += 128) kbs[t] = kb[t];
    float e[32];
#pragma unroll
    for (int kbo = 0; kbo < 32; kbo++) e[kbo] = E1[((size_t)i * 32 + kbo) * HID + hd];
    __syncthreads();
    for (int j = 0; j < 256; j++) {
        float acc = 0.f;
#pragma unroll
        for (int kbo = 0; kbo < 32; kbo++) acc += e[kbo] * kbs[kbo * 256 + j];
        FULL[((size_t)(i * 256 + j)) * HID + hd] = acc;
    }
}

// ---------------- scatter deterministic rows ----------------
__global__ void scatter_det_kernel(const float* __restrict__ AO, const int* __restrict__ topk_list,
                                   float* __restrict__ FULL) {
    int j = blockIdx.x;
    int pos = topk_list[j];
    for (int t = threadIdx.x; t < HID; t += blockDim.x)
        FULL[(size_t)pos * HID + t] = AO[(size_t)j * HID + t];
}

// ---------------- host launcher ----------------
extern "C" void kernel_launch(void* const* d_in, const int* in_sizes, int n_in,
                              void* d_out, int out_size) {
    const float* hs    = (const float*)d_in[0];
    const float* cosb  = (const float*)d_in[1];
    const float* sinb  = (const float*)d_in[2];
    const float* wq    = (const float*)d_in[3];
    const float* wk    = (const float*)d_in[4];
    const float* wv    = (const float*)d_in[5];
    const float* wo    = (const float*)d_in[6];
    const float* qnw   = (const float*)d_in[7];
    const float* knw   = (const float*)d_in[8];
    const float* w1    = (const float*)d_in[9];
    const float* b1    = (const float*)d_in[10];
    const float* w2    = (const float*)d_in[11];
    const float* b2    = (const float*)d_in[12];
    const float* ka    = (const float*)d_in[13];
    const float* kb    = (const float*)d_in[14];
    const float* sscale= (const float*)d_in[15];
    float* out = (float*)d_out;

    float *pT, *pLg, *pW, *pQ, *pK, *pV, *pP, *pQF, *pKF, *pVF, *pAO, *pE1, *pFULL, *pBT;
    int *pTop, *pIs;
    cudaGetSymbolAddress((void**)&pT, g_T);
    cudaGetSymbolAddress((void**)&pLg, g_logits);
    cudaGetSymbolAddress((void**)&pW, g_weights);
    cudaGetSymbolAddress((void**)&pQ, g_q);
    cudaGetSymbolAddress((void**)&pK, g_k);
    cudaGetSymbolAddress((void**)&pV, g_v);
    cudaGetSymbolAddress((void**)&pP, g_P);
    cudaGetSymbolAddress((void**)&pQF, g_qf);
    cudaGetSymbolAddress((void**)&pKF, g_kf);
    cudaGetSymbolAddress((void**)&pVF, g_vf);
    cudaGetSymbolAddress((void**)&pAO, g_AO);
    cudaGetSymbolAddress((void**)&pE1, g_E1);
    cudaGetSymbolAddress((void**)&pFULL, g_FULL);
    cudaGetSymbolAddress((void**)&pBT, g_BT);
    cudaGetSymbolAddress((void**)&pTop, g_topk);
    cudaGetSymbolAddress((void**)&pIs, g_istop);

    cudaFuncSetAttribute(topk_kernel, cudaFuncAttributeMaxDynamicSharedMemorySize, SEQ * 8);
    cudaFuncSetAttribute(fa_kernel, cudaFuncAttributeMaxDynamicSharedMemorySize, FA_SMEM);

    dim3 tb(32, 8);

    // 1) importance MLP first GEMM (fp32 — feeds top-k; must stay accurate)
    sgemm_kernel<128, 64, 16, 8, 4><<<dim3(1, SEQ / 128), 256>>>(hs, w1, pT, SEQ, 64, HID);
    // 2) logits + weights
    imp_logits_kernel<<<SEQ, 32>>>(pT, b1, w2, b2, pLg, pW);
    // 3-5) QKV projections — tf32 mma.sync
    transpose_kernel<<<dim3(HID / 32, HID / 32), tb>>>(wq, pBT, HID, HID);
    mma_gemm_kernel<<<dim3(HID / 128, SEQ / 128), 256>>>(hs, pBT, pQ, SEQ, HID, HID);
    transpose_kernel<<<dim3(512 / 32, HID / 32), tb>>>(wk, pBT, HID, 512);
    mma_gemm_kernel<<<dim3(512 / 128, SEQ / 128), 256>>>(hs, pBT, pK, SEQ, 512, HID);
    transpose_kernel<<<dim3(512 / 32, HID / 32), tb>>>(wv, pBT, HID, 512);
    mma_gemm_kernel<<<dim3(512 / 128, SEQ / 128), 256>>>(hs, pBT, pV, SEQ, 512, HID);
    // 6-7) RMSNorm q, k
    rmsnorm_kernel<<<SEQ * NH, DH>>>(pQ, qnw);
    rmsnorm_kernel<<<SEQ * NKV, DH>>>(pK, knw);
    // 8) top-k selection
    topk_kernel<<<1, 1024, SEQ * 8>>>(pLg, pTop, pIs);
    // 9-14) sketches
    sketchA_kernel<<<dim3(NH, 32), DH>>>(pQ, NH, pW, pIs, 0, kb, pP);
    sketchB_kernel<<<dim3(NH, 32), DH>>>(pP, NH, ka, sscale, pQF);
    sketchA_kernel<<<dim3(NKV, 32), DH>>>(pK, NKV, pW, pIs, 1, kb, pP);
    sketchB_kernel<<<dim3(NKV, 32), DH>>>(pP, NKV, ka, sscale, pKF);
    sketchA_kernel<<<dim3(NKV, 32), DH>>>(pV, NKV, pW, pIs, 1, kb, pP);
    sketchB_kernel<<<dim3(NKV, 32), DH>>>(pP, NKV, ka, sscale, pVF);
    // 15) gather top-k rows + RoPE
    gather_rope_kernel<<<dim3(TK, 24), DH>>>(pQ, pK, pV, cosb, sinb, pTop, pQF, pKF, pVF);
    // 16) attention
    fa_kernel<<<dim3(NQF / 64, NH), 256, FA_SMEM>>>(pQF, pKF, pVF, pAO);
    // 17-18) expand sketch part of attention output
    expandC_kernel<<<dim3(HID / 256, 32), 256>>>(pAO, ka, pE1);
    expandD_kernel<<<dim3(HID / 128, 32), DH>>>(pE1, kb, pFULL);
    // 19) overwrite top-k positions with deterministic attention output
    scatter_det_kernel<<<TK, 256>>>(pAO, pTop, pFULL);
    // 20) output projection — tf32 mma.sync
    transpose_kernel<<<dim3(HID / 32, HID / 32), tb>>>(wo, pBT, HID, HID);
    mma_gemm_kernel<<<dim3(HID / 128, SEQ / 128), 256>>>(pFULL, pBT, out, SEQ, HID, HID);
}

// round 4
// speedup vs baseline: 2.3848x; 1.6960x over previous
#include <cuda_runtime.h>
#include <cuda_bf16.h>
#include <math.h>
#include <cstdint>

// Problem constants
#define SEQ   8192
#define HID   2048
#define NH    16
#define NKV   4
#define DH    128
#define TK    2048
#define SK    640
#define NQF   (TK + SK)        // 2688
#define NQT   (NQF / 128)      // 21 q tiles
#define NKT   (NQF / 64)       // 42 key tiles
#define ATT_SCALE 0.08838834764831843f   // 1/sqrt(128)

// ---------------- scratch (device globals; no allocation) ----------------
__device__ float g_T[4 * SEQ * 64];        // split-K partials
__device__ float g_logits[SEQ];
__device__ float g_weights[SEQ];
__device__ float g_q[SEQ * NH * DH];       // normalized q  [s][h][d]
__device__ float g_k[SEQ * NKV * DH];      // normalized k
__device__ float g_v[SEQ * NKV * DH];
__device__ int   g_topk[TK];
__device__ int   g_istop[SEQ];
__device__ float g_P[NH * 32 * 32 * DH];   // sketch stage-A scratch
__device__ float g_Qfr[NH * NQT * 16 * 8 * 32 * 4];    // Q mma-fragments
__device__ float g_Kfr[NKV * NKT * 16 * 8 * 32 * 2];   // K mma-fragments
__device__ float g_Vfr[NKV * NKT * 8 * 16 * 32 * 2];   // V mma-fragments
__device__ float g_AO[NQF * NH * DH];      // attention output [q][h][d]
__device__ float g_E1[32 * 32 * HID];      // expand stage-C scratch [i][kb][hd]
__device__ float g_FULL[SEQ * HID];
__device__ float g_BT[HID * HID];          // transposed weight scratch [N][K]

// ======================= tf32 mma.sync helpers =======================
__device__ __forceinline__ float tf32f(float x) {
    uint32_t r; asm("cvt.rna.tf32.f32 %0, %1;" : "=r"(r) : "f"(x));
    return __uint_as_float(r);
}

__device__ __forceinline__ void mma_tf32(float* c, const uint32_t* a, const uint32_t* b) {
    asm volatile("mma.sync.aligned.m16n8k8.row.col.f32.tf32.tf32.f32 "
        "{%0,%1,%2,%3}, {%4,%5,%6,%7}, {%8,%9}, {%0,%1,%2,%3};"
        : "+f"(c[0]), "+f"(c[1]), "+f"(c[2]), "+f"(c[3])
        : "r"(a[0]), "r"(a[1]), "r"(a[2]), "r"(a[3]), "r"(b[0]), "r"(b[1]));
}

// fragment-layout gmem stores (producers write these; fa copies verbatim to smem)
// A-frag (m16 x k8 tiles): lane = ((m&7)<<2)|(k&3), reg = 2*((k&7)>=4) + ((m&15)>=8)
__device__ __forceinline__ void store_qfrag(float* Qg, int h, int tok, int d, float v) {
    int qt = tok >> 7, m = tok & 127;
    int k8 = d >> 3, mf = m >> 4;
    int lane = ((m & 7) << 2) | (d & 3);
    int reg = 2 * ((d & 7) >= 4) + ((m & 15) >= 8);
    size_t idx = ((((size_t)(h * NQT + qt) * 16 + k8) * 8 + mf) * 32 + lane) * 4 + reg;
    Qg[idx] = tf32f(v);
}
// B-frag for K (n=key8 x k=d8): lane = ((n&7)<<2)|(k&3), reg = (k&7)>=4
__device__ __forceinline__ void store_kfrag(float* Kg, int kvh, int tok, int d, float v) {
    int kt = tok >> 6, key = tok & 63;
    int k8 = d >> 3, nf = key >> 3;
    int lane = ((key & 7) << 2) | (d & 3);
    int reg = ((d & 7) >= 4);
    size_t idx = ((((size_t)(kvh * NKT + kt) * 16 + k8) * 8 + nf) * 32 + lane) * 2 + reg;
    Kg[idx] = tf32f(v);
}
// B-frag for V (n=d x k=key): lane = ((d&7)<<2)|(key&3), reg = (key&7)>=4
__device__ __forceinline__ void store_vfrag(float* Vg, int kvh, int tok, int d, float v) {
    int kt = tok >> 6, key = tok & 63;
    int k8 = key >> 3, nf = d >> 3;
    int lane = ((d & 7) << 2) | (key & 3);
    int reg = ((key & 7) >= 4);
    size_t idx = ((((size_t)(kvh * NKT + kt) * 8 + k8) * 16 + nf) * 32 + lane) * 2 + reg;
    Vg[idx] = tf32f(v);
}

// ======================= tf32 projection GEMM (unchanged from R3) =======================
__device__ __forceinline__ void frag_store_A(float* sAbuf, int r, int c4, float4 v) {
    int k8 = c4 >> 1, khi = c4 & 1;
    int mf = r >> 4, gid = r & 7, mhi = (r >> 3) & 1;
    int base = ((k8 * 8 + mf) * 32 + gid * 4) * 4 + khi * 2 + mhi;
    sAbuf[base + 0]  = tf32f(v.x);
    sAbuf[base + 4]  = tf32f(v.y);
    sAbuf[base + 8]  = tf32f(v.z);
    sAbuf[base + 12] = tf32f(v.w);
}
__device__ __forceinline__ void frag_store_B(float* sBbuf, int r, int c4, float4 v) {
    int k8 = c4 >> 1, half = c4 & 1;
    int nf = r >> 3, gid = r & 7;
    int base = ((k8 * 16 + nf) * 32 + gid * 4) * 2 + half;
    sBbuf[base + 0] = tf32f(v.x);
    sBbuf[base + 2] = tf32f(v.y);
    sBbuf[base + 4] = tf32f(v.z);
    sBbuf[base + 6] = tf32f(v.w);
}

__global__ void __launch_bounds__(256) mma_gemm_kernel(
    const float* __restrict__ A, const float* __restrict__ BT,
    float* __restrict__ C, int M, int N, int K)
{
    __shared__ float sA[2][2048];
    __shared__ float sB[2][2048];

    const int tid = threadIdx.x;
    const int lane = tid & 31;
    const int wid = tid >> 5;
    const int wm = wid >> 2;
    const int wn = wid & 3;
    const int row0 = blockIdx.y * 128;
    const int col0 = blockIdx.x * 128;

    const float* Ab = A + (size_t)row0 * K;
    const float* Bb = BT + (size_t)col0 * K;

    const int r0 = tid >> 2,          c40 = tid & 3;
    const int r1 = (tid + 256) >> 2,  c41 = c40;

    float acc[4][4][4] = {};
    float4 pa0, pa1, pb0, pb1;

    pa0 = *reinterpret_cast<const float4*>(Ab + (size_t)r0 * K + c40 * 4);
    pa1 = *reinterpret_cast<const float4*>(Ab + (size_t)r1 * K + c41 * 4);
    pb0 = *reinterpret_cast<const float4*>(Bb + (size_t)r0 * K + c40 * 4);
    pb1 = *reinterpret_cast<const float4*>(Bb + (size_t)r1 * K + c41 * 4);
    frag_store_A(sA[0], r0, c40, pa0);
    frag_store_A(sA[0], r1, c41, pa1);
    frag_store_B(sB[0], r0, c40, pb0);
    frag_store_B(sB[0], r1, c41, pb1);
    __syncthreads();

    const int NC = K >> 4;
    for (int c = 0; c < NC; c++) {
        const int buf = c & 1;
        if (c + 1 < NC) {
            const float* An = Ab + (c + 1) * 16;
            const float* Bn = Bb + (c + 1) * 16;
            pa0 = *reinterpret_cast<const float4*>(An + (size_t)r0 * K + c40 * 4);
            pa1 = *reinterpret_cast<const float4*>(An + (size_t)r1 * K + c41 * 4);
            pb0 = *reinterpret_cast<const float4*>(Bn + (size_t)r0 * K + c40 * 4);
            pb1 = *reinterpret_cast<const float4*>(Bn + (size_t)r1 * K + c41 * 4);
        }
        const float4* A4 = reinterpret_cast<const float4*>(sA[buf]);
        const float2* B2 = reinterpret_cast<const float2*>(sB[buf]);
#pragma unroll
        for (int k8 = 0; k8 < 2; k8++) {
            float4 af[4];
            float2 bf[4];
#pragma unroll
            for (int mf = 0; mf < 4; mf++)
                af[mf] = A4[(k8 * 8 + wm * 4 + mf) * 32 + lane];
#pragma unroll
            for (int nf = 0; nf < 4; nf++)
                bf[nf] = B2[(k8 * 16 + wn * 4 + nf) * 32 + lane];
#pragma unroll
            for (int mf = 0; mf < 4; mf++)
#pragma unroll
                for (int nf = 0; nf < 4; nf++)
                    mma_tf32(acc[mf][nf],
                             reinterpret_cast<const uint32_t*>(&af[mf]),
                             reinterpret_cast<const uint32_t*>(&bf[nf]));
        }
        if (c + 1 < NC) {
            const int nb = (c + 1) & 1;
            frag_store_A(sA[nb], r0, c40, pa0);
            frag_store_A(sA[nb], r1, c41, pa1);
            frag_store_B(sB[nb], r0, c40, pb0);
            frag_store_B(sB[nb], r1, c41, pb1);
        }
        __syncthreads();
    }

    const int gid = lane >> 2, tig = lane & 3;
#pragma unroll
    for (int mf = 0; mf < 4; mf++) {
#pragma unroll
        for (int nf = 0; nf < 4; nf++) {
            int m = row0 + wm * 64 + mf * 16 + gid;
            int n = col0 + wn * 32 + nf * 8 + tig * 2;
            float2 lo = make_float2(acc[mf][nf][0], acc[mf][nf][1]);
            float2 hi = make_float2(acc[mf][nf][2], acc[mf][nf][3]);
            *reinterpret_cast<float2*>(&C[(size_t)m * N + n]) = lo;
            *reinterpret_cast<float2*>(&C[(size_t)(m + 8) * N + n]) = hi;
        }
    }
}

// ---------------- transpose: in[R][C] -> out[C][R] ----------------
__global__ void transpose_kernel(const float* __restrict__ in, float* __restrict__ out,
                                 int R, int C) {
    __shared__ float t[32][33];
    int c0 = blockIdx.x * 32, r0 = blockIdx.y * 32;
    int x = threadIdx.x, y = threadIdx.y;  // 32 x 8
#pragma unroll
    for (int i = y; i < 32; i += 8) t[i][x] = in[(size_t)(r0 + i) * C + c0 + x];
    __syncthreads();
#pragma unroll
    for (int i = y; i < 32; i += 8) out[(size_t)(c0 + i) * R + r0 + x] = t[x][i];
}

// ---------------- importance GEMM: fp32 split-K (top-k needs fp32) -----------
__global__ void __launch_bounds__(256) imp_gemm_kernel(
    const float* __restrict__ A, const float* __restrict__ B, float* __restrict__ Cp)
{
    __shared__ float As[16][64];
    __shared__ float Bs[16][64];
    const int tid = threadIdx.x;
    const int row0 = blockIdx.y * 64;
    const int z = blockIdx.z;
    const float* Ab = A + (size_t)row0 * HID + z * 512;
    const float* Bb = B + (size_t)z * 512 * 64;
    float acc[4][4] = {};
    const int tc = (tid & 15) * 4, tr = (tid >> 4) * 4;
    const int ar = tid >> 2, ac = (tid & 3) * 4;
    const int br = tid >> 4, bc = (tid & 15) * 4;

    for (int k0 = 0; k0 < 512; k0 += 16) {
        float4 va = *reinterpret_cast<const float4*>(Ab + (size_t)ar * HID + k0 + ac);
        As[ac + 0][ar] = va.x; As[ac + 1][ar] = va.y;
        As[ac + 2][ar] = va.z; As[ac + 3][ar] = va.w;
        float4 vb = *reinterpret_cast<const float4*>(Bb + (size_t)(k0 + br) * 64 + bc);
        *reinterpret_cast<float4*>(&Bs[br][bc]) = vb;
        __syncthreads();
#pragma unroll
        for (int k = 0; k < 16; k++) {
            float ra[4], rb[4];
#pragma unroll
            for (int m = 0; m < 4; m++) ra[m] = As[k][tr + m];
#pragma unroll
            for (int n = 0; n < 4; n++) rb[n] = Bs[k][tc + n];
#pragma unroll
            for (int m = 0; m < 4; m++)
#pragma unroll
                for (int n = 0; n < 4; n++) acc[m][n] += ra[m] * rb[n];
        }
        __syncthreads();
    }
#pragma unroll
    for (int m = 0; m < 4; m++) {
        float4 v = make_float4(acc[m][0], acc[m][1], acc[m][2], acc[m][3]);
        *reinterpret_cast<float4*>(&Cp[((size_t)z * SEQ + row0 + tr + m) * 64 + tc]) = v;
    }
}

// ---------------- importance logits epilogue (sums split-K partials) --------
__global__ void imp_logits_kernel(const float* __restrict__ T, const float* __restrict__ b1,
                                  const float* __restrict__ w2, const float* __restrict__ b2,
                                  float* __restrict__ logits, float* __restrict__ weights) {
    const float LOG_ADJ = 2.5494451709255714f;   // log(8192/640)
    int s = blockIdx.x;
    int j = threadIdx.x;  // 32
    float v1 = 0.f, v2 = 0.f;
#pragma unroll
    for (int z = 0; z < 4; z++) {
        v1 += T[((size_t)z * SEQ + s) * 64 + j];
        v2 += T[((size_t)z * SEQ + s) * 64 + j + 32];
    }
    float v = tanhf(v1 + b1[j]) * w2[j] + tanhf(v2 + b1[j + 32]) * w2[j + 32];
#pragma unroll
    for (int o = 16; o > 0; o >>= 1) v += __shfl_xor_sync(0xffffffffu, v, o);
    if (j == 0) {
        float lg = v + b2[0] - LOG_ADJ;
        logits[s] = lg;
        weights[s] = 1.0f / (1.0f + expf(-lg));
    }
}

// ---------------- RMSNorm (in-place, rows of 128) ----------------
__global__ void rmsnorm_kernel(float* __restrict__ X, const float* __restrict__ w) {
    size_t row = blockIdx.x;
    int d = threadIdx.x;   // 128
    float x = X[row * DH + d];
    float ss = x * x;
#pragma unroll
    for (int o = 16; o > 0; o >>= 1) ss += __shfl_xor_sync(0xffffffffu, ss, o);
    __shared__ float sm[4];
    if ((d & 31) == 0) sm[d >> 5] = ss;
    __syncthreads();
    float tot = sm[0] + sm[1] + sm[2] + sm[3];
    X[row * DH + d] = x * rsqrtf(tot * (1.0f / 128.0f) + 1e-6f) * w[d];
}

// ---------------- top-k via single-block bitonic sort ----------------
__global__ void topk_kernel(const float* __restrict__ logits,
                            int* __restrict__ topk_list, int* __restrict__ is_topk) {
    extern __shared__ unsigned long long skeys[];
    int tid = threadIdx.x;  // 1024
    for (int i = tid; i < SEQ; i += 1024) {
        unsigned u = __float_as_uint(logits[i]);
        u = (u & 0x80000000u) ? ~u : (u | 0x80000000u);
        skeys[i] = ((unsigned long long)(~u) << 32) | (unsigned)i;
        is_topk[i] = 0;
    }
    __syncthreads();
    for (int k = 2; k <= SEQ; k <<= 1) {
        for (int j = k >> 1; j > 0; j >>= 1) {
            for (int i = tid; i < SEQ; i += 1024) {
                int ixj = i ^ j;
                if (ixj > i) {
                    bool up = ((i & k) == 0);
                    unsigned long long a = skeys[i], b = skeys[ixj];
                    if ((a > b) == up) { skeys[i] = b; skeys[ixj] = a; }
                }
            }
            __syncthreads();
        }
    }
    for (int i = tid; i < TK; i += 1024) {
        int pos = (int)(skeys[i] & 0xffffffffu);
        topk_list[i] = pos;
        is_topk[pos] = 1;
    }
}

// ---------------- sketch stage A ----------------
__global__ void sketchA_kernel(const float* __restrict__ X, int heads,
                               const float* __restrict__ weights,
                               const int* __restrict__ is_topk, int rest,
                               const float* __restrict__ kb, float* __restrict__ P) {
    int h = blockIdx.x;
    int ib = blockIdx.y;   // 0..31
    int d = threadIdx.x;   // 128
    __shared__ float kbs[32 * 256];
    for (int t = d; t < 32 * 256; t += 128) kbs[t] = kb[t];
    __shared__ float ws[256];
    for (int j = d; j < 256; j += 128) {
        int t = ib * 256 + j;
        float w = weights[t];
        if (rest && is_topk[t]) w = 0.0f;
        ws[j] = w;
    }
    __syncthreads();
    float acc[32] = {};
    for (int j = 0; j < 256; j++) {
        float xv = X[((size_t)(ib * 256 + j) * heads + h) * DH + d] * ws[j];
#pragma unroll
        for (int kbo = 0; kbo < 32; kbo++) acc[kbo] += xv * kbs[kbo * 256 + j];
    }
#pragma unroll
    for (int kbo = 0; kbo < 32; kbo++)
        P[(((size_t)h * 32 + kbo) * 32 + ib) * DH + d] = acc[kbo];
}

// ---------------- sketch stage B: writes mma fragments ----------------
// mode: 0 = q (apply ATT_SCALE too), 1 = k, 2 = v
__global__ void sketchB_kernel(const float* __restrict__ P, int heads,
                               const float* __restrict__ ka,
                               const float* __restrict__ scale_p,
                               float* __restrict__ dstfrag, int mode) {
    int h = blockIdx.x;
    int kbo = blockIdx.y;
    int d = threadIdx.x;   // 128
    __shared__ float kas[20 * 32];
    for (int t = d; t < 20 * 32; t += 128) kas[t] = ka[(t / 32) * DH + (t % 32)];
    __syncthreads();
    float p[32];
#pragma unroll
    for (int i = 0; i < 32; i++) p[i] = P[(((size_t)h * 32 + kbo) * 32 + i) * DH + d];
    float scale = scale_p[0];
    if (mode == 0) scale *= ATT_SCALE;
#pragma unroll
    for (int kao = 0; kao < 20; kao++) {
        float acc = 0.f;
#pragma unroll
        for (int i = 0; i < 32; i++) acc += p[i] * kas[kao * 32 + i];
        int s = TK + kbo * 20 + kao;
        float val = acc * scale;
        if (mode == 0)      store_qfrag(dstfrag, h, s, d, val);
        else if (mode == 1) store_kfrag(dstfrag, h, s, d, val);
        else                store_vfrag(dstfrag, h, s, d, val);
    }
}

// ---------------- gather + RoPE for top-k rows -> mma fragments ----------------
__global__ void gather_rope_kernel(const float* __restrict__ q, const float* __restrict__ k,
                                   const float* __restrict__ v,
                                   const float* __restrict__ cosb, const float* __restrict__ sinb,
                                   const int* __restrict__ topk_list,
                                   float* __restrict__ Qfr, float* __restrict__ Kfr,
                                   float* __restrict__ Vfr) {
    int j = blockIdx.x;    // 0..2047 (token slot)
    int hy = blockIdx.y;   // 0..23
    int d = threadIdx.x;
    int pos = topk_list[j];
    float c = cosb[(size_t)pos * DH + d];
    float s = sinb[(size_t)pos * DH + d];
    if (hy < 16) {
        const float* src = q + ((size_t)pos * NH + hy) * DH;
        float x = src[d];
        float r = (d < 64) ? -src[d + 64] : src[d - 64];
        store_qfrag(Qfr, hy, j, d, (x * c + r * s) * ATT_SCALE);
    } else if (hy < 20) {
        int h = hy - 16;
        const float* src = k + ((size_t)pos * NKV + h) * DH;
        float x = src[d];
        float r = (d < 64) ? -src[d + 64] : src[d - 64];
        store_kfrag(Kfr, h, j, d, x * c + r * s);
    } else {
        int h = hy - 20;
        store_vfrag(Vfr, h, j, d, v[((size_t)pos * NKV + h) * DH + d]);
    }
}

// ---------------- tensor-core flash attention ----------------
// 128 q x 64 key tiles, 8 warps (4m x 2n), tf32 mma for QK^T and PV.
#define FA2_SMEM ((16384 + 8192 + 8192 + 8192 + 512) * 4)
__global__ void __launch_bounds__(256, 1) fa_mma_kernel(
    const float* __restrict__ Qfr, const float* __restrict__ Kfr,
    const float* __restrict__ Vfr, float* __restrict__ AO)
{
    extern __shared__ float fsm[];
    float* Qsm = fsm;                    // 16384 floats
    float* Ksm = Qsm + 16384;            // 8192
    float* Vsm = Ksm + 8192;             // 8192
    float* Psm = Vsm + 8192;             // 8192
    float* mpart = Psm + 8192;           // 256
    float* spart = mpart + 256;          // 256

    const int qt = blockIdx.x;           // 0..20
    const int h  = blockIdx.y;           // 0..15
    const int kvh = h >> 2;
    const int tid = threadIdx.x;
    const int lane = tid & 31, wid = tid >> 5;
    const int wm = wid >> 1, wn = wid & 1;
    const int gid = lane >> 2, tig = lane & 3;

    // stage Q fragments (verbatim copy)
    {
        const float4* Qg = reinterpret_cast<const float4*>(Qfr + (size_t)(h * NQT + qt) * 16384);
        float4* Qs4w = reinterpret_cast<float4*>(Qsm);
#pragma unroll
        for (int i = 0; i < 16; i++) Qs4w[tid + i * 256] = Qg[tid + i * 256];
    }

    float m_old[2][2], l_run[2][2];
#pragma unroll
    for (int a = 0; a < 2; a++)
#pragma unroll
        for (int b = 0; b < 2; b++) { m_old[a][b] = -1e30f; l_run[a][b] = 0.f; }
    float oacc[2][8][4] = {};

    const float4* Qs4 = reinterpret_cast<const float4*>(Qsm);
    const float2* Ks2 = reinterpret_cast<const float2*>(Ksm);
    const float2* Vs2 = reinterpret_cast<const float2*>(Vsm);
    const float4* Ps4 = reinterpret_cast<const float4*>(Psm);

    for (int kt = 0; kt < NKT; kt++) {
        // stage K, V fragments
        {
            const float4* Kg = reinterpret_cast<const float4*>(Kfr + (size_t)(kvh * NKT + kt) * 8192);
            const float4* Vg = reinterpret_cast<const float4*>(Vfr + (size_t)(kvh * NKT + kt) * 8192);
            float4* Ks4w = reinterpret_cast<float4*>(Ksm);
            float4* Vs4w = reinterpret_cast<float4*>(Vsm);
#pragma unroll
            for (int i = 0; i < 8; i++) Ks4w[tid + i * 256] = Kg[tid + i * 256];
#pragma unroll
            for (int i = 0; i < 8; i++) Vs4w[tid + i * 256] = Vg[tid + i * 256];
        }
        __syncthreads();

        // S = Q K^T (warp tile 32q x 32key)
        float sacc[2][4][4] = {};
#pragma unroll
        for (int k8 = 0; k8 < 16; k8++) {
            float4 af[2];
            float2 bf[4];
            af[0] = Qs4[(k8 * 8 + wm * 2 + 0) * 32 + lane];
            af[1] = Qs4[(k8 * 8 + wm * 2 + 1) * 32 + lane];
#pragma unroll
            for (int nf = 0; nf < 4; nf++) bf[nf] = Ks2[(k8 * 8 + wn * 4 + nf) * 32 + lane];
#pragma unroll
            for (int mf = 0; mf < 2; mf++)
#pragma unroll
                for (int nf = 0; nf < 4; nf++)
                    mma_tf32(sacc[mf][nf],
                             reinterpret_cast<const uint32_t*>(&af[mf]),
                             reinterpret_cast<const uint32_t*>(&bf[nf]));
        }

        // warp-local row max + quad reduce
        float mloc[2][2];
#pragma unroll
        for (int mf = 0; mf < 2; mf++) {
            float m0 = fmaxf(sacc[mf][0][0], sacc[mf][0][1]);
            float m1 = fmaxf(sacc[mf][0][2], sacc[mf][0][3]);
#pragma unroll
            for (int nf = 1; nf < 4; nf++) {
                m0 = fmaxf(m0, fmaxf(sacc[mf][nf][0], sacc[mf][nf][1]));
                m1 = fmaxf(m1, fmaxf(sacc[mf][nf][2], sacc[mf][nf][3]));
            }
            m0 = fmaxf(m0, __shfl_xor_sync(0xffffffffu, m0, 1));
            m0 = fmaxf(m0, __shfl_xor_sync(0xffffffffu, m0, 2));
            m1 = fmaxf(m1, __shfl_xor_sync(0xffffffffu, m1, 1));
            m1 = fmaxf(m1, __shfl_xor_sync(0xffffffffu, m1, 2));
            mloc[mf][0] = m0; mloc[mf][1] = m1;
        }
        if (tig == 0) {
#pragma unroll
            for (int mf = 0; mf < 2; mf++) {
                int r = wm * 32 + mf * 16 + gid;
                mpart[wn * 128 + r] = mloc[mf][0];
                mpart[wn * 128 + r + 8] = mloc[mf][1];
            }
        }
        __syncthreads();

        float mnew[2][2], corr[2][2];
#pragma unroll
        for (int mf = 0; mf < 2; mf++)
#pragma unroll
            for (int hi = 0; hi < 2; hi++) {
                int r = wm * 32 + mf * 16 + gid + hi * 8;
                float mt = fmaxf(mpart[r], mpart[128 + r]);
                float mn = fmaxf(m_old[mf][hi], mt);
                corr[mf][hi] = __expf(m_old[mf][hi] - mn);
                mnew[mf][hi] = mn;
                m_old[mf][hi] = mn;
            }

        // p = exp(s - m), warp-local row sums
        float sloc[2][2] = {};
#pragma unroll
        for (int mf = 0; mf < 2; mf++)
#pragma unroll
            for (int nf = 0; nf < 4; nf++) {
                sacc[mf][nf][0] = __expf(sacc[mf][nf][0] - mnew[mf][0]);
                sacc[mf][nf][1] = __expf(sacc[mf][nf][1] - mnew[mf][0]);
                sacc[mf][nf][2] = __expf(sacc[mf][nf][2] - mnew[mf][1]);
                sacc[mf][nf][3] = __expf(sacc[mf][nf][3] - mnew[mf][1]);
                sloc[mf][0] += sacc[mf][nf][0] + sacc[mf][nf][1];
                sloc[mf][1] += sacc[mf][nf][2] + sacc[mf][nf][3];
            }
#pragma unroll
        for (int mf = 0; mf < 2; mf++) {
            sloc[mf][0] += __shfl_xor_sync(0xffffffffu, sloc[mf][0], 1);
            sloc[mf][0] += __shfl_xor_sync(0xffffffffu, sloc[mf][0], 2);
            sloc[mf][1] += __shfl_xor_sync(0xffffffffu, sloc[mf][1], 1);
            sloc[mf][1] += __shfl_xor_sync(0xffffffffu, sloc[mf][1], 2);
        }
        if (tig == 0) {
#pragma unroll
            for (int mf = 0; mf < 2; mf++) {
                int r = wm * 32 + mf * 16 + gid;
                spart[wn * 128 + r] = sloc[mf][0];
                spart[wn * 128 + r + 8] = sloc[mf][1];
            }
        }

        // store P as A-fragments (tf32) into Psm
#pragma unroll
        for (int mf = 0; mf < 2; mf++)
#pragma unroll
            for (int nf = 0; nf < 4; nf++) {
                int k8p = wn * 4 + nf;
                int mfg = wm * 2 + mf;
#pragma unroll
                for (int b = 0; b < 2; b++) {
                    int c = tig * 2 + b;
                    int khi = (c >= 4);
                    int base = ((k8p * 8 + mfg) * 32 + (gid << 2) + (c & 3)) * 4 + khi * 2;
                    *reinterpret_cast<float2*>(Psm + base) =
                        make_float2(tf32f(sacc[mf][nf][b]), tf32f(sacc[mf][nf][2 + b]));
                }
            }
        __syncthreads();

        // l update, O rescale
#pragma unroll
        for (int mf = 0; mf < 2; mf++)
#pragma unroll
            for (int hi = 0; hi < 2; hi++) {
                int r = wm * 32 + mf * 16 + gid + hi * 8;
                l_run[mf][hi] = l_run[mf][hi] * corr[mf][hi] + spart[r] + spart[128 + r];
            }
#pragma unroll
        for (int mf = 0; mf < 2; mf++)
#pragma unroll
            for (int nf = 0; nf < 8; nf++) {
                oacc[mf][nf][0] *= corr[mf][0]; oacc[mf][nf][1] *= corr[mf][0];
                oacc[mf][nf][2] *= corr[mf][1]; oacc[mf][nf][3] *= corr[mf][1];
            }

        // O += P V (warp tile 32q x 64d)
#pragma unroll
        for (int k8 = 0; k8 < 8; k8++) {
            float4 af[2];
            af[0] = Ps4[(k8 * 8 + wm * 2 + 0) * 32 + lane];
            af[1] = Ps4[(k8 * 8 + wm * 2 + 1) * 32 + lane];
#pragma unroll
            for (int nf = 0; nf < 8; nf++) {
                float2 bf = Vs2[(k8 * 16 + wn * 8 + nf) * 32 + lane];
#pragma unroll
                for (int mf = 0; mf < 2; mf++)
                    mma_tf32(oacc[mf][nf],
                             reinterpret_cast<const uint32_t*>(&af[mf]),
                             reinterpret_cast<const uint32_t*>(&bf));
            }
        }
        __syncthreads();
    }

    // epilogue: O / l -> AO[q][h][d]
#pragma unroll
    for (int mf = 0; mf < 2; mf++) {
        float inv0 = 1.0f / l_run[mf][0];
        float inv1 = 1.0f / l_run[mf][1];
        int r0 = qt * 128 + wm * 32 + mf * 16 + gid;
#pragma unroll
        for (int nf = 0; nf < 8; nf++) {
            int col = wn * 64 + nf * 8 + tig * 2;
            *reinterpret_cast<float2*>(&AO[((size_t)r0 * NH + h) * DH + col]) =
                make_float2(oacc[mf][nf][0] * inv0, oacc[mf][nf][1] * inv0);
            *reinterpret_cast<float2*>(&AO[((size_t)(r0 + 8) * NH + h) * DH + col]) =
                make_float2(oacc[mf][nf][2] * inv1, oacc[mf][nf][3] * inv1);
        }
    }
}

// ---------------- expand stage C ----------------
__global__ void expandC_kernel(const float* __restrict__ AO, const float* __restrict__ ka,
                               float* __restrict__ E1) {
    int i = blockIdx.y;
    int hd = blockIdx.x * 256 + threadIdx.x;
    __shared__ float kav[20];
    if (threadIdx.x < 20) kav[threadIdx.x] = ka[threadIdx.x * DH + i];
    __syncthreads();
    for (int kbo = 0; kbo < 32; kbo++) {
        float acc = 0.f;
#pragma unroll
        for (int kao = 0; kao < 20; kao++)
            acc += AO[((size_t)(TK + kbo * 20 + kao)) * HID + hd] * kav[kao];
        E1[((size_t)i * 32 + kbo) * HID + hd] = acc;
    }
}

// ---------------- expand stage D ----------------
__global__ void expandD_kernel(const float* __restrict__ E1, const float* __restrict__ kb,
                               float* __restrict__ FULL) {
    int i = blockIdx.y;
    int hd = blockIdx.x * 128 + threadIdx.x;
    __shared__ float kbs[32 * 256];
    for (int t = threadIdx.x; t < 32 * 256; t += 128) kbs[t] = kb[t];
    float e[32];
#pragma unroll
    for (int kbo = 0; kbo < 32; kbo++) e[kbo] = E1[((size_t)i * 32 + kbo) * HID + hd];
    __syncthreads();
    for (int j = 0; j < 256; j++) {
        float acc = 0.f;
#pragma unroll
        for (int kbo = 0; kbo < 32; kbo++) acc += e[kbo] * kbs[kbo * 256 + j];
        FULL[((size_t)(i * 256 + j)) * HID + hd] = acc;
    }
}

// ---------------- scatter deterministic rows ----------------
__global__ void scatter_det_kernel(const float* __restrict__ AO, const int* __restrict__ topk_list,
                                   float* __restrict__ FULL) {
    int j = blockIdx.x;
    int pos = topk_list[j];
    for (int t = threadIdx.x; t < HID; t += blockDim.x)
        FULL[(size_t)pos * HID + t] = AO[(size_t)j * HID + t];
}

// ---------------- host launcher ----------------
extern "C" void kernel_launch(void* const* d_in, const int* in_sizes, int n_in,
                              void* d_out, int out_size) {
    const float* hs    = (const float*)d_in[0];
    const float* cosb  = (const float*)d_in[1];
    const float* sinb  = (const float*)d_in[2];
    const float* wq    = (const float*)d_in[3];
    const float* wk    = (const float*)d_in[4];
    const float* wv    = (const float*)d_in[5];
    const float* wo    = (const float*)d_in[6];
    const float* qnw   = (const float*)d_in[7];
    const float* knw   = (const float*)d_in[8];
    const float* w1    = (const float*)d_in[9];
    const float* b1    = (const float*)d_in[10];
    const float* w2    = (const float*)d_in[11];
    const float* b2    = (const float*)d_in[12];
    const float* ka    = (const float*)d_in[13];
    const float* kb    = (const float*)d_in[14];
    const float* sscale= (const float*)d_in[15];
    float* out = (float*)d_out;

    float *pT, *pLg, *pW, *pQ, *pK, *pV, *pP, *pQfr, *pKfr, *pVfr, *pAO, *pE1, *pFULL, *pBT;
    int *pTop, *pIs;
    cudaGetSymbolAddress((void**)&pT, g_T);
    cudaGetSymbolAddress((void**)&pLg, g_logits);
    cudaGetSymbolAddress((void**)&pW, g_weights);
    cudaGetSymbolAddress((void**)&pQ, g_q);
    cudaGetSymbolAddress((void**)&pK, g_k);
    cudaGetSymbolAddress((void**)&pV, g_v);
    cudaGetSymbolAddress((void**)&pP, g_P);
    cudaGetSymbolAddress((void**)&pQfr, g_Qfr);
    cudaGetSymbolAddress((void**)&pKfr, g_Kfr);
    cudaGetSymbolAddress((void**)&pVfr, g_Vfr);
    cudaGetSymbolAddress((void**)&pAO, g_AO);
    cudaGetSymbolAddress((void**)&pE1, g_E1);
    cudaGetSymbolAddress((void**)&pFULL, g_FULL);
    cudaGetSymbolAddress((void**)&pBT, g_BT);
    cudaGetSymbolAddress((void**)&pTop, g_topk);
    cudaGetSymbolAddress((void**)&pIs, g_istop);

    cudaFuncSetAttribute(topk_kernel, cudaFuncAttributeMaxDynamicSharedMemorySize, SEQ * 8);
    cudaFuncSetAttribute(fa_mma_kernel, cudaFuncAttributeMaxDynamicSharedMemorySize, FA2_SMEM);

    dim3 tb(32, 8);

    // 1) importance MLP first GEMM — fp32 split-K x4 (feeds top-k)
    imp_gemm_kernel<<<dim3(1, SEQ / 64, 4), 256>>>(hs, w1, pT);
    // 2) logits + weights
    imp_logits_kernel<<<SEQ, 32>>>(pT, b1, w2, b2, pLg, pW);
    // 3-5) QKV projections — tf32 mma.sync
    transpose_kernel<<<dim3(HID / 32, HID / 32), tb>>>(wq, pBT, HID, HID);
    mma_gemm_kernel<<<dim3(HID / 128, SEQ / 128), 256>>>(hs, pBT, pQ, SEQ, HID, HID);
    transpose_kernel<<<dim3(512 / 32, HID / 32), tb>>>(wk, pBT, HID, 512);
    mma_gemm_kernel<<<dim3(512 / 128, SEQ / 128), 256>>>(hs, pBT, pK, SEQ, 512, HID);
    transpose_kernel<<<dim3(512 / 32, HID / 32), tb>>>(wv, pBT, HID, 512);
    mma_gemm_kernel<<<dim3(512 / 128, SEQ / 128), 256>>>(hs, pBT, pV, SEQ, 512, HID);
    // 6-7) RMSNorm q, k
    rmsnorm_kernel<<<SEQ * NH, DH>>>(pQ, qnw);
    rmsnorm_kernel<<<SEQ * NKV, DH>>>(pK, knw);
    // 8) top-k selection
    topk_kernel<<<1, 1024, SEQ * 8>>>(pLg, pTop, pIs);
    // 9-14) sketches -> fragment buffers
    sketchA_kernel<<<dim3(NH, 32), DH>>>(pQ, NH, pW, pIs, 0, kb, pP);
    sketchB_kernel<<<dim3(NH, 32), DH>>>(pP, NH, ka, sscale, pQfr, 0);
    sketchA_kernel<<<dim3(NKV, 32), DH>>>(pK, NKV, pW, pIs, 1, kb, pP);
    sketchB_kernel<<<dim3(NKV, 32), DH>>>(pP, NKV, ka, sscale, pKfr, 1);
    sketchA_kernel<<<dim3(NKV, 32), DH>>>(pV, NKV, pW, pIs, 1, kb, pP);
    sketchB_kernel<<<dim3(NKV, 32), DH>>>(pP, NKV, ka, sscale, pVfr, 2);
    // 15) gather top-k rows + RoPE -> fragment buffers
    gather_rope_kernel<<<dim3(TK, 24), DH>>>(pQ, pK, pV, cosb, sinb, pTop, pQfr, pKfr, pVfr);
    // 16) attention — tensor-core FA2
    fa_mma_kernel<<<dim3(NQT, NH), 256, FA2_SMEM>>>(pQfr, pKfr, pVfr, pAO);
    // 17-18) expand sketch part of attention output
    expandC_kernel<<<dim3(HID / 256, 32), 256>>>(pAO, ka, pE1);
    expandD_kernel<<<dim3(HID / 128, 32), DH>>>(pE1, kb, pFULL);
    // 19) overwrite top-k positions with deterministic attention output
    scatter_det_kernel<<<TK, 256>>>(pAO, pTop, pFULL);
    // 20) output projection — tf32 mma.sync
    transpose_kernel<<<dim3(HID / 32, HID / 32), tb>>>(wo, pBT, HID, HID);
    mma_gemm_kernel<<<dim3(HID / 128, SEQ / 128), 256>>>(pFULL, pBT, out, SEQ, HID, HID);
}

// round 5
// speedup vs baseline: 2.9411x; 1.2333x over previous
#include <cuda_runtime.h>
#include <cuda_bf16.h>
#include <math.h>
#include <cstdint>

// Problem constants
#define SEQ   8192
#define HID   2048
#define NH    16
#define NKV   4
#define DH    128
#define TK    2048
#define SK    640
#define NQF   (TK + SK)        // 2688
#define NQT   (NQF / 128)      // 21 q tiles
#define NKT   (NQF / 64)       // 42 key tiles
#define ATT_SCALE 0.08838834764831843f   // 1/sqrt(128)

// ---------------- scratch (device globals; no allocation) ----------------
__device__ float g_T[4 * SEQ * 64];        // split-K partials
__device__ float g_logits[SEQ];
__device__ float g_weights[SEQ];
__device__ float g_q[SEQ * NH * DH];       // normalized q  [s][h][d]
__device__ float g_k[SEQ * NKV * DH];      // normalized k
__device__ float g_v[SEQ * NKV * DH];
__device__ int   g_topk[TK];
__device__ int   g_istop[SEQ];
__device__ float g_P[NH * 32 * 32 * DH];   // sketch stage-A scratch
__device__ float g_Qfr[NH * NQT * 16 * 8 * 32 * 4];    // Q mma-fragments
__device__ float g_Kfr[NKV * NKT * 16 * 8 * 32 * 2];   // K mma-fragments
__device__ float g_Vfr[NKV * NKT * 8 * 16 * 32 * 2];   // V mma-fragments
__device__ float g_AO[NQF * NH * DH];      // attention output [q][h][d]
__device__ float g_E1[32 * 32 * HID];      // expand stage-C scratch [i][kb][hd]
__device__ float g_FULL[SEQ * HID];
__device__ float g_Afr[SEQ * HID];         // A fragments (hs, later FULL)
__device__ float g_Bfr[HID * HID];         // B fragments (weights)

// ======================= tf32 mma.sync helpers =======================
__device__ __forceinline__ float tf32f(float x) {
    uint32_t r; asm("cvt.rna.tf32.f32 %0, %1;" : "=r"(r) : "f"(x));
    return __uint_as_float(r);
}

__device__ __forceinline__ void mma_tf32(float* c, const uint32_t* a, const uint32_t* b) {
    asm volatile("mma.sync.aligned.m16n8k8.row.col.f32.tf32.tf32.f32 "
        "{%0,%1,%2,%3}, {%4,%5,%6,%7}, {%8,%9}, {%0,%1,%2,%3};"
        : "+f"(c[0]), "+f"(c[1]), "+f"(c[2]), "+f"(c[3])
        : "r"(a[0]), "r"(a[1]), "r"(a[2]), "r"(a[3]), "r"(b[0]), "r"(b[1]));
}

// fragment-layout gmem stores for attention operands
__device__ __forceinline__ void store_qfrag(float* Qg, int h, int tok, int d, float v) {
    int qt = tok >> 7, m = tok & 127;
    int k8 = d >> 3, mf = m >> 4;
    int lane = ((m & 7) << 2) | (d & 3);
    int reg = 2 * ((d & 7) >= 4) + ((m & 15) >= 8);
    size_t idx = ((((size_t)(h * NQT + qt) * 16 + k8) * 8 + mf) * 32 + lane) * 4 + reg;
    Qg[idx] = tf32f(v);
}
__device__ __forceinline__ void store_kfrag(float* Kg, int kvh, int tok, int d, float v) {
    int kt = tok >> 6, key = tok & 63;
    int k8 = d >> 3, nf = key >> 3;
    int lane = ((key & 7) << 2) | (d & 3);
    int reg = ((d & 7) >= 4);
    size_t idx = ((((size_t)(kvh * NKT + kt) * 16 + k8) * 8 + nf) * 32 + lane) * 2 + reg;
    Kg[idx] = tf32f(v);
}
__device__ __forceinline__ void store_vfrag(float* Vg, int kvh, int tok, int d, float v) {
    int kt = tok >> 6, key = tok & 63;
    int k8 = key >> 3, nf = d >> 3;
    int lane = ((d & 7) << 2) | (key & 3);
    int reg = ((key & 7) >= 4);
    size_t idx = ((((size_t)(kvh * NKT + kt) * 8 + k8) * 16 + nf) * 32 + lane) * 2 + reg;
    Vg[idx] = tf32f(v);
}

// ======================= fragment conversion pre-passes =======================
// A[M][K] row-major -> A-fragment-major: [(rt*(K/16)+c)*2048] blocks
__global__ void __launch_bounds__(256) convA_kernel(const float* __restrict__ A,
                                                    float* __restrict__ Afr, int K) {
    __shared__ float sm[2048];
    const int rt = blockIdx.y, c = blockIdx.x;
    const int tid = threadIdx.x;
    const float* Ab = A + ((size_t)rt * 128) * K + c * 16;
#pragma unroll
    for (int i = 0; i < 2; i++) {
        int f = tid + i * 256;
        int r = f >> 2, c4 = f & 3;
        float4 v = *reinterpret_cast<const float4*>(Ab + (size_t)r * K + c4 * 4);
        int mf = r >> 4, gid = r & 7, mhi = (r >> 3) & 1;
        float vv[4] = {v.x, v.y, v.z, v.w};
#pragma unroll
        for (int j = 0; j < 4; j++) {
            int k = c4 * 4 + j;
            int slot = ((k >> 3) * 8 + mf) * 128 + ((gid << 2) | (k & 3)) * 4
                     + 2 * ((k & 7) >= 4) + mhi;
            sm[slot] = tf32f(vv[j]);
        }
    }
    __syncthreads();
    float4* out = reinterpret_cast<float4*>(Afr + ((size_t)(rt * (K >> 4) + c)) * 2048);
    const float4* s4 = reinterpret_cast<const float4*>(sm);
#pragma unroll
    for (int i = 0; i < 2; i++) out[tid + i * 256] = s4[tid + i * 256];
}

// B[K][N] row-major (weights) -> B-fragment-major per column tile: transpose+frag fused
__global__ void __launch_bounds__(256) convB_kernel(const float* __restrict__ B,
                                                    float* __restrict__ Bfr, int K, int N) {
    __shared__ float sm[2048];
    const int ct = blockIdx.y, c = blockIdx.x;
    const int tid = threadIdx.x;
    const float* Bb = B + ((size_t)(c * 16)) * N + ct * 128;
#pragma unroll
    for (int i = 0; i < 2; i++) {
        int f = tid + i * 256;
        int kk = f >> 5, n4 = f & 31;
        float4 v = *reinterpret_cast<const float4*>(Bb + (size_t)kk * N + n4 * 4);
        int k8in = kk >> 3, reg = ((kk & 7) >= 4);
        float vv[4] = {v.x, v.y, v.z, v.w};
#pragma unroll
        for (int j = 0; j < 4; j++) {
            int n = n4 * 4 + j;
            int slot = (k8in * 16 + (n >> 3)) * 64 + (((n & 7) << 2) | (kk & 3)) * 2 + reg;
            sm[slot] = tf32f(vv[j]);
        }
    }
    __syncthreads();
    float4* out = reinterpret_cast<float4*>(Bfr + ((size_t)(ct * (K >> 4) + c)) * 2048);
    const float4* s4 = reinterpret_cast<const float4*>(sm);
#pragma unroll
    for (int i = 0; i < 2; i++) out[tid + i * 256] = s4[tid + i * 256];
}

// ======================= tf32 projection GEMM (fragment-major operands) ============
// C[M,N] = A @ B^T from pre-fragmented gmem. CTA 128x128, BK=16, 8 warps 2x4.
__global__ void __launch_bounds__(256) mma_gemm_kernel(
    const float* __restrict__ Afr, const float* __restrict__ Bfr,
    float* __restrict__ C, int M, int N, int K)
{
    __shared__ float sA[2][2048];
    __shared__ float sB[2][2048];

    const int tid = threadIdx.x;
    const int lane = tid & 31;
    const int wid = tid >> 5;
    const int wm = wid >> 2;
    const int wn = wid & 3;
    const int NCH = K >> 4;

    const float4* Ag = reinterpret_cast<const float4*>(Afr) + (size_t)blockIdx.y * NCH * 512;
    const float4* Bg = reinterpret_cast<const float4*>(Bfr) + (size_t)blockIdx.x * NCH * 512;

    float acc[4][4][4] = {};
    float4 pa0, pa1, pb0, pb1;

    pa0 = Ag[tid];        pa1 = Ag[tid + 256];
    pb0 = Bg[tid];        pb1 = Bg[tid + 256];
    {
        float4* a4 = reinterpret_cast<float4*>(sA[0]);
        float4* b4 = reinterpret_cast<float4*>(sB[0]);
        a4[tid] = pa0; a4[tid + 256] = pa1;
        b4[tid] = pb0; b4[tid + 256] = pb1;
    }
    __syncthreads();

    for (int c = 0; c < NCH; c++) {
        const int buf = c & 1;
        if (c + 1 < NCH) {
            pa0 = Ag[(c + 1) * 512 + tid];  pa1 = Ag[(c + 1) * 512 + tid + 256];
            pb0 = Bg[(c + 1) * 512 + tid];  pb1 = Bg[(c + 1) * 512 + tid + 256];
        }
        const float4* A4 = reinterpret_cast<const float4*>(sA[buf]);
        const float2* B2 = reinterpret_cast<const float2*>(sB[buf]);
#pragma unroll
        for (int k8 = 0; k8 < 2; k8++) {
            float4 af[4];
            float2 bf[4];
#pragma unroll
            for (int mf = 0; mf < 4; mf++)
                af[mf] = A4[(k8 * 8 + wm * 4 + mf) * 32 + lane];
#pragma unroll
            for (int nf = 0; nf < 4; nf++)
                bf[nf] = B2[(k8 * 16 + wn * 4 + nf) * 32 + lane];
#pragma unroll
            for (int mf = 0; mf < 4; mf++)
#pragma unroll
                for (int nf = 0; nf < 4; nf++)
                    mma_tf32(acc[mf][nf],
                             reinterpret_cast<const uint32_t*>(&af[mf]),
                             reinterpret_cast<const uint32_t*>(&bf[nf]));
        }
        if (c + 1 < NCH) {
            const int nb = (c + 1) & 1;
            float4* a4 = reinterpret_cast<float4*>(sA[nb]);
            float4* b4 = reinterpret_cast<float4*>(sB[nb]);
            a4[tid] = pa0; a4[tid + 256] = pa1;
            b4[tid] = pb0; b4[tid + 256] = pb1;
        }
        __syncthreads();
    }

    const int row0 = blockIdx.y * 128;
    const int col0 = blockIdx.x * 128;
    const int gid = lane >> 2, tig = lane & 3;
#pragma unroll
    for (int mf = 0; mf < 4; mf++) {
#pragma unroll
        for (int nf = 0; nf < 4; nf++) {
            int m = row0 + wm * 64 + mf * 16 + gid;
            int n = col0 + wn * 32 + nf * 8 + tig * 2;
            float2 lo = make_float2(acc[mf][nf][0], acc[mf][nf][1]);
            float2 hi = make_float2(acc[mf][nf][2], acc[mf][nf][3]);
            *reinterpret_cast<float2*>(&C[(size_t)m * N + n]) = lo;
            *reinterpret_cast<float2*>(&C[(size_t)(m + 8) * N + n]) = hi;
        }
    }
}

// ---------------- importance GEMM: fp32 split-K (top-k needs fp32) -----------
__global__ void __launch_bounds__(256) imp_gemm_kernel(
    const float* __restrict__ A, const float* __restrict__ B, float* __restrict__ Cp)
{
    __shared__ float As[16][64];
    __shared__ float Bs[16][64];
    const int tid = threadIdx.x;
    const int row0 = blockIdx.y * 64;
    const int z = blockIdx.z;
    const float* Ab = A + (size_t)row0 * HID + z * 512;
    const float* Bb = B + (size_t)z * 512 * 64;
    float acc[4][4] = {};
    const int tc = (tid & 15) * 4, tr = (tid >> 4) * 4;
    const int ar = tid >> 2, ac = (tid & 3) * 4;
    const int br = tid >> 4, bc = (tid & 15) * 4;

    for (int k0 = 0; k0 < 512; k0 += 16) {
        float4 va = *reinterpret_cast<const float4*>(Ab + (size_t)ar * HID + k0 + ac);
        As[ac + 0][ar] = va.x; As[ac + 1][ar] = va.y;
        As[ac + 2][ar] = va.z; As[ac + 3][ar] = va.w;
        float4 vb = *reinterpret_cast<const float4*>(Bb + (size_t)(k0 + br) * 64 + bc);
        *reinterpret_cast<float4*>(&Bs[br][bc]) = vb;
        __syncthreads();
#pragma unroll
        for (int k = 0; k < 16; k++) {
            float ra[4], rb[4];
#pragma unroll
            for (int m = 0; m < 4; m++) ra[m] = As[k][tr + m];
#pragma unroll
            for (int n = 0; n < 4; n++) rb[n] = Bs[k][tc + n];
#pragma unroll
            for (int m = 0; m < 4; m++)
#pragma unroll
                for (int n = 0; n < 4; n++) acc[m][n] += ra[m] * rb[n];
        }
        __syncthreads();
    }
#pragma unroll
    for (int m = 0; m < 4; m++) {
        float4 v = make_float4(acc[m][0], acc[m][1], acc[m][2], acc[m][3]);
        *reinterpret_cast<float4*>(&Cp[((size_t)z * SEQ + row0 + tr + m) * 64 + tc]) = v;
    }
}

// ---------------- importance logits epilogue ----------------
__global__ void imp_logits_kernel(const float* __restrict__ T, const float* __restrict__ b1,
                                  const float* __restrict__ w2, const float* __restrict__ b2,
                                  float* __restrict__ logits, float* __restrict__ weights) {
    const float LOG_ADJ = 2.5494451709255714f;   // log(8192/640)
    int s = blockIdx.x;
    int j = threadIdx.x;  // 32
    float v1 = 0.f, v2 = 0.f;
#pragma unroll
    for (int z = 0; z < 4; z++) {
        v1 += T[((size_t)z * SEQ + s) * 64 + j];
        v2 += T[((size_t)z * SEQ + s) * 64 + j + 32];
    }
    float v = tanhf(v1 + b1[j]) * w2[j] + tanhf(v2 + b1[j + 32]) * w2[j + 32];
#pragma unroll
    for (int o = 16; o > 0; o >>= 1) v += __shfl_xor_sync(0xffffffffu, v, o);
    if (j == 0) {
        float lg = v + b2[0] - LOG_ADJ;
        logits[s] = lg;
        weights[s] = 1.0f / (1.0f + expf(-lg));
    }
}

// ---------------- RMSNorm ----------------
__global__ void rmsnorm_kernel(float* __restrict__ X, const float* __restrict__ w) {
    size_t row = blockIdx.x;
    int d = threadIdx.x;   // 128
    float x = X[row * DH + d];
    float ss = x * x;
#pragma unroll
    for (int o = 16; o > 0; o >>= 1) ss += __shfl_xor_sync(0xffffffffu, ss, o);
    __shared__ float sm[4];
    if ((d & 31) == 0) sm[d >> 5] = ss;
    __syncthreads();
    float tot = sm[0] + sm[1] + sm[2] + sm[3];
    X[row * DH + d] = x * rsqrtf(tot * (1.0f / 128.0f) + 1e-6f) * w[d];
}

// ---------------- top-k via single-block bitonic sort ----------------
__global__ void topk_kernel(const float* __restrict__ logits,
                            int* __restrict__ topk_list, int* __restrict__ is_topk) {
    extern __shared__ unsigned long long skeys[];
    int tid = threadIdx.x;  // 1024
    for (int i = tid; i < SEQ; i += 1024) {
        unsigned u = __float_as_uint(logits[i]);
        u = (u & 0x80000000u) ? ~u : (u | 0x80000000u);
        skeys[i] = ((unsigned long long)(~u) << 32) | (unsigned)i;
        is_topk[i] = 0;
    }
    __syncthreads();
    for (int k = 2; k <= SEQ; k <<= 1) {
        for (int j = k >> 1; j > 0; j >>= 1) {
            for (int i = tid; i < SEQ; i += 1024) {
                int ixj = i ^ j;
                if (ixj > i) {
                    bool up = ((i & k) == 0);
                    unsigned long long a = skeys[i], b = skeys[ixj];
                    if ((a > b) == up) { skeys[i] = b; skeys[ixj] = a; }
                }
            }
            __syncthreads();
        }
    }
    for (int i = tid; i < TK; i += 1024) {
        int pos = (int)(skeys[i] & 0xffffffffu);
        topk_list[i] = pos;
        is_topk[pos] = 1;
    }
}

// ---------------- sketch stage A ----------------
__global__ void sketchA_kernel(const float* __restrict__ X, int heads,
                               const float* __restrict__ weights,
                               const int* __restrict__ is_topk, int rest,
                               const float* __restrict__ kb, float* __restrict__ P) {
    int h = blockIdx.x;
    int ib = blockIdx.y;   // 0..31
    int d = threadIdx.x;   // 128
    __shared__ float kbs[32 * 256];
    for (int t = d; t < 32 * 256; t += 128) kbs[t] = kb[t];
    __shared__ float ws[256];
    for (int j = d; j < 256; j += 128) {
        int t = ib * 256 + j;
        float w = weights[t];
        if (rest && is_topk[t]) w = 0.0f;
        ws[j] = w;
    }
    __syncthreads();
    float acc[32] = {};
    for (int j = 0; j < 256; j++) {
        float xv = X[((size_t)(ib * 256 + j) * heads + h) * DH + d] * ws[j];
#pragma unroll
        for (int kbo = 0; kbo < 32; kbo++) acc[kbo] += xv * kbs[kbo * 256 + j];
    }
#pragma unroll
    for (int kbo = 0; kbo < 32; kbo++)
        P[(((size_t)h * 32 + kbo) * 32 + ib) * DH + d] = acc[kbo];
}

// ---------------- sketch stage B ----------------
__global__ void sketchB_kernel(const float* __restrict__ P, int heads,
                               const float* __restrict__ ka,
                               const float* __restrict__ scale_p,
                               float* __restrict__ dstfrag, int mode) {
    int h = blockIdx.x;
    int kbo = blockIdx.y;
    int d = threadIdx.x;   // 128
    __shared__ float kas[20 * 32];
    for (int t = d; t < 20 * 32; t += 128) kas[t] = ka[(t / 32) * DH + (t % 32)];
    __syncthreads();
    float p[32];
#pragma unroll
    for (int i = 0; i < 32; i++) p[i] = P[(((size_t)h * 32 + kbo) * 32 + i) * DH + d];
    float scale = scale_p[0];
    if (mode == 0) scale *= ATT_SCALE;
#pragma unroll
    for (int kao = 0; kao < 20; kao++) {
        float acc = 0.f;
#pragma unroll
        for (int i = 0; i < 32; i++) acc += p[i] * kas[kao * 32 + i];
        int s = TK + kbo * 20 + kao;
        float val = acc * scale;
        if (mode == 0)      store_qfrag(dstfrag, h, s, d, val);
        else if (mode == 1) store_kfrag(dstfrag, h, s, d, val);
        else                store_vfrag(dstfrag, h, s, d, val);
    }
}

// ---------------- gather + RoPE for top-k rows -> mma fragments ----------------
__global__ void gather_rope_kernel(const float* __restrict__ q, const float* __restrict__ k,
                                   const float* __restrict__ v,
                                   const float* __restrict__ cosb, const float* __restrict__ sinb,
                                   const int* __restrict__ topk_list,
                                   float* __restrict__ Qfr, float* __restrict__ Kfr,
                                   float* __restrict__ Vfr) {
    int j = blockIdx.x;    // 0..2047
    int hy = blockIdx.y;   // 0..23
    int d = threadIdx.x;
    int pos = topk_list[j];
    float c = cosb[(size_t)pos * DH + d];
    float s = sinb[(size_t)pos * DH + d];
    if (hy < 16) {
        const float* src = q + ((size_t)pos * NH + hy) * DH;
        float x = src[d];
        float r = (d < 64) ? -src[d + 64] : src[d - 64];
        store_qfrag(Qfr, hy, j, d, (x * c + r * s) * ATT_SCALE);
    } else if (hy < 20) {
        int h = hy - 16;
        const float* src = k + ((size_t)pos * NKV + h) * DH;
        float x = src[d];
        float r = (d < 64) ? -src[d + 64] : src[d - 64];
        store_kfrag(Kfr, h, j, d, x * c + r * s);
    } else {
        int h = hy - 20;
        store_vfrag(Vfr, h, j, d, v[((size_t)pos * NKV + h) * DH + d]);
    }
}

// ---------------- tensor-core flash attention ----------------
#define FA2_SMEM ((16384 + 8192 + 8192 + 8192 + 512) * 4)
__global__ void __launch_bounds__(256, 1) fa_mma_kernel(
    const float* __restrict__ Qfr, const float* __restrict__ Kfr,
    const float* __restrict__ Vfr, float* __restrict__ AO)
{
    extern __shared__ float fsm[];
    float* Qsm = fsm;
    float* Ksm = Qsm + 16384;
    float* Vsm = Ksm + 8192;
    float* Psm = Vsm + 8192;
    float* mpart = Psm + 8192;
    float* spart = mpart + 256;

    const int qt = blockIdx.x;
    const int h  = blockIdx.y;
    const int kvh = h >> 2;
    const int tid = threadIdx.x;
    const int lane = tid & 31, wid = tid >> 5;
    const int wm = wid >> 1, wn = wid & 1;
    const int gid = lane >> 2, tig = lane & 3;

    {
        const float4* Qg = reinterpret_cast<const float4*>(Qfr + (size_t)(h * NQT + qt) * 16384);
        float4* Qs4w = reinterpret_cast<float4*>(Qsm);
#pragma unroll
        for (int i = 0; i < 16; i++) Qs4w[tid + i * 256] = Qg[tid + i * 256];
    }

    float m_old[2][2], l_run[2][2];
#pragma unroll
    for (int a = 0; a < 2; a++)
#pragma unroll
        for (int b = 0; b < 2; b++) { m_old[a][b] = -1e30f; l_run[a][b] = 0.f; }
    float oacc[2][8][4] = {};

    const float4* Qs4 = reinterpret_cast<const float4*>(Qsm);
    const float2* Ks2 = reinterpret_cast<const float2*>(Ksm);
    const float2* Vs2 = reinterpret_cast<const float2*>(Vsm);
    const float4* Ps4 = reinterpret_cast<const float4*>(Psm);

    for (int kt = 0; kt < NKT; kt++) {
        {
            const float4* Kg = reinterpret_cast<const float4*>(Kfr + (size_t)(kvh * NKT + kt) * 8192);
            const float4* Vg = reinterpret_cast<const float4*>(Vfr + (size_t)(kvh * NKT + kt) * 8192);
            float4* Ks4w = reinterpret_cast<float4*>(Ksm);
            float4* Vs4w = reinterpret_cast<float4*>(Vsm);
#pragma unroll
            for (int i = 0; i < 8; i++) Ks4w[tid + i * 256] = Kg[tid + i * 256];
#pragma unroll
            for (int i = 0; i < 8; i++) Vs4w[tid + i * 256] = Vg[tid + i * 256];
        }
        __syncthreads();

        float sacc[2][4][4] = {};
#pragma unroll
        for (int k8 = 0; k8 < 16; k8++) {
            float4 af[2];
            float2 bf[4];
            af[0] = Qs4[(k8 * 8 + wm * 2 + 0) * 32 + lane];
            af[1] = Qs4[(k8 * 8 + wm * 2 + 1) * 32 + lane];
#pragma unroll
            for (int nf = 0; nf < 4; nf++) bf[nf] = Ks2[(k8 * 8 + wn * 4 + nf) * 32 + lane];
#pragma unroll
            for (int mf = 0; mf < 2; mf++)
#pragma unroll
                for (int nf = 0; nf < 4; nf++)
                    mma_tf32(sacc[mf][nf],
                             reinterpret_cast<const uint32_t*>(&af[mf]),
                             reinterpret_cast<const uint32_t*>(&bf[nf]));
        }

        float mloc[2][2];
#pragma unroll
        for (int mf = 0; mf < 2; mf++) {
            float m0 = fmaxf(sacc[mf][0][0], sacc[mf][0][1]);
            float m1 = fmaxf(sacc[mf][0][2], sacc[mf][0][3]);
#pragma unroll
            for (int nf = 1; nf < 4; nf++) {
                m0 = fmaxf(m0, fmaxf(sacc[mf][nf][0], sacc[mf][nf][1]));
                m1 = fmaxf(m1, fmaxf(sacc[mf][nf][2], sacc[mf][nf][3]));
            }
            m0 = fmaxf(m0, __shfl_xor_sync(0xffffffffu, m0, 1));
            m0 = fmaxf(m0, __shfl_xor_sync(0xffffffffu, m0, 2));
            m1 = fmaxf(m1, __shfl_xor_sync(0xffffffffu, m1, 1));
            m1 = fmaxf(m1, __shfl_xor_sync(0xffffffffu, m1, 2));
            mloc[mf][0] = m0; mloc[mf][1] = m1;
        }
        if (tig == 0) {
#pragma unroll
            for (int mf = 0; mf < 2; mf++) {
                int r = wm * 32 + mf * 16 + gid;
                mpart[wn * 128 + r] = mloc[mf][0];
                mpart[wn * 128 + r + 8] = mloc[mf][1];
            }
        }
        __syncthreads();

        float mnew[2][2], corr[2][2];
#pragma unroll
        for (int mf = 0; mf < 2; mf++)
#pragma unroll
            for (int hi = 0; hi < 2; hi++) {
                int r = wm * 32 + mf * 16 + gid + hi * 8;
                float mt = fmaxf(mpart[r], mpart[128 + r]);
                float mn = fmaxf(m_old[mf][hi], mt);
                corr[mf][hi] = __expf(m_old[mf][hi] - mn);
                mnew[mf][hi] = mn;
                m_old[mf][hi] = mn;
            }

        float sloc[2][2] = {};
#pragma unroll
        for (int mf = 0; mf < 2; mf++)
#pragma unroll
            for (int nf = 0; nf < 4; nf++) {
                sacc[mf][nf][0] = __expf(sacc[mf][nf][0] - mnew[mf][0]);
                sacc[mf][nf][1] = __expf(sacc[mf][nf][1] - mnew[mf][0]);
                sacc[mf][nf][2] = __expf(sacc[mf][nf][2] - mnew[mf][1]);
                sacc[mf][nf][3] = __expf(sacc[mf][nf][3] - mnew[mf][1]);
                sloc[mf][0] += sacc[mf][nf][0] + sacc[mf][nf][1];
                sloc[mf][1] += sacc[mf][nf][2] + sacc[mf][nf][3];
            }
#pragma unroll
        for (int mf = 0; mf < 2; mf++) {
            sloc[mf][0] += __shfl_xor_sync(0xffffffffu, sloc[mf][0], 1);
            sloc[mf][0] += __shfl_xor_sync(0xffffffffu, sloc[mf][0], 2);
            sloc[mf][1] += __shfl_xor_sync(0xffffffffu, sloc[mf][1], 1);
            sloc[mf][1] += __shfl_xor_sync(0xffffffffu, sloc[mf][1], 2);
        }
        if (tig == 0) {
#pragma unroll
            for (int mf = 0; mf < 2; mf++) {
                int r = wm * 32 + mf * 16 + gid;
                spart[wn * 128 + r] = sloc[mf][0];
                spart[wn * 128 + r + 8] = sloc[mf][1];
            }
        }

#pragma unroll
        for (int mf = 0; mf < 2; mf++)
#pragma unroll
            for (int nf = 0; nf < 4; nf++) {
                int k8p = wn * 4 + nf;
                int mfg = wm * 2 + mf;
#pragma unroll
                for (int b = 0; b < 2; b++) {
                    int c = tig * 2 + b;
                    int khi = (c >= 4);
                    int base = ((k8p * 8 + mfg) * 32 + (gid << 2) + (c & 3)) * 4 + khi * 2;
                    *reinterpret_cast<float2*>(Psm + base) =
                        make_float2(tf32f(sacc[mf][nf][b]), tf32f(sacc[mf][nf][2 + b]));
                }
            }
        __syncthreads();

#pragma unroll
        for (int mf = 0; mf < 2; mf++)
#pragma unroll
            for (int hi = 0; hi < 2; hi++) {
                int r = wm * 32 + mf * 16 + gid + hi * 8;
                l_run[mf][hi] = l_run[mf][hi] * corr[mf][hi] + spart[r] + spart[128 + r];
            }
#pragma unroll
        for (int mf = 0; mf < 2; mf++)
#pragma unroll
            for (int nf = 0; nf < 8; nf++) {
                oacc[mf][nf][0] *= corr[mf][0]; oacc[mf][nf][1] *= corr[mf][0];
                oacc[mf][nf][2] *= corr[mf][1]; oacc[mf][nf][3] *= corr[mf][1];
            }

#pragma unroll
        for (int k8 = 0; k8 < 8; k8++) {
            float4 af[2];
            af[0] = Ps4[(k8 * 8 + wm * 2 + 0) * 32 + lane];
            af[1] = Ps4[(k8 * 8 + wm * 2 + 1) * 32 + lane];
#pragma unroll
            for (int nf = 0; nf < 8; nf++) {
                float2 bf = Vs2[(k8 * 16 + wn * 8 + nf) * 32 + lane];
#pragma unroll
                for (int mf = 0; mf < 2; mf++)
                    mma_tf32(oacc[mf][nf],
                             reinterpret_cast<const uint32_t*>(&af[mf]),
                             reinterpret_cast<const uint32_t*>(&bf));
            }
        }
        __syncthreads();
    }

#pragma unroll
    for (int mf = 0; mf < 2; mf++) {
        float inv0 = 1.0f / l_run[mf][0];
        float inv1 = 1.0f / l_run[mf][1];
        int r0 = qt * 128 + wm * 32 + mf * 16 + gid;
#pragma unroll
        for (int nf = 0; nf < 8; nf++) {
            int col = wn * 64 + nf * 8 + tig * 2;
            *reinterpret_cast<float2*>(&AO[((size_t)r0 * NH + h) * DH + col]) =
                make_float2(oacc[mf][nf][0] * inv0, oacc[mf][nf][1] * inv0);
            *reinterpret_cast<float2*>(&AO[((size_t)(r0 + 8) * NH + h) * DH + col]) =
                make_float2(oacc[mf][nf][2] * inv1, oacc[mf][nf][3] * inv1);
        }
    }
}

// ---------------- expand stage C ----------------
__global__ void expandC_kernel(const float* __restrict__ AO, const float* __restrict__ ka,
                               float* __restrict__ E1) {
    int i = blockIdx.y;
    int hd = blockIdx.x * 256 + threadIdx.x;
    __shared__ float kav[20];
    if (threadIdx.x < 20) kav[threadIdx.x] = ka[threadIdx.x * DH + i];
    __syncthreads();
    for (int kbo = 0; kbo < 32; kbo++) {
        float acc = 0.f;
#pragma unroll
        for (int kao = 0; kao < 20; kao++)
            acc += AO[((size_t)(TK + kbo * 20 + kao)) * HID + hd] * kav[kao];
        E1[((size_t)i * 32 + kbo) * HID + hd] = acc;
    }
}

// ---------------- expand stage D ----------------
__global__ void expandD_kernel(const float* __restrict__ E1, const float* __restrict__ kb,
                               float* __restrict__ FULL) {
    int i = blockIdx.y;
    int hd = blockIdx.x * 128 + threadIdx.x;
    __shared__ float kbs[32 * 256];
    for (int t = threadIdx.x; t < 32 * 256; t += 128) kbs[t] = kb[t];
    float e[32];
#pragma unroll
    for (int kbo = 0; kbo < 32; kbo++) e[kbo] = E1[((size_t)i * 32 + kbo) * HID + hd];
    __syncthreads();
    for (int j = 0; j < 256; j++) {
        float acc = 0.f;
#pragma unroll
        for (int kbo = 0; kbo < 32; kbo++) acc += e[kbo] * kbs[kbo * 256 + j];
        FULL[((size_t)(i * 256 + j)) * HID + hd] = acc;
    }
}

// ---------------- scatter deterministic rows ----------------
__global__ void scatter_det_kernel(const float* __restrict__ AO, const int* __restrict__ topk_list,
                                   float* __restrict__ FULL) {
    int j = blockIdx.x;
    int pos = topk_list[j];
    for (int t = threadIdx.x; t < HID; t += blockDim.x)
        FULL[(size_t)pos * HID + t] = AO[(size_t)j * HID + t];
}

// ---------------- host launcher ----------------
extern "C" void kernel_launch(void* const* d_in, const int* in_sizes, int n_in,
                              void* d_out, int out_size) {
    const float* hs    = (const float*)d_in[0];
    const float* cosb  = (const float*)d_in[1];
    const float* sinb  = (const float*)d_in[2];
    const float* wq    = (const float*)d_in[3];
    const float* wk    = (const float*)d_in[4];
    const float* wv    = (const float*)d_in[5];
    const float* wo    = (const float*)d_in[6];
    const float* qnw   = (const float*)d_in[7];
    const float* knw   = (const float*)d_in[8];
    const float* w1    = (const float*)d_in[9];
    const float* b1    = (const float*)d_in[10];
    const float* w2    = (const float*)d_in[11];
    const float* b2    = (const float*)d_in[12];
    const float* ka    = (const float*)d_in[13];
    const float* kb    = (const float*)d_in[14];
    const float* sscale= (const float*)d_in[15];
    float* out = (float*)d_out;

    float *pT, *pLg, *pW, *pQ, *pK, *pV, *pP, *pQfr, *pKfr, *pVfr, *pAO, *pE1, *pFULL, *pAfr, *pBfr;
    int *pTop, *pIs;
    cudaGetSymbolAddress((void**)&pT, g_T);
    cudaGetSymbolAddress((void**)&pLg, g_logits);
    cudaGetSymbolAddress((void**)&pW, g_weights);
    cudaGetSymbolAddress((void**)&pQ, g_q);
    cudaGetSymbolAddress((void**)&pK, g_k);
    cudaGetSymbolAddress((void**)&pV, g_v);
    cudaGetSymbolAddress((void**)&pP, g_P);
    cudaGetSymbolAddress((void**)&pQfr, g_Qfr);
    cudaGetSymbolAddress((void**)&pKfr, g_Kfr);
    cudaGetSymbolAddress((void**)&pVfr, g_Vfr);
    cudaGetSymbolAddress((void**)&pAO, g_AO);
    cudaGetSymbolAddress((void**)&pE1, g_E1);
    cudaGetSymbolAddress((void**)&pFULL, g_FULL);
    cudaGetSymbolAddress((void**)&pAfr, g_Afr);
    cudaGetSymbolAddress((void**)&pBfr, g_Bfr);
    cudaGetSymbolAddress((void**)&pTop, g_topk);
    cudaGetSymbolAddress((void**)&pIs, g_istop);

    cudaFuncSetAttribute(topk_kernel, cudaFuncAttributeMaxDynamicSharedMemorySize, SEQ * 8);
    cudaFuncSetAttribute(fa_mma_kernel, cudaFuncAttributeMaxDynamicSharedMemorySize, FA2_SMEM);

    // 1) importance MLP first GEMM — fp32 split-K x4 (feeds top-k)
    imp_gemm_kernel<<<dim3(1, SEQ / 64, 4), 256>>>(hs, w1, pT);
    // 2) logits + weights
    imp_logits_kernel<<<SEQ, 32>>>(pT, b1, w2, b2, pLg, pW);
    // 3) convert hs to A-fragments (shared by wq/wk/wv)
    convA_kernel<<<dim3(HID / 16, SEQ / 128), 256>>>(hs, pAfr, HID);
    // 4-6) QKV projections — tf32 mma.sync on pre-fragmented operands
    convB_kernel<<<dim3(HID / 16, HID / 128), 256>>>(wq, pBfr, HID, HID);
    mma_gemm_kernel<<<dim3(HID / 128, SEQ / 128), 256>>>(pAfr, pBfr, pQ, SEQ, HID, HID);
    convB_kernel<<<dim3(HID / 16, 512 / 128), 256>>>(wk, pBfr, HID, 512);
    mma_gemm_kernel<<<dim3(512 / 128, SEQ / 128), 256>>>(pAfr, pBfr, pK, SEQ, 512, HID);
    convB_kernel<<<dim3(HID / 16, 512 / 128), 256>>>(wv, pBfr, HID, 512);
    mma_gemm_kernel<<<dim3(512 / 128, SEQ / 128), 256>>>(pAfr, pBfr, pV, SEQ, 512, HID);
    // 7-8) RMSNorm q, k
    rmsnorm_kernel<<<SEQ * NH, DH>>>(pQ, qnw);
    rmsnorm_kernel<<<SEQ * NKV, DH>>>(pK, knw);
    // 9) top-k selection
    topk_kernel<<<1, 1024, SEQ * 8>>>(pLg, pTop, pIs);
    // 10-15) sketches -> fragment buffers
    sketchA_kernel<<<dim3(NH, 32), DH>>>(pQ, NH, pW, pIs, 0, kb, pP);
    sketchB_kernel<<<dim3(NH, 32), DH>>>(pP, NH, ka, sscale, pQfr, 0);
    sketchA_kernel<<<dim3(NKV, 32), DH>>>(pK, NKV, pW, pIs, 1, kb, pP);
    sketchB_kernel<<<dim3(NKV, 32), DH>>>(pP, NKV, ka, sscale, pKfr, 1);
    sketchA_kernel<<<dim3(NKV, 32), DH>>>(pV, NKV, pW, pIs, 1, kb, pP);
    sketchB_kernel<<<dim3(NKV, 32), DH>>>(pP, NKV, ka, sscale, pVfr, 2);
    // 16) gather top-k rows + RoPE -> fragment buffers
    gather_rope_kernel<<<dim3(TK, 24), DH>>>(pQ, pK, pV, cosb, sinb, pTop, pQfr, pKfr, pVfr);
    // 17) attention — tensor-core FA2
    fa_mma_kernel<<<dim3(NQT, NH), 256, FA2_SMEM>>>(pQfr, pKfr, pVfr, pAO);
    // 18-19) expand sketch part of attention output
    expandC_kernel<<<dim3(HID / 256, 32), 256>>>(pAO, ka, pE1);
    expandD_kernel<<<dim3(HID / 128, 32), DH>>>(pE1, kb, pFULL);
    // 20) overwrite top-k positions with deterministic attention output
    scatter_det_kernel<<<TK, 256>>>(pAO, pTop, pFULL);
    // 21) output projection — convert FULL (reuse Afr) then GEMM
    convA_kernel<<<dim3(HID / 16, SEQ / 128), 256>>>(pFULL, pAfr, HID);
    convB_kernel<<<dim3(HID / 16, HID / 128), 256>>>(wo, pBfr, HID, HID);
    mma_gemm_kernel<<<dim3(HID / 128, SEQ / 128), 256>>>(pAfr, pBfr, out, SEQ, HID, HID);
}

// round 6
// speedup vs baseline: 3.0884x; 1.0501x over previous
#include <cuda_runtime.h>
#include <cuda_bf16.h>
#include <math.h>
#include <cstdint>

// Problem constants
#define SEQ   8192
#define HID   2048
#define NH    16
#define NKV   4
#define DH    128
#define TK    2048
#define SK    640
#define NQF   (TK + SK)        // 2688
#define NQT   (NQF / 128)      // 21 q tiles
#define NKT   (NQF / 64)       // 42 key tiles
#define ATT_SCALE 0.08838834764831843f   // 1/sqrt(128)

// ---------------- scratch (device globals; no allocation) ----------------
__device__ float g_T[8 * SEQ * 64];        // split-K partials
__device__ float g_logits[SEQ];
__device__ float g_weights[SEQ];
__device__ float g_q[SEQ * NH * DH];       // normalized q  [s][h][d]
__device__ float g_kv[SEQ * 1024];         // fused k(0:512)|v(512:1024) per row
__device__ int   g_topk[TK];
__device__ int   g_istop[SEQ];
__device__ float g_P[NH * 32 * 32 * DH];   // sketch stage-A scratch
__device__ float g_Qfr[NH * NQT * 16 * 8 * 32 * 4];    // Q mma-fragments
__device__ float g_Kfr[NKV * NKT * 16 * 8 * 32 * 2];   // K mma-fragments
__device__ float g_Vfr[NKV * NKT * 8 * 16 * 32 * 2];   // V mma-fragments
__device__ float g_AO[NQF * NH * DH];      // attention output [q][h][d]
__device__ float g_E1[32 * 32 * HID];      // expand stage-C scratch [i][kb][hd]
__device__ float g_Z[SK * HID];            // sketch-part @ wo
__device__ float g_Afr[SEQ * HID];         // A fragments (hs / AO)
__device__ float g_Bfr[HID * HID];         // B fragments (weights)

// ======================= tf32 mma.sync helpers =======================
__device__ __forceinline__ float tf32f(float x) {
    uint32_t r; asm("cvt.rna.tf32.f32 %0, %1;" : "=r"(r) : "f"(x));
    return __uint_as_float(r);
}

__device__ __forceinline__ void mma_tf32(float* c, const uint32_t* a, const uint32_t* b) {
    asm volatile("mma.sync.aligned.m16n8k8.row.col.f32.tf32.tf32.f32 "
        "{%0,%1,%2,%3}, {%4,%5,%6,%7}, {%8,%9}, {%0,%1,%2,%3};"
        : "+f"(c[0]), "+f"(c[1]), "+f"(c[2]), "+f"(c[3])
        : "r"(a[0]), "r"(a[1]), "r"(a[2]), "r"(a[3]), "r"(b[0]), "r"(b[1]));
}

// fragment-layout gmem stores for attention operands
__device__ __forceinline__ void store_qfrag(float* Qg, int h, int tok, int d, float v) {
    int qt = tok >> 7, m = tok & 127;
    int k8 = d >> 3, mf = m >> 4;
    int lane = ((m & 7) << 2) | (d & 3);
    int reg = 2 * ((d & 7) >= 4) + ((m & 15) >= 8);
    size_t idx = ((((size_t)(h * NQT + qt) * 16 + k8) * 8 + mf) * 32 + lane) * 4 + reg;
    Qg[idx] = tf32f(v);
}
__device__ __forceinline__ void store_kfrag(float* Kg, int kvh, int tok, int d, float v) {
    int kt = tok >> 6, key = tok & 63;
    int k8 = d >> 3, nf = key >> 3;
    int lane = ((key & 7) << 2) | (d & 3);
    int reg = ((d & 7) >= 4);
    size_t idx = ((((size_t)(kvh * NKT + kt) * 16 + k8) * 8 + nf) * 32 + lane) * 2 + reg;
    Kg[idx] = tf32f(v);
}
__device__ __forceinline__ void store_vfrag(float* Vg, int kvh, int tok, int d, float v) {
    int kt = tok >> 6, key = tok & 63;
    int k8 = key >> 3, nf = d >> 3;
    int lane = ((d & 7) << 2) | (key & 3);
    int reg = ((key & 7) >= 4);
    size_t idx = ((((size_t)(kvh * NKT + kt) * 8 + k8) * 16 + nf) * 32 + lane) * 2 + reg;
    Vg[idx] = tf32f(v);
}

// ======================= fragment conversion pre-passes =======================
// A[M][K] row-major -> A-fragment-major: [(rt*(K/16)+c)*2048] blocks
__global__ void __launch_bounds__(256) convA_kernel(const float* __restrict__ A,
                                                    float* __restrict__ Afr, int K) {
    __shared__ float sm[2048];
    const int rt = blockIdx.y, c = blockIdx.x;
    const int tid = threadIdx.x;
    const float* Ab = A + ((size_t)rt * 128) * K + c * 16;
#pragma unroll
    for (int i = 0; i < 2; i++) {
        int f = tid + i * 256;
        int r = f >> 2, c4 = f & 3;
        float4 v = *reinterpret_cast<const float4*>(Ab + (size_t)r * K + c4 * 4);
        int mf = r >> 4, gid = r & 7, mhi = (r >> 3) & 1;
        float vv[4] = {v.x, v.y, v.z, v.w};
#pragma unroll
        for (int j = 0; j < 4; j++) {
            int k = c4 * 4 + j;
            int slot = ((k >> 3) * 8 + mf) * 128 + ((gid << 2) | (k & 3)) * 4
                     + 2 * ((k & 7) >= 4) + mhi;
            sm[slot] = tf32f(vv[j]);
        }
    }
    __syncthreads();
    float4* out = reinterpret_cast<float4*>(Afr + ((size_t)(rt * (K >> 4) + c)) * 2048);
    const float4* s4 = reinterpret_cast<const float4*>(sm);
#pragma unroll
    for (int i = 0; i < 2; i++) out[tid + i * 256] = s4[tid + i * 256];
}

// B[K][N] row-major -> B-fragment-major per 128-col tile (ct = blockIdx.y + ctbase)
__global__ void __launch_bounds__(256) convB_kernel(const float* __restrict__ B,
                                                    float* __restrict__ Bfr, int K, int N,
                                                    int ctbase) {
    __shared__ float sm[2048];
    const int ct = blockIdx.y + ctbase, c = blockIdx.x;
    const int tid = threadIdx.x;
    const float* Bb = B + ((size_t)(c * 16)) * N + blockIdx.y * 128;
#pragma unroll
    for (int i = 0; i < 2; i++) {
        int f = tid + i * 256;
        int kk = f >> 5, n4 = f & 31;
        float4 v = *reinterpret_cast<const float4*>(Bb + (size_t)kk * N + n4 * 4);
        int k8in = kk >> 3, reg = ((kk & 7) >= 4);
        float vv[4] = {v.x, v.y, v.z, v.w};
#pragma unroll
        for (int j = 0; j < 4; j++) {
            int n = n4 * 4 + j;
            int slot = (k8in * 16 + (n >> 3)) * 64 + (((n & 7) << 2) | (kk & 3)) * 2 + reg;
            sm[slot] = tf32f(vv[j]);
        }
    }
    __syncthreads();
    float4* out = reinterpret_cast<float4*>(Bfr + ((size_t)(ct * (K >> 4) + c)) * 2048);
    const float4* s4 = reinterpret_cast<const float4*>(sm);
#pragma unroll
    for (int i = 0; i < 2; i++) out[tid + i * 256] = s4[tid + i * 256];
}

// ======================= tf32 GEMM: CTA 128x256, warp 64x64, BK=16 ============
// C[m][n] (+ optional row remap) = A @ B^T from fragment-major gmem.
#define GEMM_SMEM (12288 * 4)
__global__ void __launch_bounds__(256) mma_gemm_kernel(
    const float* __restrict__ Afr, const float* __restrict__ Bfr,
    float* __restrict__ C, const int* __restrict__ remap, int N, int K)
{
    extern __shared__ float gs[];
    float* sA = gs;             // [2][2048]
    float* sB = gs + 4096;      // [2][4096] : ct0 block then ct1 block

    const int tid = threadIdx.x;
    const int lane = tid & 31, wid = tid >> 5;
    const int wm = wid >> 2, wn = wid & 3;
    const int NCH = K >> 4;

    const float4* Ag  = reinterpret_cast<const float4*>(Afr) + (size_t)blockIdx.y * NCH * 512;
    const float4* Bg0 = reinterpret_cast<const float4*>(Bfr) + (size_t)(2 * blockIdx.x) * NCH * 512;
    const float4* Bg1 = reinterpret_cast<const float4*>(Bfr) + (size_t)(2 * blockIdx.x + 1) * NCH * 512;

    float acc[4][8][4] = {};
    float4 pa0, pa1, pb0, pb1, pb2, pb3;

    pa0 = Ag[tid];        pa1 = Ag[tid + 256];
    pb0 = Bg0[tid];       pb1 = Bg0[tid + 256];
    pb2 = Bg1[tid];       pb3 = Bg1[tid + 256];
    {
        float4* a4 = reinterpret_cast<float4*>(sA);
        float4* b4 = reinterpret_cast<float4*>(sB);
        a4[tid] = pa0; a4[tid + 256] = pa1;
        b4[tid] = pb0; b4[tid + 256] = pb1;
        b4[tid + 512] = pb2; b4[tid + 768] = pb3;
    }
    __syncthreads();

    const int nfb = (wn & 1) * 8;
    for (int c = 0; c < NCH; c++) {
        const int buf = c & 1;
        if (c + 1 < NCH) {
            pa0 = Ag[(c + 1) * 512 + tid];   pa1 = Ag[(c + 1) * 512 + tid + 256];
            pb0 = Bg0[(c + 1) * 512 + tid];  pb1 = Bg0[(c + 1) * 512 + tid + 256];
            pb2 = Bg1[(c + 1) * 512 + tid];  pb3 = Bg1[(c + 1) * 512 + tid + 256];
        }
        const float4* A4 = reinterpret_cast<const float4*>(sA + buf * 2048);
        const float2* B2 = reinterpret_cast<const float2*>(sB + buf * 4096 + (wn >> 1) * 2048);
#pragma unroll
        for (int k8 = 0; k8 < 2; k8++) {
            float4 af[4];
            float2 bf[8];
#pragma unroll
            for (int mf = 0; mf < 4; mf++)
                af[mf] = A4[(k8 * 8 + wm * 4 + mf) * 32 + lane];
#pragma unroll
            for (int nf = 0; nf < 8; nf++)
                bf[nf] = B2[(k8 * 16 + nfb + nf) * 32 + lane];
#pragma unroll
            for (int mf = 0; mf < 4; mf++)
#pragma unroll
                for (int nf = 0; nf < 8; nf++)
                    mma_tf32(acc[mf][nf],
                             reinterpret_cast<const uint32_t*>(&af[mf]),
                             reinterpret_cast<const uint32_t*>(&bf[nf]));
        }
        if (c + 1 < NCH) {
            const int nb = (c + 1) & 1;
            float4* a4 = reinterpret_cast<float4*>(sA + nb * 2048);
            float4* b4 = reinterpret_cast<float4*>(sB + nb * 4096);
            a4[tid] = pa0; a4[tid + 256] = pa1;
            b4[tid] = pb0; b4[tid + 256] = pb1;
            b4[tid + 512] = pb2; b4[tid + 768] = pb3;
        }
        __syncthreads();
    }

    const int row0 = blockIdx.y * 128;
    const int col0 = blockIdx.x * 256;
    const int gid = lane >> 2, tig = lane & 3;
#pragma unroll
    for (int mf = 0; mf < 4; mf++) {
        int m = row0 + wm * 64 + mf * 16 + gid;
        int m1 = remap ? __ldg(&remap[m]) : m;
        int m2 = remap ? __ldg(&remap[m + 8]) : (m + 8);
#pragma unroll
        for (int nf = 0; nf < 8; nf++) {
            int n = col0 + wn * 64 + nf * 8 + tig * 2;
            *reinterpret_cast<float2*>(&C[(size_t)m1 * N + n]) =
                make_float2(acc[mf][nf][0], acc[mf][nf][1]);
            *reinterpret_cast<float2*>(&C[(size_t)m2 * N + n]) =
                make_float2(acc[mf][nf][2], acc[mf][nf][3]);
        }
    }
}

// ---------------- importance GEMM: fp32 split-K x8 (top-k needs fp32) -----------
__global__ void __launch_bounds__(256) imp_gemm_kernel(
    const float* __restrict__ A, const float* __restrict__ B, float* __restrict__ Cp)
{
    __shared__ float As[16][64];
    __shared__ float Bs[16][64];
    const int tid = threadIdx.x;
    const int row0 = blockIdx.y * 64;
    const int z = blockIdx.z;
    const float* Ab = A + (size_t)row0 * HID + z * 256;
    const float* Bb = B + (size_t)z * 256 * 64;
    float acc[4][4] = {};
    const int tc = (tid & 15) * 4, tr = (tid >> 4) * 4;
    const int ar = tid >> 2, ac = (tid & 3) * 4;
    const int br = tid >> 4, bc = (tid & 15) * 4;

    for (int k0 = 0; k0 < 256; k0 += 16) {
        float4 va = *reinterpret_cast<const float4*>(Ab + (size_t)ar * HID + k0 + ac);
        As[ac + 0][ar] = va.x; As[ac + 1][ar] = va.y;
        As[ac + 2][ar] = va.z; As[ac + 3][ar] = va.w;
        float4 vb = *reinterpret_cast<const float4*>(Bb + (size_t)(k0 + br) * 64 + bc);
        *reinterpret_cast<float4*>(&Bs[br][bc]) = vb;
        __syncthreads();
#pragma unroll
        for (int k = 0; k < 16; k++) {
            float ra[4], rb[4];
#pragma unroll
            for (int m = 0; m < 4; m++) ra[m] = As[k][tr + m];
#pragma unroll
            for (int n = 0; n < 4; n++) rb[n] = Bs[k][tc + n];
#pragma unroll
            for (int m = 0; m < 4; m++)
#pragma unroll
                for (int n = 0; n < 4; n++) acc[m][n] += ra[m] * rb[n];
        }
        __syncthreads();
    }
#pragma unroll
    for (int m = 0; m < 4; m++) {
        float4 v = make_float4(acc[m][0], acc[m][1], acc[m][2], acc[m][3]);
        *reinterpret_cast<float4*>(&Cp[((size_t)z * SEQ + row0 + tr + m) * 64 + tc]) = v;
    }
}

// ---------------- importance logits epilogue ----------------
__global__ void imp_logits_kernel(const float* __restrict__ T, const float* __restrict__ b1,
                                  const float* __restrict__ w2, const float* __restrict__ b2,
                                  float* __restrict__ logits, float* __restrict__ weights) {
    const float LOG_ADJ = 2.5494451709255714f;   // log(8192/640)
    int s = blockIdx.x;
    int j = threadIdx.x;  // 32
    float v1 = 0.f, v2 = 0.f;
#pragma unroll
    for (int z = 0; z < 8; z++) {
        v1 += T[((size_t)z * SEQ + s) * 64 + j];
        v2 += T[((size_t)z * SEQ + s) * 64 + j + 32];
    }
    float v = tanhf(v1 + b1[j]) * w2[j] + tanhf(v2 + b1[j + 32]) * w2[j + 32];
#pragma unroll
    for (int o = 16; o > 0; o >>= 1) v += __shfl_xor_sync(0xffffffffu, v, o);
    if (j == 0) {
        float lg = v + b2[0] - LOG_ADJ;
        logits[s] = lg;
        weights[s] = 1.0f / (1.0f + expf(-lg));
    }
}

// ---------------- RMSNorm (generic head addressing) ----------------
__global__ void rmsnorm_kernel(float* __restrict__ X, const float* __restrict__ w,
                               int stride, int nh) {
    int r = blockIdx.x;
    int s = r / nh, h = r % nh;
    float* row = X + (size_t)s * stride + h * DH;
    int d = threadIdx.x;   // 128
    float x = row[d];
    float ss = x * x;
#pragma unroll
    for (int o = 16; o > 0; o >>= 1) ss += __shfl_xor_sync(0xffffffffu, ss, o);
    __shared__ float sm[4];
    if ((d & 31) == 0) sm[d >> 5] = ss;
    __syncthreads();
    float tot = sm[0] + sm[1] + sm[2] + sm[3];
    row[d] = x * rsqrtf(tot * (1.0f / 128.0f) + 1e-6f) * w[d];
}

// ---------------- top-k via single-block bitonic sort ----------------
__global__ void topk_kernel(const float* __restrict__ logits,
                            int* __restrict__ topk_list, int* __restrict__ is_topk) {
    extern __shared__ unsigned long long skeys[];
    int tid = threadIdx.x;  // 1024
    for (int i = tid; i < SEQ; i += 1024) {
        unsigned u = __float_as_uint(logits[i]);
        u = (u & 0x80000000u) ? ~u : (u | 0x80000000u);
        skeys[i] = ((unsigned long long)(~u) << 32) | (unsigned)i;
        is_topk[i] = 0;
    }
    __syncthreads();
    for (int k = 2; k <= SEQ; k <<= 1) {
        for (int j = k >> 1; j > 0; j >>= 1) {
            for (int i = tid; i < SEQ; i += 1024) {
                int ixj = i ^ j;
                if (ixj > i) {
                    bool up = ((i & k) == 0);
                    unsigned long long a = skeys[i], b = skeys[ixj];
                    if ((a > b) == up) { skeys[i] = b; skeys[ixj] = a; }
                }
            }
            __syncthreads();
        }
    }
    for (int i = tid; i < TK; i += 1024) {
        int pos = (int)(skeys[i] & 0xffffffffu);
        topk_list[i] = pos;
        is_topk[pos] = 1;
    }
}

// ---------------- sketch stage A (generic head addressing) ----------------
__global__ void sketchA_kernel(const float* __restrict__ X, int hstride, int hbase,
                               const float* __restrict__ weights,
                               const int* __restrict__ is_topk, int rest,
                               const float* __restrict__ kb, float* __restrict__ P) {
    int h = blockIdx.x;
    int ib = blockIdx.y;   // 0..31
    int d = threadIdx.x;   // 128
    __shared__ float kbs[32 * 256];
    for (int t = d; t < 32 * 256; t += 128) kbs[t] = kb[t];
    __shared__ float ws[256];
    for (int j = d; j < 256; j += 128) {
        int t = ib * 256 + j;
        float w = weights[t];
        if (rest && is_topk[t]) w = 0.0f;
        ws[j] = w;
    }
    __syncthreads();
    float acc[32] = {};
    for (int j = 0; j < 256; j++) {
        float xv = X[((size_t)(ib * 256 + j) * hstride + hbase + h) * DH + d] * ws[j];
#pragma unroll
        for (int kbo = 0; kbo < 32; kbo++) acc[kbo] += xv * kbs[kbo * 256 + j];
    }
#pragma unroll
    for (int kbo = 0; kbo < 32; kbo++)
        P[(((size_t)h * 32 + kbo) * 32 + ib) * DH + d] = acc[kbo];
}

// ---------------- sketch stage B ----------------
__global__ void sketchB_kernel(const float* __restrict__ P, int heads,
                               const float* __restrict__ ka,
                               const float* __restrict__ scale_p,
                               float* __restrict__ dstfrag, int mode) {
    int h = blockIdx.x;
    int kbo = blockIdx.y;
    int d = threadIdx.x;   // 128
    __shared__ float kas[20 * 32];
    for (int t = d; t < 20 * 32; t += 128) kas[t] = ka[(t / 32) * DH + (t % 32)];
    __syncthreads();
    float p[32];
#pragma unroll
    for (int i = 0; i < 32; i++) p[i] = P[(((size_t)h * 32 + kbo) * 32 + i) * DH + d];
    float scale = scale_p[0];
    if (mode == 0) scale *= ATT_SCALE;
#pragma unroll
    for (int kao = 0; kao < 20; kao++) {
        float acc = 0.f;
#pragma unroll
        for (int i = 0; i < 32; i++) acc += p[i] * kas[kao * 32 + i];
        int s = TK + kbo * 20 + kao;
        float val = acc * scale;
        if (mode == 0)      store_qfrag(dstfrag, h, s, d, val);
        else if (mode == 1) store_kfrag(dstfrag, h, s, d, val);
        else                store_vfrag(dstfrag, h, s, d, val);
    }
}

// ---------------- gather + RoPE for top-k rows -> mma fragments ----------------
__global__ void gather_rope_kernel(const float* __restrict__ q, const float* __restrict__ kv,
                                   const float* __restrict__ cosb, const float* __restrict__ sinb,
                                   const int* __restrict__ topk_list,
                                   float* __restrict__ Qfr, float* __restrict__ Kfr,
                                   float* __restrict__ Vfr) {
    int j = blockIdx.x;    // 0..2047
    int hy = blockIdx.y;   // 0..23
    int d = threadIdx.x;
    int pos = topk_list[j];
    float c = cosb[(size_t)pos * DH + d];
    float s = sinb[(size_t)pos * DH + d];
    if (hy < 16) {
        const float* src = q + ((size_t)pos * NH + hy) * DH;
        float x = src[d];
        float r = (d < 64) ? -src[d + 64] : src[d - 64];
        store_qfrag(Qfr, hy, j, d, (x * c + r * s) * ATT_SCALE);
    } else if (hy < 20) {
        int h = hy - 16;
        const float* src = kv + (size_t)pos * 1024 + h * DH;
        float x = src[d];
        float r = (d < 64) ? -src[d + 64] : src[d - 64];
        store_kfrag(Kfr, h, j, d, x * c + r * s);
    } else {
        int h = hy - 20;
        store_vfrag(Vfr, h, j, d, kv[(size_t)pos * 1024 + 512 + h * DH + d]);
    }
}

// ---------------- tensor-core flash attention ----------------
#define FA2_SMEM ((16384 + 8192 + 8192 + 8192 + 512) * 4)
__global__ void __launch_bounds__(256, 1) fa_mma_kernel(
    const float* __restrict__ Qfr, const float* __restrict__ Kfr,
    const float* __restrict__ Vfr, float* __restrict__ AO)
{
    extern __shared__ float fsm[];
    float* Qsm = fsm;
    float* Ksm = Qsm + 16384;
    float* Vsm = Ksm + 8192;
    float* Psm = Vsm + 8192;
    float* mpart = Psm + 8192;
    float* spart = mpart + 256;

    const int qt = blockIdx.x;
    const int h  = blockIdx.y;
    const int kvh = h >> 2;
    const int tid = threadIdx.x;
    const int lane = tid & 31, wid = tid >> 5;
    const int wm = wid >> 1, wn = wid & 1;
    const int gid = lane >> 2, tig = lane & 3;

    {
        const float4* Qg = reinterpret_cast<const float4*>(Qfr + (size_t)(h * NQT + qt) * 16384);
        float4* Qs4w = reinterpret_cast<float4*>(Qsm);
#pragma unroll
        for (int i = 0; i < 16; i++) Qs4w[tid + i * 256] = Qg[tid + i * 256];
    }

    float m_old[2][2], l_run[2][2];
#pragma unroll
    for (int a = 0; a < 2; a++)
#pragma unroll
        for (int b = 0; b < 2; b++) { m_old[a][b] = -1e30f; l_run[a][b] = 0.f; }
    float oacc[2][8][4] = {};

    const float4* Qs4 = reinterpret_cast<const float4*>(Qsm);
    const float2* Ks2 = reinterpret_cast<const float2*>(Ksm);
    const float2* Vs2 = reinterpret_cast<const float2*>(Vsm);
    const float4* Ps4 = reinterpret_cast<const float4*>(Psm);

    for (int kt = 0; kt < NKT; kt++) {
        {
            const float4* Kg = reinterpret_cast<const float4*>(Kfr + (size_t)(kvh * NKT + kt) * 8192);
            const float4* Vg = reinterpret_cast<const float4*>(Vfr + (size_t)(kvh * NKT + kt) * 8192);
            float4* Ks4w = reinterpret_cast<float4*>(Ksm);
            float4* Vs4w = reinterpret_cast<float4*>(Vsm);
#pragma unroll
            for (int i = 0; i < 8; i++) Ks4w[tid + i * 256] = Kg[tid + i * 256];
#pragma unroll
            for (int i = 0; i < 8; i++) Vs4w[tid + i * 256] = Vg[tid + i * 256];
        }
        __syncthreads();

        float sacc[2][4][4] = {};
#pragma unroll
        for (int k8 = 0; k8 < 16; k8++) {
            float4 af[2];
            float2 bf[4];
            af[0] = Qs4[(k8 * 8 + wm * 2 + 0) * 32 + lane];
            af[1] = Qs4[(k8 * 8 + wm * 2 + 1) * 32 + lane];
#pragma unroll
            for (int nf = 0; nf < 4; nf++) bf[nf] = Ks2[(k8 * 8 + wn * 4 + nf) * 32 + lane];
#pragma unroll
            for (int mf = 0; mf < 2; mf++)
#pragma unroll
                for (int nf = 0; nf < 4; nf++)
                    mma_tf32(sacc[mf][nf],
                             reinterpret_cast<const uint32_t*>(&af[mf]),
                             reinterpret_cast<const uint32_t*>(&bf[nf]));
        }

        float mloc[2][2];
#pragma unroll
        for (int mf = 0; mf < 2; mf++) {
            float m0 = fmaxf(sacc[mf][0][0], sacc[mf][0][1]);
            float m1 = fmaxf(sacc[mf][0][2], sacc[mf][0][3]);
#pragma unroll
            for (int nf = 1; nf < 4; nf++) {
                m0 = fmaxf(m0, fmaxf(sacc[mf][nf][0], sacc[mf][nf][1]));
                m1 = fmaxf(m1, fmaxf(sacc[mf][nf][2], sacc[mf][nf][3]));
            }
            m0 = fmaxf(m0, __shfl_xor_sync(0xffffffffu, m0, 1));
            m0 = fmaxf(m0, __shfl_xor_sync(0xffffffffu, m0, 2));
            m1 = fmaxf(m1, __shfl_xor_sync(0xffffffffu, m1, 1));
            m1 = fmaxf(m1, __shfl_xor_sync(0xffffffffu, m1, 2));
            mloc[mf][0] = m0; mloc[mf][1] = m1;
        }
        if (tig == 0) {
#pragma unroll
            for (int mf = 0; mf < 2; mf++) {
                int r = wm * 32 + mf * 16 + gid;
                mpart[wn * 128 + r] = mloc[mf][0];
                mpart[wn * 128 + r + 8] = mloc[mf][1];
            }
        }
        __syncthreads();

        float mnew[2][2], corr[2][2];
#pragma unroll
        for (int mf = 0; mf < 2; mf++)
#pragma unroll
            for (int hi = 0; hi < 2; hi++) {
                int r = wm * 32 + mf * 16 + gid + hi * 8;
                float mt = fmaxf(mpart[r], mpart[128 + r]);
                float mn = fmaxf(m_old[mf][hi], mt);
                corr[mf][hi] = __expf(m_old[mf][hi] - mn);
                mnew[mf][hi] = mn;
                m_old[mf][hi] = mn;
            }

        float sloc[2][2] = {};
#pragma unroll
        for (int mf = 0; mf < 2; mf++)
#pragma unroll
            for (int nf = 0; nf < 4; nf++) {
                sacc[mf][nf][0] = __expf(sacc[mf][nf][0] - mnew[mf][0]);
                sacc[mf][nf][1] = __expf(sacc[mf][nf][1] - mnew[mf][0]);
                sacc[mf][nf][2] = __expf(sacc[mf][nf][2] - mnew[mf][1]);
                sacc[mf][nf][3] = __expf(sacc[mf][nf][3] - mnew[mf][1]);
                sloc[mf][0] += sacc[mf][nf][0] + sacc[mf][nf][1];
                sloc[mf][1] += sacc[mf][nf][2] + sacc[mf][nf][3];
            }
#pragma unroll
        for (int mf = 0; mf < 2; mf++) {
            sloc[mf][0] += __shfl_xor_sync(0xffffffffu, sloc[mf][0], 1);
            sloc[mf][0] += __shfl_xor_sync(0xffffffffu, sloc[mf][0], 2);
            sloc[mf][1] += __shfl_xor_sync(0xffffffffu, sloc[mf][1], 1);
            sloc[mf][1] += __shfl_xor_sync(0xffffffffu, sloc[mf][1], 2);
        }
        if (tig == 0) {
#pragma unroll
            for (int mf = 0; mf < 2; mf++) {
                int r = wm * 32 + mf * 16 + gid;
                spart[wn * 128 + r] = sloc[mf][0];
                spart[wn * 128 + r + 8] = sloc[mf][1];
            }
        }

#pragma unroll
        for (int mf = 0; mf < 2; mf++)
#pragma unroll
            for (int nf = 0; nf < 4; nf++) {
                int k8p = wn * 4 + nf;
                int mfg = wm * 2 + mf;
#pragma unroll
                for (int b = 0; b < 2; b++) {
                    int c = tig * 2 + b;
                    int khi = (c >= 4);
                    int base = ((k8p * 8 + mfg) * 32 + (gid << 2) + (c & 3)) * 4 + khi * 2;
                    *reinterpret_cast<float2*>(Psm + base) =
                        make_float2(tf32f(sacc[mf][nf][b]), tf32f(sacc[mf][nf][2 + b]));
                }
            }
        __syncthreads();

#pragma unroll
        for (int mf = 0; mf < 2; mf++)
#pragma unroll
            for (int hi = 0; hi < 2; hi++) {
                int r = wm * 32 + mf * 16 + gid + hi * 8;
                l_run[mf][hi] = l_run[mf][hi] * corr[mf][hi] + spart[r] + spart[128 + r];
            }
#pragma unroll
        for (int mf = 0; mf < 2; mf++)
#pragma unroll
            for (int nf = 0; nf < 8; nf++) {
                oacc[mf][nf][0] *= corr[mf][0]; oacc[mf][nf][1] *= corr[mf][0];
                oacc[mf][nf][2] *= corr[mf][1]; oacc[mf][nf][3] *= corr[mf][1];
            }

#pragma unroll
        for (int k8 = 0; k8 < 8; k8++) {
            float4 af[2];
            af[0] = Ps4[(k8 * 8 + wm * 2 + 0) * 32 + lane];
            af[1] = Ps4[(k8 * 8 + wm * 2 + 1) * 32 + lane];
#pragma unroll
            for (int nf = 0; nf < 8; nf++) {
                float2 bf = Vs2[(k8 * 16 + wn * 8 + nf) * 32 + lane];
#pragma unroll
                for (int mf = 0; mf < 2; mf++)
                    mma_tf32(oacc[mf][nf],
                             reinterpret_cast<const uint32_t*>(&af[mf]),
                             reinterpret_cast<const uint32_t*>(&bf));
            }
        }
        __syncthreads();
    }

#pragma unroll
    for (int mf = 0; mf < 2; mf++) {
        float inv0 = 1.0f / l_run[mf][0];
        float inv1 = 1.0f / l_run[mf][1];
        int r0 = qt * 128 + wm * 32 + mf * 16 + gid;
#pragma unroll
        for (int nf = 0; nf < 8; nf++) {
            int col = wn * 64 + nf * 8 + tig * 2;
            *reinterpret_cast<float2*>(&AO[((size_t)r0 * NH + h) * DH + col]) =
                make_float2(oacc[mf][nf][0] * inv0, oacc[mf][nf][1] * inv0);
            *reinterpret_cast<float2*>(&AO[((size_t)(r0 + 8) * NH + h) * DH + col]) =
                make_float2(oacc[mf][nf][2] * inv1, oacc[mf][nf][3] * inv1);
        }
    }
}

// ---------------- expand stage C (reads Z = AO_sk @ wo) ----------------
__global__ void expandC_kernel(const float* __restrict__ Z, const float* __restrict__ ka,
                               float* __restrict__ E1) {
    int i = blockIdx.y;
    int hd = blockIdx.x * 256 + threadIdx.x;
    __shared__ float kav[20];
    if (threadIdx.x < 20) kav[threadIdx.x] = ka[threadIdx.x * DH + i];
    __syncthreads();
    for (int kbo = 0; kbo < 32; kbo++) {
        float acc = 0.f;
#pragma unroll
        for (int kao = 0; kao < 20; kao++)
            acc += Z[((size_t)(kbo * 20 + kao)) * HID + hd] * kav[kao];
        E1[((size_t)i * 32 + kbo) * HID + hd] = acc;
    }
}

// ---------------- expand stage D (writes final out rows) ----------------
__global__ void expandD_kernel(const float* __restrict__ E1, const float* __restrict__ kb,
                               float* __restrict__ OUT) {
    int i = blockIdx.y;
    int hd = blockIdx.x * 128 + threadIdx.x;
    __shared__ float kbs[32 * 256];
    for (int t = threadIdx.x; t < 32 * 256; t += 128) kbs[t] = kb[t];
    float e[32];
#pragma unroll
    for (int kbo = 0; kbo < 32; kbo++) e[kbo] = E1[((size_t)i * 32 + kbo) * HID + hd];
    __syncthreads();
    for (int j = 0; j < 256; j++) {
        float acc = 0.f;
#pragma unroll
        for (int kbo = 0; kbo < 32; kbo++) acc += e[kbo] * kbs[kbo * 256 + j];
        OUT[((size_t)(i * 256 + j)) * HID + hd] = acc;
    }
}

// ---------------- host launcher ----------------
extern "C" void kernel_launch(void* const* d_in, const int* in_sizes, int n_in,
                              void* d_out, int out_size) {
    const float* hs    = (const float*)d_in[0];
    const float* cosb  = (const float*)d_in[1];
    const float* sinb  = (const float*)d_in[2];
    const float* wq    = (const float*)d_in[3];
    const float* wk    = (const float*)d_in[4];
    const float* wv    = (const float*)d_in[5];
    const float* wo    = (const float*)d_in[6];
    const float* qnw   = (const float*)d_in[7];
    const float* knw   = (const float*)d_in[8];
    const float* w1    = (const float*)d_in[9];
    const float* b1    = (const float*)d_in[10];
    const float* w2    = (const float*)d_in[11];
    const float* b2    = (const float*)d_in[12];
    const float* ka    = (const float*)d_in[13];
    const float* kb    = (const float*)d_in[14];
    const float* sscale= (const float*)d_in[15];
    float* out = (float*)d_out;

    float *pT, *pLg, *pW, *pQ, *pKV, *pP, *pQfr, *pKfr, *pVfr, *pAO, *pE1, *pZ, *pAfr, *pBfr;
    int *pTop, *pIs;
    cudaGetSymbolAddress((void**)&pT, g_T);
    cudaGetSymbolAddress((void**)&pLg, g_logits);
    cudaGetSymbolAddress((void**)&pW, g_weights);
    cudaGetSymbolAddress((void**)&pQ, g_q);
    cudaGetSymbolAddress((void**)&pKV, g_kv);
    cudaGetSymbolAddress((void**)&pP, g_P);
    cudaGetSymbolAddress((void**)&pQfr, g_Qfr);
    cudaGetSymbolAddress((void**)&pKfr, g_Kfr);
    cudaGetSymbolAddress((void**)&pVfr, g_Vfr);
    cudaGetSymbolAddress((void**)&pAO, g_AO);
    cudaGetSymbolAddress((void**)&pE1, g_E1);
    cudaGetSymbolAddress((void**)&pZ, g_Z);
    cudaGetSymbolAddress((void**)&pAfr, g_Afr);
    cudaGetSymbolAddress((void**)&pBfr, g_Bfr);
    cudaGetSymbolAddress((void**)&pTop, g_topk);
    cudaGetSymbolAddress((void**)&pIs, g_istop);

    cudaFuncSetAttribute(topk_kernel, cudaFuncAttributeMaxDynamicSharedMemorySize, SEQ * 8);
    cudaFuncSetAttribute(fa_mma_kernel, cudaFuncAttributeMaxDynamicSharedMemorySize, FA2_SMEM);
    cudaFuncSetAttribute(mma_gemm_kernel, cudaFuncAttributeMaxDynamicSharedMemorySize, GEMM_SMEM);

    // 1) importance MLP first GEMM — fp32 split-K x8 (feeds top-k)
    imp_gemm_kernel<<<dim3(1, SEQ / 64, 8), 256>>>(hs, w1, pT);
    imp_logits_kernel<<<SEQ, 32>>>(pT, b1, w2, b2, pLg, pW);
    // 2) convert hs to A-fragments (shared by q and kv GEMMs)
    convA_kernel<<<dim3(HID / 16, SEQ / 128), 256>>>(hs, pAfr, HID);
    // 3) Q projection
    convB_kernel<<<dim3(HID / 16, HID / 128), 256>>>(wq, pBfr, HID, HID, 0);
    mma_gemm_kernel<<<dim3(HID / 256, SEQ / 128), 256, GEMM_SMEM>>>(pAfr, pBfr, pQ, nullptr, HID, HID);
    // 4) fused K|V projection (N=1024)
    convB_kernel<<<dim3(HID / 16, 512 / 128), 256>>>(wk, pBfr, HID, 512, 0);
    convB_kernel<<<dim3(HID / 16, 512 / 128), 256>>>(wv, pBfr, HID, 512, 4);
    mma_gemm_kernel<<<dim3(1024 / 256, SEQ / 128), 256, GEMM_SMEM>>>(pAfr, pBfr, pKV, nullptr, 1024, HID);
    // 5) RMSNorm q, k
    rmsnorm_kernel<<<SEQ * NH, DH>>>(pQ, qnw, HID, NH);
    rmsnorm_kernel<<<SEQ * NKV, DH>>>(pKV, knw, 1024, NKV);
    // 6) top-k selection
    topk_kernel<<<1, 1024, SEQ * 8>>>(pLg, pTop, pIs);
    // 7) sketches -> fragment buffers
    sketchA_kernel<<<dim3(NH, 32), DH>>>(pQ, 16, 0, pW, pIs, 0, kb, pP);
    sketchB_kernel<<<dim3(NH, 32), DH>>>(pP, NH, ka, sscale, pQfr, 0);
    sketchA_kernel<<<dim3(NKV, 32), DH>>>(pKV, 8, 0, pW, pIs, 1, kb, pP);
    sketchB_kernel<<<dim3(NKV, 32), DH>>>(pP, NKV, ka, sscale, pKfr, 1);
    sketchA_kernel<<<dim3(NKV, 32), DH>>>(pKV, 8, 4, pW, pIs, 1, kb, pP);
    sketchB_kernel<<<dim3(NKV, 32), DH>>>(pP, NKV, ka, sscale, pVfr, 2);
    // 8) gather top-k rows + RoPE -> fragment buffers
    gather_rope_kernel<<<dim3(TK, 24), DH>>>(pQ, pKV, cosb, sinb, pTop, pQfr, pKfr, pVfr);
    // 9) attention — tensor-core FA2
    fa_mma_kernel<<<dim3(NQT, NH), 256, FA2_SMEM>>>(pQfr, pKfr, pVfr, pAO);
    // 10) convert AO (all 2688 rows) and wo
    convA_kernel<<<dim3(HID / 16, NQF / 128), 256>>>(pAO, pAfr, HID);
    convB_kernel<<<dim3(HID / 16, HID / 128), 256>>>(wo, pBfr, HID, HID, 0);
    // 11) Z = AO_sk @ wo  (rows 2048..2687 -> A-frag row tiles 16..20)
    mma_gemm_kernel<<<dim3(HID / 256, SK / 128), 256, GEMM_SMEM>>>(
        pAfr + (size_t)16 * (HID / 16) * 2048, pBfr, pZ, nullptr, HID, HID);
    // 12) expand Z to all positions, writing out directly
    expandC_kernel<<<dim3(HID / 256, 32), 256>>>(pZ, ka, pE1);
    expandD_kernel<<<dim3(HID / 128, 32), DH>>>(pE1, kb, out);
    // 13) deterministic rows: (AO_det @ wo) scattered to out[topk[m]]
    mma_gemm_kernel<<<dim3(HID / 256, TK / 128), 256, GEMM_SMEM>>>(pAfr, pBfr, out, pTop, HID, HID);
}

// round 7
// speedup vs baseline: 3.5065x; 1.1354x over previous
#include <cuda_runtime.h>
#include <cuda_bf16.h>
#include <math.h>
#include <cstdint>

// Problem constants
#define SEQ   8192
#define HID   2048
#define NH    16
#define NKV   4
#define DH    128
#define TK    2048
#define SK    640
#define NQF   (TK + SK)        // 2688
#define NQT   (NQF / 128)      // 21 q tiles
#define NKT   (NQF / 64)       // 42 key tiles
#define ATT_SCALE 0.08838834764831843f   // 1/sqrt(128)

// ---------------- scratch (device globals; no allocation) ----------------
__device__ float g_T[8 * SEQ * 64];        // split-K partials
__device__ float g_logits[SEQ];
__device__ float g_weights[SEQ];
__device__ float g_q[SEQ * NH * DH];       // normalized q  [s][h][d]
__device__ float g_kv[SEQ * 1024];         // fused k(0:512)|v(512:1024) per row
__device__ int   g_topk[TK];
__device__ int   g_istop[SEQ];
__device__ float g_P[NH * 32 * 32 * DH];   // sketch stage-A scratch
__device__ float g_Qfr[NH * NQT * 16 * 8 * 32 * 4];    // Q mma-fragments
__device__ float g_Kfr[NKV * NKT * 16 * 8 * 32 * 2];   // K mma-fragments
__device__ float g_Vfr[NKV * NKT * 8 * 16 * 32 * 2];   // V mma-fragments
__device__ float g_AO[NQF * NH * DH];      // attention output [q][h][d]
__device__ float g_E1[32 * 32 * HID];      // expand stage-C scratch [i][kb][hd]
__device__ float g_Z[SK * HID];            // sketch-part @ wo
__device__ float g_Afr[SEQ * HID];         // A fragments (hs / AO)
__device__ float g_Bfr[HID * HID];         // B fragments (weights)

// ======================= tf32 mma.sync helpers =======================
__device__ __forceinline__ float tf32f(float x) {
    uint32_t r; asm("cvt.rna.tf32.f32 %0, %1;" : "=r"(r) : "f"(x));
    return __uint_as_float(r);
}

__device__ __forceinline__ void mma_tf32(float* c, const uint32_t* a, const uint32_t* b) {
    asm volatile("mma.sync.aligned.m16n8k8.row.col.f32.tf32.tf32.f32 "
        "{%0,%1,%2,%3}, {%4,%5,%6,%7}, {%8,%9}, {%0,%1,%2,%3};"
        : "+f"(c[0]), "+f"(c[1]), "+f"(c[2]), "+f"(c[3])
        : "r"(a[0]), "r"(a[1]), "r"(a[2]), "r"(a[3]), "r"(b[0]), "r"(b[1]));
}

#define CP_ASYNC16(dst_u32, src_ptr) \
    asm volatile("cp.async.cg.shared.global [%0], [%1], 16;" :: "r"(dst_u32), "l"(src_ptr))
#define CP_COMMIT() asm volatile("cp.async.commit_group;")

// fragment-layout gmem stores for attention operands
__device__ __forceinline__ void store_qfrag(float* Qg, int h, int tok, int d, float v) {
    int qt = tok >> 7, m = tok & 127;
    int k8 = d >> 3, mf = m >> 4;
    int lane = ((m & 7) << 2) | (d & 3);
    int reg = 2 * ((d & 7) >= 4) + ((m & 15) >= 8);
    size_t idx = ((((size_t)(h * NQT + qt) * 16 + k8) * 8 + mf) * 32 + lane) * 4 + reg;
    Qg[idx] = tf32f(v);
}
__device__ __forceinline__ void store_kfrag(float* Kg, int kvh, int tok, int d, float v) {
    int kt = tok >> 6, key = tok & 63;
    int k8 = d >> 3, nf = key >> 3;
    int lane = ((key & 7) << 2) | (d & 3);
    int reg = ((d & 7) >= 4);
    size_t idx = ((((size_t)(kvh * NKT + kt) * 16 + k8) * 8 + nf) * 32 + lane) * 2 + reg;
    Kg[idx] = tf32f(v);
}
__device__ __forceinline__ void store_vfrag(float* Vg, int kvh, int tok, int d, float v) {
    int kt = tok >> 6, key = tok & 63;
    int k8 = key >> 3, nf = d >> 3;
    int lane = ((d & 7) << 2) | (key & 3);
    int reg = ((key & 7) >= 4);
    size_t idx = ((((size_t)(kvh * NKT + kt) * 8 + k8) * 16 + nf) * 32 + lane) * 2 + reg;
    Vg[idx] = tf32f(v);
}

// ======================= fragment conversion pre-passes =======================
__global__ void __launch_bounds__(256) convA_kernel(const float* __restrict__ A,
                                                    float* __restrict__ Afr, int K) {
    __shared__ float sm[2048];
    const int rt = blockIdx.y, c = blockIdx.x;
    const int tid = threadIdx.x;
    const float* Ab = A + ((size_t)rt * 128) * K + c * 16;
#pragma unroll
    for (int i = 0; i < 2; i++) {
        int f = tid + i * 256;
        int r = f >> 2, c4 = f & 3;
        float4 v = *reinterpret_cast<const float4*>(Ab + (size_t)r * K + c4 * 4);
        int mf = r >> 4, gid = r & 7, mhi = (r >> 3) & 1;
        float vv[4] = {v.x, v.y, v.z, v.w};
#pragma unroll
        for (int j = 0; j < 4; j++) {
            int k = c4 * 4 + j;
            int slot = ((k >> 3) * 8 + mf) * 128 + ((gid << 2) | (k & 3)) * 4
                     + 2 * ((k & 7) >= 4) + mhi;
            sm[slot] = tf32f(vv[j]);
        }
    }
    __syncthreads();
    float4* out = reinterpret_cast<float4*>(Afr + ((size_t)(rt * (K >> 4) + c)) * 2048);
    const float4* s4 = reinterpret_cast<const float4*>(sm);
#pragma unroll
    for (int i = 0; i < 2; i++) out[tid + i * 256] = s4[tid + i * 256];
}

__global__ void __launch_bounds__(256) convB_kernel(const float* __restrict__ B,
                                                    float* __restrict__ Bfr, int K, int N,
                                                    int ctbase) {
    __shared__ float sm[2048];
    const int ct = blockIdx.y + ctbase, c = blockIdx.x;
    const int tid = threadIdx.x;
    const float* Bb = B + ((size_t)(c * 16)) * N + blockIdx.y * 128;
#pragma unroll
    for (int i = 0; i < 2; i++) {
        int f = tid + i * 256;
        int kk = f >> 5, n4 = f & 31;
        float4 v = *reinterpret_cast<const float4*>(Bb + (size_t)kk * N + n4 * 4);
        int k8in = kk >> 3, reg = ((kk & 7) >= 4);
        float vv[4] = {v.x, v.y, v.z, v.w};
#pragma unroll
        for (int j = 0; j < 4; j++) {
            int n = n4 * 4 + j;
            int slot = (k8in * 16 + (n >> 3)) * 64 + (((n & 7) << 2) | (kk & 3)) * 2 + reg;
            sm[slot] = tf32f(vv[j]);
        }
    }
    __syncthreads();
    float4* out = reinterpret_cast<float4*>(Bfr + ((size_t)(ct * (K >> 4) + c)) * 2048);
    const float4* s4 = reinterpret_cast<const float4*>(sm);
#pragma unroll
    for (int i = 0; i < 2; i++) out[tid + i * 256] = s4[tid + i * 256];
}

// ======================= tf32 GEMM: CTA 128x128, cp.async 3-stage, 2 CTA/SM ========
__global__ void __launch_bounds__(256, 2) mma_gemm_kernel(
    const float* __restrict__ Afr, const float* __restrict__ Bfr,
    float* __restrict__ C, const int* __restrict__ remap, int N, int K)
{
    __shared__ float sA[3][2048];
    __shared__ float sB[3][2048];

    const int tid = threadIdx.x;
    const int lane = tid & 31, wid = tid >> 5;
    const int wm = wid >> 2, wn = wid & 3;
    const int NCH = K >> 4;

    const float4* Ag = reinterpret_cast<const float4*>(Afr) + (size_t)blockIdx.y * NCH * 512;
    const float4* Bg = reinterpret_cast<const float4*>(Bfr) + (size_t)blockIdx.x * NCH * 512;

    const uint32_t sAu = (uint32_t)__cvta_generic_to_shared(&sA[0][0]) + tid * 16;
    const uint32_t sBu = (uint32_t)__cvta_generic_to_shared(&sB[0][0]) + tid * 16;

    // prologue: stage chunks 0 and 1
    {
        const float4* ga = Ag + tid;  const float4* gb = Bg + tid;
        CP_ASYNC16(sAu, ga); CP_ASYNC16(sAu + 4096, ga + 256);
        CP_ASYNC16(sBu, gb); CP_ASYNC16(sBu + 4096, gb + 256);
        CP_COMMIT();
        if (NCH > 1) {
            ga += 512; gb += 512;
            CP_ASYNC16(sAu + 8192, ga); CP_ASYNC16(sAu + 8192 + 4096, ga + 256);
            CP_ASYNC16(sBu + 8192, gb); CP_ASYNC16(sBu + 8192 + 4096, gb + 256);
            CP_COMMIT();
        }
    }

    float acc[4][4][4] = {};
    for (int c = 0; c < NCH; c++) {
        if (c + 1 < NCH) asm volatile("cp.async.wait_group 1;");
        else             asm volatile("cp.async.wait_group 0;");
        __syncthreads();

        const int buf = c % 3;
        const float4* A4 = reinterpret_cast<const float4*>(sA[buf]);
        const float2* B2 = reinterpret_cast<const float2*>(sB[buf]);
#pragma unroll
        for (int k8 = 0; k8 < 2; k8++) {
            float4 af[4];
            float2 bf[4];
#pragma unroll
            for (int mf = 0; mf < 4; mf++)
                af[mf] = A4[(k8 * 8 + wm * 4 + mf) * 32 + lane];
#pragma unroll
            for (int nf = 0; nf < 4; nf++)
                bf[nf] = B2[(k8 * 16 + wn * 4 + nf) * 32 + lane];
#pragma unroll
            for (int mf = 0; mf < 4; mf++)
#pragma unroll
                for (int nf = 0; nf < 4; nf++)
                    mma_tf32(acc[mf][nf],
                             reinterpret_cast<const uint32_t*>(&af[mf]),
                             reinterpret_cast<const uint32_t*>(&bf[nf]));
        }
        // stage chunk c+2 into buf (c+2)%3 — last read at iter c-1, all warps past
        // the barrier at top of this iteration, so the buffer is free.
        if (c + 2 < NCH) {
            const int st = (c + 2) % 3;
            const float4* ga = Ag + (c + 2) * 512 + tid;
            const float4* gb = Bg + (c + 2) * 512 + tid;
            CP_ASYNC16(sAu + st * 8192, ga); CP_ASYNC16(sAu + st * 8192 + 4096, ga + 256);
            CP_ASYNC16(sBu + st * 8192, gb); CP_ASYNC16(sBu + st * 8192 + 4096, gb + 256);
            CP_COMMIT();
        }
    }

    const int row0 = blockIdx.y * 128;
    const int col0 = blockIdx.x * 128;
    const int gid = lane >> 2, tig = lane & 3;
#pragma unroll
    for (int mf = 0; mf < 4; mf++) {
        int m = row0 + wm * 64 + mf * 16 + gid;
        int m1 = remap ? __ldg(&remap[m]) : m;
        int m2 = remap ? __ldg(&remap[m + 8]) : (m + 8);
#pragma unroll
        for (int nf = 0; nf < 4; nf++) {
            int n = col0 + wn * 32 + nf * 8 + tig * 2;
            *reinterpret_cast<float2*>(&C[(size_t)m1 * N + n]) =
                make_float2(acc[mf][nf][0], acc[mf][nf][1]);
            *reinterpret_cast<float2*>(&C[(size_t)m2 * N + n]) =
                make_float2(acc[mf][nf][2], acc[mf][nf][3]);
        }
    }
}

// ---------------- importance GEMM: fp32 split-K x8 (top-k needs fp32) -----------
__global__ void __launch_bounds__(256) imp_gemm_kernel(
    const float* __restrict__ A, const float* __restrict__ B, float* __restrict__ Cp)
{
    __shared__ float As[16][64];
    __shared__ float Bs[16][64];
    const int tid = threadIdx.x;
    const int row0 = blockIdx.y * 64;
    const int z = blockIdx.z;
    const float* Ab = A + (size_t)row0 * HID + z * 256;
    const float* Bb = B + (size_t)z * 256 * 64;
    float acc[4][4] = {};
    const int tc = (tid & 15) * 4, tr = (tid >> 4) * 4;
    const int ar = tid >> 2, ac = (tid & 3) * 4;
    const int br = tid >> 4, bc = (tid & 15) * 4;

    for (int k0 = 0; k0 < 256; k0 += 16) {
        float4 va = *reinterpret_cast<const float4*>(Ab + (size_t)ar * HID + k0 + ac);
        As[ac + 0][ar] = va.x; As[ac + 1][ar] = va.y;
        As[ac + 2][ar] = va.z; As[ac + 3][ar] = va.w;
        float4 vb = *reinterpret_cast<const float4*>(Bb + (size_t)(k0 + br) * 64 + bc);
        *reinterpret_cast<float4*>(&Bs[br][bc]) = vb;
        __syncthreads();
#pragma unroll
        for (int k = 0; k < 16; k++) {
            float ra[4], rb[4];
#pragma unroll
            for (int m = 0; m < 4; m++) ra[m] = As[k][tr + m];
#pragma unroll
            for (int n = 0; n < 4; n++) rb[n] = Bs[k][tc + n];
#pragma unroll
            for (int m = 0; m < 4; m++)
#pragma unroll
                for (int n = 0; n < 4; n++) acc[m][n] += ra[m] * rb[n];
        }
        __syncthreads();
    }
#pragma unroll
    for (int m = 0; m < 4; m++) {
        float4 v = make_float4(acc[m][0], acc[m][1], acc[m][2], acc[m][3]);
        *reinterpret_cast<float4*>(&Cp[((size_t)z * SEQ + row0 + tr + m) * 64 + tc]) = v;
    }
}

// ---------------- importance logits epilogue ----------------
__global__ void imp_logits_kernel(const float* __restrict__ T, const float* __restrict__ b1,
                                  const float* __restrict__ w2, const float* __restrict__ b2,
                                  float* __restrict__ logits, float* __restrict__ weights) {
    const float LOG_ADJ = 2.5494451709255714f;   // log(8192/640)
    int s = blockIdx.x;
    int j = threadIdx.x;  // 32
    float v1 = 0.f, v2 = 0.f;
#pragma unroll
    for (int z = 0; z < 8; z++) {
        v1 += T[((size_t)z * SEQ + s) * 64 + j];
        v2 += T[((size_t)z * SEQ + s) * 64 + j + 32];
    }
    float v = tanhf(v1 + b1[j]) * w2[j] + tanhf(v2 + b1[j + 32]) * w2[j + 32];
#pragma unroll
    for (int o = 16; o > 0; o >>= 1) v += __shfl_xor_sync(0xffffffffu, v, o);
    if (j == 0) {
        float lg = v + b2[0] - LOG_ADJ;
        logits[s] = lg;
        weights[s] = 1.0f / (1.0f + expf(-lg));
    }
}

// ---------------- RMSNorm (generic head addressing) ----------------
__global__ void rmsnorm_kernel(float* __restrict__ X, const float* __restrict__ w,
                               int stride, int nh) {
    int r = blockIdx.x;
    int s = r / nh, h = r % nh;
    float* row = X + (size_t)s * stride + h * DH;
    int d = threadIdx.x;   // 128
    float x = row[d];
    float ss = x * x;
#pragma unroll
    for (int o = 16; o > 0; o >>= 1) ss += __shfl_xor_sync(0xffffffffu, ss, o);
    __shared__ float sm[4];
    if ((d & 31) == 0) sm[d >> 5] = ss;
    __syncthreads();
    float tot = sm[0] + sm[1] + sm[2] + sm[3];
    row[d] = x * rsqrtf(tot * (1.0f / 128.0f) + 1e-6f) * w[d];
}

// ---------------- top-k via single-block bitonic sort ----------------
__global__ void topk_kernel(const float* __restrict__ logits,
                            int* __restrict__ topk_list, int* __restrict__ is_topk) {
    extern __shared__ unsigned long long skeys[];
    int tid = threadIdx.x;  // 1024
    for (int i = tid; i < SEQ; i += 1024) {
        unsigned u = __float_as_uint(logits[i]);
        u = (u & 0x80000000u) ? ~u : (u | 0x80000000u);
        skeys[i] = ((unsigned long long)(~u) << 32) | (unsigned)i;
        is_topk[i] = 0;
    }
    __syncthreads();
    for (int k = 2; k <= SEQ; k <<= 1) {
        for (int j = k >> 1; j > 0; j >>= 1) {
            for (int i = tid; i < SEQ; i += 1024) {
                int ixj = i ^ j;
                if (ixj > i) {
                    bool up = ((i & k) == 0);
                    unsigned long long a = skeys[i], b = skeys[ixj];
                    if ((a > b) == up) { skeys[i] = b; skeys[ixj] = a; }
                }
            }
            __syncthreads();
        }
    }
    for (int i = tid; i < TK; i += 1024) {
        int pos = (int)(skeys[i] & 0xffffffffu);
        topk_list[i] = pos;
        is_topk[pos] = 1;
    }
}

// ---------------- sketch stage A (generic head addressing) ----------------
__global__ void sketchA_kernel(const float* __restrict__ X, int hstride, int hbase,
                               const float* __restrict__ weights,
                               const int* __restrict__ is_topk, int rest,
                               const float* __restrict__ kb, float* __restrict__ P) {
    int h = blockIdx.x;
    int ib = blockIdx.y;   // 0..31
    int d = threadIdx.x;   // 128
    __shared__ float kbs[32 * 256];
    for (int t = d; t < 32 * 256; t += 128) kbs[t] = kb[t];
    __shared__ float ws[256];
    for (int j = d; j < 256; j += 128) {
        int t = ib * 256 + j;
        float w = weights[t];
        if (rest && is_topk[t]) w = 0.0f;
        ws[j] = w;
    }
    __syncthreads();
    float acc[32] = {};
    for (int j = 0; j < 256; j++) {
        float xv = X[((size_t)(ib * 256 + j) * hstride + hbase + h) * DH + d] * ws[j];
#pragma unroll
        for (int kbo = 0; kbo < 32; kbo++) acc[kbo] += xv * kbs[kbo * 256 + j];
    }
#pragma unroll
    for (int kbo = 0; kbo < 32; kbo++)
        P[(((size_t)h * 32 + kbo) * 32 + ib) * DH + d] = acc[kbo];
}

// ---------------- sketch stage B ----------------
__global__ void sketchB_kernel(const float* __restrict__ P, int heads,
                               const float* __restrict__ ka,
                               const float* __restrict__ scale_p,
                               float* __restrict__ dstfrag, int mode) {
    int h = blockIdx.x;
    int kbo = blockIdx.y;
    int d = threadIdx.x;   // 128
    __shared__ float kas[20 * 32];
    for (int t = d; t < 20 * 32; t += 128) kas[t] = ka[(t / 32) * DH + (t % 32)];
    __syncthreads();
    float p[32];
#pragma unroll
    for (int i = 0; i < 32; i++) p[i] = P[(((size_t)h * 32 + kbo) * 32 + i) * DH + d];
    float scale = scale_p[0];
    if (mode == 0) scale *= ATT_SCALE;
#pragma unroll
    for (int kao = 0; kao < 20; kao++) {
        float acc = 0.f;
#pragma unroll
        for (int i = 0; i < 32; i++) acc += p[i] * kas[kao * 32 + i];
        int s = TK + kbo * 20 + kao;
        float val = acc * scale;
        if (mode == 0)      store_qfrag(dstfrag, h, s, d, val);
        else if (mode == 1) store_kfrag(dstfrag, h, s, d, val);
        else                store_vfrag(dstfrag, h, s, d, val);
    }
}

// ---------------- gather + RoPE for top-k rows -> mma fragments ----------------
__global__ void gather_rope_kernel(const float* __restrict__ q, const float* __restrict__ kv,
                                   const float* __restrict__ cosb, const float* __restrict__ sinb,
                                   const int* __restrict__ topk_list,
                                   float* __restrict__ Qfr, float* __restrict__ Kfr,
                                   float* __restrict__ Vfr) {
    int j = blockIdx.x;    // 0..2047
    int hy = blockIdx.y;   // 0..23
    int d = threadIdx.x;
    int pos = topk_list[j];
    float c = cosb[(size_t)pos * DH + d];
    float s = sinb[(size_t)pos * DH + d];
    if (hy < 16) {
        const float* src = q + ((size_t)pos * NH + hy) * DH;
        float x = src[d];
        float r = (d < 64) ? -src[d + 64] : src[d - 64];
        store_qfrag(Qfr, hy, j, d, (x * c + r * s) * ATT_SCALE);
    } else if (hy < 20) {
        int h = hy - 16;
        const float* src = kv + (size_t)pos * 1024 + h * DH;
        float x = src[d];
        float r = (d < 64) ? -src[d + 64] : src[d - 64];
        store_kfrag(Kfr, h, j, d, x * c + r * s);
    } else {
        int h = hy - 20;
        store_vfrag(Vfr, h, j, d, kv[(size_t)pos * 1024 + 512 + h * DH + d]);
    }
}

// ---------------- tensor-core flash attention ----------------
#define FA2_SMEM ((16384 + 8192 + 8192 + 8192 + 512) * 4)
__global__ void __launch_bounds__(256, 1) fa_mma_kernel(
    const float* __restrict__ Qfr, const float* __restrict__ Kfr,
    const float* __restrict__ Vfr, float* __restrict__ AO)
{
    extern __shared__ float fsm[];
    float* Qsm = fsm;
    float* Ksm = Qsm + 16384;
    float* Vsm = Ksm + 8192;
    float* Psm = Vsm + 8192;
    float* mpart = Psm + 8192;
    float* spart = mpart + 256;

    const int qt = blockIdx.x;
    const int h  = blockIdx.y;
    const int kvh = h >> 2;
    const int tid = threadIdx.x;
    const int lane = tid & 31, wid = tid >> 5;
    const int wm = wid >> 1, wn = wid & 1;
    const int gid = lane >> 2, tig = lane & 3;

    {
        const float4* Qg = reinterpret_cast<const float4*>(Qfr + (size_t)(h * NQT + qt) * 16384);
        float4* Qs4w = reinterpret_cast<float4*>(Qsm);
#pragma unroll
        for (int i = 0; i < 16; i++) Qs4w[tid + i * 256] = Qg[tid + i * 256];
    }

    float m_old[2][2], l_run[2][2];
#pragma unroll
    for (int a = 0; a < 2; a++)
#pragma unroll
        for (int b = 0; b < 2; b++) { m_old[a][b] = -1e30f; l_run[a][b] = 0.f; }
    float oacc[2][8][4] = {};

    const float4* Qs4 = reinterpret_cast<const float4*>(Qsm);
    const float2* Ks2 = reinterpret_cast<const float2*>(Ksm);
    const float2* Vs2 = reinterpret_cast<const float2*>(Vsm);
    const float4* Ps4 = reinterpret_cast<const float4*>(Psm);

    for (int kt = 0; kt < NKT; kt++) {
        {
            const float4* Kg = reinterpret_cast<const float4*>(Kfr + (size_t)(kvh * NKT + kt) * 8192);
            const float4* Vg = reinterpret_cast<const float4*>(Vfr + (size_t)(kvh * NKT + kt) * 8192);
            float4* Ks4w = reinterpret_cast<float4*>(Ksm);
            float4* Vs4w = reinterpret_cast<float4*>(Vsm);
#pragma unroll
            for (int i = 0; i < 8; i++) Ks4w[tid + i * 256] = Kg[tid + i * 256];
#pragma unroll
            for (int i = 0; i < 8; i++) Vs4w[tid + i * 256] = Vg[tid + i * 256];
        }
        __syncthreads();

        float sacc[2][4][4] = {};
#pragma unroll
        for (int k8 = 0; k8 < 16; k8++) {
            float4 af[2];
            float2 bf[4];
            af[0] = Qs4[(k8 * 8 + wm * 2 + 0) * 32 + lane];
            af[1] = Qs4[(k8 * 8 + wm * 2 + 1) * 32 + lane];
#pragma unroll
            for (int nf = 0; nf < 4; nf++) bf[nf] = Ks2[(k8 * 8 + wn * 4 + nf) * 32 + lane];
#pragma unroll
            for (int mf = 0; mf < 2; mf++)
#pragma unroll
                for (int nf = 0; nf < 4; nf++)
                    mma_tf32(sacc[mf][nf],
                             reinterpret_cast<const uint32_t*>(&af[mf]),
                             reinterpret_cast<const uint32_t*>(&bf[nf]));
        }

        float mloc[2][2];
#pragma unroll
        for (int mf = 0; mf < 2; mf++) {
            float m0 = fmaxf(sacc[mf][0][0], sacc[mf][0][1]);
            float m1 = fmaxf(sacc[mf][0][2], sacc[mf][0][3]);
#pragma unroll
            for (int nf = 1; nf < 4; nf++) {
                m0 = fmaxf(m0, fmaxf(sacc[mf][nf][0], sacc[mf][nf][1]));
                m1 = fmaxf(m1, fmaxf(sacc[mf][nf][2], sacc[mf][nf][3]));
            }
            m0 = fmaxf(m0, __shfl_xor_sync(0xffffffffu, m0, 1));
            m0 = fmaxf(m0, __shfl_xor_sync(0xffffffffu, m0, 2));
            m1 = fmaxf(m1, __shfl_xor_sync(0xffffffffu, m1, 1));
            m1 = fmaxf(m1, __shfl_xor_sync(0xffffffffu, m1, 2));
            mloc[mf][0] = m0; mloc[mf][1] = m1;
        }
        if (tig == 0) {
#pragma unroll
            for (int mf = 0; mf < 2; mf++) {
                int r = wm * 32 + mf * 16 + gid;
                mpart[wn * 128 + r] = mloc[mf][0];
                mpart[wn * 128 + r + 8] = mloc[mf][1];
            }
        }
        __syncthreads();

        float mnew[2][2], corr[2][2];
#pragma unroll
        for (int mf = 0; mf < 2; mf++)
#pragma unroll
            for (int hi = 0; hi < 2; hi++) {
                int r = wm * 32 + mf * 16 + gid + hi * 8;
                float mt = fmaxf(mpart[r], mpart[128 + r]);
                float mn = fmaxf(m_old[mf][hi], mt);
                corr[mf][hi] = __expf(m_old[mf][hi] - mn);
                mnew[mf][hi] = mn;
                m_old[mf][hi] = mn;
            }

        float sloc[2][2] = {};
#pragma unroll
        for (int mf = 0; mf < 2; mf++)
#pragma unroll
            for (int nf = 0; nf < 4; nf++) {
                sacc[mf][nf][0] = __expf(sacc[mf][nf][0] - mnew[mf][0]);
                sacc[mf][nf][1] = __expf(sacc[mf][nf][1] - mnew[mf][0]);
                sacc[mf][nf][2] = __expf(sacc[mf][nf][2] - mnew[mf][1]);
                sacc[mf][nf][3] = __expf(sacc[mf][nf][3] - mnew[mf][1]);
                sloc[mf][0] += sacc[mf][nf][0] + sacc[mf][nf][1];
                sloc[mf][1] += sacc[mf][nf][2] + sacc[mf][nf][3];
            }
#pragma unroll
        for (int mf = 0; mf < 2; mf++) {
            sloc[mf][0] += __shfl_xor_sync(0xffffffffu, sloc[mf][0], 1);
            sloc[mf][0] += __shfl_xor_sync(0xffffffffu, sloc[mf][0], 2);
            sloc[mf][1] += __shfl_xor_sync(0xffffffffu, sloc[mf][1], 1);
            sloc[mf][1] += __shfl_xor_sync(0xffffffffu, sloc[mf][1], 2);
        }
        if (tig == 0) {
#pragma unroll
            for (int mf = 0; mf < 2; mf++) {
                int r = wm * 32 + mf * 16 + gid;
                spart[wn * 128 + r] = sloc[mf][0];
                spart[wn * 128 + r + 8] = sloc[mf][1];
            }
        }

#pragma unroll
        for (int mf = 0; mf < 2; mf++)
#pragma unroll
            for (int nf = 0; nf < 4; nf++) {
                int k8p = wn * 4 + nf;
                int mfg = wm * 2 + mf;
#pragma unroll
                for (int b = 0; b < 2; b++) {
                    int c = tig * 2 + b;
                    int khi = (c >= 4);
                    int base = ((k8p * 8 + mfg) * 32 + (gid << 2) + (c & 3)) * 4 + khi * 2;
                    *reinterpret_cast<float2*>(Psm + base) =
                        make_float2(tf32f(sacc[mf][nf][b]), tf32f(sacc[mf][nf][2 + b]));
                }
            }
        __syncthreads();

#pragma unroll
        for (int mf = 0; mf < 2; mf++)
#pragma unroll
            for (int hi = 0; hi < 2; hi++) {
                int r = wm * 32 + mf * 16 + gid + hi * 8;
                l_run[mf][hi] = l_run[mf][hi] * corr[mf][hi] + spart[r] + spart[128 + r];
            }
#pragma unroll
        for (int mf = 0; mf < 2; mf++)
#pragma unroll
            for (int nf = 0; nf < 8; nf++) {
                oacc[mf][nf][0] *= corr[mf][0]; oacc[mf][nf][1] *= corr[mf][0];
                oacc[mf][nf][2] *= corr[mf][1]; oacc[mf][nf][3] *= corr[mf][1];
            }

#pragma unroll
        for (int k8 = 0; k8 < 8; k8++) {
            float4 af[2];
            af[0] = Ps4[(k8 * 8 + wm * 2 + 0) * 32 + lane];
            af[1] = Ps4[(k8 * 8 + wm * 2 + 1) * 32 + lane];
#pragma unroll
            for (int nf = 0; nf < 8; nf++) {
                float2 bf = Vs2[(k8 * 16 + wn * 8 + nf) * 32 + lane];
#pragma unroll
                for (int mf = 0; mf < 2; mf++)
                    mma_tf32(oacc[mf][nf],
                             reinterpret_cast<const uint32_t*>(&af[mf]),
                             reinterpret_cast<const uint32_t*>(&bf));
            }
        }
        __syncthreads();
    }

#pragma unroll
    for (int mf = 0; mf < 2; mf++) {
        float inv0 = 1.0f / l_run[mf][0];
        float inv1 = 1.0f / l_run[mf][1];
        int r0 = qt * 128 + wm * 32 + mf * 16 + gid;
#pragma unroll
        for (int nf = 0; nf < 8; nf++) {
            int col = wn * 64 + nf * 8 + tig * 2;
            *reinterpret_cast<float2*>(&AO[((size_t)r0 * NH + h) * DH + col]) =
                make_float2(oacc[mf][nf][0] * inv0, oacc[mf][nf][1] * inv0);
            *reinterpret_cast<float2*>(&AO[((size_t)(r0 + 8) * NH + h) * DH + col]) =
                make_float2(oacc[mf][nf][2] * inv1, oacc[mf][nf][3] * inv1);
        }
    }
}

// ---------------- expand stage C (reads Z = AO_sk @ wo) ----------------
__global__ void expandC_kernel(const float* __restrict__ Z, const float* __restrict__ ka,
                               float* __restrict__ E1) {
    int i = blockIdx.y;
    int hd = blockIdx.x * 256 + threadIdx.x;
    __shared__ float kav[20];
    if (threadIdx.x < 20) kav[threadIdx.x] = ka[threadIdx.x * DH + i];
    __syncthreads();
    for (int kbo = 0; kbo < 32; kbo++) {
        float acc = 0.f;
#pragma unroll
        for (int kao = 0; kao < 20; kao++)
            acc += Z[((size_t)(kbo * 20 + kao)) * HID + hd] * kav[kao];
        E1[((size_t)i * 32 + kbo) * HID + hd] = acc;
    }
}

// ---------------- expand stage D (writes final out rows) ----------------
__global__ void expandD_kernel(const float* __restrict__ E1, const float* __restrict__ kb,
                               float* __restrict__ OUT) {
    int i = blockIdx.y;
    int hd = blockIdx.x * 128 + threadIdx.x;
    __shared__ float kbs[32 * 256];
    for (int t = threadIdx.x; t < 32 * 256; t += 128) kbs[t] = kb[t];
    float e[32];
#pragma unroll
    for (int kbo = 0; kbo < 32; kbo++) e[kbo] = E1[((size_t)i * 32 + kbo) * HID + hd];
    __syncthreads();
    for (int j = 0; j < 256; j++) {
        float acc = 0.f;
#pragma unroll
        for (int kbo = 0; kbo < 32; kbo++) acc += e[kbo] * kbs[kbo * 256 + j];
        OUT[((size_t)(i * 256 + j)) * HID + hd] = acc;
    }
}

// ---------------- host launcher ----------------
extern "C" void kernel_launch(void* const* d_in, const int* in_sizes, int n_in,
                              void* d_out, int out_size) {
    const float* hs    = (const float*)d_in[0];
    const float* cosb  = (const float*)d_in[1];
    const float* sinb  = (const float*)d_in[2];
    const float* wq    = (const float*)d_in[3];
    const float* wk    = (const float*)d_in[4];
    const float* wv    = (const float*)d_in[5];
    const float* wo    = (const float*)d_in[6];
    const float* qnw   = (const float*)d_in[7];
    const float* knw   = (const float*)d_in[8];
    const float* w1    = (const float*)d_in[9];
    const float* b1    = (const float*)d_in[10];
    const float* w2    = (const float*)d_in[11];
    const float* b2    = (const float*)d_in[12];
    const float* ka    = (const float*)d_in[13];
    const float* kb    = (const float*)d_in[14];
    const float* sscale= (const float*)d_in[15];
    float* out = (float*)d_out;

    float *pT, *pLg, *pW, *pQ, *pKV, *pP, *pQfr, *pKfr, *pVfr, *pAO, *pE1, *pZ, *pAfr, *pBfr;
    int *pTop, *pIs;
    cudaGetSymbolAddress((void**)&pT, g_T);
    cudaGetSymbolAddress((void**)&pLg, g_logits);
    cudaGetSymbolAddress((void**)&pW, g_weights);
    cudaGetSymbolAddress((void**)&pQ, g_q);
    cudaGetSymbolAddress((void**)&pKV, g_kv);
    cudaGetSymbolAddress((void**)&pP, g_P);
    cudaGetSymbolAddress((void**)&pQfr, g_Qfr);
    cudaGetSymbolAddress((void**)&pKfr, g_Kfr);
    cudaGetSymbolAddress((void**)&pVfr, g_Vfr);
    cudaGetSymbolAddress((void**)&pAO, g_AO);
    cudaGetSymbolAddress((void**)&pE1, g_E1);
    cudaGetSymbolAddress((void**)&pZ, g_Z);
    cudaGetSymbolAddress((void**)&pAfr, g_Afr);
    cudaGetSymbolAddress((void**)&pBfr, g_Bfr);
    cudaGetSymbolAddress((void**)&pTop, g_topk);
    cudaGetSymbolAddress((void**)&pIs, g_istop);

    cudaFuncSetAttribute(topk_kernel, cudaFuncAttributeMaxDynamicSharedMemorySize, SEQ * 8);
    cudaFuncSetAttribute(fa_mma_kernel, cudaFuncAttributeMaxDynamicSharedMemorySize, FA2_SMEM);

    // 1) importance MLP first GEMM — fp32 split-K x8 (feeds top-k)
    imp_gemm_kernel<<<dim3(1, SEQ / 64, 8), 256>>>(hs, w1, pT);
    imp_logits_kernel<<<SEQ, 32>>>(pT, b1, w2, b2, pLg, pW);
    // 2) convert hs to A-fragments (shared by q and kv GEMMs)
    convA_kernel<<<dim3(HID / 16, SEQ / 128), 256>>>(hs, pAfr, HID);
    // 3) Q projection
    convB_kernel<<<dim3(HID / 16, HID / 128), 256>>>(wq, pBfr, HID, HID, 0);
    mma_gemm_kernel<<<dim3(HID / 128, SEQ / 128), 256>>>(pAfr, pBfr, pQ, nullptr, HID, HID);
    // 4) fused K|V projection (N=1024)
    convB_kernel<<<dim3(HID / 16, 512 / 128), 256>>>(wk, pBfr, HID, 512, 0);
    convB_kernel<<<dim3(HID / 16, 512 / 128), 256>>>(wv, pBfr, HID, 512, 4);
    mma_gemm_kernel<<<dim3(1024 / 128, SEQ / 128), 256>>>(pAfr, pBfr, pKV, nullptr, 1024, HID);
    // 5) RMSNorm q, k
    rmsnorm_kernel<<<SEQ * NH, DH>>>(pQ, qnw, HID, NH);
    rmsnorm_kernel<<<SEQ * NKV, DH>>>(pKV, knw, 1024, NKV);
    // 6) top-k selection
    topk_kernel<<<1, 1024, SEQ * 8>>>(pLg, pTop, pIs);
    // 7) sketches -> fragment buffers
    sketchA_kernel<<<dim3(NH, 32), DH>>>(pQ, 16, 0, pW, pIs, 0, kb, pP);
    sketchB_kernel<<<dim3(NH, 32), DH>>>(pP, NH, ka, sscale, pQfr, 0);
    sketchA_kernel<<<dim3(NKV, 32), DH>>>(pKV, 8, 0, pW, pIs, 1, kb, pP);
    sketchB_kernel<<<dim3(NKV, 32), DH>>>(pP, NKV, ka, sscale, pKfr, 1);
    sketchA_kernel<<<dim3(NKV, 32), DH>>>(pKV, 8, 4, pW, pIs, 1, kb, pP);
    sketchB_kernel<<<dim3(NKV, 32), DH>>>(pP, NKV, ka, sscale, pVfr, 2);
    // 8) gather top-k rows + RoPE -> fragment buffers
    gather_rope_kernel<<<dim3(TK, 24), DH>>>(pQ, pKV, cosb, sinb, pTop, pQfr, pKfr, pVfr);
    // 9) attention — tensor-core FA2
    fa_mma_kernel<<<dim3(NQT, NH), 256, FA2_SMEM>>>(pQfr, pKfr, pVfr, pAO);
    // 10) convert AO (all 2688 rows) and wo
    convA_kernel<<<dim3(HID / 16, NQF / 128), 256>>>(pAO, pAfr, HID);
    convB_kernel<<<dim3(HID / 16, HID / 128), 256>>>(wo, pBfr, HID, HID, 0);
    // 11) Z = AO_sk @ wo  (rows 2048..2687 -> A-frag row tiles 16..20)
    mma_gemm_kernel<<<dim3(HID / 128, SK / 128), 256>>>(
        pAfr + (size_t)16 * (HID / 16) * 2048, pBfr, pZ, nullptr, HID, HID);
    // 12) expand Z to all positions, writing out directly
    expandC_kernel<<<dim3(HID / 256, 32), 256>>>(pZ, ka, pE1);
    expandD_kernel<<<dim3(HID / 128, 32), DH>>>(pE1, kb, out);
    // 13) deterministic rows: (AO_det @ wo) scattered to out[topk[m]]
    mma_gemm_kernel<<<dim3(HID / 128, TK / 128), 256>>>(pAfr, pBfr, out, pTop, HID, HID);
}

// round 8
// speedup vs baseline: 3.6132x; 1.0304x over previous
#include <cuda_runtime.h>
#include <cuda_bf16.h>
#include <math.h>
#include <cstdint>

// Problem constants
#define SEQ   8192
#define HID   2048
#define NH    16
#define NKV   4
#define DH    128
#define TK    2048
#define SK    640
#define NQF   (TK + SK)        // 2688
#define NQT   (NQF / 128)      // 21 q tiles
#define NKT   (NQF / 64)       // 42 key tiles
#define ATT_SCALE 0.08838834764831843f   // 1/sqrt(128)

// ---------------- scratch (device globals; no allocation) ----------------
__device__ float g_T[8 * SEQ * 64];        // split-K partials
__device__ float g_logits[SEQ];
__device__ float g_weights[SEQ];
__device__ float g_q[SEQ * NH * DH];       // normalized q  [s][h][d]
__device__ float g_kv[SEQ * 1024];         // fused k(0:512)|v(512:1024) per row
__device__ int   g_topk[TK];
__device__ int   g_istop[SEQ];
__device__ float g_P[NH * 32 * 32 * DH];   // sketch stage-A scratch
__device__ float g_Qfr[NH * NQT * 16 * 8 * 32 * 4];    // Q mma-fragments
__device__ float g_Kfr[NKV * NKT * 16 * 8 * 32 * 2];   // K mma-fragments
__device__ float g_Vfr[NKV * NKT * 8 * 16 * 32 * 2];   // V mma-fragments
__device__ float g_AO[NQF * NH * DH];      // attention output [q][h][d]
__device__ float g_E1[32 * 32 * HID];      // expand stage-C scratch [i][kb][hd]
__device__ float g_Z[SK * HID];            // sketch-part @ wo
__device__ float g_Afr[SEQ * HID];         // A fragments (hs / AO)
__device__ float g_Bfr[HID * HID];         // B fragments (weights)

// ======================= tf32 mma.sync helpers =======================
__device__ __forceinline__ float tf32f(float x) {
    uint32_t r; asm("cvt.rna.tf32.f32 %0, %1;" : "=r"(r) : "f"(x));
    return __uint_as_float(r);
}

__device__ __forceinline__ void mma_tf32(float* c, const uint32_t* a, const uint32_t* b) {
    asm volatile("mma.sync.aligned.m16n8k8.row.col.f32.tf32.tf32.f32 "
        "{%0,%1,%2,%3}, {%4,%5,%6,%7}, {%8,%9}, {%0,%1,%2,%3};"
        : "+f"(c[0]), "+f"(c[1]), "+f"(c[2]), "+f"(c[3])
        : "r"(a[0]), "r"(a[1]), "r"(a[2]), "r"(a[3]), "r"(b[0]), "r"(b[1]));
}

#define CP_ASYNC16(dst_u32, src_ptr) \
    asm volatile("cp.async.cg.shared.global [%0], [%1], 16;" :: "r"(dst_u32), "l"(src_ptr))
#define CP_COMMIT() asm volatile("cp.async.commit_group;")

// fragment-layout gmem stores for attention operands
__device__ __forceinline__ void store_qfrag(float* Qg, int h, int tok, int d, float v) {
    int qt = tok >> 7, m = tok & 127;
    int k8 = d >> 3, mf = m >> 4;
    int lane = ((m & 7) << 2) | (d & 3);
    int reg = 2 * ((d & 7) >= 4) + ((m & 15) >= 8);
    size_t idx = ((((size_t)(h * NQT + qt) * 16 + k8) * 8 + mf) * 32 + lane) * 4 + reg;
    Qg[idx] = tf32f(v);
}
__device__ __forceinline__ void store_kfrag(float* Kg, int kvh, int tok, int d, float v) {
    int kt = tok >> 6, key = tok & 63;
    int k8 = d >> 3, nf = key >> 3;
    int lane = ((key & 7) << 2) | (d & 3);
    int reg = ((d & 7) >= 4);
    size_t idx = ((((size_t)(kvh * NKT + kt) * 16 + k8) * 8 + nf) * 32 + lane) * 2 + reg;
    Kg[idx] = tf32f(v);
}
__device__ __forceinline__ void store_vfrag(float* Vg, int kvh, int tok, int d, float v) {
    int kt = tok >> 6, key = tok & 63;
    int k8 = key >> 3, nf = d >> 3;
    int lane = ((d & 7) << 2) | (key & 3);
    int reg = ((key & 7) >= 4);
    size_t idx = ((((size_t)(kvh * NKT + kt) * 8 + k8) * 16 + nf) * 32 + lane) * 2 + reg;
    Vg[idx] = tf32f(v);
}

// ======================= fragment conversion pre-passes =======================
__global__ void __launch_bounds__(256) convA_kernel(const float* __restrict__ A,
                                                    float* __restrict__ Afr, int K) {
    __shared__ float sm[2048];
    const int rt = blockIdx.y, c = blockIdx.x;
    const int tid = threadIdx.x;
    const float* Ab = A + ((size_t)rt * 128) * K + c * 16;
#pragma unroll
    for (int i = 0; i < 2; i++) {
        int f = tid + i * 256;
        int r = f >> 2, c4 = f & 3;
        float4 v = *reinterpret_cast<const float4*>(Ab + (size_t)r * K + c4 * 4);
        int mf = r >> 4, gid = r & 7, mhi = (r >> 3) & 1;
        float vv[4] = {v.x, v.y, v.z, v.w};
#pragma unroll
        for (int j = 0; j < 4; j++) {
            int k = c4 * 4 + j;
            int slot = ((k >> 3) * 8 + mf) * 128 + ((gid << 2) | (k & 3)) * 4
                     + 2 * ((k & 7) >= 4) + mhi;
            sm[slot] = tf32f(vv[j]);
        }
    }
    __syncthreads();
    float4* out = reinterpret_cast<float4*>(Afr + ((size_t)(rt * (K >> 4) + c)) * 2048);
    const float4* s4 = reinterpret_cast<const float4*>(sm);
#pragma unroll
    for (int i = 0; i < 2; i++) out[tid + i * 256] = s4[tid + i * 256];
}

__global__ void __launch_bounds__(256) convB_kernel(const float* __restrict__ B,
                                                    float* __restrict__ Bfr, int K, int N,
                                                    int ctbase) {
    __shared__ float sm[2048];
    const int ct = blockIdx.y + ctbase, c = blockIdx.x;
    const int tid = threadIdx.x;
    const float* Bb = B + ((size_t)(c * 16)) * N + blockIdx.y * 128;
#pragma unroll
    for (int i = 0; i < 2; i++) {
        int f = tid + i * 256;
        int kk = f >> 5, n4 = f & 31;
        float4 v = *reinterpret_cast<const float4*>(Bb + (size_t)kk * N + n4 * 4);
        int k8in = kk >> 3, reg = ((kk & 7) >= 4);
        float vv[4] = {v.x, v.y, v.z, v.w};
#pragma unroll
        for (int j = 0; j < 4; j++) {
            int n = n4 * 4 + j;
            int slot = (k8in * 16 + (n >> 3)) * 64 + (((n & 7) << 2) | (kk & 3)) * 2 + reg;
            sm[slot] = tf32f(vv[j]);
        }
    }
    __syncthreads();
    float4* out = reinterpret_cast<float4*>(Bfr + ((size_t)(ct * (K >> 4) + c)) * 2048);
    const float4* s4 = reinterpret_cast<const float4*>(sm);
#pragma unroll
    for (int i = 0; i < 2; i++) out[tid + i * 256] = s4[tid + i * 256];
}

// ======================= tf32 GEMM: CTA 128x128, cp.async 3-stage, 2 CTA/SM ========
__global__ void __launch_bounds__(256, 2) mma_gemm_kernel(
    const float* __restrict__ Afr, const float* __restrict__ Bfr,
    float* __restrict__ C, const int* __restrict__ remap, int N, int K)
{
    __shared__ float sA[3][2048];
    __shared__ float sB[3][2048];

    const int tid = threadIdx.x;
    const int lane = tid & 31, wid = tid >> 5;
    const int wm = wid >> 2, wn = wid & 3;
    const int NCH = K >> 4;

    const float4* Ag = reinterpret_cast<const float4*>(Afr) + (size_t)blockIdx.y * NCH * 512;
    const float4* Bg = reinterpret_cast<const float4*>(Bfr) + (size_t)blockIdx.x * NCH * 512;

    const uint32_t sAu = (uint32_t)__cvta_generic_to_shared(&sA[0][0]) + tid * 16;
    const uint32_t sBu = (uint32_t)__cvta_generic_to_shared(&sB[0][0]) + tid * 16;

    {
        const float4* ga = Ag + tid;  const float4* gb = Bg + tid;
        CP_ASYNC16(sAu, ga); CP_ASYNC16(sAu + 4096, ga + 256);
        CP_ASYNC16(sBu, gb); CP_ASYNC16(sBu + 4096, gb + 256);
        CP_COMMIT();
        if (NCH > 1) {
            ga += 512; gb += 512;
            CP_ASYNC16(sAu + 8192, ga); CP_ASYNC16(sAu + 8192 + 4096, ga + 256);
            CP_ASYNC16(sBu + 8192, gb); CP_ASYNC16(sBu + 8192 + 4096, gb + 256);
            CP_COMMIT();
        }
    }

    float acc[4][4][4] = {};
    for (int c = 0; c < NCH; c++) {
        if (c + 1 < NCH) asm volatile("cp.async.wait_group 1;");
        else             asm volatile("cp.async.wait_group 0;");
        __syncthreads();

        const int buf = c % 3;
        const float4* A4 = reinterpret_cast<const float4*>(sA[buf]);
        const float2* B2 = reinterpret_cast<const float2*>(sB[buf]);
#pragma unroll
        for (int k8 = 0; k8 < 2; k8++) {
            float4 af[4];
            float2 bf[4];
#pragma unroll
            for (int mf = 0; mf < 4; mf++)
                af[mf] = A4[(k8 * 8 + wm * 4 + mf) * 32 + lane];
#pragma unroll
            for (int nf = 0; nf < 4; nf++)
                bf[nf] = B2[(k8 * 16 + wn * 4 + nf) * 32 + lane];
#pragma unroll
            for (int mf = 0; mf < 4; mf++)
#pragma unroll
                for (int nf = 0; nf < 4; nf++)
                    mma_tf32(acc[mf][nf],
                             reinterpret_cast<const uint32_t*>(&af[mf]),
                             reinterpret_cast<const uint32_t*>(&bf[nf]));
        }
        if (c + 2 < NCH) {
            const int st = (c + 2) % 3;
            const float4* ga = Ag + (c + 2) * 512 + tid;
            const float4* gb = Bg + (c + 2) * 512 + tid;
            CP_ASYNC16(sAu + st * 8192, ga); CP_ASYNC16(sAu + st * 8192 + 4096, ga + 256);
            CP_ASYNC16(sBu + st * 8192, gb); CP_ASYNC16(sBu + st * 8192 + 4096, gb + 256);
            CP_COMMIT();
        }
    }

    const int row0 = blockIdx.y * 128;
    const int col0 = blockIdx.x * 128;
    const int gid = lane >> 2, tig = lane & 3;
#pragma unroll
    for (int mf = 0; mf < 4; mf++) {
        int m = row0 + wm * 64 + mf * 16 + gid;
        int m1 = remap ? __ldg(&remap[m]) : m;
        int m2 = remap ? __ldg(&remap[m + 8]) : (m + 8);
#pragma unroll
        for (int nf = 0; nf < 4; nf++) {
            int n = col0 + wn * 32 + nf * 8 + tig * 2;
            *reinterpret_cast<float2*>(&C[(size_t)m1 * N + n]) =
                make_float2(acc[mf][nf][0], acc[mf][nf][1]);
            *reinterpret_cast<float2*>(&C[(size_t)m2 * N + n]) =
                make_float2(acc[mf][nf][2], acc[mf][nf][3]);
        }
    }
}

// ---------------- importance GEMM: fp32 split-K x8 (top-k needs fp32) -----------
__global__ void __launch_bounds__(256) imp_gemm_kernel(
    const float* __restrict__ A, const float* __restrict__ B, float* __restrict__ Cp)
{
    __shared__ float As[16][64];
    __shared__ float Bs[16][64];
    const int tid = threadIdx.x;
    const int row0 = blockIdx.y * 64;
    const int z = blockIdx.z;
    const float* Ab = A + (size_t)row0 * HID + z * 256;
    const float* Bb = B + (size_t)z * 256 * 64;
    float acc[4][4] = {};
    const int tc = (tid & 15) * 4, tr = (tid >> 4) * 4;
    const int ar = tid >> 2, ac = (tid & 3) * 4;
    const int br = tid >> 4, bc = (tid & 15) * 4;

    for (int k0 = 0; k0 < 256; k0 += 16) {
        float4 va = *reinterpret_cast<const float4*>(Ab + (size_t)ar * HID + k0 + ac);
        As[ac + 0][ar] = va.x; As[ac + 1][ar] = va.y;
        As[ac + 2][ar] = va.z; As[ac + 3][ar] = va.w;
        float4 vb = *reinterpret_cast<const float4*>(Bb + (size_t)(k0 + br) * 64 + bc);
        *reinterpret_cast<float4*>(&Bs[br][bc]) = vb;
        __syncthreads();
#pragma unroll
        for (int k = 0; k < 16; k++) {
            float ra[4], rb[4];
#pragma unroll
            for (int m = 0; m < 4; m++) ra[m] = As[k][tr + m];
#pragma unroll
            for (int n = 0; n < 4; n++) rb[n] = Bs[k][tc + n];
#pragma unroll
            for (int m = 0; m < 4; m++)
#pragma unroll
                for (int n = 0; n < 4; n++) acc[m][n] += ra[m] * rb[n];
        }
        __syncthreads();
    }
#pragma unroll
    for (int m = 0; m < 4; m++) {
        float4 v = make_float4(acc[m][0], acc[m][1], acc[m][2], acc[m][3]);
        *reinterpret_cast<float4*>(&Cp[((size_t)z * SEQ + row0 + tr + m) * 64 + tc]) = v;
    }
}

// ---------------- importance logits epilogue ----------------
__global__ void imp_logits_kernel(const float* __restrict__ T, const float* __restrict__ b1,
                                  const float* __restrict__ w2, const float* __restrict__ b2,
                                  float* __restrict__ logits, float* __restrict__ weights) {
    const float LOG_ADJ = 2.5494451709255714f;   // log(8192/640)
    int s = blockIdx.x;
    int j = threadIdx.x;  // 32
    float v1 = 0.f, v2 = 0.f;
#pragma unroll
    for (int z = 0; z < 8; z++) {
        v1 += T[((size_t)z * SEQ + s) * 64 + j];
        v2 += T[((size_t)z * SEQ + s) * 64 + j + 32];
    }
    float v = tanhf(v1 + b1[j]) * w2[j] + tanhf(v2 + b1[j + 32]) * w2[j + 32];
#pragma unroll
    for (int o = 16; o > 0; o >>= 1) v += __shfl_xor_sync(0xffffffffu, v, o);
    if (j == 0) {
        float lg = v + b2[0] - LOG_ADJ;
        logits[s] = lg;
        weights[s] = 1.0f / (1.0f + expf(-lg));
    }
}

// ---------------- RMSNorm (generic head addressing) ----------------
__global__ void rmsnorm_kernel(float* __restrict__ X, const float* __restrict__ w,
                               int stride, int nh) {
    int r = blockIdx.x;
    int s = r / nh, h = r % nh;
    float* row = X + (size_t)s * stride + h * DH;
    int d = threadIdx.x;   // 128
    float x = row[d];
    float ss = x * x;
#pragma unroll
    for (int o = 16; o > 0; o >>= 1) ss += __shfl_xor_sync(0xffffffffu, ss, o);
    __shared__ float sm[4];
    if ((d & 31) == 0) sm[d >> 5] = ss;
    __syncthreads();
    float tot = sm[0] + sm[1] + sm[2] + sm[3];
    row[d] = x * rsqrtf(tot * (1.0f / 128.0f) + 1e-6f) * w[d];
}

// ---------------- top-k via single-block bitonic sort ----------------
__global__ void topk_kernel(const float* __restrict__ logits,
                            int* __restrict__ topk_list, int* __restrict__ is_topk) {
    extern __shared__ unsigned long long skeys[];
    int tid = threadIdx.x;  // 1024
    for (int i = tid; i < SEQ; i += 1024) {
        unsigned u = __float_as_uint(logits[i]);
        u = (u & 0x80000000u) ? ~u : (u | 0x80000000u);
        skeys[i] = ((unsigned long long)(~u) << 32) | (unsigned)i;
        is_topk[i] = 0;
    }
    __syncthreads();
    for (int k = 2; k <= SEQ; k <<= 1) {
        for (int j = k >> 1; j > 0; j >>= 1) {
            for (int i = tid; i < SEQ; i += 1024) {
                int ixj = i ^ j;
                if (ixj > i) {
                    bool up = ((i & k) == 0);
                    unsigned long long a = skeys[i], b = skeys[ixj];
                    if ((a > b) == up) { skeys[i] = b; skeys[ixj] = a; }
                }
            }
            __syncthreads();
        }
    }
    for (int i = tid; i < TK; i += 1024) {
        int pos = (int)(skeys[i] & 0xffffffffu);
        topk_list[i] = pos;
        is_topk[pos] = 1;
    }
}

// ---------------- sketch stage A (generic head addressing) ----------------
__global__ void sketchA_kernel(const float* __restrict__ X, int hstride, int hbase,
                               const float* __restrict__ weights,
                               const int* __restrict__ is_topk, int rest,
                               const float* __restrict__ kb, float* __restrict__ P) {
    int h = blockIdx.x;
    int ib = blockIdx.y;   // 0..31
    int d = threadIdx.x;   // 128
    __shared__ float kbs[32 * 256];
    for (int t = d; t < 32 * 256; t += 128) kbs[t] = kb[t];
    __shared__ float ws[256];
    for (int j = d; j < 256; j += 128) {
        int t = ib * 256 + j;
        float w = weights[t];
        if (rest && is_topk[t]) w = 0.0f;
        ws[j] = w;
    }
    __syncthreads();
    float acc[32] = {};
    for (int j = 0; j < 256; j++) {
        float xv = X[((size_t)(ib * 256 + j) * hstride + hbase + h) * DH + d] * ws[j];
#pragma unroll
        for (int kbo = 0; kbo < 32; kbo++) acc[kbo] += xv * kbs[kbo * 256 + j];
    }
#pragma unroll
    for (int kbo = 0; kbo < 32; kbo++)
        P[(((size_t)h * 32 + kbo) * 32 + ib) * DH + d] = acc[kbo];
}

// ---------------- sketch stage B ----------------
__global__ void sketchB_kernel(const float* __restrict__ P, int heads,
                               const float* __restrict__ ka,
                               const float* __restrict__ scale_p,
                               float* __restrict__ dstfrag, int mode) {
    int h = blockIdx.x;
    int kbo = blockIdx.y;
    int d = threadIdx.x;   // 128
    __shared__ float kas[20 * 32];
    for (int t = d; t < 20 * 32; t += 128) kas[t] = ka[(t / 32) * DH + (t % 32)];
    __syncthreads();
    float p[32];
#pragma unroll
    for (int i = 0; i < 32; i++) p[i] = P[(((size_t)h * 32 + kbo) * 32 + i) * DH + d];
    float scale = scale_p[0];
    if (mode == 0) scale *= ATT_SCALE;
#pragma unroll
    for (int kao = 0; kao < 20; kao++) {
        float acc = 0.f;
#pragma unroll
        for (int i = 0; i < 32; i++) acc += p[i] * kas[kao * 32 + i];
        int s = TK + kbo * 20 + kao;
        float val = acc * scale;
        if (mode == 0)      store_qfrag(dstfrag, h, s, d, val);
        else if (mode == 1) store_kfrag(dstfrag, h, s, d, val);
        else                store_vfrag(dstfrag, h, s, d, val);
    }
}

// ---------------- gather + RoPE for top-k rows -> mma fragments ----------------
__global__ void gather_rope_kernel(const float* __restrict__ q, const float* __restrict__ kv,
                                   const float* __restrict__ cosb, const float* __restrict__ sinb,
                                   const int* __restrict__ topk_list,
                                   float* __restrict__ Qfr, float* __restrict__ Kfr,
                                   float* __restrict__ Vfr) {
    int j = blockIdx.x;    // 0..2047
    int hy = blockIdx.y;   // 0..23
    int d = threadIdx.x;
    int pos = topk_list[j];
    float c = cosb[(size_t)pos * DH + d];
    float s = sinb[(size_t)pos * DH + d];
    if (hy < 16) {
        const float* src = q + ((size_t)pos * NH + hy) * DH;
        float x = src[d];
        float r = (d < 64) ? -src[d + 64] : src[d - 64];
        store_qfrag(Qfr, hy, j, d, (x * c + r * s) * ATT_SCALE);
    } else if (hy < 20) {
        int h = hy - 16;
        const float* src = kv + (size_t)pos * 1024 + h * DH;
        float x = src[d];
        float r = (d < 64) ? -src[d + 64] : src[d - 64];
        store_kfrag(Kfr, h, j, d, x * c + r * s);
    } else {
        int h = hy - 20;
        store_vfrag(Vfr, h, j, d, kv[(size_t)pos * 1024 + 512 + h * DH + d]);
    }
}

// ---------------- tensor-core flash attention (cp.async double-buffered K/V) -------
// smem: Q 16384 | K 2x8192 | V 2x8192 | mpart 256 | spart 256  = 49664 floats (198.7KB)
// P-fragment scratch aliases the CURRENT K buffer (safe: P written only after the
// post-QK barrier, read before the end-of-iteration barrier; prefetch targets 1-buf).
#define FA2_SMEM ((16384 + 2*8192 + 2*8192 + 512) * 4)
__global__ void __launch_bounds__(256, 1) fa_mma_kernel(
    const float* __restrict__ Qfr, const float* __restrict__ Kfr,
    const float* __restrict__ Vfr, float* __restrict__ AO)
{
    extern __shared__ float fsm[];
    float* Qsm = fsm;                       // 16384
    float* Ksm = fsm + 16384;               // 2 x 8192
    float* Vsm = fsm + 32768;               // 2 x 8192
    float* mpart = fsm + 49152;             // 256
    float* spart = fsm + 49408;             // 256

    const int qt = blockIdx.x;
    const int h  = blockIdx.y;
    const int kvh = h >> 2;
    const int tid = threadIdx.x;
    const int lane = tid & 31, wid = tid >> 5;
    const int wm = wid >> 1, wn = wid & 1;
    const int gid = lane >> 2, tig = lane & 3;

    const uint32_t ksmU = (uint32_t)__cvta_generic_to_shared(Ksm) + tid * 16;
    const uint32_t vsmU = (uint32_t)__cvta_generic_to_shared(Vsm) + tid * 16;

    // prefetch tile 0 K/V
    {
        const float4* Kg = reinterpret_cast<const float4*>(Kfr + (size_t)(kvh * NKT) * 8192);
        const float4* Vg = reinterpret_cast<const float4*>(Vfr + (size_t)(kvh * NKT) * 8192);
#pragma unroll
        for (int i = 0; i < 8; i++) {
            CP_ASYNC16(ksmU + i * 4096, Kg + tid + i * 256);
            CP_ASYNC16(vsmU + i * 4096, Vg + tid + i * 256);
        }
        CP_COMMIT();
    }

    // stage Q (plain copy; covered by first barrier)
    {
        const float4* Qg = reinterpret_cast<const float4*>(Qfr + (size_t)(h * NQT + qt) * 16384);
        float4* Qs4w = reinterpret_cast<float4*>(Qsm);
#pragma unroll
        for (int i = 0; i < 16; i++) Qs4w[tid + i * 256] = Qg[tid + i * 256];
    }

    float m_old[2][2], l_run[2][2];
#pragma unroll
    for (int a = 0; a < 2; a++)
#pragma unroll
        for (int b = 0; b < 2; b++) { m_old[a][b] = -1e30f; l_run[a][b] = 0.f; }
    float oacc[2][8][4] = {};

    const float4* Qs4 = reinterpret_cast<const float4*>(Qsm);

    for (int kt = 0; kt < NKT; kt++) {
        const int buf = kt & 1;
        // prefetch tile kt+1 into 1-buf
        if (kt + 1 < NKT) {
            const float4* Kg = reinterpret_cast<const float4*>(Kfr + (size_t)(kvh * NKT + kt + 1) * 8192);
            const float4* Vg = reinterpret_cast<const float4*>(Vfr + (size_t)(kvh * NKT + kt + 1) * 8192);
            const uint32_t kd = ksmU + (1 - buf) * 32768;
            const uint32_t vd = vsmU + (1 - buf) * 32768;
#pragma unroll
            for (int i = 0; i < 8; i++) {
                CP_ASYNC16(kd + i * 4096, Kg + tid + i * 256);
                CP_ASYNC16(vd + i * 4096, Vg + tid + i * 256);
            }
            CP_COMMIT();
            asm volatile("cp.async.wait_group 1;");
        } else {
            asm volatile("cp.async.wait_group 0;");
        }
        __syncthreads();

        const float2* Ks2 = reinterpret_cast<const float2*>(Ksm + buf * 8192);
        const float2* Vs2 = reinterpret_cast<const float2*>(Vsm + buf * 8192);
        float* Psm = Ksm + buf * 8192;                 // alias onto current K buffer
        const float4* Ps4 = reinterpret_cast<const float4*>(Psm);

        float sacc[2][4][4] = {};
#pragma unroll
        for (int k8 = 0; k8 < 16; k8++) {
            float4 af[2];
            float2 bf[4];
            af[0] = Qs4[(k8 * 8 + wm * 2 + 0) * 32 + lane];
            af[1] = Qs4[(k8 * 8 + wm * 2 + 1) * 32 + lane];
#pragma unroll
            for (int nf = 0; nf < 4; nf++) bf[nf] = Ks2[(k8 * 8 + wn * 4 + nf) * 32 + lane];
#pragma unroll
            for (int mf = 0; mf < 2; mf++)
#pragma unroll
                for (int nf = 0; nf < 4; nf++)
                    mma_tf32(sacc[mf][nf],
                             reinterpret_cast<const uint32_t*>(&af[mf]),
                             reinterpret_cast<const uint32_t*>(&bf[nf]));
        }

        float mloc[2][2];
#pragma unroll
        for (int mf = 0; mf < 2; mf++) {
            float m0 = fmaxf(sacc[mf][0][0], sacc[mf][0][1]);
            float m1 = fmaxf(sacc[mf][0][2], sacc[mf][0][3]);
#pragma unroll
            for (int nf = 1; nf < 4; nf++) {
                m0 = fmaxf(m0, fmaxf(sacc[mf][nf][0], sacc[mf][nf][1]));
                m1 = fmaxf(m1, fmaxf(sacc[mf][nf][2], sacc[mf][nf][3]));
            }
            m0 = fmaxf(m0, __shfl_xor_sync(0xffffffffu, m0, 1));
            m0 = fmaxf(m0, __shfl_xor_sync(0xffffffffu, m0, 2));
            m1 = fmaxf(m1, __shfl_xor_sync(0xffffffffu, m1, 1));
            m1 = fmaxf(m1, __shfl_xor_sync(0xffffffffu, m1, 2));
            mloc[mf][0] = m0; mloc[mf][1] = m1;
        }
        if (tig == 0) {
#pragma unroll
            for (int mf = 0; mf < 2; mf++) {
                int r = wm * 32 + mf * 16 + gid;
                mpart[wn * 128 + r] = mloc[mf][0];
                mpart[wn * 128 + r + 8] = mloc[mf][1];
            }
        }
        __syncthreads();   // also orders: all K reads done before P overwrites Ksm[buf]

        float mnew[2][2], corr[2][2];
#pragma unroll
        for (int mf = 0; mf < 2; mf++)
#pragma unroll
            for (int hi = 0; hi < 2; hi++) {
                int r = wm * 32 + mf * 16 + gid + hi * 8;
                float mt = fmaxf(mpart[r], mpart[128 + r]);
                float mn = fmaxf(m_old[mf][hi], mt);
                corr[mf][hi] = __expf(m_old[mf][hi] - mn);
                mnew[mf][hi] = mn;
                m_old[mf][hi] = mn;
            }

        float sloc[2][2] = {};
#pragma unroll
        for (int mf = 0; mf < 2; mf++)
#pragma unroll
            for (int nf = 0; nf < 4; nf++) {
                sacc[mf][nf][0] = __expf(sacc[mf][nf][0] - mnew[mf][0]);
                sacc[mf][nf][1] = __expf(sacc[mf][nf][1] - mnew[mf][0]);
                sacc[mf][nf][2] = __expf(sacc[mf][nf][2] - mnew[mf][1]);
                sacc[mf][nf][3] = __expf(sacc[mf][nf][3] - mnew[mf][1]);
                sloc[mf][0] += sacc[mf][nf][0] + sacc[mf][nf][1];
                sloc[mf][1] += sacc[mf][nf][2] + sacc[mf][nf][3];
            }
#pragma unroll
        for (int mf = 0; mf < 2; mf++) {
            sloc[mf][0] += __shfl_xor_sync(0xffffffffu, sloc[mf][0], 1);
            sloc[mf][0] += __shfl_xor_sync(0xffffffffu, sloc[mf][0], 2);
            sloc[mf][1] += __shfl_xor_sync(0xffffffffu, sloc[mf][1], 1);
            sloc[mf][1] += __shfl_xor_sync(0xffffffffu, sloc[mf][1], 2);
        }
        if (tig == 0) {
#pragma unroll
            for (int mf = 0; mf < 2; mf++) {
                int r = wm * 32 + mf * 16 + gid;
                spart[wn * 128 + r] = sloc[mf][0];
                spart[wn * 128 + r + 8] = sloc[mf][1];
            }
        }

        // store P as A-fragments (tf32) into Psm (= Ksm[buf])
#pragma unroll
        for (int mf = 0; mf < 2; mf++)
#pragma unroll
            for (int nf = 0; nf < 4; nf++) {
                int k8p = wn * 4 + nf;
                int mfg = wm * 2 + mf;
#pragma unroll
                for (int b = 0; b < 2; b++) {
                    int c = tig * 2 + b;
                    int khi = (c >= 4);
                    int base = ((k8p * 8 + mfg) * 32 + (gid << 2) + (c & 3)) * 4 + khi * 2;
                    *reinterpret_cast<float2*>(Psm + base) =
                        make_float2(tf32f(sacc[mf][nf][b]), tf32f(sacc[mf][nf][2 + b]));
                }
            }
        __syncthreads();

#pragma unroll
        for (int mf = 0; mf < 2; mf++)
#pragma unroll
            for (int hi = 0; hi < 2; hi++) {
                int r = wm * 32 + mf * 16 + gid + hi * 8;
                l_run[mf][hi] = l_run[mf][hi] * corr[mf][hi] + spart[r] + spart[128 + r];
            }
#pragma unroll
        for (int mf = 0; mf < 2; mf++)
#pragma unroll
            for (int nf = 0; nf < 8; nf++) {
                oacc[mf][nf][0] *= corr[mf][0]; oacc[mf][nf][1] *= corr[mf][0];
                oacc[mf][nf][2] *= corr[mf][1]; oacc[mf][nf][3] *= corr[mf][1];
            }

#pragma unroll
        for (int k8 = 0; k8 < 8; k8++) {
            float4 af[2];
            af[0] = Ps4[(k8 * 8 + wm * 2 + 0) * 32 + lane];
            af[1] = Ps4[(k8 * 8 + wm * 2 + 1) * 32 + lane];
#pragma unroll
            for (int nf = 0; nf < 8; nf++) {
                float2 bf = Vs2[(k8 * 16 + wn * 8 + nf) * 32 + lane];
#pragma unroll
                for (int mf = 0; mf < 2; mf++)
                    mma_tf32(oacc[mf][nf],
                             reinterpret_cast<const uint32_t*>(&af[mf]),
                             reinterpret_cast<const uint32_t*>(&bf));
            }
        }
        __syncthreads();   // P reads done before next iteration's prefetch hits Ksm[buf]
    }

#pragma unroll
    for (int mf = 0; mf < 2; mf++) {
        float inv0 = 1.0f / l_run[mf][0];
        float inv1 = 1.0f / l_run[mf][1];
        int r0 = qt * 128 + wm * 32 + mf * 16 + gid;
#pragma unroll
        for (int nf = 0; nf < 8; nf++) {
            int col = wn * 64 + nf * 8 + tig * 2;
            *reinterpret_cast<float2*>(&AO[((size_t)r0 * NH + h) * DH + col]) =
                make_float2(oacc[mf][nf][0] * inv0, oacc[mf][nf][1] * inv0);
            *reinterpret_cast<float2*>(&AO[((size_t)(r0 + 8) * NH + h) * DH + col]) =
                make_float2(oacc[mf][nf][2] * inv1, oacc[mf][nf][3] * inv1);
        }
    }
}

// ---------------- expand stage C (reads Z = AO_sk @ wo) ----------------
__global__ void expandC_kernel(const float* __restrict__ Z, const float* __restrict__ ka,
                               float* __restrict__ E1) {
    int i = blockIdx.y;
    int hd = blockIdx.x * 256 + threadIdx.x;
    __shared__ float kav[20];
    if (threadIdx.x < 20) kav[threadIdx.x] = ka[threadIdx.x * DH + i];
    __syncthreads();
    for (int kbo = 0; kbo < 32; kbo++) {
        float acc = 0.f;
#pragma unroll
        for (int kao = 0; kao < 20; kao++)
            acc += Z[((size_t)(kbo * 20 + kao)) * HID + hd] * kav[kao];
        E1[((size_t)i * 32 + kbo) * HID + hd] = acc;
    }
}

// ---------------- expand stage D (writes final out rows) ----------------
__global__ void expandD_kernel(const float* __restrict__ E1, const float* __restrict__ kb,
                               float* __restrict__ OUT) {
    int i = blockIdx.y;
    int hd = blockIdx.x * 128 + threadIdx.x;
    __shared__ float kbs[32 * 256];
    for (int t = threadIdx.x; t < 32 * 256; t += 128) kbs[t] = kb[t];
    float e[32];
#pragma unroll
    for (int kbo = 0; kbo < 32; kbo++) e[kbo] = E1[((size_t)i * 32 + kbo) * HID + hd];
    __syncthreads();
    for (int j = 0; j < 256; j++) {
        float acc = 0.f;
#pragma unroll
        for (int kbo = 0; kbo < 32; kbo++) acc += e[kbo] * kbs[kbo * 256 + j];
        OUT[((size_t)(i * 256 + j)) * HID + hd] = acc;
    }
}

// ---------------- host launcher ----------------
extern "C" void kernel_launch(void* const* d_in, const int* in_sizes, int n_in,
                              void* d_out, int out_size) {
    const float* hs    = (const float*)d_in[0];
    const float* cosb  = (const float*)d_in[1];
    const float* sinb  = (const float*)d_in[2];
    const float* wq    = (const float*)d_in[3];
    const float* wk    = (const float*)d_in[4];
    const float* wv    = (const float*)d_in[5];
    const float* wo    = (const float*)d_in[6];
    const float* qnw   = (const float*)d_in[7];
    const float* knw   = (const float*)d_in[8];
    const float* w1    = (const float*)d_in[9];
    const float* b1    = (const float*)d_in[10];
    const float* w2    = (const float*)d_in[11];
    const float* b2    = (const float*)d_in[12];
    const float* ka    = (const float*)d_in[13];
    const float* kb    = (const float*)d_in[14];
    const float* sscale= (const float*)d_in[15];
    float* out = (float*)d_out;

    float *pT, *pLg, *pW, *pQ, *pKV, *pP, *pQfr, *pKfr, *pVfr, *pAO, *pE1, *pZ, *pAfr, *pBfr;
    int *pTop, *pIs;
    cudaGetSymbolAddress((void**)&pT, g_T);
    cudaGetSymbolAddress((void**)&pLg, g_logits);
    cudaGetSymbolAddress((void**)&pW, g_weights);
    cudaGetSymbolAddress((void**)&pQ, g_q);
    cudaGetSymbolAddress((void**)&pKV, g_kv);
    cudaGetSymbolAddress((void**)&pP, g_P);
    cudaGetSymbolAddress((void**)&pQfr, g_Qfr);
    cudaGetSymbolAddress((void**)&pKfr, g_Kfr);
    cudaGetSymbolAddress((void**)&pVfr, g_Vfr);
    cudaGetSymbolAddress((void**)&pAO, g_AO);
    cudaGetSymbolAddress((void**)&pE1, g_E1);
    cudaGetSymbolAddress((void**)&pZ, g_Z);
    cudaGetSymbolAddress((void**)&pAfr, g_Afr);
    cudaGetSymbolAddress((void**)&pBfr, g_Bfr);
    cudaGetSymbolAddress((void**)&pTop, g_topk);
    cudaGetSymbolAddress((void**)&pIs, g_istop);

    cudaFuncSetAttribute(topk_kernel, cudaFuncAttributeMaxDynamicSharedMemorySize, SEQ * 8);
    cudaFuncSetAttribute(fa_mma_kernel, cudaFuncAttributeMaxDynamicSharedMemorySize, FA2_SMEM);

    // 1) importance MLP first GEMM — fp32 split-K x8 (feeds top-k)
    imp_gemm_kernel<<<dim3(1, SEQ / 64, 8), 256>>>(hs, w1, pT);
    imp_logits_kernel<<<SEQ, 32>>>(pT, b1, w2, b2, pLg, pW);
    // 2) convert hs to A-fragments (shared by q and kv GEMMs)
    convA_kernel<<<dim3(HID / 16, SEQ / 128), 256>>>(hs, pAfr, HID);
    // 3) Q projection
    convB_kernel<<<dim3(HID / 16, HID / 128), 256>>>(wq, pBfr, HID, HID, 0);
    mma_gemm_kernel<<<dim3(HID / 128, SEQ / 128), 256>>>(pAfr, pBfr, pQ, nullptr, HID, HID);
    // 4) fused K|V projection (N=1024)
    convB_kernel<<<dim3(HID / 16, 512 / 128), 256>>>(wk, pBfr, HID, 512, 0);
    convB_kernel<<<dim3(HID / 16, 512 / 128), 256>>>(wv, pBfr, HID, 512, 4);
    mma_gemm_kernel<<<dim3(1024 / 128, SEQ / 128), 256>>>(pAfr, pBfr, pKV, nullptr, 1024, HID);
    // 5) RMSNorm q, k
    rmsnorm_kernel<<<SEQ * NH, DH>>>(pQ, qnw, HID, NH);
    rmsnorm_kernel<<<SEQ * NKV, DH>>>(pKV, knw, 1024, NKV);
    // 6) top-k selection
    topk_kernel<<<1, 1024, SEQ * 8>>>(pLg, pTop, pIs);
    // 7) sketches -> fragment buffers
    sketchA_kernel<<<dim3(NH, 32), DH>>>(pQ, 16, 0, pW, pIs, 0, kb, pP);
    sketchB_kernel<<<dim3(NH, 32), DH>>>(pP, NH, ka, sscale, pQfr, 0);
    sketchA_kernel<<<dim3(NKV, 32), DH>>>(pKV, 8, 0, pW, pIs, 1, kb, pP);
    sketchB_kernel<<<dim3(NKV, 32), DH>>>(pP, NKV, ka, sscale, pKfr, 1);
    sketchA_kernel<<<dim3(NKV, 32), DH>>>(pKV, 8, 4, pW, pIs, 1, kb, pP);
    sketchB_kernel<<<dim3(NKV, 32), DH>>>(pP, NKV, ka, sscale, pVfr, 2);
    // 8) gather top-k rows + RoPE -> fragment buffers
    gather_rope_kernel<<<dim3(TK, 24), DH>>>(pQ, pKV, cosb, sinb, pTop, pQfr, pKfr, pVfr);
    // 9) attention — tensor-core FA2 with cp.async K/V pipeline
    fa_mma_kernel<<<dim3(NQT, NH), 256, FA2_SMEM>>>(pQfr, pKfr, pVfr, pAO);
    // 10) convert AO (all 2688 rows) and wo
    convA_kernel<<<dim3(HID / 16, NQF / 128), 256>>>(pAO, pAfr, HID);
    convB_kernel<<<dim3(HID / 16, HID / 128), 256>>>(wo, pBfr, HID, HID, 0);
    // 11) Z = AO_sk @ wo  (rows 2048..2687 -> A-frag row tiles 16..20)
    mma_gemm_kernel<<<dim3(HID / 128, SK / 128), 256>>>(
        pAfr + (size_t)16 * (HID / 16) * 2048, pBfr, pZ, nullptr, HID, HID);
    // 12) expand Z to all positions, writing out directly
    expandC_kernel<<<dim3(HID / 256, 32), 256>>>(pZ, ka, pE1);
    expandD_kernel<<<dim3(HID / 128, 32), DH>>>(pE1, kb, out);
    // 13) deterministic rows: (AO_det @ wo) scattered to out[topk[m]]
    mma_gemm_kernel<<<dim3(HID / 128, TK / 128), 256>>>(pAfr, pBfr, out, pTop, HID, HID);
}

// round 9
// speedup vs baseline: 4.3670x; 1.2086x over previous
#include <cuda_runtime.h>
#include <cuda_bf16.h>
#include <math.h>
#include <cstdint>

// Problem constants
#define SEQ   8192
#define HID   2048
#define NH    16
#define NKV   4
#define DH    128
#define TK    2048
#define SK    640
#define NQF   (TK + SK)        // 2688
#define NQT   (NQF / 128)      // 21 q tiles
#define NKT   (NQF / 64)       // 42 key tiles
#define ATT_SCALE 0.08838834764831843f   // 1/sqrt(128)

// ---------------- scratch (device globals; no allocation) ----------------
__device__ float g_T[8 * SEQ * 64];        // split-K partials
__device__ float g_logits[SEQ];
__device__ float g_weights[SEQ];
__device__ float g_q[SEQ * NH * DH];       // normalized q  [s][h][d]
__device__ float g_kv[SEQ * 1024];         // fused k(0:512)|v(512:1024) per row
__device__ int   g_topk[TK];
__device__ int   g_istop[SEQ];
__device__ float g_Pq[NH * 32 * 32 * DH];  // sketch stage-A scratch (q)
__device__ float g_Pk[NKV * 32 * 32 * DH]; // sketch stage-A scratch (k)
__device__ float g_Pv[NKV * 32 * 32 * DH]; // sketch stage-A scratch (v)
__device__ float g_Qfr[NH * NQT * 16 * 8 * 32 * 4];    // Q mma-fragments
__device__ float g_Kfr[NKV * NKT * 16 * 8 * 32 * 2];   // K mma-fragments
__device__ float g_Vfr[NKV * NKT * 8 * 16 * 32 * 2];   // V mma-fragments
__device__ float g_AO[NQF * NH * DH];      // attention output [q][h][d]
__device__ float g_E1[32 * 32 * HID];      // expand stage-C scratch [i][kb][hd]
__device__ float g_Z[SK * HID];            // sketch-part @ wo
__device__ float g_Afr[SEQ * HID];         // A fragments (hs / AO)
__device__ float g_Bfr[40 * 128 * 2048];   // B fragments: wq[0:16) | kv[16:24) | wo[24:40) col tiles

// ======================= tf32 mma.sync helpers =======================
__device__ __forceinline__ float tf32f(float x) {
    uint32_t r; asm("cvt.rna.tf32.f32 %0, %1;" : "=r"(r) : "f"(x));
    return __uint_as_float(r);
}

__device__ __forceinline__ void mma_tf32(float* c, const uint32_t* a, const uint32_t* b) {
    asm volatile("mma.sync.aligned.m16n8k8.row.col.f32.tf32.tf32.f32 "
        "{%0,%1,%2,%3}, {%4,%5,%6,%7}, {%8,%9}, {%0,%1,%2,%3};"
        : "+f"(c[0]), "+f"(c[1]), "+f"(c[2]), "+f"(c[3])
        : "r"(a[0]), "r"(a[1]), "r"(a[2]), "r"(a[3]), "r"(b[0]), "r"(b[1]));
}

#define CP_ASYNC16(dst_u32, src_ptr) \
    asm volatile("cp.async.cg.shared.global [%0], [%1], 16;" :: "r"(dst_u32), "l"(src_ptr))
#define CP_COMMIT() asm volatile("cp.async.commit_group;")

// fragment-layout gmem stores for attention operands
__device__ __forceinline__ void store_qfrag(float* Qg, int h, int tok, int d, float v) {
    int qt = tok >> 7, m = tok & 127;
    int k8 = d >> 3, mf = m >> 4;
    int lane = ((m & 7) << 2) | (d & 3);
    int reg = 2 * ((d & 7) >= 4) + ((m & 15) >= 8);
    size_t idx = ((((size_t)(h * NQT + qt) * 16 + k8) * 8 + mf) * 32 + lane) * 4 + reg;
    Qg[idx] = tf32f(v);
}
__device__ __forceinline__ void store_kfrag(float* Kg, int kvh, int tok, int d, float v) {
    int kt = tok >> 6, key = tok & 63;
    int k8 = d >> 3, nf = key >> 3;
    int lane = ((key & 7) << 2) | (d & 3);
    int reg = ((d & 7) >= 4);
    size_t idx = ((((size_t)(kvh * NKT + kt) * 16 + k8) * 8 + nf) * 32 + lane) * 2 + reg;
    Kg[idx] = tf32f(v);
}
__device__ __forceinline__ void store_vfrag(float* Vg, int kvh, int tok, int d, float v) {
    int kt = tok >> 6, key = tok & 63;
    int k8 = key >> 3, nf = d >> 3;
    int lane = ((d & 7) << 2) | (key & 3);
    int reg = ((key & 7) >= 4);
    size_t idx = ((((size_t)(kvh * NKT + kt) * 8 + k8) * 16 + nf) * 32 + lane) * 2 + reg;
    Vg[idx] = tf32f(v);
}

// ======================= fragment conversion pre-passes =======================
__global__ void __launch_bounds__(256) convA_kernel(const float* __restrict__ A,
                                                    float* __restrict__ Afr, int K) {
    __shared__ float sm[2048];
    const int rt = blockIdx.y, c = blockIdx.x;
    const int tid = threadIdx.x;
    const float* Ab = A + ((size_t)rt * 128) * K + c * 16;
#pragma unroll
    for (int i = 0; i < 2; i++) {
        int f = tid + i * 256;
        int r = f >> 2, c4 = f & 3;
        float4 v = *reinterpret_cast<const float4*>(Ab + (size_t)r * K + c4 * 4);
        int mf = r >> 4, gid = r & 7, mhi = (r >> 3) & 1;
        float vv[4] = {v.x, v.y, v.z, v.w};
#pragma unroll
        for (int j = 0; j < 4; j++) {
            int k = c4 * 4 + j;
            int slot = ((k >> 3) * 8 + mf) * 128 + ((gid << 2) | (k & 3)) * 4
                     + 2 * ((k & 7) >= 4) + mhi;
            sm[slot] = tf32f(vv[j]);
        }
    }
    __syncthreads();
    float4* out = reinterpret_cast<float4*>(Afr + ((size_t)(rt * (K >> 4) + c)) * 2048);
    const float4* s4 = reinterpret_cast<const float4*>(sm);
#pragma unroll
    for (int i = 0; i < 2; i++) out[tid + i * 256] = s4[tid + i * 256];
}

__global__ void __launch_bounds__(256) convB_kernel(const float* __restrict__ B,
                                                    float* __restrict__ Bfr, int K, int N,
                                                    int ctbase) {
    __shared__ float sm[2048];
    const int ct = blockIdx.y + ctbase, c = blockIdx.x;
    const int tid = threadIdx.x;
    const float* Bb = B + ((size_t)(c * 16)) * N + blockIdx.y * 128;
#pragma unroll
    for (int i = 0; i < 2; i++) {
        int f = tid + i * 256;
        int kk = f >> 5, n4 = f & 31;
        float4 v = *reinterpret_cast<const float4*>(Bb + (size_t)kk * N + n4 * 4);
        int k8in = kk >> 3, reg = ((kk & 7) >= 4);
        float vv[4] = {v.x, v.y, v.z, v.w};
#pragma unroll
        for (int j = 0; j < 4; j++) {
            int n = n4 * 4 + j;
            int slot = (k8in * 16 + (n >> 3)) * 64 + (((n & 7) << 2) | (kk & 3)) * 2 + reg;
            sm[slot] = tf32f(vv[j]);
        }
    }
    __syncthreads();
    float4* out = reinterpret_cast<float4*>(Bfr + ((size_t)(ct * (K >> 4) + c)) * 2048);
    const float4* s4 = reinterpret_cast<const float4*>(sm);
#pragma unroll
    for (int i = 0; i < 2; i++) out[tid + i * 256] = s4[tid + i * 256];
}

// ======================= tf32 GEMM: CTA 128x128, cp.async 3-stage, 2 CTA/SM ========
__global__ void __launch_bounds__(256, 2) mma_gemm_kernel(
    const float* __restrict__ Afr, const float* __restrict__ Bfr,
    float* __restrict__ C, const int* __restrict__ remap, int N, int K)
{
    __shared__ float sA[3][2048];
    __shared__ float sB[3][2048];

    const int tid = threadIdx.x;
    const int lane = tid & 31, wid = tid >> 5;
    const int wm = wid >> 2, wn = wid & 3;
    const int NCH = K >> 4;

    const float4* Ag = reinterpret_cast<const float4*>(Afr) + (size_t)blockIdx.y * NCH * 512;
    const float4* Bg = reinterpret_cast<const float4*>(Bfr) + (size_t)blockIdx.x * NCH * 512;

    const uint32_t sAu = (uint32_t)__cvta_generic_to_shared(&sA[0][0]) + tid * 16;
    const uint32_t sBu = (uint32_t)__cvta_generic_to_shared(&sB[0][0]) + tid * 16;

    {
        const float4* ga = Ag + tid;  const float4* gb = Bg + tid;
        CP_ASYNC16(sAu, ga); CP_ASYNC16(sAu + 4096, ga + 256);
        CP_ASYNC16(sBu, gb); CP_ASYNC16(sBu + 4096, gb + 256);
        CP_COMMIT();
        if (NCH > 1) {
            ga += 512; gb += 512;
            CP_ASYNC16(sAu + 8192, ga); CP_ASYNC16(sAu + 8192 + 4096, ga + 256);
            CP_ASYNC16(sBu + 8192, gb); CP_ASYNC16(sBu + 8192 + 4096, gb + 256);
            CP_COMMIT();
        }
    }

    float acc[4][4][4] = {};
    for (int c = 0; c < NCH; c++) {
        if (c + 1 < NCH) asm volatile("cp.async.wait_group 1;");
        else             asm volatile("cp.async.wait_group 0;");
        __syncthreads();

        const int buf = c % 3;
        const float4* A4 = reinterpret_cast<const float4*>(sA[buf]);
        const float2* B2 = reinterpret_cast<const float2*>(sB[buf]);
#pragma unroll
        for (int k8 = 0; k8 < 2; k8++) {
            float4 af[4];
            float2 bf[4];
#pragma unroll
            for (int mf = 0; mf < 4; mf++)
                af[mf] = A4[(k8 * 8 + wm * 4 + mf) * 32 + lane];
#pragma unroll
            for (int nf = 0; nf < 4; nf++)
                bf[nf] = B2[(k8 * 16 + wn * 4 + nf) * 32 + lane];
#pragma unroll
            for (int mf = 0; mf < 4; mf++)
#pragma unroll
                for (int nf = 0; nf < 4; nf++)
                    mma_tf32(acc[mf][nf],
                             reinterpret_cast<const uint32_t*>(&af[mf]),
                             reinterpret_cast<const uint32_t*>(&bf[nf]));
        }
        if (c + 2 < NCH) {
            const int st = (c + 2) % 3;
            const float4* ga = Ag + (c + 2) * 512 + tid;
            const float4* gb = Bg + (c + 2) * 512 + tid;
            CP_ASYNC16(sAu + st * 8192, ga); CP_ASYNC16(sAu + st * 8192 + 4096, ga + 256);
            CP_ASYNC16(sBu + st * 8192, gb); CP_ASYNC16(sBu + st * 8192 + 4096, gb + 256);
            CP_COMMIT();
        }
    }

    const int row0 = blockIdx.y * 128;
    const int col0 = blockIdx.x * 128;
    const int gid = lane >> 2, tig = lane & 3;
#pragma unroll
    for (int mf = 0; mf < 4; mf++) {
        int m = row0 + wm * 64 + mf * 16 + gid;
        int m1 = remap ? __ldg(&remap[m]) : m;
        int m2 = remap ? __ldg(&remap[m + 8]) : (m + 8);
#pragma unroll
        for (int nf = 0; nf < 4; nf++) {
            int n = col0 + wn * 32 + nf * 8 + tig * 2;
            *reinterpret_cast<float2*>(&C[(size_t)m1 * N + n]) =
                make_float2(acc[mf][nf][0], acc[mf][nf][1]);
            *reinterpret_cast<float2*>(&C[(size_t)m2 * N + n]) =
                make_float2(acc[mf][nf][2], acc[mf][nf][3]);
        }
    }
}

// ---------------- importance GEMM: fp32 split-K x8 (top-k needs fp32) -----------
__global__ void __launch_bounds__(256) imp_gemm_kernel(
    const float* __restrict__ A, const float* __restrict__ B, float* __restrict__ Cp)
{
    __shared__ float As[16][64];
    __shared__ float Bs[16][64];
    const int tid = threadIdx.x;
    const int row0 = blockIdx.y * 64;
    const int z = blockIdx.z;
    const float* Ab = A + (size_t)row0 * HID + z * 256;
    const float* Bb = B + (size_t)z * 256 * 64;
    float acc[4][4] = {};
    const int tc = (tid & 15) * 4, tr = (tid >> 4) * 4;
    const int ar = tid >> 2, ac = (tid & 3) * 4;
    const int br = tid >> 4, bc = (tid & 15) * 4;

    for (int k0 = 0; k0 < 256; k0 += 16) {
        float4 va = *reinterpret_cast<const float4*>(Ab + (size_t)ar * HID + k0 + ac);
        As[ac + 0][ar] = va.x; As[ac + 1][ar] = va.y;
        As[ac + 2][ar] = va.z; As[ac + 3][ar] = va.w;
        float4 vb = *reinterpret_cast<const float4*>(Bb + (size_t)(k0 + br) * 64 + bc);
        *reinterpret_cast<float4*>(&Bs[br][bc]) = vb;
        __syncthreads();
#pragma unroll
        for (int k = 0; k < 16; k++) {
            float ra[4], rb[4];
#pragma unroll
            for (int m = 0; m < 4; m++) ra[m] = As[k][tr + m];
#pragma unroll
            for (int n = 0; n < 4; n++) rb[n] = Bs[k][tc + n];
#pragma unroll
            for (int m = 0; m < 4; m++)
#pragma unroll
                for (int n = 0; n < 4; n++) acc[m][n] += ra[m] * rb[n];
        }
        __syncthreads();
    }
#pragma unroll
    for (int m = 0; m < 4; m++) {
        float4 v = make_float4(acc[m][0], acc[m][1], acc[m][2], acc[m][3]);
        *reinterpret_cast<float4*>(&Cp[((size_t)z * SEQ + row0 + tr + m) * 64 + tc]) = v;
    }
}

// ---------------- importance logits epilogue ----------------
__global__ void imp_logits_kernel(const float* __restrict__ T, const float* __restrict__ b1,
                                  const float* __restrict__ w2, const float* __restrict__ b2,
                                  float* __restrict__ logits, float* __restrict__ weights) {
    const float LOG_ADJ = 2.5494451709255714f;   // log(8192/640)
    int s = blockIdx.x;
    int j = threadIdx.x;  // 32
    float v1 = 0.f, v2 = 0.f;
#pragma unroll
    for (int z = 0; z < 8; z++) {
        v1 += T[((size_t)z * SEQ + s) * 64 + j];
        v2 += T[((size_t)z * SEQ + s) * 64 + j + 32];
    }
    float v = tanhf(v1 + b1[j]) * w2[j] + tanhf(v2 + b1[j + 32]) * w2[j + 32];
#pragma unroll
    for (int o = 16; o > 0; o >>= 1) v += __shfl_xor_sync(0xffffffffu, v, o);
    if (j == 0) {
        float lg = v + b2[0] - LOG_ADJ;
        logits[s] = lg;
        weights[s] = 1.0f / (1.0f + expf(-lg));
    }
}

// ---------------- RMSNorm (generic head addressing) ----------------
__global__ void rmsnorm_kernel(float* __restrict__ X, const float* __restrict__ w,
                               int stride, int nh) {
    int r = blockIdx.x;
    int s = r / nh, h = r % nh;
    float* row = X + (size_t)s * stride + h * DH;
    int d = threadIdx.x;   // 128
    float x = row[d];
    float ss = x * x;
#pragma unroll
    for (int o = 16; o > 0; o >>= 1) ss += __shfl_xor_sync(0xffffffffu, ss, o);
    __shared__ float sm[4];
    if ((d & 31) == 0) sm[d >> 5] = ss;
    __syncthreads();
    float tot = sm[0] + sm[1] + sm[2] + sm[3];
    row[d] = x * rsqrtf(tot * (1.0f / 128.0f) + 1e-6f) * w[d];
}

// ---------------- top-k via single-block bitonic sort ----------------
__global__ void topk_kernel(const float* __restrict__ logits,
                            int* __restrict__ topk_list, int* __restrict__ is_topk) {
    extern __shared__ unsigned long long skeys[];
    int tid = threadIdx.x;  // 1024
    for (int i = tid; i < SEQ; i += 1024) {
        unsigned u = __float_as_uint(logits[i]);
        u = (u & 0x80000000u) ? ~u : (u | 0x80000000u);
        skeys[i] = ((unsigned long long)(~u) << 32) | (unsigned)i;
        is_topk[i] = 0;
    }
    __syncthreads();
    for (int k = 2; k <= SEQ; k <<= 1) {
        for (int j = k >> 1; j > 0; j >>= 1) {
            for (int i = tid; i < SEQ; i += 1024) {
                int ixj = i ^ j;
                if (ixj > i) {
                    bool up = ((i & k) == 0);
                    unsigned long long a = skeys[i], b = skeys[ixj];
                    if ((a > b) == up) { skeys[i] = b; skeys[ixj] = a; }
                }
            }
            __syncthreads();
        }
    }
    for (int i = tid; i < TK; i += 1024) {
        int pos = (int)(skeys[i] & 0xffffffffu);
        topk_list[i] = pos;
        is_topk[pos] = 1;
    }
}

// ---------------- sketch stage A (generic head addressing) ----------------
__global__ void sketchA_kernel(const float* __restrict__ X, int hstride, int hbase,
                               const float* __restrict__ weights,
                               const int* __restrict__ is_topk, int rest,
                               const float* __restrict__ kb, float* __restrict__ P) {
    int h = blockIdx.x;
    int ib = blockIdx.y;   // 0..31
    int d = threadIdx.x;   // 128
    __shared__ float kbs[32 * 256];
    for (int t = d; t < 32 * 256; t += 128) kbs[t] = kb[t];
    __shared__ float ws[256];
    for (int j = d; j < 256; j += 128) {
        int t = ib * 256 + j;
        float w = weights[t];
        if (rest && is_topk[t]) w = 0.0f;
        ws[j] = w;
    }
    __syncthreads();
    float acc[32] = {};
    for (int j = 0; j < 256; j++) {
        float xv = X[((size_t)(ib * 256 + j) * hstride + hbase + h) * DH + d] * ws[j];
#pragma unroll
        for (int kbo = 0; kbo < 32; kbo++) acc[kbo] += xv * kbs[kbo * 256 + j];
    }
#pragma unroll
    for (int kbo = 0; kbo < 32; kbo++)
        P[(((size_t)h * 32 + kbo) * 32 + ib) * DH + d] = acc[kbo];
}

// ---------------- sketch stage B ----------------
__global__ void sketchB_kernel(const float* __restrict__ P, int heads,
                               const float* __restrict__ ka,
                               const float* __restrict__ scale_p,
                               float* __restrict__ dstfrag, int mode) {
    int h = blockIdx.x;
    int kbo = blockIdx.y;
    int d = threadIdx.x;   // 128
    __shared__ float kas[20 * 32];
    for (int t = d; t < 20 * 32; t += 128) kas[t] = ka[(t / 32) * DH + (t % 32)];
    __syncthreads();
    float p[32];
#pragma unroll
    for (int i = 0; i < 32; i++) p[i] = P[(((size_t)h * 32 + kbo) * 32 + i) * DH + d];
    float scale = scale_p[0];
    if (mode == 0) scale *= ATT_SCALE;
#pragma unroll
    for (int kao = 0; kao < 20; kao++) {
        float acc = 0.f;
#pragma unroll
        for (int i = 0; i < 32; i++) acc += p[i] * kas[kao * 32 + i];
        int s = TK + kbo * 20 + kao;
        float val = acc * scale;
        if (mode == 0)      store_qfrag(dstfrag, h, s, d, val);
        else if (mode == 1) store_kfrag(dstfrag, h, s, d, val);
        else                store_vfrag(dstfrag, h, s, d, val);
    }
}

// ---------------- gather + RoPE for top-k rows -> mma fragments ----------------
__global__ void gather_rope_kernel(const float* __restrict__ q, const float* __restrict__ kv,
                                   const float* __restrict__ cosb, const float* __restrict__ sinb,
                                   const int* __restrict__ topk_list,
                                   float* __restrict__ Qfr, float* __restrict__ Kfr,
                                   float* __restrict__ Vfr) {
    int j = blockIdx.x;    // 0..2047
    int hy = blockIdx.y;   // 0..23
    int d = threadIdx.x;
    int pos = topk_list[j];
    float c = cosb[(size_t)pos * DH + d];
    float s = sinb[(size_t)pos * DH + d];
    if (hy < 16) {
        const float* src = q + ((size_t)pos * NH + hy) * DH;
        float x = src[d];
        float r = (d < 64) ? -src[d + 64] : src[d - 64];
        store_qfrag(Qfr, hy, j, d, (x * c + r * s) * ATT_SCALE);
    } else if (hy < 20) {
        int h = hy - 16;
        const float* src = kv + (size_t)pos * 1024 + h * DH;
        float x = src[d];
        float r = (d < 64) ? -src[d + 64] : src[d - 64];
        store_kfrag(Kfr, h, j, d, x * c + r * s);
    } else {
        int h = hy - 20;
        store_vfrag(Vfr, h, j, d, kv[(size_t)pos * 1024 + 512 + h * DH + d]);
    }
}

// ---------------- tensor-core flash attention (cp.async double-buffered K/V) -------
#define FA2_SMEM ((16384 + 2*8192 + 2*8192 + 512) * 4)
__global__ void __launch_bounds__(256, 1) fa_mma_kernel(
    const float* __restrict__ Qfr, const float* __restrict__ Kfr,
    const float* __restrict__ Vfr, float* __restrict__ AO)
{
    extern __shared__ float fsm[];
    float* Qsm = fsm;                       // 16384
    float* Ksm = fsm + 16384;               // 2 x 8192
    float* Vsm = fsm + 32768;               // 2 x 8192
    float* mpart = fsm + 49152;             // 256
    float* spart = fsm + 49408;             // 256

    const int qt = blockIdx.x;
    const int h  = blockIdx.y;
    const int kvh = h >> 2;
    const int tid = threadIdx.x;
    const int lane = tid & 31, wid = tid >> 5;
    const int wm = wid >> 1, wn = wid & 1;
    const int gid = lane >> 2, tig = lane & 3;

    const uint32_t ksmU = (uint32_t)__cvta_generic_to_shared(Ksm) + tid * 16;
    const uint32_t vsmU = (uint32_t)__cvta_generic_to_shared(Vsm) + tid * 16;

    {
        const float4* Kg = reinterpret_cast<const float4*>(Kfr + (size_t)(kvh * NKT) * 8192);
        const float4* Vg = reinterpret_cast<const float4*>(Vfr + (size_t)(kvh * NKT) * 8192);
#pragma unroll
        for (int i = 0; i < 8; i++) {
            CP_ASYNC16(ksmU + i * 4096, Kg + tid + i * 256);
            CP_ASYNC16(vsmU + i * 4096, Vg + tid + i * 256);
        }
        CP_COMMIT();
    }

    {
        const float4* Qg = reinterpret_cast<const float4*>(Qfr + (size_t)(h * NQT + qt) * 16384);
        float4* Qs4w = reinterpret_cast<float4*>(Qsm);
#pragma unroll
        for (int i = 0; i < 16; i++) Qs4w[tid + i * 256] = Qg[tid + i * 256];
    }

    float m_old[2][2], l_run[2][2];
#pragma unroll
    for (int a = 0; a < 2; a++)
#pragma unroll
        for (int b = 0; b < 2; b++) { m_old[a][b] = -1e30f; l_run[a][b] = 0.f; }
    float oacc[2][8][4] = {};

    const float4* Qs4 = reinterpret_cast<const float4*>(Qsm);

    for (int kt = 0; kt < NKT; kt++) {
        const int buf = kt & 1;
        if (kt + 1 < NKT) {
            const float4* Kg = reinterpret_cast<const float4*>(Kfr + (size_t)(kvh * NKT + kt + 1) * 8192);
            const float4* Vg = reinterpret_cast<const float4*>(Vfr + (size_t)(kvh * NKT + kt + 1) * 8192);
            const uint32_t kd = ksmU + (1 - buf) * 32768;
            const uint32_t vd = vsmU + (1 - buf) * 32768;
#pragma unroll
            for (int i = 0; i < 8; i++) {
                CP_ASYNC16(kd + i * 4096, Kg + tid + i * 256);
                CP_ASYNC16(vd + i * 4096, Vg + tid + i * 256);
            }
            CP_COMMIT();
            asm volatile("cp.async.wait_group 1;");
        } else {
            asm volatile("cp.async.wait_group 0;");
        }
        __syncthreads();

        const float2* Ks2 = reinterpret_cast<const float2*>(Ksm + buf * 8192);
        const float2* Vs2 = reinterpret_cast<const float2*>(Vsm + buf * 8192);
        float* Psm = Ksm + buf * 8192;
        const float4* Ps4 = reinterpret_cast<const float4*>(Psm);

        float sacc[2][4][4] = {};
#pragma unroll
        for (int k8 = 0; k8 < 16; k8++) {
            float4 af[2];
            float2 bf[4];
            af[0] = Qs4[(k8 * 8 + wm * 2 + 0) * 32 + lane];
            af[1] = Qs4[(k8 * 8 + wm * 2 + 1) * 32 + lane];
#pragma unroll
            for (int nf = 0; nf < 4; nf++) bf[nf] = Ks2[(k8 * 8 + wn * 4 + nf) * 32 + lane];
#pragma unroll
            for (int mf = 0; mf < 2; mf++)
#pragma unroll
                for (int nf = 0; nf < 4; nf++)
                    mma_tf32(sacc[mf][nf],
                             reinterpret_cast<const uint32_t*>(&af[mf]),
                             reinterpret_cast<const uint32_t*>(&bf[nf]));
        }

        float mloc[2][2];
#pragma unroll
        for (int mf = 0; mf < 2; mf++) {
            float m0 = fmaxf(sacc[mf][0][0], sacc[mf][0][1]);
            float m1 = fmaxf(sacc[mf][0][2], sacc[mf][0][3]);
#pragma unroll
            for (int nf = 1; nf < 4; nf++) {
                m0 = fmaxf(m0, fmaxf(sacc[mf][nf][0], sacc[mf][nf][1]));
                m1 = fmaxf(m1, fmaxf(sacc[mf][nf][2], sacc[mf][nf][3]));
            }
            m0 = fmaxf(m0, __shfl_xor_sync(0xffffffffu, m0, 1));
            m0 = fmaxf(m0, __shfl_xor_sync(0xffffffffu, m0, 2));
            m1 = fmaxf(m1, __shfl_xor_sync(0xffffffffu, m1, 1));
            m1 = fmaxf(m1, __shfl_xor_sync(0xffffffffu, m1, 2));
            mloc[mf][0] = m0; mloc[mf][1] = m1;
        }
        if (tig == 0) {
#pragma unroll
            for (int mf = 0; mf < 2; mf++) {
                int r = wm * 32 + mf * 16 + gid;
                mpart[wn * 128 + r] = mloc[mf][0];
                mpart[wn * 128 + r + 8] = mloc[mf][1];
            }
        }
        __syncthreads();

        float mnew[2][2], corr[2][2];
#pragma unroll
        for (int mf = 0; mf < 2; mf++)
#pragma unroll
            for (int hi = 0; hi < 2; hi++) {
                int r = wm * 32 + mf * 16 + gid + hi * 8;
                float mt = fmaxf(mpart[r], mpart[128 + r]);
                float mn = fmaxf(m_old[mf][hi], mt);
                corr[mf][hi] = __expf(m_old[mf][hi] - mn);
                mnew[mf][hi] = mn;
                m_old[mf][hi] = mn;
            }

        float sloc[2][2] = {};
#pragma unroll
        for (int mf = 0; mf < 2; mf++)
#pragma unroll
            for (int nf = 0; nf < 4; nf++) {
                sacc[mf][nf][0] = __expf(sacc[mf][nf][0] - mnew[mf][0]);
                sacc[mf][nf][1] = __expf(sacc[mf][nf][1] - mnew[mf][0]);
                sacc[mf][nf][2] = __expf(sacc[mf][nf][2] - mnew[mf][1]);
                sacc[mf][nf][3] = __expf(sacc[mf][nf][3] - mnew[mf][1]);
                sloc[mf][0] += sacc[mf][nf][0] + sacc[mf][nf][1];
                sloc[mf][1] += sacc[mf][nf][2] + sacc[mf][nf][3];
            }
#pragma unroll
        for (int mf = 0; mf < 2; mf++) {
            sloc[mf][0] += __shfl_xor_sync(0xffffffffu, sloc[mf][0], 1);
            sloc[mf][0] += __shfl_xor_sync(0xffffffffu, sloc[mf][0], 2);
            sloc[mf][1] += __shfl_xor_sync(0xffffffffu, sloc[mf][1], 1);
            sloc[mf][1] += __shfl_xor_sync(0xffffffffu, sloc[mf][1], 2);
        }
        if (tig == 0) {
#pragma unroll
            for (int mf = 0; mf < 2; mf++) {
                int r = wm * 32 + mf * 16 + gid;
                spart[wn * 128 + r] = sloc[mf][0];
                spart[wn * 128 + r + 8] = sloc[mf][1];
            }
        }

#pragma unroll
        for (int mf = 0; mf < 2; mf++)
#pragma unroll
            for (int nf = 0; nf < 4; nf++) {
                int k8p = wn * 4 + nf;
                int mfg = wm * 2 + mf;
#pragma unroll
                for (int b = 0; b < 2; b++) {
                    int c = tig * 2 + b;
                    int khi = (c >= 4);
                    int base = ((k8p * 8 + mfg) * 32 + (gid << 2) + (c & 3)) * 4 + khi * 2;
                    *reinterpret_cast<float2*>(Psm + base) =
                        make_float2(tf32f(sacc[mf][nf][b]), tf32f(sacc[mf][nf][2 + b]));
                }
            }
        __syncthreads();

#pragma unroll
        for (int mf = 0; mf < 2; mf++)
#pragma unroll
            for (int hi = 0; hi < 2; hi++) {
                int r = wm * 32 + mf * 16 + gid + hi * 8;
                l_run[mf][hi] = l_run[mf][hi] * corr[mf][hi] + spart[r] + spart[128 + r];
            }
#pragma unroll
        for (int mf = 0; mf < 2; mf++)
#pragma unroll
            for (int nf = 0; nf < 8; nf++) {
                oacc[mf][nf][0] *= corr[mf][0]; oacc[mf][nf][1] *= corr[mf][0];
                oacc[mf][nf][2] *= corr[mf][1]; oacc[mf][nf][3] *= corr[mf][1];
            }

#pragma unroll
        for (int k8 = 0; k8 < 8; k8++) {
            float4 af[2];
            af[0] = Ps4[(k8 * 8 + wm * 2 + 0) * 32 + lane];
            af[1] = Ps4[(k8 * 8 + wm * 2 + 1) * 32 + lane];
#pragma unroll
            for (int nf = 0; nf < 8; nf++) {
                float2 bf = Vs2[(k8 * 16 + wn * 8 + nf) * 32 + lane];
#pragma unroll
                for (int mf = 0; mf < 2; mf++)
                    mma_tf32(oacc[mf][nf],
                             reinterpret_cast<const uint32_t*>(&af[mf]),
                             reinterpret_cast<const uint32_t*>(&bf));
            }
        }
        __syncthreads();
    }

#pragma unroll
    for (int mf = 0; mf < 2; mf++) {
        float inv0 = 1.0f / l_run[mf][0];
        float inv1 = 1.0f / l_run[mf][1];
        int r0 = qt * 128 + wm * 32 + mf * 16 + gid;
#pragma unroll
        for (int nf = 0; nf < 8; nf++) {
            int col = wn * 64 + nf * 8 + tig * 2;
            *reinterpret_cast<float2*>(&AO[((size_t)r0 * NH + h) * DH + col]) =
                make_float2(oacc[mf][nf][0] * inv0, oacc[mf][nf][1] * inv0);
            *reinterpret_cast<float2*>(&AO[((size_t)(r0 + 8) * NH + h) * DH + col]) =
                make_float2(oacc[mf][nf][2] * inv1, oacc[mf][nf][3] * inv1);
        }
    }
}

// ---------------- expand stage C (reads Z = AO_sk @ wo) ----------------
__global__ void expandC_kernel(const float* __restrict__ Z, const float* __restrict__ ka,
                               float* __restrict__ E1) {
    int i = blockIdx.y;
    int hd = blockIdx.x * 256 + threadIdx.x;
    __shared__ float kav[20];
    if (threadIdx.x < 20) kav[threadIdx.x] = ka[threadIdx.x * DH + i];
    __syncthreads();
    for (int kbo = 0; kbo < 32; kbo++) {
        float acc = 0.f;
#pragma unroll
        for (int kao = 0; kao < 20; kao++)
            acc += Z[((size_t)(kbo * 20 + kao)) * HID + hd] * kav[kao];
        E1[((size_t)i * 32 + kbo) * HID + hd] = acc;
    }
}

// ---------------- expand stage D (skips topk rows; det GEMM owns them) ----------------
__global__ void expandD_kernel(const float* __restrict__ E1, const float* __restrict__ kb,
                               const int* __restrict__ is_topk, float* __restrict__ OUT) {
    int i = blockIdx.y;
    int hd = blockIdx.x * 128 + threadIdx.x;
    __shared__ float kbs[32 * 256];
    for (int t = threadIdx.x; t < 32 * 256; t += 128) kbs[t] = kb[t];
    float e[32];
#pragma unroll
    for (int kbo = 0; kbo < 32; kbo++) e[kbo] = E1[((size_t)i * 32 + kbo) * HID + hd];
    __syncthreads();
    for (int j = 0; j < 256; j++) {
        int row = i * 256 + j;
        if (is_topk[row]) continue;
        float acc = 0.f;
#pragma unroll
        for (int kbo = 0; kbo < 32; kbo++) acc += e[kbo] * kbs[kbo * 256 + j];
        OUT[(size_t)row * HID + hd] = acc;
    }
}

// ---------------- host launcher ----------------
extern "C" void kernel_launch(void* const* d_in, const int* in_sizes, int n_in,
                              void* d_out, int out_size) {
    const float* hs    = (const float*)d_in[0];
    const float* cosb  = (const float*)d_in[1];
    const float* sinb  = (const float*)d_in[2];
    const float* wq    = (const float*)d_in[3];
    const float* wk    = (const float*)d_in[4];
    const float* wv    = (const float*)d_in[5];
    const float* wo    = (const float*)d_in[6];
    const float* qnw   = (const float*)d_in[7];
    const float* knw   = (const float*)d_in[8];
    const float* w1    = (const float*)d_in[9];
    const float* b1    = (const float*)d_in[10];
    const float* w2    = (const float*)d_in[11];
    const float* b2    = (const float*)d_in[12];
    const float* ka    = (const float*)d_in[13];
    const float* kb    = (const float*)d_in[14];
    const float* sscale= (const float*)d_in[15];
    float* out = (float*)d_out;

    float *pT, *pLg, *pW, *pQ, *pKV, *pPq, *pPk, *pPv, *pQfr, *pKfr, *pVfr,
          *pAO, *pE1, *pZ, *pAfr, *pBfr;
    int *pTop, *pIs;
    cudaGetSymbolAddress((void**)&pT, g_T);
    cudaGetSymbolAddress((void**)&pLg, g_logits);
    cudaGetSymbolAddress((void**)&pW, g_weights);
    cudaGetSymbolAddress((void**)&pQ, g_q);
    cudaGetSymbolAddress((void**)&pKV, g_kv);
    cudaGetSymbolAddress((void**)&pPq, g_Pq);
    cudaGetSymbolAddress((void**)&pPk, g_Pk);
    cudaGetSymbolAddress((void**)&pPv, g_Pv);
    cudaGetSymbolAddress((void**)&pQfr, g_Qfr);
    cudaGetSymbolAddress((void**)&pKfr, g_Kfr);
    cudaGetSymbolAddress((void**)&pVfr, g_Vfr);
    cudaGetSymbolAddress((void**)&pAO, g_AO);
    cudaGetSymbolAddress((void**)&pE1, g_E1);
    cudaGetSymbolAddress((void**)&pZ, g_Z);
    cudaGetSymbolAddress((void**)&pAfr, g_Afr);
    cudaGetSymbolAddress((void**)&pBfr, g_Bfr);
    cudaGetSymbolAddress((void**)&pTop, g_topk);
    cudaGetSymbolAddress((void**)&pIs, g_istop);

    float* pBkv = pBfr + (size_t)16 * 128 * 2048;   // kv weight fragments
    float* pBwo = pBfr + (size_t)24 * 128 * 2048;   // wo weight fragments

    cudaFuncSetAttribute(topk_kernel, cudaFuncAttributeMaxDynamicSharedMemorySize, SEQ * 8);
    cudaFuncSetAttribute(fa_mma_kernel, cudaFuncAttributeMaxDynamicSharedMemorySize, FA2_SMEM);

    // lazy-create side stream + events (host resources, created once; identical
    // launch sequence on every call)
    static cudaStream_t s1 = nullptr;
    static cudaEvent_t evFork = nullptr, evImp = nullptr, evNorm = nullptr,
                       evSkv = nullptr, evAO = nullptr, evZ = nullptr;
    if (s1 == nullptr) {
        cudaStreamCreateWithFlags(&s1, cudaStreamNonBlocking);
        cudaEventCreateWithFlags(&evFork, cudaEventDisableTiming);
        cudaEventCreateWithFlags(&evImp, cudaEventDisableTiming);
        cudaEventCreateWithFlags(&evNorm, cudaEventDisableTiming);
        cudaEventCreateWithFlags(&evSkv, cudaEventDisableTiming);
        cudaEventCreateWithFlags(&evAO, cudaEventDisableTiming);
        cudaEventCreateWithFlags(&evZ, cudaEventDisableTiming);
    }

    // ---- fork: side stream s1 branches off the capture (default) stream ----
    cudaEventRecord(evFork, 0);
    cudaStreamWaitEvent(s1, evFork, 0);

    // ---- s1: importance chain + wo weight conversion (independent of QKV) ----
    imp_gemm_kernel<<<dim3(1, SEQ / 64, 8), 256, 0, s1>>>(hs, w1, pT);
    imp_logits_kernel<<<SEQ, 32, 0, s1>>>(pT, b1, w2, b2, pLg, pW);
    topk_kernel<<<1, 1024, SEQ * 8, s1>>>(pLg, pTop, pIs);
    cudaEventRecord(evImp, s1);
    convB_kernel<<<dim3(HID / 16, HID / 128), 256, 0, s1>>>(wo, pBwo, HID, HID, 0);

    // ---- default stream: QKV projection chain ----
    convA_kernel<<<dim3(HID / 16, SEQ / 128), 256>>>(hs, pAfr, HID);
    convB_kernel<<<dim3(HID / 16, HID / 128), 256>>>(wq, pBfr, HID, HID, 0);
    convB_kernel<<<dim3(HID / 16, 512 / 128), 256>>>(wk, pBkv, HID, 512, 0);
    convB_kernel<<<dim3(HID / 16, 512 / 128), 256>>>(wv, pBkv, HID, 512, 4);
    mma_gemm_kernel<<<dim3(HID / 128, SEQ / 128), 256>>>(pAfr, pBfr, pQ, nullptr, HID, HID);
    mma_gemm_kernel<<<dim3(1024 / 128, SEQ / 128), 256>>>(pAfr, pBkv, pKV, nullptr, 1024, HID);
    rmsnorm_kernel<<<SEQ * NH, DH>>>(pQ, qnw, HID, NH);
    rmsnorm_kernel<<<SEQ * NKV, DH>>>(pKV, knw, 1024, NKV);
    cudaEventRecord(evNorm, 0);

    // ---- join importance results into default stream; split sketches ----
    cudaStreamWaitEvent(0, evImp, 0);
    cudaStreamWaitEvent(s1, evNorm, 0);

    // s1: k/v sketches (needs norm kv + weights/istop, both satisfied)
    sketchA_kernel<<<dim3(NKV, 32), DH, 0, s1>>>(pKV, 8, 0, pW, pIs, 1, kb, pPk);
    sketchB_kernel<<<dim3(NKV, 32), DH, 0, s1>>>(pPk, NKV, ka, sscale, pKfr, 1);
    sketchA_kernel<<<dim3(NKV, 32), DH, 0, s1>>>(pKV, 8, 4, pW, pIs, 1, kb, pPv);
    sketchB_kernel<<<dim3(NKV, 32), DH, 0, s1>>>(pPv, NKV, ka, sscale, pVfr, 2);
    cudaEventRecord(evSkv, s1);

    // default: q sketch + gather (needs topk via evImp + norms in-order)
    sketchA_kernel<<<dim3(NH, 32), DH>>>(pQ, 16, 0, pW, pIs, 0, kb, pPq);
    sketchB_kernel<<<dim3(NH, 32), DH>>>(pPq, NH, ka, sscale, pQfr, 0);
    gather_rope_kernel<<<dim3(TK, 24), DH>>>(pQ, pKV, cosb, sinb, pTop, pQfr, pKfr, pVfr);

    // ---- attention (needs k/v sketches from s1) ----
    cudaStreamWaitEvent(0, evSkv, 0);
    fa_mma_kernel<<<dim3(NQT, NH), 256, FA2_SMEM>>>(pQfr, pKfr, pVfr, pAO);

    // ---- epilogue: convert AO, then Z/expand on s1 concurrent with det GEMM ----
    convA_kernel<<<dim3(HID / 16, NQF / 128), 256>>>(pAO, pAfr, HID);
    cudaEventRecord(evAO, 0);
    cudaStreamWaitEvent(s1, evAO, 0);
    // s1: Z = AO_sk @ wo, expand to non-topk rows of out
    mma_gemm_kernel<<<dim3(HID / 128, SK / 128), 256, 0, s1>>>(
        pAfr + (size_t)16 * (HID / 16) * 2048, pBwo, pZ, nullptr, HID, HID);
    expandC_kernel<<<dim3(HID / 256, 32), 256, 0, s1>>>(pZ, ka, pE1);
    expandD_kernel<<<dim3(HID / 128, 32), DH, 0, s1>>>(pE1, kb, pIs, out);
    cudaEventRecord(evZ, s1);
    // default: det rows -> out[topk[m]] (disjoint rows from expandD)
    mma_gemm_kernel<<<dim3(HID / 128, TK / 128), 256>>>(pAfr, pBwo, out, pTop, HID, HID);

    // ---- join s1 back into capture stream ----
    cudaStreamWaitEvent(0, evZ, 0);
}

// round 10
// speedup vs baseline: 4.7161x; 1.0799x over previous
#include <cuda_runtime.h>
#include <cuda_bf16.h>
#include <math.h>
#include <cstdint>

// Problem constants
#define SEQ   8192
#define HID   2048
#define NH    16
#define NKV   4
#define DH    128
#define TK    2048
#define SK    640
#define NQF   (TK + SK)        // 2688
#define NQT   (NQF / 128)      // 21 q tiles
#define NKT   (NQF / 64)       // 42 key tiles
#define KSPL  21               // key tiles per split (2 splits)
#define ATT_SCALE 0.08838834764831843f   // 1/sqrt(128)

// ---------------- scratch (device globals; no allocation) ----------------
__device__ float g_T[8 * SEQ * 64];
__device__ float g_logits[SEQ];
__device__ float g_weights[SEQ];
__device__ float g_q[SEQ * NH * DH];
__device__ float g_kv[SEQ * 1024];
__device__ int   g_topk[TK];
__device__ int   g_istop[SEQ];
__device__ float g_Pq[NH * 32 * 32 * DH];
__device__ float g_Pk[NKV * 32 * 32 * DH];
__device__ float g_Pv[NKV * 32 * 32 * DH];
__device__ float g_Qfr[NH * NQT * 16 * 8 * 32 * 4];
__device__ float g_Kfr[NKV * NKT * 16 * 8 * 32 * 2];
__device__ float g_Vfr[NKV * NKT * 8 * 16 * 32 * 2];
__device__ float g_AO[NQF * NH * DH];      // split-0 partial, then combined AO
__device__ float g_AO2[NQF * NH * DH];     // split-1 partial
__device__ float g_ML[2 * NQF * NH * 2];
__device__ float g_E1[32 * 32 * HID];
__device__ float g_Z[SK * HID];
__device__ float g_Afr[SEQ * HID];
__device__ float g_Bfr[40 * 128 * 2048];   // wq[0:16) | kv[16:24) | wo[24:40)

// ======================= tf32 mma.sync helpers =======================
__device__ __forceinline__ float tf32f(float x) {
    uint32_t r; asm("cvt.rna.tf32.f32 %0, %1;" : "=r"(r) : "f"(x));
    return __uint_as_float(r);
}

__device__ __forceinline__ void mma_tf32(float* c, const uint32_t* a, const uint32_t* b) {
    asm volatile("mma.sync.aligned.m16n8k8.row.col.f32.tf32.tf32.f32 "
        "{%0,%1,%2,%3}, {%4,%5,%6,%7}, {%8,%9}, {%0,%1,%2,%3};"
        : "+f"(c[0]), "+f"(c[1]), "+f"(c[2]), "+f"(c[3])
        : "r"(a[0]), "r"(a[1]), "r"(a[2]), "r"(a[3]), "r"(b[0]), "r"(b[1]));
}

#define CP_ASYNC16(dst_u32, src_ptr) \
    asm volatile("cp.async.cg.shared.global [%0], [%1], 16;" :: "r"(dst_u32), "l"(src_ptr))
#define CP_COMMIT() asm volatile("cp.async.commit_group;")

__device__ __forceinline__ void store_qfrag(float* Qg, int h, int tok, int d, float v) {
    int qt = tok >> 7, m = tok & 127;
    int k8 = d >> 3, mf = m >> 4;
    int lane = ((m & 7) << 2) | (d & 3);
    int reg = 2 * ((d & 7) >= 4) + ((m & 15) >= 8);
    size_t idx = ((((size_t)(h * NQT + qt) * 16 + k8) * 8 + mf) * 32 + lane) * 4 + reg;
    Qg[idx] = tf32f(v);
}
__device__ __forceinline__ void store_kfrag(float* Kg, int kvh, int tok, int d, float v) {
    int kt = tok >> 6, key = tok & 63;
    int k8 = d >> 3, nf = key >> 3;
    int lane = ((key & 7) << 2) | (d & 3);
    int reg = ((d & 7) >= 4);
    size_t idx = ((((size_t)(kvh * NKT + kt) * 16 + k8) * 8 + nf) * 32 + lane) * 2 + reg;
    Kg[idx] = tf32f(v);
}
__device__ __forceinline__ void store_vfrag(float* Vg, int kvh, int tok, int d, float v) {
    int kt = tok >> 6, key = tok & 63;
    int k8 = key >> 3, nf = d >> 3;
    int lane = ((d & 7) << 2) | (key & 3);
    int reg = ((key & 7) >= 4);
    size_t idx = ((((size_t)(kvh * NKT + kt) * 8 + k8) * 16 + nf) * 32 + lane) * 2 + reg;
    Vg[idx] = tf32f(v);
}

// ======================= fragment conversion pre-passes =======================
__global__ void __launch_bounds__(256) convA_kernel(const float* __restrict__ A,
                                                    float* __restrict__ Afr, int K) {
    __shared__ float sm[2048];
    const int rt = blockIdx.y, c = blockIdx.x;
    const int tid = threadIdx.x;
    const float* Ab = A + ((size_t)rt * 128) * K + c * 16;
#pragma unroll
    for (int i = 0; i < 2; i++) {
        int f = tid + i * 256;
        int r = f >> 2, c4 = f & 3;
        float4 v = *reinterpret_cast<const float4*>(Ab + (size_t)r * K + c4 * 4);
        int mf = r >> 4, gid = r & 7, mhi = (r >> 3) & 1;
        float vv[4] = {v.x, v.y, v.z, v.w};
#pragma unroll
        for (int j = 0; j < 4; j++) {
            int k = c4 * 4 + j;
            int slot = ((k >> 3) * 8 + mf) * 128 + ((gid << 2) | (k & 3)) * 4
                     + 2 * ((k & 7) >= 4) + mhi;
            sm[slot] = tf32f(vv[j]);
        }
    }
    __syncthreads();
    float4* out = reinterpret_cast<float4*>(Afr + ((size_t)(rt * (K >> 4) + c)) * 2048);
    const float4* s4 = reinterpret_cast<const float4*>(sm);
#pragma unroll
    for (int i = 0; i < 2; i++) out[tid + i * 256] = s4[tid + i * 256];
}

__global__ void __launch_bounds__(256) convB_kernel(const float* __restrict__ B,
                                                    float* __restrict__ Bfr, int K, int N,
                                                    int ctbase) {
    __shared__ float sm[2048];
    const int ct = blockIdx.y + ctbase, c = blockIdx.x;
    const int tid = threadIdx.x;
    const float* Bb = B + ((size_t)(c * 16)) * N + blockIdx.y * 128;
#pragma unroll
    for (int i = 0; i < 2; i++) {
        int f = tid + i * 256;
        int kk = f >> 5, n4 = f & 31;
        float4 v = *reinterpret_cast<const float4*>(Bb + (size_t)kk * N + n4 * 4);
        int k8in = kk >> 3, reg = ((kk & 7) >= 4);
        float vv[4] = {v.x, v.y, v.z, v.w};
#pragma unroll
        for (int j = 0; j < 4; j++) {
            int n = n4 * 4 + j;
            int slot = (k8in * 16 + (n >> 3)) * 64 + (((n & 7) << 2) | (kk & 3)) * 2 + reg;
            sm[slot] = tf32f(vv[j]);
        }
    }
    __syncthreads();
    float4* out = reinterpret_cast<float4*>(Bfr + ((size_t)(ct * (K >> 4) + c)) * 2048);
    const float4* s4 = reinterpret_cast<const float4*>(sm);
#pragma unroll
    for (int i = 0; i < 2; i++) out[tid + i * 256] = s4[tid + i * 256];
}

// ======= tf32 GEMM: CTA 128x128, cp.async 3-stage, 2 CTA/SM, optional fused rmsnorm ===
__global__ void __launch_bounds__(256, 2) mma_gemm_kernel(
    const float* __restrict__ Afr, const float* __restrict__ Bfr,
    float* __restrict__ C, const int* __restrict__ remap,
    const float* __restrict__ normw, int normct, int N, int K)
{
    __shared__ float sA[3][2048];
    __shared__ float sB[3][2048];

    const int tid = threadIdx.x;
    const int lane = tid & 31, wid = tid >> 5;
    const int wm = wid >> 2, wn = wid & 3;
    const int NCH = K >> 4;

    const float4* Ag = reinterpret_cast<const float4*>(Afr) + (size_t)blockIdx.y * NCH * 512;
    const float4* Bg = reinterpret_cast<const float4*>(Bfr) + (size_t)blockIdx.x * NCH * 512;

    const uint32_t sAu = (uint32_t)__cvta_generic_to_shared(&sA[0][0]) + tid * 16;
    const uint32_t sBu = (uint32_t)__cvta_generic_to_shared(&sB[0][0]) + tid * 16;

    {
        const float4* ga = Ag + tid;  const float4* gb = Bg + tid;
        CP_ASYNC16(sAu, ga); CP_ASYNC16(sAu + 4096, ga + 256);
        CP_ASYNC16(sBu, gb); CP_ASYNC16(sBu + 4096, gb + 256);
        CP_COMMIT();
        if (NCH > 1) {
            ga += 512; gb += 512;
            CP_ASYNC16(sAu + 8192, ga); CP_ASYNC16(sAu + 8192 + 4096, ga + 256);
            CP_ASYNC16(sBu + 8192, gb); CP_ASYNC16(sBu + 8192 + 4096, gb + 256);
            CP_COMMIT();
        }
    }

    float acc[4][4][4] = {};
    for (int c = 0; c < NCH; c++) {
        if (c + 1 < NCH) asm volatile("cp.async.wait_group 1;");
        else             asm volatile("cp.async.wait_group 0;");
        __syncthreads();

        const int buf = c % 3;
        const float4* A4 = reinterpret_cast<const float4*>(sA[buf]);
        const float2* B2 = reinterpret_cast<const float2*>(sB[buf]);
#pragma unroll
        for (int k8 = 0; k8 < 2; k8++) {
            float4 af[4];
            float2 bf[4];
#pragma unroll
            for (int mf = 0; mf < 4; mf++)
                af[mf] = A4[(k8 * 8 + wm * 4 + mf) * 32 + lane];
#pragma unroll
            for (int nf = 0; nf < 4; nf++)
                bf[nf] = B2[(k8 * 16 + wn * 4 + nf) * 32 + lane];
#pragma unroll
            for (int mf = 0; mf < 4; mf++)
#pragma unroll
                for (int nf = 0; nf < 4; nf++)
                    mma_tf32(acc[mf][nf],
                             reinterpret_cast<const uint32_t*>(&af[mf]),
                             reinterpret_cast<const uint32_t*>(&bf[nf]));
        }
        if (c + 2 < NCH) {
            const int st = (c + 2) % 3;
            const float4* ga = Ag + (c + 2) * 512 + tid;
            const float4* gb = Bg + (c + 2) * 512 + tid;
            CP_ASYNC16(sAu + st * 8192, ga); CP_ASYNC16(sAu + st * 8192 + 4096, ga + 256);
            CP_ASYNC16(sBu + st * 8192, gb); CP_ASYNC16(sBu + st * 8192 + 4096, gb + 256);
            CP_COMMIT();
        }
    }

    const int gid = lane >> 2, tig = lane & 3;

    // ---- optional fused rmsnorm over this 128-col (one-head) tile ----
    if (normw != nullptr && blockIdx.x < normct) {
        float* ssm = &sA[0][0];
        __syncthreads();
        float ss0[4], ss1[4];
#pragma unroll
        for (int mf = 0; mf < 4; mf++) {
            float s0 = 0.f, s1 = 0.f;
#pragma unroll
            for (int nf = 0; nf < 4; nf++) {
                s0 += acc[mf][nf][0] * acc[mf][nf][0] + acc[mf][nf][1] * acc[mf][nf][1];
                s1 += acc[mf][nf][2] * acc[mf][nf][2] + acc[mf][nf][3] * acc[mf][nf][3];
            }
            s0 += __shfl_xor_sync(0xffffffffu, s0, 1);
            s0 += __shfl_xor_sync(0xffffffffu, s0, 2);
            s1 += __shfl_xor_sync(0xffffffffu, s1, 1);
            s1 += __shfl_xor_sync(0xffffffffu, s1, 2);
            ss0[mf] = s0; ss1[mf] = s1;
        }
        if (tig == 0) {
#pragma unroll
            for (int mf = 0; mf < 4; mf++) {
                int r = wm * 64 + mf * 16 + gid;
                ssm[r * 4 + wn] = ss0[mf];
                ssm[(r + 8) * 4 + wn] = ss1[mf];
            }
        }
        __syncthreads();
#pragma unroll
        for (int mf = 0; mf < 4; mf++) {
            int r = wm * 64 + mf * 16 + gid;
            float t0 = ssm[r * 4] + ssm[r * 4 + 1] + ssm[r * 4 + 2] + ssm[r * 4 + 3];
            float t1 = ssm[(r + 8) * 4] + ssm[(r + 8) * 4 + 1]
                     + ssm[(r + 8) * 4 + 2] + ssm[(r + 8) * 4 + 3];
            float sc0 = rsqrtf(t0 * (1.0f / 128.0f) + 1e-6f);
            float sc1 = rsqrtf(t1 * (1.0f / 128.0f) + 1e-6f);
#pragma unroll
            for (int nf = 0; nf < 4; nf++) {
                int n = wn * 32 + nf * 8 + tig * 2;
                float w0 = __ldg(&normw[n]), w1 = __ldg(&normw[n + 1]);
                acc[mf][nf][0] *= sc0 * w0; acc[mf][nf][1] *= sc0 * w1;
                acc[mf][nf][2] *= sc1 * w0; acc[mf][nf][3] *= sc1 * w1;
            }
        }
    }

    const int row0 = blockIdx.y * 128;
    const int col0 = blockIdx.x * 128;
#pragma unroll
    for (int mf = 0; mf < 4; mf++) {
        int m = row0 + wm * 64 + mf * 16 + gid;
        int m1 = remap ? __ldg(&remap[m]) : m;
        int m2 = remap ? __ldg(&remap[m + 8]) : (m + 8);
#pragma unroll
        for (int nf = 0; nf < 4; nf++) {
            int n = col0 + wn * 32 + nf * 8 + tig * 2;
            *reinterpret_cast<float2*>(&C[(size_t)m1 * N + n]) =
                make_float2(acc[mf][nf][0], acc[mf][nf][1]);
            *reinterpret_cast<float2*>(&C[(size_t)m2 * N + n]) =
                make_float2(acc[mf][nf][2], acc[mf][nf][3]);
        }
    }
}

// ---------------- importance GEMM: fp32 split-K x8 ----------------
__global__ void __launch_bounds__(256) imp_gemm_kernel(
    const float* __restrict__ A, const float* __restrict__ B, float* __restrict__ Cp)
{
    __shared__ float As[16][64];
    __shared__ float Bs[16][64];
    const int tid = threadIdx.x;
    const int row0 = blockIdx.y * 64;
    const int z = blockIdx.z;
    const float* Ab = A + (size_t)row0 * HID + z * 256;
    const float* Bb = B + (size_t)z * 256 * 64;
    float acc[4][4] = {};
    const int tc = (tid & 15) * 4, tr = (tid >> 4) * 4;
    const int ar = tid >> 2, ac = (tid & 3) * 4;
    const int br = tid >> 4, bc = (tid & 15) * 4;

    for (int k0 = 0; k0 < 256; k0 += 16) {
        float4 va = *reinterpret_cast<const float4*>(Ab + (size_t)ar * HID + k0 + ac);
        As[ac + 0][ar] = va.x; As[ac + 1][ar] = va.y;
        As[ac + 2][ar] = va.z; As[ac + 3][ar] = va.w;
        float4 vb = *reinterpret_cast<const float4*>(Bb + (size_t)(k0 + br) * 64 + bc);
        *reinterpret_cast<float4*>(&Bs[br][bc]) = vb;
        __syncthreads();
#pragma unroll
        for (int k = 0; k < 16; k++) {
            float ra[4], rb[4];
#pragma unroll
            for (int m = 0; m < 4; m++) ra[m] = As[k][tr + m];
#pragma unroll
            for (int n = 0; n < 4; n++) rb[n] = Bs[k][tc + n];
#pragma unroll
            for (int m = 0; m < 4; m++)
#pragma unroll
                for (int n = 0; n < 4; n++) acc[m][n] += ra[m] * rb[n];
        }
        __syncthreads();
    }
#pragma unroll
    for (int m = 0; m < 4; m++) {
        float4 v = make_float4(acc[m][0], acc[m][1], acc[m][2], acc[m][3]);
        *reinterpret_cast<float4*>(&Cp[((size_t)z * SEQ + row0 + tr + m) * 64 + tc]) = v;
    }
}

// ---------------- importance logits epilogue ----------------
__global__ void imp_logits_kernel(const float* __restrict__ T, const float* __restrict__ b1,
                                  const float* __restrict__ w2, const float* __restrict__ b2,
                                  float* __restrict__ logits, float* __restrict__ weights) {
    const float LOG_ADJ = 2.5494451709255714f;
    int s = blockIdx.x;
    int j = threadIdx.x;
    float v1 = 0.f, v2 = 0.f;
#pragma unroll
    for (int z = 0; z < 8; z++) {
        v1 += T[((size_t)z * SEQ + s) * 64 + j];
        v2 += T[((size_t)z * SEQ + s) * 64 + j + 32];
    }
    float v = tanhf(v1 + b1[j]) * w2[j] + tanhf(v2 + b1[j + 32]) * w2[j + 32];
#pragma unroll
    for (int o = 16; o > 0; o >>= 1) v += __shfl_xor_sync(0xffffffffu, v, o);
    if (j == 0) {
        float lg = v + b2[0] - LOG_ADJ;
        logits[s] = lg;
        weights[s] = 1.0f / (1.0f + expf(-lg));
    }
}

// ---------------- top-k via single-block bitonic sort ----------------
__global__ void topk_kernel(const float* __restrict__ logits,
                            int* __restrict__ topk_list, int* __restrict__ is_topk) {
    extern __shared__ unsigned long long skeys[];
    int tid = threadIdx.x;
    for (int i = tid; i < SEQ; i += 1024) {
        unsigned u = __float_as_uint(logits[i]);
        u = (u & 0x80000000u) ? ~u : (u | 0x80000000u);
        skeys[i] = ((unsigned long long)(~u) << 32) | (unsigned)i;
        is_topk[i] = 0;
    }
    __syncthreads();
    for (int k = 2; k <= SEQ; k <<= 1) {
        for (int j = k >> 1; j > 0; j >>= 1) {
            for (int i = tid; i < SEQ; i += 1024) {
                int ixj = i ^ j;
                if (ixj > i) {
                    bool up = ((i & k) == 0);
                    unsigned long long a = skeys[i], b = skeys[ixj];
                    if ((a > b) == up) { skeys[i] = b; skeys[ixj] = a; }
                }
            }
            __syncthreads();
        }
    }
    for (int i = tid; i < TK; i += 1024) {
        int pos = (int)(skeys[i] & 0xffffffffu);
        topk_list[i] = pos;
        is_topk[pos] = 1;
    }
}

// ---------------- sketch stage A ----------------
__global__ void sketchA_kernel(const float* __restrict__ X, int hstride, int hbase,
                               const float* __restrict__ weights,
                               const int* __restrict__ is_topk, int rest,
                               const float* __restrict__ kb, float* __restrict__ P) {
    int h = blockIdx.x;
    int ib = blockIdx.y;
    int d = threadIdx.x;
    __shared__ float kbs[32 * 256];
    for (int t = d; t < 32 * 256; t += 128) kbs[t] = kb[t];
    __shared__ float ws[256];
    for (int j = d; j < 256; j += 128) {
        int t = ib * 256 + j;
        float w = weights[t];
        if (rest && is_topk[t]) w = 0.0f;
        ws[j] = w;
    }
    __syncthreads();
    float acc[32] = {};
    for (int j = 0; j < 256; j++) {
        float xv = X[((size_t)(ib * 256 + j) * hstride + hbase + h) * DH + d] * ws[j];
#pragma unroll
        for (int kbo = 0; kbo < 32; kbo++) acc[kbo] += xv * kbs[kbo * 256 + j];
    }
#pragma unroll
    for (int kbo = 0; kbo < 32; kbo++)
        P[(((size_t)h * 32 + kbo) * 32 + ib) * DH + d] = acc[kbo];
}

// ---------------- sketch stage B ----------------
__global__ void sketchB_kernel(const float* __restrict__ P, int heads,
                               const float* __restrict__ ka,
                               const float* __restrict__ scale_p,
                               float* __restrict__ dstfrag, int mode) {
    int h = blockIdx.x;
    int kbo = blockIdx.y;
    int d = threadIdx.x;
    __shared__ float kas[20 * 32];
    for (int t = d; t < 20 * 32; t += 128) kas[t] = ka[(t / 32) * DH + (t % 32)];
    __syncthreads();
    float p[32];
#pragma unroll
    for (int i = 0; i < 32; i++) p[i] = P[(((size_t)h * 32 + kbo) * 32 + i) * DH + d];
    float scale = scale_p[0];
    if (mode == 0) scale *= ATT_SCALE;
#pragma unroll
    for (int kao = 0; kao < 20; kao++) {
        float acc = 0.f;
#pragma unroll
        for (int i = 0; i < 32; i++) acc += p[i] * kas[kao * 32 + i];
        int s = TK + kbo * 20 + kao;
        float val = acc * scale;
        if (mode == 0)      store_qfrag(dstfrag, h, s, d, val);
        else if (mode == 1) store_kfrag(dstfrag, h, s, d, val);
        else                store_vfrag(dstfrag, h, s, d, val);
    }
}

// ---------------- gather + RoPE ----------------
__global__ void gather_rope_kernel(const float* __restrict__ q, const float* __restrict__ kv,
                                   const float* __restrict__ cosb, const float* __restrict__ sinb,
                                   const int* __restrict__ topk_list,
                                   float* __restrict__ Qfr, float* __restrict__ Kfr,
                                   float* __restrict__ Vfr) {
    int j = blockIdx.x;
    int hy = blockIdx.y;
    int d = threadIdx.x;
    int pos = topk_list[j];
    float c = cosb[(size_t)pos * DH + d];
    float s = sinb[(size_t)pos * DH + d];
    if (hy < 16) {
        const float* src = q + ((size_t)pos * NH + hy) * DH;
        float x = src[d];
        float r = (d < 64) ? -src[d + 64] : src[d - 64];
        store_qfrag(Qfr, hy, j, d, (x * c + r * s) * ATT_SCALE);
    } else if (hy < 20) {
        int h = hy - 16;
        const float* src = kv + (size_t)pos * 1024 + h * DH;
        float x = src[d];
        float r = (d < 64) ? -src[d + 64] : src[d - 64];
        store_kfrag(Kfr, h, j, d, x * c + r * s);
    } else {
        int h = hy - 20;
        store_vfrag(Vfr, h, j, d, kv[(size_t)pos * 1024 + 512 + h * DH + d]);
    }
}

// ---------------- tensor-core flash attention (split-KV, cp.async K/V) -------
#define FA2_SMEM ((16384 + 2*8192 + 2*8192 + 512) * 4)
__global__ void __launch_bounds__(256, 1) fa_mma_kernel(
    const float* __restrict__ Qfr, const float* __restrict__ Kfr,
    const float* __restrict__ Vfr, float* __restrict__ Op,
    float* __restrict__ ML, int kt0)
{
    extern __shared__ float fsm[];
    float* Qsm = fsm;
    float* Ksm = fsm + 16384;
    float* Vsm = fsm + 32768;
    float* mpart = fsm + 49152;
    float* spart = fsm + 49408;

    const int qt = blockIdx.x;
    const int h  = blockIdx.y;
    const int kvh = h >> 2;
    const int tid = threadIdx.x;
    const int lane = tid & 31, wid = tid >> 5;
    const int wm = wid >> 1, wn = wid & 1;
    const int gid = lane >> 2, tig = lane & 3;

    const uint32_t ksmU = (uint32_t)__cvta_generic_to_shared(Ksm) + tid * 16;
    const uint32_t vsmU = (uint32_t)__cvta_generic_to_shared(Vsm) + tid * 16;

    {
        const float4* Kg = reinterpret_cast<const float4*>(Kfr + (size_t)(kvh * NKT + kt0) * 8192);
        const float4* Vg = reinterpret_cast<const float4*>(Vfr + (size_t)(kvh * NKT + kt0) * 8192);
#pragma unroll
        for (int i = 0; i < 8; i++) {
            CP_ASYNC16(ksmU + i * 4096, Kg + tid + i * 256);
            CP_ASYNC16(vsmU + i * 4096, Vg + tid + i * 256);
        }
        CP_COMMIT();
    }

    {
        const float4* Qg = reinterpret_cast<const float4*>(Qfr + (size_t)(h * NQT + qt) * 16384);
        float4* Qs4w = reinterpret_cast<float4*>(Qsm);
#pragma unroll
        for (int i = 0; i < 16; i++) Qs4w[tid + i * 256] = Qg[tid + i * 256];
    }

    float m_old[2][2], l_run[2][2];
#pragma unroll
    for (int a = 0; a < 2; a++)
#pragma unroll
        for (int b = 0; b < 2; b++) { m_old[a][b] = -1e30f; l_run[a][b] = 0.f; }
    float oacc[2][8][4] = {};

    const float4* Qs4 = reinterpret_cast<const float4*>(Qsm);

    for (int t = 0; t < KSPL; t++) {
        const int buf = t & 1;
        if (t + 1 < KSPL) {
            const float4* Kg = reinterpret_cast<const float4*>(Kfr + (size_t)(kvh * NKT + kt0 + t + 1) * 8192);
            const float4* Vg = reinterpret_cast<const float4*>(Vfr + (size_t)(kvh * NKT + kt0 + t + 1) * 8192);
            const uint32_t kd = ksmU + (1 - buf) * 32768;
            const uint32_t vd = vsmU + (1 - buf) * 32768;
#pragma unroll
            for (int i = 0; i < 8; i++) {
                CP_ASYNC16(kd + i * 4096, Kg + tid + i * 256);
                CP_ASYNC16(vd + i * 4096, Vg + tid + i * 256);
            }
            CP_COMMIT();
            asm volatile("cp.async.wait_group 1;");
        } else {
            asm volatile("cp.async.wait_group 0;");
        }
        __syncthreads();

        const float2* Ks2 = reinterpret_cast<const float2*>(Ksm + buf * 8192);
        const float2* Vs2 = reinterpret_cast<const float2*>(Vsm + buf * 8192);
        float* Psm = Ksm + buf * 8192;
        const float4* Ps4 = reinterpret_cast<const float4*>(Psm);

        float sacc[2][4][4] = {};
#pragma unroll
        for (int k8 = 0; k8 < 16; k8++) {
            float4 af[2];
            float2 bf[4];
            af[0] = Qs4[(k8 * 8 + wm * 2 + 0) * 32 + lane];
            af[1] = Qs4[(k8 * 8 + wm * 2 + 1) * 32 + lane];
#pragma unroll
            for (int nf = 0; nf < 4; nf++) bf[nf] = Ks2[(k8 * 8 + wn * 4 + nf) * 32 + lane];
#pragma unroll
            for (int mf = 0; mf < 2; mf++)
#pragma unroll
                for (int nf = 0; nf < 4; nf++)
                    mma_tf32(sacc[mf][nf],
                             reinterpret_cast<const uint32_t*>(&af[mf]),
                             reinterpret_cast<const uint32_t*>(&bf[nf]));
        }

        float mloc[2][2];
#pragma unroll
        for (int mf = 0; mf < 2; mf++) {
            float m0 = fmaxf(sacc[mf][0][0], sacc[mf][0][1]);
            float m1 = fmaxf(sacc[mf][0][2], sacc[mf][0][3]);
#pragma unroll
            for (int nf = 1; nf < 4; nf++) {
                m0 = fmaxf(m0, fmaxf(sacc[mf][nf][0], sacc[mf][nf][1]));
                m1 = fmaxf(m1, fmaxf(sacc[mf][nf][2], sacc[mf][nf][3]));
            }
            m0 = fmaxf(m0, __shfl_xor_sync(0xffffffffu, m0, 1));
            m0 = fmaxf(m0, __shfl_xor_sync(0xffffffffu, m0, 2));
            m1 = fmaxf(m1, __shfl_xor_sync(0xffffffffu, m1, 1));
            m1 = fmaxf(m1, __shfl_xor_sync(0xffffffffu, m1, 2));
            mloc[mf][0] = m0; mloc[mf][1] = m1;
        }
        if (tig == 0) {
#pragma unroll
            for (int mf = 0; mf < 2; mf++) {
                int r = wm * 32 + mf * 16 + gid;
                mpart[wn * 128 + r] = mloc[mf][0];
                mpart[wn * 128 + r + 8] = mloc[mf][1];
            }
        }
        __syncthreads();

        float mnew[2][2], corr[2][2];
#pragma unroll
        for (int mf = 0; mf < 2; mf++)
#pragma unroll
            for (int hi = 0; hi < 2; hi++) {
                int r = wm * 32 + mf * 16 + gid + hi * 8;
                float mt = fmaxf(mpart[r], mpart[128 + r]);
                float mn = fmaxf(m_old[mf][hi], mt);
                corr[mf][hi] = __expf(m_old[mf][hi] - mn);
                mnew[mf][hi] = mn;
                m_old[mf][hi] = mn;
            }

        float sloc[2][2] = {};
#pragma unroll
        for (int mf = 0; mf < 2; mf++)
#pragma unroll
            for (int nf = 0; nf < 4; nf++) {
                sacc[mf][nf][0] = __expf(sacc[mf][nf][0] - mnew[mf][0]);
                sacc[mf][nf][1] = __expf(sacc[mf][nf][1] - mnew[mf][0]);
                sacc[mf][nf][2] = __expf(sacc[mf][nf][2] - mnew[mf][1]);
                sacc[mf][nf][3] = __expf(sacc[mf][nf][3] - mnew[mf][1]);
                sloc[mf][0] += sacc[mf][nf][0] + sacc[mf][nf][1];
                sloc[mf][1] += sacc[mf][nf][2] + sacc[mf][nf][3];
            }
#pragma unroll
        for (int mf = 0; mf < 2; mf++) {
            sloc[mf][0] += __shfl_xor_sync(0xffffffffu, sloc[mf][0], 1);
            sloc[mf][0] += __shfl_xor_sync(0xffffffffu, sloc[mf][0], 2);
            sloc[mf][1] += __shfl_xor_sync(0xffffffffu, sloc[mf][1], 1);
            sloc[mf][1] += __shfl_xor_sync(0xffffffffu, sloc[mf][1], 2);
        }
        if (tig == 0) {
#pragma unroll
            for (int mf = 0; mf < 2; mf++) {
                int r = wm * 32 + mf * 16 + gid;
                spart[wn * 128 + r] = sloc[mf][0];
                spart[wn * 128 + r + 8] = sloc[mf][1];
            }
        }

#pragma unroll
        for (int mf = 0; mf < 2; mf++)
#pragma unroll
            for (int nf = 0; nf < 4; nf++) {
                int k8p = wn * 4 + nf;
                int mfg = wm * 2 + mf;
#pragma unroll
                for (int b = 0; b < 2; b++) {
                    int c = tig * 2 + b;
                    int khi = (c >= 4);
                    int base = ((k8p * 8 + mfg) * 32 + (gid << 2) + (c & 3)) * 4 + khi * 2;
                    *reinterpret_cast<float2*>(Psm + base) =
                        make_float2(tf32f(sacc[mf][nf][b]), tf32f(sacc[mf][nf][2 + b]));
                }
            }
        __syncthreads();

#pragma unroll
        for (int mf = 0; mf < 2; mf++)
#pragma unroll
            for (int hi = 0; hi < 2; hi++) {
                int r = wm * 32 + mf * 16 + gid + hi * 8;
                l_run[mf][hi] = l_run[mf][hi] * corr[mf][hi] + spart[r] + spart[128 + r];
            }
#pragma unroll
        for (int mf = 0; mf < 2; mf++)
#pragma unroll
            for (int nf = 0; nf < 8; nf++) {
                oacc[mf][nf][0] *= corr[mf][0]; oacc[mf][nf][1] *= corr[mf][0];
                oacc[mf][nf][2] *= corr[mf][1]; oacc[mf][nf][3] *= corr[mf][1];
            }

#pragma unroll
        for (int k8 = 0; k8 < 8; k8++) {
            float4 af[2];
            af[0] = Ps4[(k8 * 8 + wm * 2 + 0) * 32 + lane];
            af[1] = Ps4[(k8 * 8 + wm * 2 + 1) * 32 + lane];
#pragma unroll
            for (int nf = 0; nf < 8; nf++) {
                float2 bf = Vs2[(k8 * 16 + wn * 8 + nf) * 32 + lane];
#pragma unroll
                for (int mf = 0; mf < 2; mf++)
                    mma_tf32(oacc[mf][nf],
                             reinterpret_cast<const uint32_t*>(&af[mf]),
                             reinterpret_cast<const uint32_t*>(&bf));
            }
        }
        __syncthreads();
    }

    // epilogue: UNNORMALIZED O partial + per-row (m, l)
#pragma unroll
    for (int mf = 0; mf < 2; mf++) {
        int r0 = qt * 128 + wm * 32 + mf * 16 + gid;
        if (wn == 0 && tig == 0) {
            size_t row0i = (size_t)r0 * NH + h;
            size_t row1i = (size_t)(r0 + 8) * NH + h;
            ML[row0i * 2] = m_old[mf][0]; ML[row0i * 2 + 1] = l_run[mf][0];
            ML[row1i * 2] = m_old[mf][1]; ML[row1i * 2 + 1] = l_run[mf][1];
        }
#pragma unroll
        for (int nf = 0; nf < 8; nf++) {
            int col = wn * 64 + nf * 8 + tig * 2;
            *reinterpret_cast<float2*>(&Op[((size_t)r0 * NH + h) * DH + col]) =
                make_float2(oacc[mf][nf][0], oacc[mf][nf][1]);
            *reinterpret_cast<float2*>(&Op[((size_t)(r0 + 8) * NH + h) * DH + col]) =
                make_float2(oacc[mf][nf][2], oacc[mf][nf][3]);
        }
    }
}

// ---------------- fa combine ----------------
__global__ void fa_combine_kernel(float* __restrict__ O0, const float* __restrict__ O1,
                                  const float* __restrict__ ML) {
    size_t row = (size_t)blockIdx.x * NH + blockIdx.y;
    int d = threadIdx.x;
    float m0 = ML[row * 2], l0 = ML[row * 2 + 1];
    float m1 = ML[(size_t)NQF * NH * 2 + row * 2], l1 = ML[(size_t)NQF * NH * 2 + row * 2 + 1];
    float m = fmaxf(m0, m1);
    float w0 = __expf(m0 - m), w1 = __expf(m1 - m);
    float inv = 1.0f / (w0 * l0 + w1 * l1);
    O0[row * DH + d] = (O0[row * DH + d] * w0 + O1[row * DH + d] * w1) * inv;
}

// ---------------- expand stage C ----------------
__global__ void expandC_kernel(const float* __restrict__ Z, const float* __restrict__ ka,
                               float* __restrict__ E1) {
    int i = blockIdx.y;
    int hd = blockIdx.x * 256 + threadIdx.x;
    __shared__ float kav[20];
    if (threadIdx.x < 20) kav[threadIdx.x] = ka[threadIdx.x * DH + i];
    __syncthreads();
    for (int kbo = 0; kbo < 32; kbo++) {
        float acc = 0.f;
#pragma unroll
        for (int kao = 0; kao < 20; kao++)
            acc += Z[((size_t)(kbo * 20 + kao)) * HID + hd] * kav[kao];
        E1[((size_t)i * 32 + kbo) * HID + hd] = acc;
    }
}

// ---------------- expand stage D ----------------
__global__ void expandD_kernel(const float* __restrict__ E1, const float* __restrict__ kb,
                               const int* __restrict__ is_topk, float* __restrict__ OUT) {
    int i = blockIdx.y;
    int hd = blockIdx.x * 128 + threadIdx.x;
    __shared__ float kbs[32 * 256];
    for (int t = threadIdx.x; t < 32 * 256; t += 128) kbs[t] = kb[t];
    float e[32];
#pragma unroll
    for (int kbo = 0; kbo < 32; kbo++) e[kbo] = E1[((size_t)i * 32 + kbo) * HID + hd];
    __syncthreads();
    for (int j = 0; j < 256; j++) {
        int row = i * 256 + j;
        if (is_topk[row]) continue;
        float acc = 0.f;
#pragma unroll
        for (int kbo = 0; kbo < 32; kbo++) acc += e[kbo] * kbs[kbo * 256 + j];
        OUT[(size_t)row * HID + hd] = acc;
    }
}

// ---------------- host launcher ----------------
extern "C" void kernel_launch(void* const* d_in, const int* in_sizes, int n_in,
                              void* d_out, int out_size) {
    const float* hs    = (const float*)d_in[0];
    const float* cosb  = (const float*)d_in[1];
    const float* sinb  = (const float*)d_in[2];
    const float* wq    = (const float*)d_in[3];
    const float* wk    = (const float*)d_in[4];
    const float* wv    = (const float*)d_in[5];
    const float* wo    = (const float*)d_in[6];
    const float* qnw   = (const float*)d_in[7];
    const float* knw   = (const float*)d_in[8];
    const float* w1    = (const float*)d_in[9];
    const float* b1    = (const float*)d_in[10];
    const float* w2    = (const float*)d_in[11];
    const float* b2    = (const float*)d_in[12];
    const float* ka    = (const float*)d_in[13];
    const float* kb    = (const float*)d_in[14];
    const float* sscale= (const float*)d_in[15];
    float* out = (float*)d_out;

    float *pT, *pLg, *pW, *pQ, *pKV, *pPq, *pPk, *pPv, *pQfr, *pKfr, *pVfr,
          *pAO, *pAO2, *pML, *pE1, *pZ, *pAfr, *pBfr;
    int *pTop, *pIs;
    cudaGetSymbolAddress((void**)&pT, g_T);
    cudaGetSymbolAddress((void**)&pLg, g_logits);
    cudaGetSymbolAddress((void**)&pW, g_weights);
    cudaGetSymbolAddress((void**)&pQ, g_q);
    cudaGetSymbolAddress((void**)&pKV, g_kv);
    cudaGetSymbolAddress((void**)&pPq, g_Pq);
    cudaGetSymbolAddress((void**)&pPk, g_Pk);
    cudaGetSymbolAddress((void**)&pPv, g_Pv);
    cudaGetSymbolAddress((void**)&pQfr, g_Qfr);
    cudaGetSymbolAddress((void**)&pKfr, g_Kfr);
    cudaGetSymbolAddress((void**)&pVfr, g_Vfr);
    cudaGetSymbolAddress((void**)&pAO, g_AO);
    cudaGetSymbolAddress((void**)&pAO2, g_AO2);
    cudaGetSymbolAddress((void**)&pML, g_ML);
    cudaGetSymbolAddress((void**)&pE1, g_E1);
    cudaGetSymbolAddress((void**)&pZ, g_Z);
    cudaGetSymbolAddress((void**)&pAfr, g_Afr);
    cudaGetSymbolAddress((void**)&pBfr, g_Bfr);
    cudaGetSymbolAddress((void**)&pTop, g_topk);
    cudaGetSymbolAddress((void**)&pIs, g_istop);

    float* pBkv = pBfr + (size_t)16 * 128 * 2048;
    float* pBwo = pBfr + (size_t)24 * 128 * 2048;
    float* pML2 = pML + (size_t)NQF * NH * 2;

    cudaFuncSetAttribute(topk_kernel, cudaFuncAttributeMaxDynamicSharedMemorySize, SEQ * 8);
    cudaFuncSetAttribute(fa_mma_kernel, cudaFuncAttributeMaxDynamicSharedMemorySize, FA2_SMEM);

    static cudaStream_t s1 = nullptr;
    static cudaEvent_t evFork = nullptr, evImp = nullptr, evNorm = nullptr,
                       evSkv = nullptr, evQg = nullptr, evFA1 = nullptr,
                       evAO = nullptr, evExp = nullptr;
    if (s1 == nullptr) {
        cudaStreamCreateWithFlags(&s1, cudaStreamNonBlocking);
        cudaEventCreateWithFlags(&evFork, cudaEventDisableTiming);
        cudaEventCreateWithFlags(&evImp, cudaEventDisableTiming);
        cudaEventCreateWithFlags(&evNorm, cudaEventDisableTiming);
        cudaEventCreateWithFlags(&evSkv, cudaEventDisableTiming);
        cudaEventCreateWithFlags(&evQg, cudaEventDisableTiming);
        cudaEventCreateWithFlags(&evFA1, cudaEventDisableTiming);
        cudaEventCreateWithFlags(&evAO, cudaEventDisableTiming);
        cudaEventCreateWithFlags(&evExp, cudaEventDisableTiming);
    }

    // ---- fork ----
    cudaEventRecord(evFork, 0);
    cudaStreamWaitEvent(s1, evFork, 0);

    // ---- s1: importance chain + wo weight conversion ----
    imp_gemm_kernel<<<dim3(1, SEQ / 64, 8), 256, 0, s1>>>(hs, w1, pT);
    imp_logits_kernel<<<SEQ, 32, 0, s1>>>(pT, b1, w2, b2, pLg, pW);
    topk_kernel<<<1, 1024, SEQ * 8, s1>>>(pLg, pTop, pIs);
    cudaEventRecord(evImp, s1);
    convB_kernel<<<dim3(HID / 16, HID / 128), 256, 0, s1>>>(wo, pBwo, HID, HID, 0);

    // ---- default: QKV projections (rmsnorm fused in GEMM epilogue) ----
    convA_kernel<<<dim3(HID / 16, SEQ / 128), 256>>>(hs, pAfr, HID);
    convB_kernel<<<dim3(HID / 16, HID / 128), 256>>>(wq, pBfr, HID, HID, 0);
    convB_kernel<<<dim3(HID / 16, 512 / 128), 256>>>(wk, pBkv, HID, 512, 0);
    convB_kernel<<<dim3(HID / 16, 512 / 128), 256>>>(wv, pBkv, HID, 512, 4);
    mma_gemm_kernel<<<dim3(HID / 128, SEQ / 128), 256>>>(pAfr, pBfr, pQ, nullptr, qnw, 16, HID, HID);
    mma_gemm_kernel<<<dim3(1024 / 128, SEQ / 128), 256>>>(pAfr, pBkv, pKV, nullptr, knw, 4, 1024, HID);
    cudaEventRecord(evNorm, 0);

    // ---- join importance; split sketches ----
    cudaStreamWaitEvent(0, evImp, 0);
    cudaStreamWaitEvent(s1, evNorm, 0);

    sketchA_kernel<<<dim3(NKV, 32), DH, 0, s1>>>(pKV, 8, 0, pW, pIs, 1, kb, pPk);
    sketchB_kernel<<<dim3(NKV, 32), DH, 0, s1>>>(pPk, NKV, ka, sscale, pKfr, 1);
    sketchA_kernel<<<dim3(NKV, 32), DH, 0, s1>>>(pKV, 8, 4, pW, pIs, 1, kb, pPv);
    sketchB_kernel<<<dim3(NKV, 32), DH, 0, s1>>>(pPv, NKV, ka, sscale, pVfr, 2);
    cudaEventRecord(evSkv, s1);

    sketchA_kernel<<<dim3(NH, 32), DH>>>(pQ, 16, 0, pW, pIs, 0, kb, pPq);
    sketchB_kernel<<<dim3(NH, 32), DH>>>(pPq, NH, ka, sscale, pQfr, 0);
    gather_rope_kernel<<<dim3(TK, 24), DH>>>(pQ, pKV, cosb, sinb, pTop, pQfr, pKfr, pVfr);
    cudaEventRecord(evQg, 0);

    // ---- attention: split-KV x2 (split0 default, split1 on s1) + combine ----
    cudaStreamWaitEvent(0, evSkv, 0);
    cudaStreamWaitEvent(s1, evQg, 0);
    fa_mma_kernel<<<dim3(NQT, NH), 256, FA2_SMEM>>>(pQfr, pKfr, pVfr, pAO, pML, 0);
    fa_mma_kernel<<<dim3(NQT, NH), 256, FA2_SMEM, s1>>>(pQfr, pKfr, pVfr, pAO2, pML2, KSPL);
    cudaEventRecord(evFA1, s1);
    cudaStreamWaitEvent(0, evFA1, 0);
    fa_combine_kernel<<<dim3(NQF, NH), DH>>>(pAO, pAO2, pML);

    // ---- epilogue ----
    convA_kernel<<<dim3(HID / 16, NQF / 128), 256>>>(pAO, pAfr, HID);
    cudaEventRecord(evAO, 0);
    cudaStreamWaitEvent(s1, evAO, 0);
    mma_gemm_kernel<<<dim3(HID / 128, SK / 128), 256, 0, s1>>>(
        pAfr + (size_t)16 * (HID / 16) * 2048, pBwo, pZ, nullptr, nullptr, 0, HID, HID);
    expandC_kernel<<<dim3(HID / 256, 32), 256, 0, s1>>>(pZ, ka, pE1);
    expandD_kernel<<<dim3(HID / 128, 32), DH, 0, s1>>>(pE1, kb, pIs, out);
    cudaEventRecord(evExp, s1);
    mma_gemm_kernel<<<dim3(HID / 128, TK / 128), 256>>>(pAfr, pBwo, out, pTop, nullptr, 0, HID, HID);

    // ---- join ----
    cudaStreamWaitEvent(0, evExp, 0);
}

// round 11
// speedup vs baseline: 4.7278x; 1.0025x over previous
#include <cuda_runtime.h>
#include <cuda_bf16.h>
#include <math.h>
#include <cstdint>

// Problem constants
#define SEQ   8192
#define HID   2048
#define NH    16
#define NKV   4
#define DH    128
#define TK    2048
#define SK    640
#define NQF   (TK + SK)        // 2688
#define NQT   (NQF / 128)      // 21 q tiles
#define NKT   (NQF / 64)       // 42 key tiles
#define KSPL  21               // key tiles per split (2 splits)
#define ATT_SCALE 0.08838834764831843f   // 1/sqrt(128)

// ---------------- scratch (device globals; no allocation) ----------------
__device__ float g_T[8 * SEQ * 64];
__device__ float g_logits[SEQ];
__device__ float g_weights[SEQ];
__device__ float g_q[SEQ * NH * DH];       // normalized q
__device__ float g_k[SEQ * 512];           // normalized k (4 heads x 128)
__device__ int   g_topk[TK];
__device__ int   g_istop[SEQ];
__device__ float g_Pq[NH * 32 * 32 * DH];  // q-sketch stage-A scratch
__device__ float g_Pk[NKV * 32 * 32 * DH]; // k-sketch stage-A scratch
__device__ float g_Ph[16 * 32 * 32 * DH];  // hs-sketch stage-A scratch
__device__ float g_HSr[SK * HID];          // rest-weighted hs sketch rows
__device__ float g_Qfr[NH * NQT * 16 * 8 * 32 * 4];
__device__ float g_Kfr[NKV * NKT * 16 * 8 * 32 * 2];
__device__ float g_Vfr[NKV * NKT * 8 * 16 * 32 * 2];
__device__ float g_AO[NQF * NH * DH];      // split-0 partial, then combined AO
__device__ float g_AO2[NQF * NH * DH];     // split-1 partial
__device__ float g_ML[2 * NQF * NH * 2];
__device__ float g_E1[32 * 32 * HID];
__device__ float g_Z[SK * HID];
__device__ float g_Afr[SEQ * HID];         // A fragments (hs, later AO)
__device__ float g_Afr2[NQF * HID];        // A fragments for V GEMM (topk hs | HSr)
__device__ float g_Bfr[40 * 128 * 2048];   // wq[0:16) | wk[16:20) | wv[20:24) | wo[24:40)

// ======================= tf32 mma.sync helpers =======================
__device__ __forceinline__ float tf32f(float x) {
    uint32_t r; asm("cvt.rna.tf32.f32 %0, %1;" : "=r"(r) : "f"(x));
    return __uint_as_float(r);
}

__device__ __forceinline__ void mma_tf32(float* c, const uint32_t* a, const uint32_t* b) {
    asm volatile("mma.sync.aligned.m16n8k8.row.col.f32.tf32.tf32.f32 "
        "{%0,%1,%2,%3}, {%4,%5,%6,%7}, {%8,%9}, {%0,%1,%2,%3};"
        : "+f"(c[0]), "+f"(c[1]), "+f"(c[2]), "+f"(c[3])
        : "r"(a[0]), "r"(a[1]), "r"(a[2]), "r"(a[3]), "r"(b[0]), "r"(b[1]));
}

#define CP_ASYNC16(dst_u32, src_ptr) \
    asm volatile("cp.async.cg.shared.global [%0], [%1], 16;" :: "r"(dst_u32), "l"(src_ptr))
#define CP_COMMIT() asm volatile("cp.async.commit_group;")

__device__ __forceinline__ void store_qfrag(float* Qg, int h, int tok, int d, float v) {
    int qt = tok >> 7, m = tok & 127;
    int k8 = d >> 3, mf = m >> 4;
    int lane = ((m & 7) << 2) | (d & 3);
    int reg = 2 * ((d & 7) >= 4) + ((m & 15) >= 8);
    size_t idx = ((((size_t)(h * NQT + qt) * 16 + k8) * 8 + mf) * 32 + lane) * 4 + reg;
    Qg[idx] = tf32f(v);
}
__device__ __forceinline__ void store_kfrag(float* Kg, int kvh, int tok, int d, float v) {
    int kt = tok >> 6, key = tok & 63;
    int k8 = d >> 3, nf = key >> 3;
    int lane = ((key & 7) << 2) | (d & 3);
    int reg = ((d & 7) >= 4);
    size_t idx = ((((size_t)(kvh * NKT + kt) * 16 + k8) * 8 + nf) * 32 + lane) * 2 + reg;
    Kg[idx] = tf32f(v);
}
__device__ __forceinline__ void store_vfrag(float* Vg, int kvh, int tok, int d, float v) {
    int kt = tok >> 6, key = tok & 63;
    int k8 = key >> 3, nf = d >> 3;
    int lane = ((d & 7) << 2) | (key & 3);
    int reg = ((key & 7) >= 4);
    size_t idx = ((((size_t)(kvh * NKT + kt) * 8 + k8) * 16 + nf) * 32 + lane) * 2 + reg;
    Vg[idx] = tf32f(v);
}

// ======================= fragment conversion pre-passes =======================
// A[M][K] row-major -> A-frag; optional row remap on load.
__global__ void __launch_bounds__(256) convA_kernel(const float* __restrict__ A,
                                                    const int* __restrict__ remap,
                                                    float* __restrict__ Afr, int K) {
    __shared__ float sm[2048];
    const int rt = blockIdx.y, c = blockIdx.x;
    const int tid = threadIdx.x;
#pragma unroll
    for (int i = 0; i < 2; i++) {
        int f = tid + i * 256;
        int r = f >> 2, c4 = f & 3;
        int act = remap ? __ldg(&remap[rt * 128 + r]) : (rt * 128 + r);
        float4 v = *reinterpret_cast<const float4*>(A + (size_t)act * K + c * 16 + c4 * 4);
        int mf = r >> 4, gid = r & 7, mhi = (r >> 3) & 1;
        float vv[4] = {v.x, v.y, v.z, v.w};
#pragma unroll
        for (int j = 0; j < 4; j++) {
            int k = c4 * 4 + j;
            int slot = ((k >> 3) * 8 + mf) * 128 + ((gid << 2) | (k & 3)) * 4
                     + 2 * ((k & 7) >= 4) + mhi;
            sm[slot] = tf32f(vv[j]);
        }
    }
    __syncthreads();
    float4* out = reinterpret_cast<float4*>(Afr + ((size_t)(rt * (K >> 4) + c)) * 2048);
    const float4* s4 = reinterpret_cast<const float4*>(sm);
#pragma unroll
    for (int i = 0; i < 2; i++) out[tid + i * 256] = s4[tid + i * 256];
}

__global__ void __launch_bounds__(256) convB_kernel(const float* __restrict__ B,
                                                    float* __restrict__ Bfr, int K, int N,
                                                    int ctbase) {
    __shared__ float sm[2048];
    const int ct = blockIdx.y + ctbase, c = blockIdx.x;
    const int tid = threadIdx.x;
    const float* Bb = B + ((size_t)(c * 16)) * N + blockIdx.y * 128;
#pragma unroll
    for (int i = 0; i < 2; i++) {
        int f = tid + i * 256;
        int kk = f >> 5, n4 = f & 31;
        float4 v = *reinterpret_cast<const float4*>(Bb + (size_t)kk * N + n4 * 4);
        int k8in = kk >> 3, reg = ((kk & 7) >= 4);
        float vv[4] = {v.x, v.y, v.z, v.w};
#pragma unroll
        for (int j = 0; j < 4; j++) {
            int n = n4 * 4 + j;
            int slot = (k8in * 16 + (n >> 3)) * 64 + (((n & 7) << 2) | (kk & 3)) * 2 + reg;
            sm[slot] = tf32f(vv[j]);
        }
    }
    __syncthreads();
    float4* out = reinterpret_cast<float4*>(Bfr + ((size_t)(ct * (K >> 4) + c)) * 2048);
    const float4* s4 = reinterpret_cast<const float4*>(sm);
#pragma unroll
    for (int i = 0; i < 2; i++) out[tid + i * 256] = s4[tid + i * 256];
}

// ======= tf32 GEMM: 128x128, cp.async 3-stage, 2 CTA/SM; optional rmsnorm / remap /
//         vfrag-epilogue (writes V mma-fragments directly) ===
__global__ void __launch_bounds__(256, 2) mma_gemm_kernel(
    const float* __restrict__ Afr, const float* __restrict__ Bfr,
    float* __restrict__ C, const int* __restrict__ remap,
    const float* __restrict__ normw, int normct, float* __restrict__ vfr,
    int N, int K)
{
    __shared__ float sA[3][2048];
    __shared__ float sB[3][2048];

    const int tid = threadIdx.x;
    const int lane = tid & 31, wid = tid >> 5;
    const int wm = wid >> 2, wn = wid & 3;
    const int NCH = K >> 4;

    const float4* Ag = reinterpret_cast<const float4*>(Afr) + (size_t)blockIdx.y * NCH * 512;
    const float4* Bg = reinterpret_cast<const float4*>(Bfr) + (size_t)blockIdx.x * NCH * 512;

    const uint32_t sAu = (uint32_t)__cvta_generic_to_shared(&sA[0][0]) + tid * 16;
    const uint32_t sBu = (uint32_t)__cvta_generic_to_shared(&sB[0][0]) + tid * 16;

    {
        const float4* ga = Ag + tid;  const float4* gb = Bg + tid;
        CP_ASYNC16(sAu, ga); CP_ASYNC16(sAu + 4096, ga + 256);
        CP_ASYNC16(sBu, gb); CP_ASYNC16(sBu + 4096, gb + 256);
        CP_COMMIT();
        if (NCH > 1) {
            ga += 512; gb += 512;
            CP_ASYNC16(sAu + 8192, ga); CP_ASYNC16(sAu + 8192 + 4096, ga + 256);
            CP_ASYNC16(sBu + 8192, gb); CP_ASYNC16(sBu + 8192 + 4096, gb + 256);
            CP_COMMIT();
        }
    }

    float acc[4][4][4] = {};
    for (int c = 0; c < NCH; c++) {
        if (c + 1 < NCH) asm volatile("cp.async.wait_group 1;");
        else             asm volatile("cp.async.wait_group 0;");
        __syncthreads();

        const int buf = c % 3;
        const float4* A4 = reinterpret_cast<const float4*>(sA[buf]);
        const float2* B2 = reinterpret_cast<const float2*>(sB[buf]);
#pragma unroll
        for (int k8 = 0; k8 < 2; k8++) {
            float4 af[4];
            float2 bf[4];
#pragma unroll
            for (int mf = 0; mf < 4; mf++)
                af[mf] = A4[(k8 * 8 + wm * 4 + mf) * 32 + lane];
#pragma unroll
            for (int nf = 0; nf < 4; nf++)
                bf[nf] = B2[(k8 * 16 + wn * 4 + nf) * 32 + lane];
#pragma unroll
            for (int mf = 0; mf < 4; mf++)
#pragma unroll
                for (int nf = 0; nf < 4; nf++)
                    mma_tf32(acc[mf][nf],
                             reinterpret_cast<const uint32_t*>(&af[mf]),
                             reinterpret_cast<const uint32_t*>(&bf[nf]));
        }
        if (c + 2 < NCH) {
            const int st = (c + 2) % 3;
            const float4* ga = Ag + (c + 2) * 512 + tid;
            const float4* gb = Bg + (c + 2) * 512 + tid;
            CP_ASYNC16(sAu + st * 8192, ga); CP_ASYNC16(sAu + st * 8192 + 4096, ga + 256);
            CP_ASYNC16(sBu + st * 8192, gb); CP_ASYNC16(sBu + st * 8192 + 4096, gb + 256);
            CP_COMMIT();
        }
    }

    const int gid = lane >> 2, tig = lane & 3;
    const int row0 = blockIdx.y * 128;
    const int col0 = blockIdx.x * 128;

    // ---- vfrag epilogue: write V mma-fragments directly ----
    if (vfr != nullptr) {
#pragma unroll
        for (int mf = 0; mf < 4; mf++) {
            int m = row0 + wm * 64 + mf * 16 + gid;
#pragma unroll
            for (int nf = 0; nf < 4; nf++) {
                int n = col0 + wn * 32 + nf * 8 + tig * 2;
                store_vfrag(vfr, n >> 7, m, n & 127, acc[mf][nf][0]);
                store_vfrag(vfr, (n + 1) >> 7, m, (n + 1) & 127, acc[mf][nf][1]);
                store_vfrag(vfr, n >> 7, m + 8, n & 127, acc[mf][nf][2]);
                store_vfrag(vfr, (n + 1) >> 7, m + 8, (n + 1) & 127, acc[mf][nf][3]);
            }
        }
        return;
    }

    // ---- optional fused rmsnorm over this 128-col (one-head) tile ----
    if (normw != nullptr && blockIdx.x < normct) {
        float* ssm = &sA[0][0];
        __syncthreads();
        float ss0[4], ss1[4];
#pragma unroll
        for (int mf = 0; mf < 4; mf++) {
            float s0 = 0.f, s1 = 0.f;
#pragma unroll
            for (int nf = 0; nf < 4; nf++) {
                s0 += acc[mf][nf][0] * acc[mf][nf][0] + acc[mf][nf][1] * acc[mf][nf][1];
                s1 += acc[mf][nf][2] * acc[mf][nf][2] + acc[mf][nf][3] * acc[mf][nf][3];
            }
            s0 += __shfl_xor_sync(0xffffffffu, s0, 1);
            s0 += __shfl_xor_sync(0xffffffffu, s0, 2);
            s1 += __shfl_xor_sync(0xffffffffu, s1, 1);
            s1 += __shfl_xor_sync(0xffffffffu, s1, 2);
            ss0[mf] = s0; ss1[mf] = s1;
        }
        if (tig == 0) {
#pragma unroll
            for (int mf = 0; mf < 4; mf++) {
                int r = wm * 64 + mf * 16 + gid;
                ssm[r * 4 + wn] = ss0[mf];
                ssm[(r + 8) * 4 + wn] = ss1[mf];
            }
        }
        __syncthreads();
#pragma unroll
        for (int mf = 0; mf < 4; mf++) {
            int r = wm * 64 + mf * 16 + gid;
            float t0 = ssm[r * 4] + ssm[r * 4 + 1] + ssm[r * 4 + 2] + ssm[r * 4 + 3];
            float t1 = ssm[(r + 8) * 4] + ssm[(r + 8) * 4 + 1]
                     + ssm[(r + 8) * 4 + 2] + ssm[(r + 8) * 4 + 3];
            float sc0 = rsqrtf(t0 * (1.0f / 128.0f) + 1e-6f);
            float sc1 = rsqrtf(t1 * (1.0f / 128.0f) + 1e-6f);
#pragma unroll
            for (int nf = 0; nf < 4; nf++) {
                int n = wn * 32 + nf * 8 + tig * 2;
                float w0 = __ldg(&normw[n]), w1 = __ldg(&normw[n + 1]);
                acc[mf][nf][0] *= sc0 * w0; acc[mf][nf][1] *= sc0 * w1;
                acc[mf][nf][2] *= sc1 * w0; acc[mf][nf][3] *= sc1 * w1;
            }
        }
    }

#pragma unroll
    for (int mf = 0; mf < 4; mf++) {
        int m = row0 + wm * 64 + mf * 16 + gid;
        int m1 = remap ? __ldg(&remap[m]) : m;
        int m2 = remap ? __ldg(&remap[m + 8]) : (m + 8);
#pragma unroll
        for (int nf = 0; nf < 4; nf++) {
            int n = col0 + wn * 32 + nf * 8 + tig * 2;
            *reinterpret_cast<float2*>(&C[(size_t)m1 * N + n]) =
                make_float2(acc[mf][nf][0], acc[mf][nf][1]);
            *reinterpret_cast<float2*>(&C[(size_t)m2 * N + n]) =
                make_float2(acc[mf][nf][2], acc[mf][nf][3]);
        }
    }
}

// ---------------- importance GEMM: fp32 split-K x8 ----------------
__global__ void __launch_bounds__(256) imp_gemm_kernel(
    const float* __restrict__ A, const float* __restrict__ B, float* __restrict__ Cp)
{
    __shared__ float As[16][64];
    __shared__ float Bs[16][64];
    const int tid = threadIdx.x;
    const int row0 = blockIdx.y * 64;
    const int z = blockIdx.z;
    const float* Ab = A + (size_t)row0 * HID + z * 256;
    const float* Bb = B + (size_t)z * 256 * 64;
    float acc[4][4] = {};
    const int tc = (tid & 15) * 4, tr = (tid >> 4) * 4;
    const int ar = tid >> 2, ac = (tid & 3) * 4;
    const int br = tid >> 4, bc = (tid & 15) * 4;

    for (int k0 = 0; k0 < 256; k0 += 16) {
        float4 va = *reinterpret_cast<const float4*>(Ab + (size_t)ar * HID + k0 + ac);
        As[ac + 0][ar] = va.x; As[ac + 1][ar] = va.y;
        As[ac + 2][ar] = va.z; As[ac + 3][ar] = va.w;
        float4 vb = *reinterpret_cast<const float4*>(Bb + (size_t)(k0 + br) * 64 + bc);
        *reinterpret_cast<float4*>(&Bs[br][bc]) = vb;
        __syncthreads();
#pragma unroll
        for (int k = 0; k < 16; k++) {
            float ra[4], rb[4];
#pragma unroll
            for (int m = 0; m < 4; m++) ra[m] = As[k][tr + m];
#pragma unroll
            for (int n = 0; n < 4; n++) rb[n] = Bs[k][tc + n];
#pragma unroll
            for (int m = 0; m < 4; m++)
#pragma unroll
                for (int n = 0; n < 4; n++) acc[m][n] += ra[m] * rb[n];
        }
        __syncthreads();
    }
#pragma unroll
    for (int m = 0; m < 4; m++) {
        float4 v = make_float4(acc[m][0], acc[m][1], acc[m][2], acc[m][3]);
        *reinterpret_cast<float4*>(&Cp[((size_t)z * SEQ + row0 + tr + m) * 64 + tc]) = v;
    }
}

// ---------------- importance logits epilogue ----------------
__global__ void imp_logits_kernel(const float* __restrict__ T, const float* __restrict__ b1,
                                  const float* __restrict__ w2, const float* __restrict__ b2,
                                  float* __restrict__ logits, float* __restrict__ weights) {
    const float LOG_ADJ = 2.5494451709255714f;
    int s = blockIdx.x;
    int j = threadIdx.x;
    float v1 = 0.f, v2 = 0.f;
#pragma unroll
    for (int z = 0; z < 8; z++) {
        v1 += T[((size_t)z * SEQ + s) * 64 + j];
        v2 += T[((size_t)z * SEQ + s) * 64 + j + 32];
    }
    float v = tanhf(v1 + b1[j]) * w2[j] + tanhf(v2 + b1[j + 32]) * w2[j + 32];
#pragma unroll
    for (int o = 16; o > 0; o >>= 1) v += __shfl_xor_sync(0xffffffffu, v, o);
    if (j == 0) {
        float lg = v + b2[0] - LOG_ADJ;
        logits[s] = lg;
        weights[s] = 1.0f / (1.0f + expf(-lg));
    }
}

// ---------------- top-k via single-block bitonic sort ----------------
__global__ void topk_kernel(const float* __restrict__ logits,
                            int* __restrict__ topk_list, int* __restrict__ is_topk) {
    extern __shared__ unsigned long long skeys[];
    int tid = threadIdx.x;
    for (int i = tid; i < SEQ; i += 1024) {
        unsigned u = __float_as_uint(logits[i]);
        u = (u & 0x80000000u) ? ~u : (u | 0x80000000u);
        skeys[i] = ((unsigned long long)(~u) << 32) | (unsigned)i;
        is_topk[i] = 0;
    }
    __syncthreads();
    for (int k = 2; k <= SEQ; k <<= 1) {
        for (int j = k >> 1; j > 0; j >>= 1) {
            for (int i = tid; i < SEQ; i += 1024) {
                int ixj = i ^ j;
                if (ixj > i) {
                    bool up = ((i & k) == 0);
                    unsigned long long a = skeys[i], b = skeys[ixj];
                    if ((a > b) == up) { skeys[i] = b; skeys[ixj] = a; }
                }
            }
            __syncthreads();
        }
    }
    for (int i = tid; i < TK; i += 1024) {
        int pos = (int)(skeys[i] & 0xffffffffu);
        topk_list[i] = pos;
        is_topk[pos] = 1;
    }
}

// ---------------- sketch stage A (generic head addressing) ----------------
__global__ void sketchA_kernel(const float* __restrict__ X, int hstride, int hbase,
                               const float* __restrict__ weights,
                               const int* __restrict__ is_topk, int rest,
                               const float* __restrict__ kb, float* __restrict__ P) {
    int h = blockIdx.x;
    int ib = blockIdx.y;
    int d = threadIdx.x;
    __shared__ float kbs[32 * 256];
    for (int t = d; t < 32 * 256; t += 128) kbs[t] = kb[t];
    __shared__ float ws[256];
    for (int j = d; j < 256; j += 128) {
        int t = ib * 256 + j;
        float w = weights[t];
        if (rest && is_topk[t]) w = 0.0f;
        ws[j] = w;
    }
    __syncthreads();
    float acc[32] = {};
    for (int j = 0; j < 256; j++) {
        float xv = X[((size_t)(ib * 256 + j) * hstride + hbase + h) * DH + d] * ws[j];
#pragma unroll
        for (int kbo = 0; kbo < 32; kbo++) acc[kbo] += xv * kbs[kbo * 256 + j];
    }
#pragma unroll
    for (int kbo = 0; kbo < 32; kbo++)
        P[(((size_t)h * 32 + kbo) * 32 + ib) * DH + d] = acc[kbo];
}

// ---------------- sketch stage B; mode: 0=qfrag,1=kfrag,3=dense [s][heads*128] ------
__global__ void sketchB_kernel(const float* __restrict__ P, int heads,
                               const float* __restrict__ ka,
                               const float* __restrict__ scale_p,
                               float* __restrict__ dst, int mode) {
    int h = blockIdx.x;
    int kbo = blockIdx.y;
    int d = threadIdx.x;
    __shared__ float kas[20 * 32];
    for (int t = d; t < 20 * 32; t += 128) kas[t] = ka[(t / 32) * DH + (t % 32)];
    __syncthreads();
    float p[32];
#pragma unroll
    for (int i = 0; i < 32; i++) p[i] = P[(((size_t)h * 32 + kbo) * 32 + i) * DH + d];
    float scale = scale_p[0];
    if (mode == 0) scale *= ATT_SCALE;
#pragma unroll
    for (int kao = 0; kao < 20; kao++) {
        float acc = 0.f;
#pragma unroll
        for (int i = 0; i < 32; i++) acc += p[i] * kas[kao * 32 + i];
        int s = TK + kbo * 20 + kao;
        float val = acc * scale;
        if (mode == 0)      store_qfrag(dst, h, s, d, val);
        else if (mode == 1) store_kfrag(dst, h, s, d, val);
        else                dst[(size_t)(s - TK) * (heads * DH) + h * DH + d] = val;
    }
}

// ---------------- gather + RoPE (q and k only; v handled by V GEMM) ----------------
__global__ void gather_rope_kernel(const float* __restrict__ q, const float* __restrict__ k,
                                   const float* __restrict__ cosb, const float* __restrict__ sinb,
                                   const int* __restrict__ topk_list,
                                   float* __restrict__ Qfr, float* __restrict__ Kfr) {
    int j = blockIdx.x;
    int hy = blockIdx.y;   // 0..19
    int d = threadIdx.x;
    int pos = topk_list[j];
    float c = cosb[(size_t)pos * DH + d];
    float s = sinb[(size_t)pos * DH + d];
    if (hy < 16) {
        const float* src = q + ((size_t)pos * NH + hy) * DH;
        float x = src[d];
        float r = (d < 64) ? -src[d + 64] : src[d - 64];
        store_qfrag(Qfr, hy, j, d, (x * c + r * s) * ATT_SCALE);
    } else {
        int h = hy - 16;
        const float* src = k + (size_t)pos * 512 + h * DH;
        float x = src[d];
        float r = (d < 64) ? -src[d + 64] : src[d - 64];
        store_kfrag(Kfr, h, j, d, x * c + r * s);
    }
}

// ---------------- tensor-core flash attention (split-KV, cp.async K/V) -------
#define FA2_SMEM ((16384 + 2*8192 + 2*8192 + 512) * 4)
__global__ void __launch_bounds__(256, 1) fa_mma_kernel(
    const float* __restrict__ Qfr, const float* __restrict__ Kfr,
    const float* __restrict__ Vfr, float* __restrict__ Op,
    float* __restrict__ ML, int kt0)
{
    extern __shared__ float fsm[];
    float* Qsm = fsm;
    float* Ksm = fsm + 16384;
    float* Vsm = fsm + 32768;
    float* mpart = fsm + 49152;
    float* spart = fsm + 49408;

    const int qt = blockIdx.x;
    const int h  = blockIdx.y;
    const int kvh = h >> 2;
    const int tid = threadIdx.x;
    const int lane = tid & 31, wid = tid >> 5;
    const int wm = wid >> 1, wn = wid & 1;
    const int gid = lane >> 2, tig = lane & 3;

    const uint32_t ksmU = (uint32_t)__cvta_generic_to_shared(Ksm) + tid * 16;
    const uint32_t vsmU = (uint32_t)__cvta_generic_to_shared(Vsm) + tid * 16;

    {
        const float4* Kg = reinterpret_cast<const float4*>(Kfr + (size_t)(kvh * NKT + kt0) * 8192);
        const float4* Vg = reinterpret_cast<const float4*>(Vfr + (size_t)(kvh * NKT + kt0) * 8192);
#pragma unroll
        for (int i = 0; i < 8; i++) {
            CP_ASYNC16(ksmU + i * 4096, Kg + tid + i * 256);
            CP_ASYNC16(vsmU + i * 4096, Vg + tid + i * 256);
        }
        CP_COMMIT();
    }

    {
        const float4* Qg = reinterpret_cast<const float4*>(Qfr + (size_t)(h * NQT + qt) * 16384);
        float4* Qs4w = reinterpret_cast<float4*>(Qsm);
#pragma unroll
        for (int i = 0; i < 16; i++) Qs4w[tid + i * 256] = Qg[tid + i * 256];
    }

    float m_old[2][2], l_run[2][2];
#pragma unroll
    for (int a = 0; a < 2; a++)
#pragma unroll
        for (int b = 0; b < 2; b++) { m_old[a][b] = -1e30f; l_run[a][b] = 0.f; }
    float oacc[2][8][4] = {};

    const float4* Qs4 = reinterpret_cast<const float4*>(Qsm);

    for (int t = 0; t < KSPL; t++) {
        const int buf = t & 1;
        if (t + 1 < KSPL) {
            const float4* Kg = reinterpret_cast<const float4*>(Kfr + (size_t)(kvh * NKT + kt0 + t + 1) * 8192);
            const float4* Vg = reinterpret_cast<const float4*>(Vfr + (size_t)(kvh * NKT + kt0 + t + 1) * 8192);
            const uint32_t kd = ksmU + (1 - buf) * 32768;
            const uint32_t vd = vsmU + (1 - buf) * 32768;
#pragma unroll
            for (int i = 0; i < 8; i++) {
                CP_ASYNC16(kd + i * 4096, Kg + tid + i * 256);
                CP_ASYNC16(vd + i * 4096, Vg + tid + i * 256);
            }
            CP_COMMIT();
            asm volatile("cp.async.wait_group 1;");
        } else {
            asm volatile("cp.async.wait_group 0;");
        }
        __syncthreads();

        const float2* Ks2 = reinterpret_cast<const float2*>(Ksm + buf * 8192);
        const float2* Vs2 = reinterpret_cast<const float2*>(Vsm + buf * 8192);
        float* Psm = Ksm + buf * 8192;
        const float4* Ps4 = reinterpret_cast<const float4*>(Psm);

        float sacc[2][4][4] = {};
#pragma unroll
        for (int k8 = 0; k8 < 16; k8++) {
            float4 af[2];
            float2 bf[4];
            af[0] = Qs4[(k8 * 8 + wm * 2 + 0) * 32 + lane];
            af[1] = Qs4[(k8 * 8 + wm * 2 + 1) * 32 + lane];
#pragma unroll
            for (int nf = 0; nf < 4; nf++) bf[nf] = Ks2[(k8 * 8 + wn * 4 + nf) * 32 + lane];
#pragma unroll
            for (int mf = 0; mf < 2; mf++)
#pragma unroll
                for (int nf = 0; nf < 4; nf++)
                    mma_tf32(sacc[mf][nf],
                             reinterpret_cast<const uint32_t*>(&af[mf]),
                             reinterpret_cast<const uint32_t*>(&bf[nf]));
        }

        float mloc[2][2];
#pragma unroll
        for (int mf = 0; mf < 2; mf++) {
            float m0 = fmaxf(sacc[mf][0][0], sacc[mf][0][1]);
            float m1 = fmaxf(sacc[mf][0][2], sacc[mf][0][3]);
#pragma unroll
            for (int nf = 1; nf < 4; nf++) {
                m0 = fmaxf(m0, fmaxf(sacc[mf][nf][0], sacc[mf][nf][1]));
                m1 = fmaxf(m1, fmaxf(sacc[mf][nf][2], sacc[mf][nf][3]));
            }
            m0 = fmaxf(m0, __shfl_xor_sync(0xffffffffu, m0, 1));
            m0 = fmaxf(m0, __shfl_xor_sync(0xffffffffu, m0, 2));
            m1 = fmaxf(m1, __shfl_xor_sync(0xffffffffu, m1, 1));
            m1 = fmaxf(m1, __shfl_xor_sync(0xffffffffu, m1, 2));
            mloc[mf][0] = m0; mloc[mf][1] = m1;
        }
        if (tig == 0) {
#pragma unroll
            for (int mf = 0; mf < 2; mf++) {
                int r = wm * 32 + mf * 16 + gid;
                mpart[wn * 128 + r] = mloc[mf][0];
                mpart[wn * 128 + r + 8] = mloc[mf][1];
            }
        }
        __syncthreads();

        float mnew[2][2], corr[2][2];
#pragma unroll
        for (int mf = 0; mf < 2; mf++)
#pragma unroll
            for (int hi = 0; hi < 2; hi++) {
                int r = wm * 32 + mf * 16 + gid + hi * 8;
                float mt = fmaxf(mpart[r], mpart[128 + r]);
                float mn = fmaxf(m_old[mf][hi], mt);
                corr[mf][hi] = __expf(m_old[mf][hi] - mn);
                mnew[mf][hi] = mn;
                m_old[mf][hi] = mn;
            }

        float sloc[2][2] = {};
#pragma unroll
        for (int mf = 0; mf < 2; mf++)
#pragma unroll
            for (int nf = 0; nf < 4; nf++) {
                sacc[mf][nf][0] = __expf(sacc[mf][nf][0] - mnew[mf][0]);
                sacc[mf][nf][1] = __expf(sacc[mf][nf][1] - mnew[mf][0]);
                sacc[mf][nf][2] = __expf(sacc[mf][nf][2] - mnew[mf][1]);
                sacc[mf][nf][3] = __expf(sacc[mf][nf][3] - mnew[mf][1]);
                sloc[mf][0] += sacc[mf][nf][0] + sacc[mf][nf][1];
                sloc[mf][1] += sacc[mf][nf][2] + sacc[mf][nf][3];
            }
#pragma unroll
        for (int mf = 0; mf < 2; mf++) {
            sloc[mf][0] += __shfl_xor_sync(0xffffffffu, sloc[mf][0], 1);
            sloc[mf][0] += __shfl_xor_sync(0xffffffffu, sloc[mf][0], 2);
            sloc[mf][1] += __shfl_xor_sync(0xffffffffu, sloc[mf][1], 1);
            sloc[mf][1] += __shfl_xor_sync(0xffffffffu, sloc[mf][1], 2);
        }
        if (tig == 0) {
#pragma unroll
            for (int mf = 0; mf < 2; mf++) {
                int r = wm * 32 + mf * 16 + gid;
                spart[wn * 128 + r] = sloc[mf][0];
                spart[wn * 128 + r + 8] = sloc[mf][1];
            }
        }

#pragma unroll
        for (int mf = 0; mf < 2; mf++)
#pragma unroll
            for (int nf = 0; nf < 4; nf++) {
                int k8p = wn * 4 + nf;
                int mfg = wm * 2 + mf;
#pragma unroll
                for (int b = 0; b < 2; b++) {
                    int c = tig * 2 + b;
                    int khi = (c >= 4);
                    int base = ((k8p * 8 + mfg) * 32 + (gid << 2) + (c & 3)) * 4 + khi * 2;
                    *reinterpret_cast<float2*>(Psm + base) =
                        make_float2(tf32f(sacc[mf][nf][b]), tf32f(sacc[mf][nf][2 + b]));
                }
            }
        __syncthreads();

#pragma unroll
        for (int mf = 0; mf < 2; mf++)
#pragma unroll
            for (int hi = 0; hi < 2; hi++) {
                int r = wm * 32 + mf * 16 + gid + hi * 8;
                l_run[mf][hi] = l_run[mf][hi] * corr[mf][hi] + spart[r] + spart[128 + r];
            }
#pragma unroll
        for (int mf = 0; mf < 2; mf++)
#pragma unroll
            for (int nf = 0; nf < 8; nf++) {
                oacc[mf][nf][0] *= corr[mf][0]; oacc[mf][nf][1] *= corr[mf][0];
                oacc[mf][nf][2] *= corr[mf][1]; oacc[mf][nf][3] *= corr[mf][1];
            }

#pragma unroll
        for (int k8 = 0; k8 < 8; k8++) {
            float4 af[2];
            af[0] = Ps4[(k8 * 8 + wm * 2 + 0) * 32 + lane];
            af[1] = Ps4[(k8 * 8 + wm * 2 + 1) * 32 + lane];
#pragma unroll
            for (int nf = 0; nf < 8; nf++) {
                float2 bf = Vs2[(k8 * 16 + wn * 8 + nf) * 32 + lane];
#pragma unroll
                for (int mf = 0; mf < 2; mf++)
                    mma_tf32(oacc[mf][nf],
                             reinterpret_cast<const uint32_t*>(&af[mf]),
                             reinterpret_cast<const uint32_t*>(&bf));
            }
        }
        __syncthreads();
    }

#pragma unroll
    for (int mf = 0; mf < 2; mf++) {
        int r0 = qt * 128 + wm * 32 + mf * 16 + gid;
        if (wn == 0 && tig == 0) {
            size_t row0i = (size_t)r0 * NH + h;
            size_t row1i = (size_t)(r0 + 8) * NH + h;
            ML[row0i * 2] = m_old[mf][0]; ML[row0i * 2 + 1] = l_run[mf][0];
            ML[row1i * 2] = m_old[mf][1]; ML[row1i * 2 + 1] = l_run[mf][1];
        }
#pragma unroll
        for (int nf = 0; nf < 8; nf++) {
            int col = wn * 64 + nf * 8 + tig * 2;
            *reinterpret_cast<float2*>(&Op[((size_t)r0 * NH + h) * DH + col]) =
                make_float2(oacc[mf][nf][0], oacc[mf][nf][1]);
            *reinterpret_cast<float2*>(&Op[((size_t)(r0 + 8) * NH + h) * DH + col]) =
                make_float2(oacc[mf][nf][2], oacc[mf][nf][3]);
        }
    }
}

// ---------------- fa combine ----------------
__global__ void fa_combine_kernel(float* __restrict__ O0, const float* __restrict__ O1,
                                  const float* __restrict__ ML) {
    size_t row = (size_t)blockIdx.x * NH + blockIdx.y;
    int d = threadIdx.x;
    float m0 = ML[row * 2], l0 = ML[row * 2 + 1];
    float m1 = ML[(size_t)NQF * NH * 2 + row * 2], l1 = ML[(size_t)NQF * NH * 2 + row * 2 + 1];
    float m = fmaxf(m0, m1);
    float w0 = __expf(m0 - m), w1 = __expf(m1 - m);
    float inv = 1.0f / (w0 * l0 + w1 * l1);
    O0[row * DH + d] = (O0[row * DH + d] * w0 + O1[row * DH + d] * w1) * inv;
}

// ---------------- expand stage C ----------------
__global__ void expandC_kernel(const float* __restrict__ Z, const float* __restrict__ ka,
                               float* __restrict__ E1) {
    int i = blockIdx.y;
    int hd = blockIdx.x * 256 + threadIdx.x;
    __shared__ float kav[20];
    if (threadIdx.x < 20) kav[threadIdx.x] = ka[threadIdx.x * DH + i];
    __syncthreads();
    for (int kbo = 0; kbo < 32; kbo++) {
        float acc = 0.f;
#pragma unroll
        for (int kao = 0; kao < 20; kao++)
            acc += Z[((size_t)(kbo * 20 + kao)) * HID + hd] * kav[kao];
        E1[((size_t)i * 32 + kbo) * HID + hd] = acc;
    }
}

// ---------------- expand stage D ----------------
__global__ void expandD_kernel(const float* __restrict__ E1, const float* __restrict__ kb,
                               const int* __restrict__ is_topk, float* __restrict__ OUT) {
    int i = blockIdx.y;
    int hd = blockIdx.x * 128 + threadIdx.x;
    __shared__ float kbs[32 * 256];
    for (int t = threadIdx.x; t < 32 * 256; t += 128) kbs[t] = kb[t];
    float e[32];
#pragma unroll
    for (int kbo = 0; kbo < 32; kbo++) e[kbo] = E1[((size_t)i * 32 + kbo) * HID + hd];
    __syncthreads();
    for (int j = 0; j < 256; j++) {
        int row = i * 256 + j;
        if (is_topk[row]) continue;
        float acc = 0.f;
#pragma unroll
        for (int kbo = 0; kbo < 32; kbo++) acc += e[kbo] * kbs[kbo * 256 + j];
        OUT[(size_t)row * HID + hd] = acc;
    }
}

// ---------------- host launcher ----------------
extern "C" void kernel_launch(void* const* d_in, const int* in_sizes, int n_in,
                              void* d_out, int out_size) {
    const float* hs    = (const float*)d_in[0];
    const float* cosb  = (const float*)d_in[1];
    const float* sinb  = (const float*)d_in[2];
    const float* wq    = (const float*)d_in[3];
    const float* wk    = (const float*)d_in[4];
    const float* wv    = (const float*)d_in[5];
    const float* wo    = (const float*)d_in[6];
    const float* qnw   = (const float*)d_in[7];
    const float* knw   = (const float*)d_in[8];
    const float* w1    = (const float*)d_in[9];
    const float* b1    = (const float*)d_in[10];
    const float* w2    = (const float*)d_in[11];
    const float* b2    = (const float*)d_in[12];
    const float* ka    = (const float*)d_in[13];
    const float* kb    = (const float*)d_in[14];
    const float* sscale= (const float*)d_in[15];
    float* out = (float*)d_out;

    float *pT, *pLg, *pW, *pQ, *pK, *pPq, *pPk, *pPh, *pHSr, *pQfr, *pKfr, *pVfr,
          *pAO, *pAO2, *pML, *pE1, *pZ, *pAfr, *pAfr2, *pBfr;
    int *pTop, *pIs;
    cudaGetSymbolAddress((void**)&pT, g_T);
    cudaGetSymbolAddress((void**)&pLg, g_logits);
    cudaGetSymbolAddress((void**)&pW, g_weights);
    cudaGetSymbolAddress((void**)&pQ, g_q);
    cudaGetSymbolAddress((void**)&pK, g_k);
    cudaGetSymbolAddress((void**)&pPq, g_Pq);
    cudaGetSymbolAddress((void**)&pPk, g_Pk);
    cudaGetSymbolAddress((void**)&pPh, g_Ph);
    cudaGetSymbolAddress((void**)&pHSr, g_HSr);
    cudaGetSymbolAddress((void**)&pQfr, g_Qfr);
    cudaGetSymbolAddress((void**)&pKfr, g_Kfr);
    cudaGetSymbolAddress((void**)&pVfr, g_Vfr);
    cudaGetSymbolAddress((void**)&pAO, g_AO);
    cudaGetSymbolAddress((void**)&pAO2, g_AO2);
    cudaGetSymbolAddress((void**)&pML, g_ML);
    cudaGetSymbolAddress((void**)&pE1, g_E1);
    cudaGetSymbolAddress((void**)&pZ, g_Z);
    cudaGetSymbolAddress((void**)&pAfr, g_Afr);
    cudaGetSymbolAddress((void**)&pAfr2, g_Afr2);
    cudaGetSymbolAddress((void**)&pBfr, g_Bfr);
    cudaGetSymbolAddress((void**)&pTop, g_topk);
    cudaGetSymbolAddress((void**)&pIs, g_istop);

    float* pBwk = pBfr + (size_t)16 * 128 * 2048;
    float* pBwv = pBfr + (size_t)20 * 128 * 2048;
    float* pBwo = pBfr + (size_t)24 * 128 * 2048;
    float* pML2 = pML + (size_t)NQF * NH * 2;
    float* pAfr2b = pAfr2 + (size_t)16 * (HID / 16) * 2048;   // HSr row tiles 16..20

    cudaFuncSetAttribute(topk_kernel, cudaFuncAttributeMaxDynamicSharedMemorySize, SEQ * 8);
    cudaFuncSetAttribute(fa_mma_kernel, cudaFuncAttributeMaxDynamicSharedMemorySize, FA2_SMEM);

    static cudaStream_t s1 = nullptr;
    static cudaEvent_t evFork = nullptr, evImp = nullptr, evAfr = nullptr,
                       evVf = nullptr, evK = nullptr, evKf = nullptr,
                       evQg = nullptr, evFA1 = nullptr, evAO = nullptr, evExp = nullptr;
    if (s1 == nullptr) {
        cudaStreamCreateWithFlags(&s1, cudaStreamNonBlocking);
        cudaEventCreateWithFlags(&evFork, cudaEventDisableTiming);
        cudaEventCreateWithFlags(&evImp, cudaEventDisableTiming);
        cudaEventCreateWithFlags(&evAfr, cudaEventDisableTiming);
        cudaEventCreateWithFlags(&evVf, cudaEventDisableTiming);
        cudaEventCreateWithFlags(&evK, cudaEventDisableTiming);
        cudaEventCreateWithFlags(&evKf, cudaEventDisableTiming);
        cudaEventCreateWithFlags(&evQg, cudaEventDisableTiming);
        cudaEventCreateWithFlags(&evFA1, cudaEventDisableTiming);
        cudaEventCreateWithFlags(&evAO, cudaEventDisableTiming);
        cudaEventCreateWithFlags(&evExp, cudaEventDisableTiming);
    }

    // ---- fork ----
    cudaEventRecord(evFork, 0);
    cudaStreamWaitEvent(s1, evFork, 0);

    // ---- s1: importance chain ----
    imp_gemm_kernel<<<dim3(1, SEQ / 64, 8), 256, 0, s1>>>(hs, w1, pT);
    imp_logits_kernel<<<SEQ, 32, 0, s1>>>(pT, b1, w2, b2, pLg, pW);
    topk_kernel<<<1, 1024, SEQ * 8, s1>>>(pLg, pTop, pIs);
    cudaEventRecord(evImp, s1);

    // ---- s1: V path (linear sketch of hs + top-k gather of hs -> small V GEMM) ----
    sketchA_kernel<<<dim3(16, 32), DH, 0, s1>>>(hs, 16, 0, pW, pIs, 1, kb, pPh);
    sketchB_kernel<<<dim3(16, 32), DH, 0, s1>>>(pPh, 16, ka, sscale, pHSr, 3);
    convA_kernel<<<dim3(HID / 16, 16), 256, 0, s1>>>(hs, pTop, pAfr2, HID);
    convA_kernel<<<dim3(HID / 16, 5), 256, 0, s1>>>(pHSr, nullptr, pAfr2b, HID);
    convB_kernel<<<dim3(HID / 16, 512 / 128), 256, 0, s1>>>(wv, pBwv, HID, 512, 0);
    mma_gemm_kernel<<<dim3(512 / 128, NQF / 128), 256, 0, s1>>>(
        pAfr2, pBwv, pVfr, nullptr, nullptr, 0, pVfr, 512, HID);
    cudaEventRecord(evVf, s1);

    // ---- default: Q projection chain ----
    convA_kernel<<<dim3(HID / 16, SEQ / 128), 256>>>(hs, nullptr, pAfr, HID);
    cudaEventRecord(evAfr, 0);
    convB_kernel<<<dim3(HID / 16, HID / 128), 256>>>(wq, pBfr, HID, HID, 0);
    mma_gemm_kernel<<<dim3(HID / 128, SEQ / 128), 256>>>(pAfr, pBfr, pQ, nullptr, qnw, 16, nullptr, HID, HID);

    // ---- s1: K projection (concurrent with wq GEMM) + k-sketch ----
    convB_kernel<<<dim3(HID / 16, 512 / 128), 256, 0, s1>>>(wk, pBwk, HID, 512, 0);
    cudaStreamWaitEvent(s1, evAfr, 0);
    mma_gemm_kernel<<<dim3(512 / 128, SEQ / 128), 256, 0, s1>>>(
        pAfr, pBwk, pK, nullptr, knw, 4, nullptr, 512, HID);
    cudaEventRecord(evK, s1);
    sketchA_kernel<<<dim3(NKV, 32), DH, 0, s1>>>(pK, 4, 0, pW, pIs, 1, kb, pPk);
    sketchB_kernel<<<dim3(NKV, 32), DH, 0, s1>>>(pPk, NKV, ka, sscale, pKfr, 1);
    cudaEventRecord(evKf, s1);
    convB_kernel<<<dim3(HID / 16, HID / 128), 256, 0, s1>>>(wo, pBwo, HID, HID, 0);

    // ---- default: q sketch + gather (needs topk + normalized k) ----
    cudaStreamWaitEvent(0, evImp, 0);
    sketchA_kernel<<<dim3(NH, 32), DH>>>(pQ, 16, 0, pW, pIs, 0, kb, pPq);
    sketchB_kernel<<<dim3(NH, 32), DH>>>(pPq, NH, ka, sscale, pQfr, 0);
    cudaStreamWaitEvent(0, evK, 0);
    gather_rope_kernel<<<dim3(TK, 20), DH>>>(pQ, pK, cosb, sinb, pTop, pQfr, pKfr);
    cudaEventRecord(evQg, 0);

    // ---- attention: split-KV x2 + combine ----
    cudaStreamWaitEvent(0, evKf, 0);
    cudaStreamWaitEvent(0, evVf, 0);
    cudaStreamWaitEvent(s1, evQg, 0);
    fa_mma_kernel<<<dim3(NQT, NH), 256, FA2_SMEM>>>(pQfr, pKfr, pVfr, pAO, pML, 0);
    fa_mma_kernel<<<dim3(NQT, NH), 256, FA2_SMEM, s1>>>(pQfr, pKfr, pVfr, pAO2, pML2, KSPL);
    cudaEventRecord(evFA1, s1);
    cudaStreamWaitEvent(0, evFA1, 0);
    fa_combine_kernel<<<dim3(NQF, NH), DH>>>(pAO, pAO2, pML);

    // ---- epilogue ----
    convA_kernel<<<dim3(HID / 16, NQF / 128), 256>>>(pAO, nullptr, pAfr, HID);
    cudaEventRecord(evAO, 0);
    cudaStreamWaitEvent(s1, evAO, 0);
    mma_gemm_kernel<<<dim3(HID / 128, SK / 128), 256, 0, s1>>>(
        pAfr + (size_t)16 * (HID / 16) * 2048, pBwo, pZ, nullptr, nullptr, 0, nullptr, HID, HID);
    expandC_kernel<<<dim3(HID / 256, 32), 256, 0, s1>>>(pZ, ka, pE1);
    expandD_kernel<<<dim3(HID / 128, 32), DH, 0, s1>>>(pE1, kb, pIs, out);
    cudaEventRecord(evExp, s1);
    mma_gemm_kernel<<<dim3(HID / 128, TK / 128), 256>>>(pAfr, pBwo, out, pTop, nullptr, 0, nullptr, HID, HID);

    // ---- join ----
    cudaStreamWaitEvent(0, evExp, 0);
}

// round 12
// speedup vs baseline: 5.0298x; 1.0639x over previous
#include <cuda_runtime.h>
#include <cuda_bf16.h>
#include <math.h>
#include <cstdint>

// Problem constants
#define SEQ   8192
#define HID   2048
#define NH    16
#define NKV   4
#define DH    128
#define TK    2048
#define SK    640
#define NQF   (TK + SK)        // 2688
#define NQT   (NQF / 128)      // 21 q tiles
#define NKT   (NQF / 64)       // 42 key tiles
#define KSPL  21               // key tiles per split (2 splits)
#define ATT_SCALE 0.08838834764831843f   // 1/sqrt(128)

// ---------------- scratch (device globals; no allocation) ----------------
__device__ float g_T[8 * SEQ * 64];
__device__ float g_logits[SEQ];
__device__ float g_weights[SEQ];
__device__ float g_q[SEQ * NH * DH];       // normalized q
__device__ float g_k[SEQ * 512];           // normalized k (4 heads x 128)
__device__ int   g_topk[TK];
__device__ int   g_istop[SEQ];
__device__ float g_Pq[NH * 32 * 32 * DH];  // q-sketch stage-A scratch
__device__ float g_Pk[NKV * 32 * 32 * DH]; // k-sketch stage-A scratch
__device__ float g_Ph[16 * 32 * 32 * DH];  // hs-sketch stage-A scratch
__device__ float g_HSr[SK * HID];          // rest-weighted hs sketch rows
__device__ float g_Qfr[NH * NQT * 16 * 8 * 32 * 4];
__device__ float g_Kfr[NKV * NKT * 16 * 8 * 32 * 2];
__device__ float g_Vfr[NKV * NKT * 8 * 16 * 32 * 2];
__device__ float g_AO[NQF * NH * DH];      // split-0 partial, then combined AO
__device__ float g_AO2[NQF * NH * DH];     // split-1 partial
__device__ float g_ML[2 * NQF * NH * 2];
__device__ float g_E1[32 * 32 * HID];
__device__ float g_Z[SK * HID];
__device__ float g_Afr[SEQ * HID];         // A fragments (hs, later AO)
__device__ float g_Afr2[NQF * HID];        // A fragments for V GEMM (topk hs | HSr)
__device__ float g_Bfr[40 * 128 * 2048];   // wq[0:16) | wk[16:20) | wv[20:24) | wo[24:40)

// ======================= tf32 mma.sync helpers =======================
__device__ __forceinline__ float tf32f(float x) {
    uint32_t r; asm("cvt.rna.tf32.f32 %0, %1;" : "=r"(r) : "f"(x));
    return __uint_as_float(r);
}

__device__ __forceinline__ void mma_tf32(float* c, const uint32_t* a, const uint32_t* b) {
    asm volatile("mma.sync.aligned.m16n8k8.row.col.f32.tf32.tf32.f32 "
        "{%0,%1,%2,%3}, {%4,%5,%6,%7}, {%8,%9}, {%0,%1,%2,%3};"
        : "+f"(c[0]), "+f"(c[1]), "+f"(c[2]), "+f"(c[3])
        : "r"(a[0]), "r"(a[1]), "r"(a[2]), "r"(a[3]), "r"(b[0]), "r"(b[1]));
}

#define CP_ASYNC16(dst_u32, src_ptr) \
    asm volatile("cp.async.cg.shared.global [%0], [%1], 16;" :: "r"(dst_u32), "l"(src_ptr))
#define CP_COMMIT() asm volatile("cp.async.commit_group;")

__device__ __forceinline__ void store_qfrag(float* Qg, int h, int tok, int d, float v) {
    int qt = tok >> 7, m = tok & 127;
    int k8 = d >> 3, mf = m >> 4;
    int lane = ((m & 7) << 2) | (d & 3);
    int reg = 2 * ((d & 7) >= 4) + ((m & 15) >= 8);
    size_t idx = ((((size_t)(h * NQT + qt) * 16 + k8) * 8 + mf) * 32 + lane) * 4 + reg;
    Qg[idx] = tf32f(v);
}
__device__ __forceinline__ void store_kfrag(float* Kg, int kvh, int tok, int d, float v) {
    int kt = tok >> 6, key = tok & 63;
    int k8 = d >> 3, nf = key >> 3;
    int lane = ((key & 7) << 2) | (d & 3);
    int reg = ((d & 7) >= 4);
    size_t idx = ((((size_t)(kvh * NKT + kt) * 16 + k8) * 8 + nf) * 32 + lane) * 2 + reg;
    Kg[idx] = tf32f(v);
}
__device__ __forceinline__ void store_vfrag(float* Vg, int kvh, int tok, int d, float v) {
    int kt = tok >> 6, key = tok & 63;
    int k8 = key >> 3, nf = d >> 3;
    int lane = ((d & 7) << 2) | (key & 3);
    int reg = ((key & 7) >= 4);
    size_t idx = ((((size_t)(kvh * NKT + kt) * 8 + k8) * 16 + nf) * 32 + lane) * 2 + reg;
    Vg[idx] = tf32f(v);
}

// ======================= fragment conversion pre-passes =======================
__global__ void __launch_bounds__(256) convA_kernel(const float* __restrict__ A,
                                                    const int* __restrict__ remap,
                                                    float* __restrict__ Afr, int K) {
    __shared__ float sm[2048];
    const int rt = blockIdx.y, c = blockIdx.x;
    const int tid = threadIdx.x;
#pragma unroll
    for (int i = 0; i < 2; i++) {
        int f = tid + i * 256;
        int r = f >> 2, c4 = f & 3;
        int act = remap ? __ldg(&remap[rt * 128 + r]) : (rt * 128 + r);
        float4 v = *reinterpret_cast<const float4*>(A + (size_t)act * K + c * 16 + c4 * 4);
        int mf = r >> 4, gid = r & 7, mhi = (r >> 3) & 1;
        float vv[4] = {v.x, v.y, v.z, v.w};
#pragma unroll
        for (int j = 0; j < 4; j++) {
            int k = c4 * 4 + j;
            int slot = ((k >> 3) * 8 + mf) * 128 + ((gid << 2) | (k & 3)) * 4
                     + 2 * ((k & 7) >= 4) + mhi;
            sm[slot] = tf32f(vv[j]);
        }
    }
    __syncthreads();
    float4* out = reinterpret_cast<float4*>(Afr + ((size_t)(rt * (K >> 4) + c)) * 2048);
    const float4* s4 = reinterpret_cast<const float4*>(sm);
#pragma unroll
    for (int i = 0; i < 2; i++) out[tid + i * 256] = s4[tid + i * 256];
}

__global__ void __launch_bounds__(256) convB_kernel(const float* __restrict__ B,
                                                    float* __restrict__ Bfr, int K, int N,
                                                    int ctbase) {
    __shared__ float sm[2048];
    const int ct = blockIdx.y + ctbase, c = blockIdx.x;
    const int tid = threadIdx.x;
    const float* Bb = B + ((size_t)(c * 16)) * N + blockIdx.y * 128;
#pragma unroll
    for (int i = 0; i < 2; i++) {
        int f = tid + i * 256;
        int kk = f >> 5, n4 = f & 31;
        float4 v = *reinterpret_cast<const float4*>(Bb + (size_t)kk * N + n4 * 4);
        int k8in = kk >> 3, reg = ((kk & 7) >= 4);
        float vv[4] = {v.x, v.y, v.z, v.w};
#pragma unroll
        for (int j = 0; j < 4; j++) {
            int n = n4 * 4 + j;
            int slot = (k8in * 16 + (n >> 3)) * 64 + (((n & 7) << 2) | (kk & 3)) * 2 + reg;
            sm[slot] = tf32f(vv[j]);
        }
    }
    __syncthreads();
    float4* out = reinterpret_cast<float4*>(Bfr + ((size_t)(ct * (K >> 4) + c)) * 2048);
    const float4* s4 = reinterpret_cast<const float4*>(sm);
#pragma unroll
    for (int i = 0; i < 2; i++) out[tid + i * 256] = s4[tid + i * 256];
}

// ======= tf32 GEMM: 128x128, cp.async 3-stage, 2 CTA/SM; optional rmsnorm / remap /
//         vfrag-epilogue ===
__global__ void __launch_bounds__(256, 2) mma_gemm_kernel(
    const float* __restrict__ Afr, const float* __restrict__ Bfr,
    float* __restrict__ C, const int* __restrict__ remap,
    const float* __restrict__ normw, int normct, float* __restrict__ vfr,
    int N, int K)
{
    __shared__ float sA[3][2048];
    __shared__ float sB[3][2048];

    const int tid = threadIdx.x;
    const int lane = tid & 31, wid = tid >> 5;
    const int wm = wid >> 2, wn = wid & 3;
    const int NCH = K >> 4;

    const float4* Ag = reinterpret_cast<const float4*>(Afr) + (size_t)blockIdx.y * NCH * 512;
    const float4* Bg = reinterpret_cast<const float4*>(Bfr) + (size_t)blockIdx.x * NCH * 512;

    const uint32_t sAu = (uint32_t)__cvta_generic_to_shared(&sA[0][0]) + tid * 16;
    const uint32_t sBu = (uint32_t)__cvta_generic_to_shared(&sB[0][0]) + tid * 16;

    {
        const float4* ga = Ag + tid;  const float4* gb = Bg + tid;
        CP_ASYNC16(sAu, ga); CP_ASYNC16(sAu + 4096, ga + 256);
        CP_ASYNC16(sBu, gb); CP_ASYNC16(sBu + 4096, gb + 256);
        CP_COMMIT();
        if (NCH > 1) {
            ga += 512; gb += 512;
            CP_ASYNC16(sAu + 8192, ga); CP_ASYNC16(sAu + 8192 + 4096, ga + 256);
            CP_ASYNC16(sBu + 8192, gb); CP_ASYNC16(sBu + 8192 + 4096, gb + 256);
            CP_COMMIT();
        }
    }

    float acc[4][4][4] = {};
    for (int c = 0; c < NCH; c++) {
        if (c + 1 < NCH) asm volatile("cp.async.wait_group 1;");
        else             asm volatile("cp.async.wait_group 0;");
        __syncthreads();

        const int buf = c % 3;
        const float4* A4 = reinterpret_cast<const float4*>(sA[buf]);
        const float2* B2 = reinterpret_cast<const float2*>(sB[buf]);
#pragma unroll
        for (int k8 = 0; k8 < 2; k8++) {
            float4 af[4];
            float2 bf[4];
#pragma unroll
            for (int mf = 0; mf < 4; mf++)
                af[mf] = A4[(k8 * 8 + wm * 4 + mf) * 32 + lane];
#pragma unroll
            for (int nf = 0; nf < 4; nf++)
                bf[nf] = B2[(k8 * 16 + wn * 4 + nf) * 32 + lane];
#pragma unroll
            for (int mf = 0; mf < 4; mf++)
#pragma unroll
                for (int nf = 0; nf < 4; nf++)
                    mma_tf32(acc[mf][nf],
                             reinterpret_cast<const uint32_t*>(&af[mf]),
                             reinterpret_cast<const uint32_t*>(&bf[nf]));
        }
        if (c + 2 < NCH) {
            const int st = (c + 2) % 3;
            const float4* ga = Ag + (c + 2) * 512 + tid;
            const float4* gb = Bg + (c + 2) * 512 + tid;
            CP_ASYNC16(sAu + st * 8192, ga); CP_ASYNC16(sAu + st * 8192 + 4096, ga + 256);
            CP_ASYNC16(sBu + st * 8192, gb); CP_ASYNC16(sBu + st * 8192 + 4096, gb + 256);
            CP_COMMIT();
        }
    }

    const int gid = lane >> 2, tig = lane & 3;
    const int row0 = blockIdx.y * 128;
    const int col0 = blockIdx.x * 128;

    if (vfr != nullptr) {
#pragma unroll
        for (int mf = 0; mf < 4; mf++) {
            int m = row0 + wm * 64 + mf * 16 + gid;
#pragma unroll
            for (int nf = 0; nf < 4; nf++) {
                int n = col0 + wn * 32 + nf * 8 + tig * 2;
                store_vfrag(vfr, n >> 7, m, n & 127, acc[mf][nf][0]);
                store_vfrag(vfr, (n + 1) >> 7, m, (n + 1) & 127, acc[mf][nf][1]);
                store_vfrag(vfr, n >> 7, m + 8, n & 127, acc[mf][nf][2]);
                store_vfrag(vfr, (n + 1) >> 7, m + 8, (n + 1) & 127, acc[mf][nf][3]);
            }
        }
        return;
    }

    if (normw != nullptr && blockIdx.x < normct) {
        float* ssm = &sA[0][0];
        __syncthreads();
        float ss0[4], ss1[4];
#pragma unroll
        for (int mf = 0; mf < 4; mf++) {
            float s0 = 0.f, s1 = 0.f;
#pragma unroll
            for (int nf = 0; nf < 4; nf++) {
                s0 += acc[mf][nf][0] * acc[mf][nf][0] + acc[mf][nf][1] * acc[mf][nf][1];
                s1 += acc[mf][nf][2] * acc[mf][nf][2] + acc[mf][nf][3] * acc[mf][nf][3];
            }
            s0 += __shfl_xor_sync(0xffffffffu, s0, 1);
            s0 += __shfl_xor_sync(0xffffffffu, s0, 2);
            s1 += __shfl_xor_sync(0xffffffffu, s1, 1);
            s1 += __shfl_xor_sync(0xffffffffu, s1, 2);
            ss0[mf] = s0; ss1[mf] = s1;
        }
        if (tig == 0) {
#pragma unroll
            for (int mf = 0; mf < 4; mf++) {
                int r = wm * 64 + mf * 16 + gid;
                ssm[r * 4 + wn] = ss0[mf];
                ssm[(r + 8) * 4 + wn] = ss1[mf];
            }
        }
        __syncthreads();
#pragma unroll
        for (int mf = 0; mf < 4; mf++) {
            int r = wm * 64 + mf * 16 + gid;
            float t0 = ssm[r * 4] + ssm[r * 4 + 1] + ssm[r * 4 + 2] + ssm[r * 4 + 3];
            float t1 = ssm[(r + 8) * 4] + ssm[(r + 8) * 4 + 1]
                     + ssm[(r + 8) * 4 + 2] + ssm[(r + 8) * 4 + 3];
            float sc0 = rsqrtf(t0 * (1.0f / 128.0f) + 1e-6f);
            float sc1 = rsqrtf(t1 * (1.0f / 128.0f) + 1e-6f);
#pragma unroll
            for (int nf = 0; nf < 4; nf++) {
                int n = wn * 32 + nf * 8 + tig * 2;
                float w0 = __ldg(&normw[n]), w1 = __ldg(&normw[n + 1]);
                acc[mf][nf][0] *= sc0 * w0; acc[mf][nf][1] *= sc0 * w1;
                acc[mf][nf][2] *= sc1 * w0; acc[mf][nf][3] *= sc1 * w1;
            }
        }
    }

#pragma unroll
    for (int mf = 0; mf < 4; mf++) {
        int m = row0 + wm * 64 + mf * 16 + gid;
        int m1 = remap ? __ldg(&remap[m]) : m;
        int m2 = remap ? __ldg(&remap[m + 8]) : (m + 8);
#pragma unroll
        for (int nf = 0; nf < 4; nf++) {
            int n = col0 + wn * 32 + nf * 8 + tig * 2;
            *reinterpret_cast<float2*>(&C[(size_t)m1 * N + n]) =
                make_float2(acc[mf][nf][0], acc[mf][nf][1]);
            *reinterpret_cast<float2*>(&C[(size_t)m2 * N + n]) =
                make_float2(acc[mf][nf][2], acc[mf][nf][3]);
        }
    }
}

// ---------------- importance GEMM: fp32 split-K x8 ----------------
__global__ void __launch_bounds__(256) imp_gemm_kernel(
    const float* __restrict__ A, const float* __restrict__ B, float* __restrict__ Cp)
{
    __shared__ float As[16][64];
    __shared__ float Bs[16][64];
    const int tid = threadIdx.x;
    const int row0 = blockIdx.y * 64;
    const int z = blockIdx.z;
    const float* Ab = A + (size_t)row0 * HID + z * 256;
    const float* Bb = B + (size_t)z * 256 * 64;
    float acc[4][4] = {};
    const int tc = (tid & 15) * 4, tr = (tid >> 4) * 4;
    const int ar = tid >> 2, ac = (tid & 3) * 4;
    const int br = tid >> 4, bc = (tid & 15) * 4;

    for (int k0 = 0; k0 < 256; k0 += 16) {
        float4 va = *reinterpret_cast<const float4*>(Ab + (size_t)ar * HID + k0 + ac);
        As[ac + 0][ar] = va.x; As[ac + 1][ar] = va.y;
        As[ac + 2][ar] = va.z; As[ac + 3][ar] = va.w;
        float4 vb = *reinterpret_cast<const float4*>(Bb + (size_t)(k0 + br) * 64 + bc);
        *reinterpret_cast<float4*>(&Bs[br][bc]) = vb;
        __syncthreads();
#pragma unroll
        for (int k = 0; k < 16; k++) {
            float ra[4], rb[4];
#pragma unroll
            for (int m = 0; m < 4; m++) ra[m] = As[k][tr + m];
#pragma unroll
            for (int n = 0; n < 4; n++) rb[n] = Bs[k][tc + n];
#pragma unroll
            for (int m = 0; m < 4; m++)
#pragma unroll
                for (int n = 0; n < 4; n++) acc[m][n] += ra[m] * rb[n];
        }
        __syncthreads();
    }
#pragma unroll
    for (int m = 0; m < 4; m++) {
        float4 v = make_float4(acc[m][0], acc[m][1], acc[m][2], acc[m][3]);
        *reinterpret_cast<float4*>(&Cp[((size_t)z * SEQ + row0 + tr + m) * 64 + tc]) = v;
    }
}

// ---------------- importance logits epilogue ----------------
__global__ void imp_logits_kernel(const float* __restrict__ T, const float* __restrict__ b1,
                                  const float* __restrict__ w2, const float* __restrict__ b2,
                                  float* __restrict__ logits, float* __restrict__ weights) {
    const float LOG_ADJ = 2.5494451709255714f;
    int s = blockIdx.x;
    int j = threadIdx.x;
    float v1 = 0.f, v2 = 0.f;
#pragma unroll
    for (int z = 0; z < 8; z++) {
        v1 += T[((size_t)z * SEQ + s) * 64 + j];
        v2 += T[((size_t)z * SEQ + s) * 64 + j + 32];
    }
    float v = tanhf(v1 + b1[j]) * w2[j] + tanhf(v2 + b1[j + 32]) * w2[j + 32];
#pragma unroll
    for (int o = 16; o > 0; o >>= 1) v += __shfl_xor_sync(0xffffffffu, v, o);
    if (j == 0) {
        float lg = v + b2[0] - LOG_ADJ;
        logits[s] = lg;
        weights[s] = 1.0f / (1.0f + expf(-lg));
    }
}

// ---------------- top-k via single-block bitonic sort ----------------
__global__ void topk_kernel(const float* __restrict__ logits,
                            int* __restrict__ topk_list, int* __restrict__ is_topk) {
    extern __shared__ unsigned long long skeys[];
    int tid = threadIdx.x;
    for (int i = tid; i < SEQ; i += 1024) {
        unsigned u = __float_as_uint(logits[i]);
        u = (u & 0x80000000u) ? ~u : (u | 0x80000000u);
        skeys[i] = ((unsigned long long)(~u) << 32) | (unsigned)i;
        is_topk[i] = 0;
    }
    __syncthreads();
    for (int k = 2; k <= SEQ; k <<= 1) {
        for (int j = k >> 1; j > 0; j >>= 1) {
            for (int i = tid; i < SEQ; i += 1024) {
                int ixj = i ^ j;
                if (ixj > i) {
                    bool up = ((i & k) == 0);
                    unsigned long long a = skeys[i], b = skeys[ixj];
                    if ((a > b) == up) { skeys[i] = b; skeys[ixj] = a; }
                }
            }
            __syncthreads();
        }
    }
    for (int i = tid; i < TK; i += 1024) {
        int pos = (int)(skeys[i] & 0xffffffffu);
        topk_list[i] = pos;
        is_topk[pos] = 1;
    }
}

// ---------------- sketch stage A (kbo-split x2 for occupancy) ----------------
__global__ void sketchA_kernel(const float* __restrict__ X, int hstride, int hbase,
                               const float* __restrict__ weights,
                               const int* __restrict__ is_topk, int rest,
                               const float* __restrict__ kb, float* __restrict__ P) {
    int h = blockIdx.x;
    int ib = blockIdx.y;
    int z = blockIdx.z;          // kbo half: 0 -> [0,16), 1 -> [16,32)
    int d = threadIdx.x;
    __shared__ float kbs[16 * 256];
    for (int t = d; t < 16 * 256; t += 128) kbs[t] = kb[z * 16 * 256 + t];
    __shared__ float ws[256];
    for (int j = d; j < 256; j += 128) {
        int t = ib * 256 + j;
        float w = weights[t];
        if (rest && is_topk[t]) w = 0.0f;
        ws[j] = w;
    }
    __syncthreads();
    float acc[16] = {};
    for (int j = 0; j < 256; j++) {
        float xv = X[((size_t)(ib * 256 + j) * hstride + hbase + h) * DH + d] * ws[j];
#pragma unroll
        for (int kbo = 0; kbo < 16; kbo++) acc[kbo] += xv * kbs[kbo * 256 + j];
    }
#pragma unroll
    for (int kbo = 0; kbo < 16; kbo++)
        P[(((size_t)h * 32 + z * 16 + kbo) * 32 + ib) * DH + d] = acc[kbo];
}

// ---------------- sketch stage B; mode: 0=qfrag,1=kfrag,3=dense ----------------
__global__ void sketchB_kernel(const float* __restrict__ P, int heads,
                               const float* __restrict__ ka,
                               const float* __restrict__ scale_p,
                               float* __restrict__ dst, int mode) {
    int h = blockIdx.x;
    int kbo = blockIdx.y;
    int d = threadIdx.x;
    __shared__ float kas[20 * 32];
    for (int t = d; t < 20 * 32; t += 128) kas[t] = ka[(t / 32) * DH + (t % 32)];
    __syncthreads();
    float p[32];
#pragma unroll
    for (int i = 0; i < 32; i++) p[i] = P[(((size_t)h * 32 + kbo) * 32 + i) * DH + d];
    float scale = scale_p[0];
    if (mode == 0) scale *= ATT_SCALE;
#pragma unroll
    for (int kao = 0; kao < 20; kao++) {
        float acc = 0.f;
#pragma unroll
        for (int i = 0; i < 32; i++) acc += p[i] * kas[kao * 32 + i];
        int s = TK + kbo * 20 + kao;
        float val = acc * scale;
        if (mode == 0)      store_qfrag(dst, h, s, d, val);
        else if (mode == 1) store_kfrag(dst, h, s, d, val);
        else                dst[(size_t)(s - TK) * (heads * DH) + h * DH + d] = val;
    }
}

// ---------------- gather + RoPE (q and k only) ----------------
__global__ void gather_rope_kernel(const float* __restrict__ q, const float* __restrict__ k,
                                   const float* __restrict__ cosb, const float* __restrict__ sinb,
                                   const int* __restrict__ topk_list,
                                   float* __restrict__ Qfr, float* __restrict__ Kfr) {
    int j = blockIdx.x;
    int hy = blockIdx.y;   // 0..19
    int d = threadIdx.x;
    int pos = topk_list[j];
    float c = cosb[(size_t)pos * DH + d];
    float s = sinb[(size_t)pos * DH + d];
    if (hy < 16) {
        const float* src = q + ((size_t)pos * NH + hy) * DH;
        float x = src[d];
        float r = (d < 64) ? -src[d + 64] : src[d - 64];
        store_qfrag(Qfr, hy, j, d, (x * c + r * s) * ATT_SCALE);
    } else {
        int h = hy - 16;
        const float* src = k + (size_t)pos * 512 + h * DH;
        float x = src[d];
        float r = (d < 64) ? -src[d + 64] : src[d - 64];
        store_kfrag(Kfr, h, j, d, x * c + r * s);
    }
}

// ---------------- tensor-core flash attention (split-KV, cp.async K/V) -------
#define FA2_SMEM ((16384 + 2*8192 + 2*8192 + 512) * 4)
__global__ void __launch_bounds__(256, 1) fa_mma_kernel(
    const float* __restrict__ Qfr, const float* __restrict__ Kfr,
    const float* __restrict__ Vfr, float* __restrict__ Op,
    float* __restrict__ ML, int kt0)
{
    extern __shared__ float fsm[];
    float* Qsm = fsm;
    float* Ksm = fsm + 16384;
    float* Vsm = fsm + 32768;
    float* mpart = fsm + 49152;
    float* spart = fsm + 49408;

    const int qt = blockIdx.x;
    const int h  = blockIdx.y;
    const int kvh = h >> 2;
    const int tid = threadIdx.x;
    const int lane = tid & 31, wid = tid >> 5;
    const int wm = wid >> 1, wn = wid & 1;
    const int gid = lane >> 2, tig = lane & 3;

    const uint32_t ksmU = (uint32_t)__cvta_generic_to_shared(Ksm) + tid * 16;
    const uint32_t vsmU = (uint32_t)__cvta_generic_to_shared(Vsm) + tid * 16;

    {
        const float4* Kg = reinterpret_cast<const float4*>(Kfr + (size_t)(kvh * NKT + kt0) * 8192);
        const float4* Vg = reinterpret_cast<const float4*>(Vfr + (size_t)(kvh * NKT + kt0) * 8192);
#pragma unroll
        for (int i = 0; i < 8; i++) {
            CP_ASYNC16(ksmU + i * 4096, Kg + tid + i * 256);
            CP_ASYNC16(vsmU + i * 4096, Vg + tid + i * 256);
        }
        CP_COMMIT();
    }

    {
        const float4* Qg = reinterpret_cast<const float4*>(Qfr + (size_t)(h * NQT + qt) * 16384);
        float4* Qs4w = reinterpret_cast<float4*>(Qsm);
#pragma unroll
        for (int i = 0; i < 16; i++) Qs4w[tid + i * 256] = Qg[tid + i * 256];
    }

    float m_old[2][2], l_run[2][2];
#pragma unroll
    for (int a = 0; a < 2; a++)
#pragma unroll
        for (int b = 0; b < 2; b++) { m_old[a][b] = -1e30f; l_run[a][b] = 0.f; }
    float oacc[2][8][4] = {};

    const float4* Qs4 = reinterpret_cast<const float4*>(Qsm);

    for (int t = 0; t < KSPL; t++) {
        const int buf = t & 1;
        if (t + 1 < KSPL) {
            const float4* Kg = reinterpret_cast<const float4*>(Kfr + (size_t)(kvh * NKT + kt0 + t + 1) * 8192);
            const float4* Vg = reinterpret_cast<const float4*>(Vfr + (size_t)(kvh * NKT + kt0 + t + 1) * 8192);
            const uint32_t kd = ksmU + (1 - buf) * 32768;
            const uint32_t vd = vsmU + (1 - buf) * 32768;
#pragma unroll
            for (int i = 0; i < 8; i++) {
                CP_ASYNC16(kd + i * 4096, Kg + tid + i * 256);
                CP_ASYNC16(vd + i * 4096, Vg + tid + i * 256);
            }
            CP_COMMIT();
            asm volatile("cp.async.wait_group 1;");
        } else {
            asm volatile("cp.async.wait_group 0;");
        }
        __syncthreads();

        const float2* Ks2 = reinterpret_cast<const float2*>(Ksm + buf * 8192);
        const float2* Vs2 = reinterpret_cast<const float2*>(Vsm + buf * 8192);
        float* Psm = Ksm + buf * 8192;
        const float4* Ps4 = reinterpret_cast<const float4*>(Psm);

        float sacc[2][4][4] = {};
#pragma unroll
        for (int k8 = 0; k8 < 16; k8++) {
            float4 af[2];
            float2 bf[4];
            af[0] = Qs4[(k8 * 8 + wm * 2 + 0) * 32 + lane];
            af[1] = Qs4[(k8 * 8 + wm * 2 + 1) * 32 + lane];
#pragma unroll
            for (int nf = 0; nf < 4; nf++) bf[nf] = Ks2[(k8 * 8 + wn * 4 + nf) * 32 + lane];
#pragma unroll
            for (int mf = 0; mf < 2; mf++)
#pragma unroll
                for (int nf = 0; nf < 4; nf++)
                    mma_tf32(sacc[mf][nf],
                             reinterpret_cast<const uint32_t*>(&af[mf]),
                             reinterpret_cast<const uint32_t*>(&bf[nf]));
        }

        float mloc[2][2];
#pragma unroll
        for (int mf = 0; mf < 2; mf++) {
            float m0 = fmaxf(sacc[mf][0][0], sacc[mf][0][1]);
            float m1 = fmaxf(sacc[mf][0][2], sacc[mf][0][3]);
#pragma unroll
            for (int nf = 1; nf < 4; nf++) {
                m0 = fmaxf(m0, fmaxf(sacc[mf][nf][0], sacc[mf][nf][1]));
                m1 = fmaxf(m1, fmaxf(sacc[mf][nf][2], sacc[mf][nf][3]));
            }
            m0 = fmaxf(m0, __shfl_xor_sync(0xffffffffu, m0, 1));
            m0 = fmaxf(m0, __shfl_xor_sync(0xffffffffu, m0, 2));
            m1 = fmaxf(m1, __shfl_xor_sync(0xffffffffu, m1, 1));
            m1 = fmaxf(m1, __shfl_xor_sync(0xffffffffu, m1, 2));
            mloc[mf][0] = m0; mloc[mf][1] = m1;
        }
        if (tig == 0) {
#pragma unroll
            for (int mf = 0; mf < 2; mf++) {
                int r = wm * 32 + mf * 16 + gid;
                mpart[wn * 128 + r] = mloc[mf][0];
                mpart[wn * 128 + r + 8] = mloc[mf][1];
            }
        }
        __syncthreads();

        float mnew[2][2], corr[2][2];
#pragma unroll
        for (int mf = 0; mf < 2; mf++)
#pragma unroll
            for (int hi = 0; hi < 2; hi++) {
                int r = wm * 32 + mf * 16 + gid + hi * 8;
                float mt = fmaxf(mpart[r], mpart[128 + r]);
                float mn = fmaxf(m_old[mf][hi], mt);
                corr[mf][hi] = __expf(m_old[mf][hi] - mn);
                mnew[mf][hi] = mn;
                m_old[mf][hi] = mn;
            }

        float sloc[2][2] = {};
#pragma unroll
        for (int mf = 0; mf < 2; mf++)
#pragma unroll
            for (int nf = 0; nf < 4; nf++) {
                sacc[mf][nf][0] = __expf(sacc[mf][nf][0] - mnew[mf][0]);
                sacc[mf][nf][1] = __expf(sacc[mf][nf][1] - mnew[mf][0]);
                sacc[mf][nf][2] = __expf(sacc[mf][nf][2] - mnew[mf][1]);
                sacc[mf][nf][3] = __expf(sacc[mf][nf][3] - mnew[mf][1]);
                sloc[mf][0] += sacc[mf][nf][0] + sacc[mf][nf][1];
                sloc[mf][1] += sacc[mf][nf][2] + sacc[mf][nf][3];
            }
#pragma unroll
        for (int mf = 0; mf < 2; mf++) {
            sloc[mf][0] += __shfl_xor_sync(0xffffffffu, sloc[mf][0], 1);
            sloc[mf][0] += __shfl_xor_sync(0xffffffffu, sloc[mf][0], 2);
            sloc[mf][1] += __shfl_xor_sync(0xffffffffu, sloc[mf][1], 1);
            sloc[mf][1] += __shfl_xor_sync(0xffffffffu, sloc[mf][1], 2);
        }
        if (tig == 0) {
#pragma unroll
            for (int mf = 0; mf < 2; mf++) {
                int r = wm * 32 + mf * 16 + gid;
                spart[wn * 128 + r] = sloc[mf][0];
                spart[wn * 128 + r + 8] = sloc[mf][1];
            }
        }

#pragma unroll
        for (int mf = 0; mf < 2; mf++)
#pragma unroll
            for (int nf = 0; nf < 4; nf++) {
                int k8p = wn * 4 + nf;
                int mfg = wm * 2 + mf;
#pragma unroll
                for (int b = 0; b < 2; b++) {
                    int c = tig * 2 + b;
                    int khi = (c >= 4);
                    int base = ((k8p * 8 + mfg) * 32 + (gid << 2) + (c & 3)) * 4 + khi * 2;
                    *reinterpret_cast<float2*>(Psm + base) =
                        make_float2(tf32f(sacc[mf][nf][b]), tf32f(sacc[mf][nf][2 + b]));
                }
            }
        __syncthreads();

#pragma unroll
        for (int mf = 0; mf < 2; mf++)
#pragma unroll
            for (int hi = 0; hi < 2; hi++) {
                int r = wm * 32 + mf * 16 + gid + hi * 8;
                l_run[mf][hi] = l_run[mf][hi] * corr[mf][hi] + spart[r] + spart[128 + r];
            }
#pragma unroll
        for (int mf = 0; mf < 2; mf++)
#pragma unroll
            for (int nf = 0; nf < 8; nf++) {
                oacc[mf][nf][0] *= corr[mf][0]; oacc[mf][nf][1] *= corr[mf][0];
                oacc[mf][nf][2] *= corr[mf][1]; oacc[mf][nf][3] *= corr[mf][1];
            }

#pragma unroll
        for (int k8 = 0; k8 < 8; k8++) {
            float4 af[2];
            af[0] = Ps4[(k8 * 8 + wm * 2 + 0) * 32 + lane];
            af[1] = Ps4[(k8 * 8 + wm * 2 + 1) * 32 + lane];
#pragma unroll
            for (int nf = 0; nf < 8; nf++) {
                float2 bf = Vs2[(k8 * 16 + wn * 8 + nf) * 32 + lane];
#pragma unroll
                for (int mf = 0; mf < 2; mf++)
                    mma_tf32(oacc[mf][nf],
                             reinterpret_cast<const uint32_t*>(&af[mf]),
                             reinterpret_cast<const uint32_t*>(&bf));
            }
        }
        __syncthreads();
    }

#pragma unroll
    for (int mf = 0; mf < 2; mf++) {
        int r0 = qt * 128 + wm * 32 + mf * 16 + gid;
        if (wn == 0 && tig == 0) {
            size_t row0i = (size_t)r0 * NH + h;
            size_t row1i = (size_t)(r0 + 8) * NH + h;
            ML[row0i * 2] = m_old[mf][0]; ML[row0i * 2 + 1] = l_run[mf][0];
            ML[row1i * 2] = m_old[mf][1]; ML[row1i * 2 + 1] = l_run[mf][1];
        }
#pragma unroll
        for (int nf = 0; nf < 8; nf++) {
            int col = wn * 64 + nf * 8 + tig * 2;
            *reinterpret_cast<float2*>(&Op[((size_t)r0 * NH + h) * DH + col]) =
                make_float2(oacc[mf][nf][0], oacc[mf][nf][1]);
            *reinterpret_cast<float2*>(&Op[((size_t)(r0 + 8) * NH + h) * DH + col]) =
                make_float2(oacc[mf][nf][2], oacc[mf][nf][3]);
        }
    }
}

// ---------------- fa combine ----------------
__global__ void fa_combine_kernel(float* __restrict__ O0, const float* __restrict__ O1,
                                  const float* __restrict__ ML) {
    size_t row = (size_t)blockIdx.x * NH + blockIdx.y;
    int d = threadIdx.x;
    float m0 = ML[row * 2], l0 = ML[row * 2 + 1];
    float m1 = ML[(size_t)NQF * NH * 2 + row * 2], l1 = ML[(size_t)NQF * NH * 2 + row * 2 + 1];
    float m = fmaxf(m0, m1);
    float w0 = __expf(m0 - m), w1 = __expf(m1 - m);
    float inv = 1.0f / (w0 * l0 + w1 * l1);
    O0[row * DH + d] = (O0[row * DH + d] * w0 + O1[row * DH + d] * w1) * inv;
}

// ---------------- expand stage C ----------------
__global__ void expandC_kernel(const float* __restrict__ Z, const float* __restrict__ ka,
                               float* __restrict__ E1) {
    int i = blockIdx.y;
    int hd = blockIdx.x * 256 + threadIdx.x;
    __shared__ float kav[20];
    if (threadIdx.x < 20) kav[threadIdx.x] = ka[threadIdx.x * DH + i];
    __syncthreads();
    for (int kbo = 0; kbo < 32; kbo++) {
        float acc = 0.f;
#pragma unroll
        for (int kao = 0; kao < 20; kao++)
            acc += Z[((size_t)(kbo * 20 + kao)) * HID + hd] * kav[kao];
        E1[((size_t)i * 32 + kbo) * HID + hd] = acc;
    }
}

// ---------------- expand stage D ----------------
__global__ void expandD_kernel(const float* __restrict__ E1, const float* __restrict__ kb,
                               const int* __restrict__ is_topk, float* __restrict__ OUT) {
    int i = blockIdx.y;
    int hd = blockIdx.x * 128 + threadIdx.x;
    __shared__ float kbs[32 * 256];
    for (int t = threadIdx.x; t < 32 * 256; t += 128) kbs[t] = kb[t];
    float e[32];
#pragma unroll
    for (int kbo = 0; kbo < 32; kbo++) e[kbo] = E1[((size_t)i * 32 + kbo) * HID + hd];
    __syncthreads();
    for (int j = 0; j < 256; j++) {
        int row = i * 256 + j;
        if (is_topk[row]) continue;
        float acc = 0.f;
#pragma unroll
        for (int kbo = 0; kbo < 32; kbo++) acc += e[kbo] * kbs[kbo * 256 + j];
        OUT[(size_t)row * HID + hd] = acc;
    }
}

// ---------------- host launcher ----------------
extern "C" void kernel_launch(void* const* d_in, const int* in_sizes, int n_in,
                              void* d_out, int out_size) {
    const float* hs    = (const float*)d_in[0];
    const float* cosb  = (const float*)d_in[1];
    const float* sinb  = (const float*)d_in[2];
    const float* wq    = (const float*)d_in[3];
    const float* wk    = (const float*)d_in[4];
    const float* wv    = (const float*)d_in[5];
    const float* wo    = (const float*)d_in[6];
    const float* qnw   = (const float*)d_in[7];
    const float* knw   = (const float*)d_in[8];
    const float* w1    = (const float*)d_in[9];
    const float* b1    = (const float*)d_in[10];
    const float* w2    = (const float*)d_in[11];
    const float* b2    = (const float*)d_in[12];
    const float* ka    = (const float*)d_in[13];
    const float* kb    = (const float*)d_in[14];
    const float* sscale= (const float*)d_in[15];
    float* out = (float*)d_out;

    float *pT, *pLg, *pW, *pQ, *pK, *pPq, *pPk, *pPh, *pHSr, *pQfr, *pKfr, *pVfr,
          *pAO, *pAO2, *pML, *pE1, *pZ, *pAfr, *pAfr2, *pBfr;
    int *pTop, *pIs;
    cudaGetSymbolAddress((void**)&pT, g_T);
    cudaGetSymbolAddress((void**)&pLg, g_logits);
    cudaGetSymbolAddress((void**)&pW, g_weights);
    cudaGetSymbolAddress((void**)&pQ, g_q);
    cudaGetSymbolAddress((void**)&pK, g_k);
    cudaGetSymbolAddress((void**)&pPq, g_Pq);
    cudaGetSymbolAddress((void**)&pPk, g_Pk);
    cudaGetSymbolAddress((void**)&pPh, g_Ph);
    cudaGetSymbolAddress((void**)&pHSr, g_HSr);
    cudaGetSymbolAddress((void**)&pQfr, g_Qfr);
    cudaGetSymbolAddress((void**)&pKfr, g_Kfr);
    cudaGetSymbolAddress((void**)&pVfr, g_Vfr);
    cudaGetSymbolAddress((void**)&pAO, g_AO);
    cudaGetSymbolAddress((void**)&pAO2, g_AO2);
    cudaGetSymbolAddress((void**)&pML, g_ML);
    cudaGetSymbolAddress((void**)&pE1, g_E1);
    cudaGetSymbolAddress((void**)&pZ, g_Z);
    cudaGetSymbolAddress((void**)&pAfr, g_Afr);
    cudaGetSymbolAddress((void**)&pAfr2, g_Afr2);
    cudaGetSymbolAddress((void**)&pBfr, g_Bfr);
    cudaGetSymbolAddress((void**)&pTop, g_topk);
    cudaGetSymbolAddress((void**)&pIs, g_istop);

    float* pBwk = pBfr + (size_t)16 * 128 * 2048;
    float* pBwv = pBfr + (size_t)20 * 128 * 2048;
    float* pBwo = pBfr + (size_t)24 * 128 * 2048;
    float* pML2 = pML + (size_t)NQF * NH * 2;
    float* pAfr2b = pAfr2 + (size_t)16 * (HID / 16) * 2048;

    cudaFuncSetAttribute(topk_kernel, cudaFuncAttributeMaxDynamicSharedMemorySize, SEQ * 8);
    cudaFuncSetAttribute(fa_mma_kernel, cudaFuncAttributeMaxDynamicSharedMemorySize, FA2_SMEM);

    static cudaStream_t s1 = nullptr;
    static cudaEvent_t evFork = nullptr, evImp = nullptr, evAfr = nullptr,
                       evVf = nullptr, evK = nullptr, evKf = nullptr,
                       evQg = nullptr, evFA1 = nullptr, evAO = nullptr, evExp = nullptr;
    if (s1 == nullptr) {
        cudaStreamCreateWithFlags(&s1, cudaStreamNonBlocking);
        cudaEventCreateWithFlags(&evFork, cudaEventDisableTiming);
        cudaEventCreateWithFlags(&evImp, cudaEventDisableTiming);
        cudaEventCreateWithFlags(&evAfr, cudaEventDisableTiming);
        cudaEventCreateWithFlags(&evVf, cudaEventDisableTiming);
        cudaEventCreateWithFlags(&evK, cudaEventDisableTiming);
        cudaEventCreateWithFlags(&evKf, cudaEventDisableTiming);
        cudaEventCreateWithFlags(&evQg, cudaEventDisableTiming);
        cudaEventCreateWithFlags(&evFA1, cudaEventDisableTiming);
        cudaEventCreateWithFlags(&evAO, cudaEventDisableTiming);
        cudaEventCreateWithFlags(&evExp, cudaEventDisableTiming);
    }

    // ---- fork ----
    cudaEventRecord(evFork, 0);
    cudaStreamWaitEvent(s1, evFork, 0);

    // ---- s1: importance chain ----
    imp_gemm_kernel<<<dim3(1, SEQ / 64, 8), 256, 0, s1>>>(hs, w1, pT);
    imp_logits_kernel<<<SEQ, 32, 0, s1>>>(pT, b1, w2, b2, pLg, pW);
    topk_kernel<<<1, 1024, SEQ * 8, s1>>>(pLg, pTop, pIs);
    cudaEventRecord(evImp, s1);

    // ---- s1: V path (linear sketch of hs + top-k gather of hs -> small V GEMM) ----
    sketchA_kernel<<<dim3(16, 32, 2), DH, 0, s1>>>(hs, 16, 0, pW, pIs, 1, kb, pPh);
    sketchB_kernel<<<dim3(16, 32), DH, 0, s1>>>(pPh, 16, ka, sscale, pHSr, 3);
    convA_kernel<<<dim3(HID / 16, 16), 256, 0, s1>>>(hs, pTop, pAfr2, HID);
    convA_kernel<<<dim3(HID / 16, 5), 256, 0, s1>>>(pHSr, nullptr, pAfr2b, HID);
    convB_kernel<<<dim3(HID / 16, 512 / 128), 256, 0, s1>>>(wv, pBwv, HID, 512, 0);
    mma_gemm_kernel<<<dim3(512 / 128, NQF / 128), 256, 0, s1>>>(
        pAfr2, pBwv, pVfr, nullptr, nullptr, 0, pVfr, 512, HID);
    cudaEventRecord(evVf, s1);

    // ---- default: Q projection chain ----
    convA_kernel<<<dim3(HID / 16, SEQ / 128), 256>>>(hs, nullptr, pAfr, HID);
    cudaEventRecord(evAfr, 0);
    convB_kernel<<<dim3(HID / 16, HID / 128), 256>>>(wq, pBfr, HID, HID, 0);
    mma_gemm_kernel<<<dim3(HID / 128, SEQ / 128), 256>>>(pAfr, pBfr, pQ, nullptr, qnw, 16, nullptr, HID, HID);

    // ---- s1: K projection (concurrent with wq GEMM) + k-sketch ----
    convB_kernel<<<dim3(HID / 16, 512 / 128), 256, 0, s1>>>(wk, pBwk, HID, 512, 0);
    cudaStreamWaitEvent(s1, evAfr, 0);
    mma_gemm_kernel<<<dim3(512 / 128, SEQ / 128), 256, 0, s1>>>(
        pAfr, pBwk, pK, nullptr, knw, 4, nullptr, 512, HID);
    cudaEventRecord(evK, s1);
    sketchA_kernel<<<dim3(NKV, 32, 2), DH, 0, s1>>>(pK, 4, 0, pW, pIs, 1, kb, pPk);
    sketchB_kernel<<<dim3(NKV, 32), DH, 0, s1>>>(pPk, NKV, ka, sscale, pKfr, 1);
    cudaEventRecord(evKf, s1);
    convB_kernel<<<dim3(HID / 16, HID / 128), 256, 0, s1>>>(wo, pBwo, HID, HID, 0);

    // ---- default: q sketch + gather ----
    cudaStreamWaitEvent(0, evImp, 0);
    sketchA_kernel<<<dim3(NH, 32, 2), DH>>>(pQ, 16, 0, pW, pIs, 0, kb, pPq);
    sketchB_kernel<<<dim3(NH, 32), DH>>>(pPq, NH, ka, sscale, pQfr, 0);
    cudaStreamWaitEvent(0, evK, 0);
    gather_rope_kernel<<<dim3(TK, 20), DH>>>(pQ, pK, cosb, sinb, pTop, pQfr, pKfr);
    cudaEventRecord(evQg, 0);

    // ---- attention: split-KV x2 + combine ----
    cudaStreamWaitEvent(0, evKf, 0);
    cudaStreamWaitEvent(0, evVf, 0);
    cudaStreamWaitEvent(s1, evQg, 0);
    fa_mma_kernel<<<dim3(NQT, NH), 256, FA2_SMEM>>>(pQfr, pKfr, pVfr, pAO, pML, 0);
    fa_mma_kernel<<<dim3(NQT, NH), 256, FA2_SMEM, s1>>>(pQfr, pKfr, pVfr, pAO2, pML2, KSPL);
    cudaEventRecord(evFA1, s1);
    cudaStreamWaitEvent(0, evFA1, 0);
    fa_combine_kernel<<<dim3(NQF, NH), DH>>>(pAO, pAO2, pML);

    // ---- epilogue ----
    convA_kernel<<<dim3(HID / 16, NQF / 128), 256>>>(pAO, nullptr, pAfr, HID);
    cudaEventRecord(evAO, 0);
    cudaStreamWaitEvent(s1, evAO, 0);
    mma_gemm_kernel<<<dim3(HID / 128, SK / 128), 256, 0, s1>>>(
        pAfr + (size_t)16 * (HID / 16) * 2048, pBwo, pZ, nullptr, nullptr, 0, nullptr, HID, HID);
    expandC_kernel<<<dim3(HID / 256, 32), 256, 0, s1>>>(pZ, ka, pE1);
    expandD_kernel<<<dim3(HID / 128, 32), DH, 0, s1>>>(pE1, kb, pIs, out);
    cudaEventRecord(evExp, s1);
    mma_gemm_kernel<<<dim3(HID / 128, TK / 128), 256>>>(pAfr, pBwo, out, pTop, nullptr, 0, nullptr, HID, HID);

    // ---- join ----
    cudaStreamWaitEvent(0, evExp, 0);
}